// round 1
// baseline (speedup 1.0000x reference)
#include <cuda_runtime.h>
#include <cuda_bf16.h>
#include <math.h>

// ---------------- problem constants ----------------
#define N_NODE 2000
#define NP     2048          // padded node dim (zero-filled cols 2000..2047)
#define BATCH  64
#define CC     64            // conv channels
#define MROWS  (BATCH*CC)    // 4096
#define DM     2048          // d_model
#define IN_D   7
#define KW     49
#define ND     40
#define ALPHA_C 0.05f
#define BETA_C  0.95f

// ---------------- scratch (device globals; no allocation allowed) ----------
__device__ float g_aT[N_NODE * NP];        // aT[w][v] = a[v][w], row-normalized adj
__device__ float g_H[4 * MROWS * NP];      // hops h0..h3, layout [hop][b*64+c][n]
__device__ float g_S[BATCH * NP];          // skip output s[b][n]
__device__ float g_Y[BATCH * DM];          // pre-layernorm y[b][d]

// ---------------- kernel 1: adjacency ----------------
// per row v: z = relu(E1[v] @ E2), softmax over w, a[v][w] = (sm + I)/2,
// stored transposed for the GEMM (B matrix, row-major [w][v]).
__global__ void k_adj(const float* __restrict__ E1, const float* __restrict__ E2) {
    int v = blockIdx.x;
    int tid = threadIdx.x;
    __shared__ float e1[ND];
    __shared__ float z[N_NODE];
    __shared__ float red[256];
    if (tid < ND) e1[tid] = E1[v * ND + tid];
    __syncthreads();

    float lmax = -1e30f;
    for (int w = tid; w < N_NODE; w += 256) {
        float acc = 0.f;
#pragma unroll
        for (int k = 0; k < ND; k++) acc += e1[k] * E2[k * N_NODE + w];
        acc = fmaxf(acc, 0.f);
        z[w] = acc;
        lmax = fmaxf(lmax, acc);
    }
    red[tid] = lmax; __syncthreads();
    for (int s = 128; s > 0; s >>= 1) { if (tid < s) red[tid] = fmaxf(red[tid], red[tid + s]); __syncthreads(); }
    float smax = red[0];
    __syncthreads();

    float lsum = 0.f;
    for (int w = tid; w < N_NODE; w += 256) { float e = expf(z[w] - smax); z[w] = e; lsum += e; }
    red[tid] = lsum; __syncthreads();
    for (int s = 128; s > 0; s >>= 1) { if (tid < s) red[tid] += red[tid + s]; __syncthreads(); }
    // softmax row sums to 1 => adj row sum == 2 exactly; a = (softmax + I)/2
    float inv = 0.5f / red[0];
    for (int w = tid; w < N_NODE; w += 256) {
        float val = z[w] * inv + ((w == v) ? 0.5f : 0.f);
        g_aT[(size_t)w * NP + v] = val;
    }
}

// zero pad columns v=2000..2047 of aT so padded-N GEMM computes zeros there
__global__ void k_padzero() {
    int w = blockIdx.x;
    int t = threadIdx.x;
    if (t < NP - N_NODE) g_aT[(size_t)w * NP + N_NODE + t] = 0.f;
}

// ---------------- kernel 2: start conv -> hop0 ----------------
// out[b,co,n] = sum_{ci,k} x[b, ci*2048 + n+k] * w[co,ci,k] + bias[co]
// block: (n-tile of 256, b). 256 thr = 32 n-lanes x 8 co-groups; 8co x 8n per thread.
__global__ __launch_bounds__(256) void k_conv(const float* __restrict__ x,
                                              const float* __restrict__ w,
                                              const float* __restrict__ bias) {
    extern __shared__ float sm[];
    float* ws = sm;                       // 64*343 = 21952 floats
    float* xs = sm + CC * IN_D * KW;      // 7*304  =  2128 floats
    int b  = blockIdx.y;
    int n0 = blockIdx.x * 256;
    int tid = threadIdx.x;
    int ng  = tid & 31;
    int cog = tid >> 5;

    for (int idx = tid; idx < CC * IN_D * KW; idx += 256) ws[idx] = w[idx];
    for (int idx = tid; idx < IN_D * 304; idx += 256) {
        int ci = idx / 304, p = idx % 304;
        int gp = n0 + p;
        xs[idx] = (gp < DM) ? x[(size_t)b * IN_D * DM + ci * DM + gp] : 0.f;
    }
    __syncthreads();

    float acc[8][8];
#pragma unroll
    for (int i = 0; i < 8; i++)
#pragma unroll
        for (int j = 0; j < 8; j++) acc[i][j] = 0.f;

    for (int ci = 0; ci < IN_D; ci++) {
        for (int k = 0; k < KW; k++) {
            float xv[8];
#pragma unroll
            for (int j = 0; j < 8; j++) xv[j] = xs[ci * 304 + ng + j * 32 + k];
#pragma unroll
            for (int i = 0; i < 8; i++) {
                float wv = ws[(cog * 8 + i) * (IN_D * KW) + ci * KW + k];
#pragma unroll
                for (int j = 0; j < 8; j++) acc[i][j] += wv * xv[j];
            }
        }
    }
#pragma unroll
    for (int i = 0; i < 8; i++) {
        int co = cog * 8 + i;
        float bb = bias[co];
        size_t row = (size_t)(b * CC + co) * NP;
#pragma unroll
        for (int j = 0; j < 8; j++) {
            int n = n0 + ng + j * 32;
            g_H[row + n] = (n < N_NODE) ? (acc[i][j] + bb) : 0.f;
        }
    }
}

// ---------------- kernel 3: mixprop GEMM ----------------
// h_dst = ALPHA * h0 + BETA * h_src @ aT     (M=4096, N=2048pad, K=2000)
__global__ __launch_bounds__(256) void k_mix(int src_hop, int dst_hop) {
    __shared__ float As[8][128];
    __shared__ float Bs[8][128];
    const float* A = g_H + (size_t)src_hop * MROWS * NP;
    const float* X = g_H;  // hop0
    float* C = g_H + (size_t)dst_hop * MROWS * NP;

    int tid = threadIdx.x;
    int tx = tid & 15, ty = tid >> 4;
    const int m0 = blockIdx.y * 128, n0 = blockIdx.x * 128;

    int a_m = tid >> 1;
    int a_k = (tid & 1) * 4;
    int b_k = tid >> 5;
    int b_n = (tid & 31) * 4;

    float acc[8][8];
#pragma unroll
    for (int i = 0; i < 8; i++)
#pragma unroll
        for (int j = 0; j < 8; j++) acc[i][j] = 0.f;

    const float* Aptr = A + (size_t)(m0 + a_m) * NP + a_k;
    const float* Bptr = g_aT + (size_t)b_k * NP + n0 + b_n;

    for (int kt = 0; kt < N_NODE; kt += 8) {
        float4 av = *(const float4*)Aptr; Aptr += 8;
        float4 bv = *(const float4*)Bptr; Bptr += 8 * NP;
        As[a_k + 0][a_m] = av.x;
        As[a_k + 1][a_m] = av.y;
        As[a_k + 2][a_m] = av.z;
        As[a_k + 3][a_m] = av.w;
        *(float4*)&Bs[b_k][b_n] = bv;
        __syncthreads();
#pragma unroll
        for (int ks = 0; ks < 8; ks++) {
            float a[8], bb[8];
            *(float4*)(a)      = *(const float4*)&As[ks][ty * 8];
            *(float4*)(a + 4)  = *(const float4*)&As[ks][ty * 8 + 4];
            *(float4*)(bb)     = *(const float4*)&Bs[ks][tx * 8];
            *(float4*)(bb + 4) = *(const float4*)&Bs[ks][tx * 8 + 4];
#pragma unroll
            for (int i = 0; i < 8; i++)
#pragma unroll
                for (int j = 0; j < 8; j++) acc[i][j] += a[i] * bb[j];
        }
        __syncthreads();
    }

#pragma unroll
    for (int i = 0; i < 8; i++) {
        int m = m0 + ty * 8 + i;
#pragma unroll
        for (int j = 0; j < 8; j += 4) {
            int n = n0 + tx * 8 + j;
            float4 xv = *(const float4*)(X + (size_t)m * NP + n);
            float4 o;
            o.x = ALPHA_C * xv.x + BETA_C * acc[i][j + 0];
            o.y = ALPHA_C * xv.y + BETA_C * acc[i][j + 1];
            o.z = ALPHA_C * xv.z + BETA_C * acc[i][j + 2];
            o.w = ALPHA_C * xv.w + BETA_C * acc[i][j + 3];
            *(float4*)(C + (size_t)m * NP + n) = o;
        }
    }
}

// ---------------- kernel 4: MLP(256->64) + GELU + end(64->1) ----------------
// block: (n-tile of 128, b). 256 thr = 32 n-lanes x 8 o-groups; 8o x 4n per thread.
__global__ __launch_bounds__(256) void k_mlp(const float* __restrict__ wmlp,
                                             const float* __restrict__ bmlp,
                                             const float* __restrict__ wend,
                                             const float* __restrict__ bend) {
    extern __shared__ float ws[];         // 64*256 floats = 64 KB
    __shared__ float red[8][128];
    int b  = blockIdx.y;
    int n0 = blockIdx.x * 128;
    int tid = threadIdx.x;
    int ng = tid & 31, og = tid >> 5;

    for (int idx = tid; idx < 64 * 256; idx += 256) ws[idx] = wmlp[idx];
    __syncthreads();

    float acc[8][4];
#pragma unroll
    for (int i = 0; i < 8; i++)
#pragma unroll
        for (int jj = 0; jj < 4; jj++) acc[i][jj] = 0.f;

    for (int jc = 0; jc < 256; jc++) {
        int j = jc >> 6, c = jc & 63;
        const float* hp = g_H + ((size_t)j * MROWS + b * CC + c) * NP + n0 + ng;
        float hv[4];
#pragma unroll
        for (int jj = 0; jj < 4; jj++) hv[jj] = hp[jj * 32];
#pragma unroll
        for (int i = 0; i < 8; i++) {
            float wv = ws[(og * 8 + i) * 256 + jc];
#pragma unroll
            for (int jj = 0; jj < 4; jj++) acc[i][jj] += wv * hv[jj];
        }
    }

    float part[4] = {0.f, 0.f, 0.f, 0.f};
#pragma unroll
    for (int i = 0; i < 8; i++) {
        int o = og * 8 + i;
        float bm = bmlp[o], we = wend[o];
#pragma unroll
        for (int jj = 0; jj < 4; jj++) {
            float v = acc[i][jj] + bm;
            float g = 0.5f * v * (1.f + erff(v * 0.70710678118654752f));  // exact gelu
            part[jj] += we * g;
        }
    }
#pragma unroll
    for (int jj = 0; jj < 4; jj++) red[og][ng + jj * 32] = part[jj];
    __syncthreads();
    if (og == 0) {
#pragma unroll
        for (int jj = 0; jj < 4; jj++) {
            int nl = ng + jj * 32;
            float s = bend[0];
#pragma unroll
            for (int g = 0; g < 8; g++) s += red[g][nl];
            int n = n0 + nl;
            if (n < N_NODE) g_S[(size_t)b * NP + n] = s;
        }
    }
}

// ---------------- kernel 5: final linear y = S @ w_lin^T + b_lin ----------------
// M=64 (batch), N=2048 (d), K=2000. block: 64 d-cols, 128 thr = 16 dg x 8 bg, 4d x 8b each.
__global__ __launch_bounds__(128) void k_lin(const float* __restrict__ wlin,
                                             const float* __restrict__ blin) {
    __shared__ float Ss[64][41];
    __shared__ float Ws[64][41];
    int d0 = blockIdx.x * 64;
    int tid = threadIdx.x;
    int dg = tid >> 3, bg = tid & 7;

    float acc[4][8];
#pragma unroll
    for (int i = 0; i < 4; i++)
#pragma unroll
        for (int j = 0; j < 8; j++) acc[i][j] = 0.f;

    for (int k0 = 0; k0 < N_NODE; k0 += 40) {
        for (int idx = tid; idx < 64 * 40; idx += 128) {
            int bb = idx / 40, kk = idx % 40;
            Ss[bb][kk] = g_S[(size_t)bb * NP + k0 + kk];
        }
        for (int idx = tid; idx < 64 * 40; idx += 128) {
            int dd = idx / 40, kk = idx % 40;
            Ws[dd][kk] = wlin[(size_t)(d0 + dd) * N_NODE + k0 + kk];
        }
        __syncthreads();
#pragma unroll 8
        for (int k = 0; k < 40; k++) {
            float wv[4];
#pragma unroll
            for (int i = 0; i < 4; i++) wv[i] = Ws[dg * 4 + i][k];
#pragma unroll
            for (int j = 0; j < 8; j++) {
                float sv = Ss[bg * 8 + j][k];
#pragma unroll
                for (int i = 0; i < 4; i++) acc[i][j] += wv[i] * sv;
            }
        }
        __syncthreads();
    }
#pragma unroll
    for (int i = 0; i < 4; i++) {
        int d = d0 + dg * 4 + i;
        float bl = blin[d];
#pragma unroll
        for (int j = 0; j < 8; j++) {
            int bb = bg * 8 + j;
            g_Y[(size_t)bb * DM + d] = acc[i][j] + bl;
        }
    }
}

// ---------------- kernel 6: layernorm ----------------
__global__ void k_ln(const float* __restrict__ gam, const float* __restrict__ bet,
                     float* __restrict__ out) {
    int b = blockIdx.x;
    int tid = threadIdx.x;
    __shared__ float red[256];
    const float* y = g_Y + (size_t)b * DM;

    float s = 0.f;
    for (int d = tid; d < DM; d += 256) s += y[d];
    red[tid] = s; __syncthreads();
    for (int st = 128; st > 0; st >>= 1) { if (tid < st) red[tid] += red[tid + st]; __syncthreads(); }
    float mu = red[0] / DM;
    __syncthreads();

    float v = 0.f;
    for (int d = tid; d < DM; d += 256) { float t = y[d] - mu; v += t * t; }
    red[tid] = v; __syncthreads();
    for (int st = 128; st > 0; st >>= 1) { if (tid < st) red[tid] += red[tid + st]; __syncthreads(); }
    float rinv = rsqrtf(red[0] / DM + 1e-5f);

    for (int d = tid; d < DM; d += 256)
        out[(size_t)b * DM + d] = (y[d] - mu) * rinv * gam[d] + bet[d];
}

// ---------------- launch ----------------
extern "C" void kernel_launch(void* const* d_in, const int* in_sizes, int n_in,
                              void* d_out, int out_size) {
    const float* x       = (const float*)d_in[0];
    const float* nv1     = (const float*)d_in[1];
    const float* nv2     = (const float*)d_in[2];
    const float* w_start = (const float*)d_in[3];
    const float* b_start = (const float*)d_in[4];
    const float* w_mlp   = (const float*)d_in[5];
    const float* b_mlp   = (const float*)d_in[6];
    const float* w_end   = (const float*)d_in[7];
    const float* b_end   = (const float*)d_in[8];
    const float* w_lin   = (const float*)d_in[9];
    const float* b_lin   = (const float*)d_in[10];
    const float* ln_g    = (const float*)d_in[11];
    const float* ln_b    = (const float*)d_in[12];
    float* out = (float*)d_out;

    const int conv_smem = (CC * IN_D * KW + IN_D * 304) * sizeof(float); // ~96.3 KB
    const int mlp_smem  = 64 * 256 * sizeof(float);                      // 64 KB
    cudaFuncSetAttribute(k_conv, cudaFuncAttributeMaxDynamicSharedMemorySize, conv_smem);
    cudaFuncSetAttribute(k_mlp,  cudaFuncAttributeMaxDynamicSharedMemorySize, mlp_smem);

    k_adj<<<N_NODE, 256>>>(nv1, nv2);
    k_padzero<<<N_NODE, 64>>>();
    k_conv<<<dim3(DM / 256, BATCH), 256, conv_smem>>>(x, w_start, b_start);
    k_mix<<<dim3(NP / 128, MROWS / 128), 256>>>(0, 1);
    k_mix<<<dim3(NP / 128, MROWS / 128), 256>>>(1, 2);
    k_mix<<<dim3(NP / 128, MROWS / 128), 256>>>(2, 3);
    k_mlp<<<dim3(NP / 128, BATCH), 256, mlp_smem>>>(w_mlp, b_mlp, w_end, b_end);
    k_lin<<<DM / 64, 128>>>(w_lin, b_lin);
    k_ln<<<BATCH, 256>>>(ln_g, ln_b, out);
}

// round 3
// speedup vs baseline: 1.6723x; 1.6723x over previous
#include <cuda_runtime.h>
#include <cuda_bf16.h>
#include <math.h>
#include <stdint.h>

// ---------------- problem constants ----------------
#define N_NODE 2000
#define NP     2048          // padded node dim
#define BATCH  64
#define CC     64
#define MROWS  (BATCH*CC)    // 4096
#define DM     2048
#define IN_D   7
#define KW     49
#define ND     40
#define ALPHA_C 0.05f
#define BETA_C  0.95f

// mix GEMM tiling
#define KC      64                    // k-chunk: 64 bf16 = 128B rows (SW128)
#define NCHUNK  (NP / KC)             // 32
#define TILE_M  128
#define TILE_N  128
#define VAR_BYTES (128 * 128)         // one 128-row x 128B tile = 16384 B
#define OFF_AHI 0
#define OFF_ALO (VAR_BYTES)
#define OFF_BHI (2 * VAR_BYTES)
#define OFF_BLO (3 * VAR_BYTES)
#define STAGE_BYTES (4 * VAR_BYTES)   // 65536
#define MIX_SMEM (2 * STAGE_BYTES)    // 131072

// ---------------- scratch ----------------
__device__ float          g_H[4 * MROWS * NP];     // fp32 hops
__device__ __nv_bfloat16  g_Ahi[4 * MROWS * NP];   // bf16 hi of hops
__device__ __nv_bfloat16  g_Alo[4 * MROWS * NP];   // bf16 lo of hops
__device__ __nv_bfloat16  g_Bhi[NP * NP];          // adjacency a[v][w] hi
__device__ __nv_bfloat16  g_Blo[NP * NP];          // adjacency a[v][w] lo
__device__ float          g_S[BATCH * NP];
__device__ float          g_Y[BATCH * DM];

// ---------------- helpers ----------------
__device__ __forceinline__ uint32_t smem_u32(const void* p) {
    uint32_t a;
    asm("{ .reg .u64 t; cvta.to.shared.u64 t, %1; cvt.u32.u64 %0, t; }" : "=r"(a) : "l"(p));
    return a;
}
__device__ __forceinline__ void cpa16(uint32_t s, const void* g) {
    asm volatile("cp.async.cg.shared.global [%0], [%1], 16;" :: "r"(s), "l"(g));
}
#define CPA_COMMIT() asm volatile("cp.async.commit_group;" ::: "memory")
#define CPA_WAIT(n)  asm volatile("cp.async.wait_group %0;" :: "n"(n) : "memory")

__device__ __forceinline__ void ldsm4(uint32_t* r, uint32_t addr) {
    asm volatile("ldmatrix.sync.aligned.m8n8.x4.shared.b16 {%0,%1,%2,%3}, [%4];"
                 : "=r"(r[0]), "=r"(r[1]), "=r"(r[2]), "=r"(r[3]) : "r"(addr));
}
__device__ __forceinline__ void mma16816(float* d, const uint32_t* a, const uint32_t* b) {
    asm volatile("mma.sync.aligned.m16n8k16.row.col.f32.bf16.bf16.f32 "
                 "{%0,%1,%2,%3}, {%4,%5,%6,%7}, {%8,%9}, {%0,%1,%2,%3};"
                 : "+f"(d[0]), "+f"(d[1]), "+f"(d[2]), "+f"(d[3])
                 : "r"(a[0]), "r"(a[1]), "r"(a[2]), "r"(a[3]), "r"(b[0]), "r"(b[1]));
}
__device__ __forceinline__ void bf16_split(float v, __nv_bfloat16& hi, __nv_bfloat16& lo) {
    hi = __float2bfloat16(v);
    lo = __float2bfloat16(v - __bfloat162float(hi));
}

// ---------------- kernel 1: adjacency -> bf16 hi/lo, a[v][w] K-major ----------------
__global__ void k_adj(const float* __restrict__ E1, const float* __restrict__ E2) {
    int v = blockIdx.x;
    int tid = threadIdx.x;
    if (v >= N_NODE) {
        for (int w = tid; w < NP; w += 256) {
            g_Bhi[(size_t)v * NP + w] = __float2bfloat16(0.f);
            g_Blo[(size_t)v * NP + w] = __float2bfloat16(0.f);
        }
        return;
    }
    __shared__ float e1[ND];
    __shared__ float z[N_NODE];
    __shared__ float red[256];
    if (tid < ND) e1[tid] = E1[v * ND + tid];
    __syncthreads();

    float lmax = -1e30f;
    for (int w = tid; w < N_NODE; w += 256) {
        float acc = 0.f;
#pragma unroll
        for (int k = 0; k < ND; k++) acc += e1[k] * E2[k * N_NODE + w];
        acc = fmaxf(acc, 0.f);
        z[w] = acc;
        lmax = fmaxf(lmax, acc);
    }
    red[tid] = lmax; __syncthreads();
    for (int s = 128; s > 0; s >>= 1) { if (tid < s) red[tid] = fmaxf(red[tid], red[tid + s]); __syncthreads(); }
    float smax = red[0];
    __syncthreads();

    float lsum = 0.f;
    for (int w = tid; w < N_NODE; w += 256) { float e = expf(z[w] - smax); z[w] = e; lsum += e; }
    red[tid] = lsum; __syncthreads();
    for (int s = 128; s > 0; s >>= 1) { if (tid < s) red[tid] += red[tid + s]; __syncthreads(); }
    float inv = 0.5f / red[0];   // a = (softmax + I)/2 (adj rows sum to exactly 2)
    for (int w = tid; w < NP; w += 256) {
        float val = (w < N_NODE) ? (z[w] * inv + ((w == v) ? 0.5f : 0.f)) : 0.f;
        __nv_bfloat16 h, l; bf16_split(val, h, l);
        g_Bhi[(size_t)v * NP + w] = h;
        g_Blo[(size_t)v * NP + w] = l;
    }
}

// ---------------- kernel 2: start conv -> hop0 (fp32 + bf16 hi/lo) ----------------
__global__ __launch_bounds__(256) void k_conv(const float* __restrict__ x,
                                              const float* __restrict__ w,
                                              const float* __restrict__ bias) {
    extern __shared__ float sm[];
    float* ws = sm;
    float* xs = sm + CC * IN_D * KW;
    int b  = blockIdx.y;
    int n0 = blockIdx.x * 256;
    int tid = threadIdx.x;
    int ng  = tid & 31;
    int cog = tid >> 5;

    for (int idx = tid; idx < CC * IN_D * KW; idx += 256) ws[idx] = w[idx];
    for (int idx = tid; idx < IN_D * 304; idx += 256) {
        int ci = idx / 304, p = idx % 304;
        int gp = n0 + p;
        xs[idx] = (gp < DM) ? x[(size_t)b * IN_D * DM + ci * DM + gp] : 0.f;
    }
    __syncthreads();

    float acc[8][8];
#pragma unroll
    for (int i = 0; i < 8; i++)
#pragma unroll
        for (int j = 0; j < 8; j++) acc[i][j] = 0.f;

    for (int ci = 0; ci < IN_D; ci++) {
        for (int k = 0; k < KW; k++) {
            float xv[8];
#pragma unroll
            for (int j = 0; j < 8; j++) xv[j] = xs[ci * 304 + ng + j * 32 + k];
#pragma unroll
            for (int i = 0; i < 8; i++) {
                float wv = ws[(cog * 8 + i) * (IN_D * KW) + ci * KW + k];
#pragma unroll
                for (int j = 0; j < 8; j++) acc[i][j] += wv * xv[j];
            }
        }
    }
#pragma unroll
    for (int i = 0; i < 8; i++) {
        int co = cog * 8 + i;
        float bb = bias[co];
        size_t row = (size_t)(b * CC + co) * NP;
#pragma unroll
        for (int j = 0; j < 8; j++) {
            int n = n0 + ng + j * 32;
            float v = (n < N_NODE) ? (acc[i][j] + bb) : 0.f;
            g_H[row + n] = v;
            __nv_bfloat16 h, l; bf16_split(v, h, l);
            g_Ahi[row + n] = h;
            g_Alo[row + n] = l;
        }
    }
}

// ---------------- kernel 3: mixprop GEMM on HMMA (mma.sync bf16, hi/lo split) -----
// D[m][v] = sum_w H_src[m][w] * a[v][w];  C = ALPHA*h0 + BETA*D
// CTA 128x128, K-chunks of 64, cp.async double buffer, SW128 xor swizzle.
// 8 warps in 2(m) x 4(n); warp tile 64x32.
__global__ __launch_bounds__(256) void k_mix_mma(int src, int dst, int wb) {
    extern __shared__ char smem[];
    const uint32_t sbase = smem_u32(smem);

    const int tid = threadIdx.x;
    const int wid = tid >> 5, lane = tid & 31;
    const int wm = wid >> 2;            // 0..1 -> m offset wm*64
    const int wn = wid & 3;             // 0..3 -> n offset wn*32
    const int m0 = blockIdx.y * TILE_M;
    const int n0 = blockIdx.x * TILE_N;

    const __nv_bfloat16* Ahi = g_Ahi + (size_t)src * MROWS * NP;
    const __nv_bfloat16* Alo = g_Alo + (size_t)src * MROWS * NP;

    // loader mapping: row = tid>>1 (0..127), 16B segs (tid&1)*4 .. +3
    const int lr = tid >> 1;
    const int ls = (tid & 1) * 4;
    const uint32_t lswz = (uint32_t)(lr & 7);
    const char* gAhi = (const char*)(Ahi + (size_t)(m0 + lr) * NP);
    const char* gAlo = (const char*)(Alo + (size_t)(m0 + lr) * NP);
    const char* gBhi = (const char*)(g_Bhi + (size_t)(n0 + lr) * NP);
    const char* gBlo = (const char*)(g_Blo + (size_t)(n0 + lr) * NP);

#define LOAD_CHUNK(cidx, buf) do {                                                   \
    uint32_t sb = sbase + (buf) * STAGE_BYTES + lr * 128;                            \
    size_t go = (size_t)(cidx) * 128 + ls * 16;                                      \
    _Pragma("unroll")                                                                \
    for (int j = 0; j < 4; j++) {                                                    \
        uint32_t so = ((uint32_t)(ls + j) ^ lswz) << 4;                              \
        cpa16(sb + OFF_AHI + so, gAhi + go + j * 16);                                \
        cpa16(sb + OFF_ALO + so, gAlo + go + j * 16);                                \
        cpa16(sb + OFF_BHI + so, gBhi + go + j * 16);                                \
        cpa16(sb + OFF_BLO + so, gBlo + go + j * 16);                                \
    }                                                                                \
} while (0)

    float acc[4][4][4];
#pragma unroll
    for (int im = 0; im < 4; im++)
#pragma unroll
        for (int in = 0; in < 4; in++)
#pragma unroll
            for (int q = 0; q < 4; q++) acc[im][in][q] = 0.f;

    // ldmatrix lane address components
    // A (m16k16, x4): row = im*16 + (lane&15), seg j = 2*ks + (lane>>4)
    const int a_row_l = (lane & 15);
    const int a_jl = lane >> 4;
    // B (two n8k16 frags, x4): nrow = inb*16 + (lane>>4)*8 + (lane&7), seg j = 2*ks + ((lane>>3)&1)
    const int b_row_l = ((lane >> 4) << 3) + (lane & 7);
    const int b_jl = (lane >> 3) & 1;

    LOAD_CHUNK(0, 0); CPA_COMMIT();

    for (int c = 0; c < NCHUNK; c++) {
        if (c + 1 < NCHUNK) {
            LOAD_CHUNK(c + 1, (c + 1) & 1); CPA_COMMIT();
            CPA_WAIT(1);
        } else {
            CPA_WAIT(0);
        }
        __syncthreads();

        uint32_t sb = sbase + (c & 1) * STAGE_BYTES;
#pragma unroll
        for (int ks = 0; ks < 4; ks++) {
            uint32_t ah[4][4], al[4][4], bh[2][4], bl[2][4];
#pragma unroll
            for (int im = 0; im < 4; im++) {
                int row = wm * 64 + im * 16 + a_row_l;
                uint32_t off = (uint32_t)row * 128 +
                               ((uint32_t)((2 * ks + a_jl) ^ (row & 7)) << 4);
                ldsm4(ah[im], sb + OFF_AHI + off);
                ldsm4(al[im], sb + OFF_ALO + off);
            }
#pragma unroll
            for (int inb = 0; inb < 2; inb++) {
                int row = wn * 32 + inb * 16 + b_row_l;
                uint32_t off = (uint32_t)row * 128 +
                               ((uint32_t)((2 * ks + b_jl) ^ (row & 7)) << 4);
                ldsm4(bh[inb], sb + OFF_BHI + off);
                ldsm4(bl[inb], sb + OFF_BLO + off);
            }
#pragma unroll
            for (int im = 0; im < 4; im++) {
#pragma unroll
                for (int in = 0; in < 4; in++) {
                    const uint32_t* bhf = &bh[in >> 1][(in & 1) * 2];
                    const uint32_t* blf = &bl[in >> 1][(in & 1) * 2];
                    mma16816(acc[im][in], ah[im], bhf);
                    mma16816(acc[im][in], ah[im], blf);
                    mma16816(acc[im][in], al[im], bhf);
                }
            }
        }
        __syncthreads();
    }

    // epilogue: fuse C = ALPHA*h0 + BETA*acc, emit fp32 + bf16 hi/lo
    const float* X = g_H;                                    // hop0
    float* C = g_H + (size_t)dst * MROWS * NP;
    __nv_bfloat16* Hh = g_Ahi + (size_t)dst * MROWS * NP;
    __nv_bfloat16* Hl = g_Alo + (size_t)dst * MROWS * NP;

#pragma unroll
    for (int im = 0; im < 4; im++) {
#pragma unroll
        for (int half = 0; half < 2; half++) {
            int m = m0 + wm * 64 + im * 16 + (lane >> 2) + half * 8;
            size_t rowo = (size_t)m * NP;
#pragma unroll
            for (int in = 0; in < 4; in++) {
                int n = n0 + wn * 32 + in * 8 + (lane & 3) * 2;
                float d0 = acc[im][in][half * 2 + 0];
                float d1 = acc[im][in][half * 2 + 1];
                float2 xv = *(const float2*)(X + rowo + n);
                float o0 = ALPHA_C * xv.x + BETA_C * d0;
                float o1 = ALPHA_C * xv.y + BETA_C * d1;
                *(float2*)(C + rowo + n) = make_float2(o0, o1);
                if (wb) {
                    __nv_bfloat16 h0, l0, h1, l1;
                    bf16_split(o0, h0, l0); bf16_split(o1, h1, l1);
                    *(__nv_bfloat162*)(Hh + rowo + n) = __nv_bfloat162(h0, h1);
                    *(__nv_bfloat162*)(Hl + rowo + n) = __nv_bfloat162(l0, l1);
                }
            }
        }
    }
#undef LOAD_CHUNK
}

// ---------------- kernel 4: MLP(256->64) + GELU + end(64->1) ----------------
__global__ __launch_bounds__(256) void k_mlp(const float* __restrict__ wmlp,
                                             const float* __restrict__ bmlp,
                                             const float* __restrict__ wend,
                                             const float* __restrict__ bend) {
    extern __shared__ float ws[];
    __shared__ float red[8][128];
    int b  = blockIdx.y;
    int n0 = blockIdx.x * 128;
    int tid = threadIdx.x;
    int ng = tid & 31, og = tid >> 5;

    for (int idx = tid; idx < 64 * 256; idx += 256) ws[idx] = wmlp[idx];
    __syncthreads();

    float acc[8][4];
#pragma unroll
    for (int i = 0; i < 8; i++)
#pragma unroll
        for (int jj = 0; jj < 4; jj++) acc[i][jj] = 0.f;

    for (int jc = 0; jc < 256; jc++) {
        int j = jc >> 6, c = jc & 63;
        const float* hp = g_H + ((size_t)j * MROWS + b * CC + c) * NP + n0 + ng;
        float hv[4];
#pragma unroll
        for (int jj = 0; jj < 4; jj++) hv[jj] = hp[jj * 32];
#pragma unroll
        for (int i = 0; i < 8; i++) {
            float wv = ws[(og * 8 + i) * 256 + jc];
#pragma unroll
            for (int jj = 0; jj < 4; jj++) acc[i][jj] += wv * hv[jj];
        }
    }

    float part[4] = {0.f, 0.f, 0.f, 0.f};
#pragma unroll
    for (int i = 0; i < 8; i++) {
        int o = og * 8 + i;
        float bm = bmlp[o], we = wend[o];
#pragma unroll
        for (int jj = 0; jj < 4; jj++) {
            float v = acc[i][jj] + bm;
            float g = 0.5f * v * (1.f + erff(v * 0.70710678118654752f));
            part[jj] += we * g;
        }
    }
#pragma unroll
    for (int jj = 0; jj < 4; jj++) red[og][ng + jj * 32] = part[jj];
    __syncthreads();
    if (og == 0) {
#pragma unroll
        for (int jj = 0; jj < 4; jj++) {
            int nl = ng + jj * 32;
            float s = bend[0];
#pragma unroll
            for (int g = 0; g < 8; g++) s += red[g][nl];
            int n = n0 + nl;
            if (n < N_NODE) g_S[(size_t)b * NP + n] = s;
        }
    }
}

// ---------------- kernel 5: final linear ----------------
__global__ __launch_bounds__(128) void k_lin(const float* __restrict__ wlin,
                                             const float* __restrict__ blin) {
    __shared__ float Ss[64][41];
    __shared__ float Ws[64][41];
    int d0 = blockIdx.x * 64;
    int tid = threadIdx.x;
    int dg = tid >> 3, bg = tid & 7;

    float acc[4][8];
#pragma unroll
    for (int i = 0; i < 4; i++)
#pragma unroll
        for (int j = 0; j < 8; j++) acc[i][j] = 0.f;

    for (int k0 = 0; k0 < N_NODE; k0 += 40) {
        for (int idx = tid; idx < 64 * 40; idx += 128) {
            int bb = idx / 40, kk = idx % 40;
            Ss[bb][kk] = g_S[(size_t)bb * NP + k0 + kk];
        }
        for (int idx = tid; idx < 64 * 40; idx += 128) {
            int dd = idx / 40, kk = idx % 40;
            Ws[dd][kk] = wlin[(size_t)(d0 + dd) * N_NODE + k0 + kk];
        }
        __syncthreads();
#pragma unroll 8
        for (int k = 0; k < 40; k++) {
            float wv[4];
#pragma unroll
            for (int i = 0; i < 4; i++) wv[i] = Ws[dg * 4 + i][k];
#pragma unroll
            for (int j = 0; j < 8; j++) {
                float sv = Ss[bg * 8 + j][k];
#pragma unroll
                for (int i = 0; i < 4; i++) acc[i][j] += wv[i] * sv;
            }
        }
        __syncthreads();
    }
#pragma unroll
    for (int i = 0; i < 4; i++) {
        int d = d0 + dg * 4 + i;
        float bl = blin[d];
#pragma unroll
        for (int j = 0; j < 8; j++) {
            int bb = bg * 8 + j;
            g_Y[(size_t)bb * DM + d] = acc[i][j] + bl;
        }
    }
}

// ---------------- kernel 6: layernorm ----------------
__global__ void k_ln(const float* __restrict__ gam, const float* __restrict__ bet,
                     float* __restrict__ out) {
    int b = blockIdx.x;
    int tid = threadIdx.x;
    __shared__ float red[256];
    const float* y = g_Y + (size_t)b * DM;

    float s = 0.f;
    for (int d = tid; d < DM; d += 256) s += y[d];
    red[tid] = s; __syncthreads();
    for (int st = 128; st > 0; st >>= 1) { if (tid < st) red[tid] += red[tid + st]; __syncthreads(); }
    float mu = red[0] / DM;
    __syncthreads();

    float v = 0.f;
    for (int d = tid; d < DM; d += 256) { float t = y[d] - mu; v += t * t; }
    red[tid] = v; __syncthreads();
    for (int st = 128; st > 0; st >>= 1) { if (tid < st) red[tid] += red[tid + st]; __syncthreads(); }
    float rinv = rsqrtf(red[0] / DM + 1e-5f);

    for (int d = tid; d < DM; d += 256)
        out[(size_t)b * DM + d] = (y[d] - mu) * rinv * gam[d] + bet[d];
}

// ---------------- launch ----------------
extern "C" void kernel_launch(void* const* d_in, const int* in_sizes, int n_in,
                              void* d_out, int out_size) {
    const float* x       = (const float*)d_in[0];
    const float* nv1     = (const float*)d_in[1];
    const float* nv2     = (const float*)d_in[2];
    const float* w_start = (const float*)d_in[3];
    const float* b_start = (const float*)d_in[4];
    const float* w_mlp   = (const float*)d_in[5];
    const float* b_mlp   = (const float*)d_in[6];
    const float* w_end   = (const float*)d_in[7];
    const float* b_end   = (const float*)d_in[8];
    const float* w_lin   = (const float*)d_in[9];
    const float* b_lin   = (const float*)d_in[10];
    const float* ln_g    = (const float*)d_in[11];
    const float* ln_b    = (const float*)d_in[12];
    float* out = (float*)d_out;

    const int conv_smem = (CC * IN_D * KW + IN_D * 304) * sizeof(float);
    const int mlp_smem  = 64 * 256 * sizeof(float);
    cudaFuncSetAttribute(k_conv,    cudaFuncAttributeMaxDynamicSharedMemorySize, conv_smem);
    cudaFuncSetAttribute(k_mlp,     cudaFuncAttributeMaxDynamicSharedMemorySize, mlp_smem);
    cudaFuncSetAttribute(k_mix_mma, cudaFuncAttributeMaxDynamicSharedMemorySize, MIX_SMEM);

    k_adj<<<NP, 256>>>(nv1, nv2);
    k_conv<<<dim3(DM / 256, BATCH), 256, conv_smem>>>(x, w_start, b_start);
    dim3 mixg(NP / TILE_N, MROWS / TILE_M);
    k_mix_mma<<<mixg, 256, MIX_SMEM>>>(0, 1, 1);
    k_mix_mma<<<mixg, 256, MIX_SMEM>>>(1, 2, 1);
    k_mix_mma<<<mixg, 256, MIX_SMEM>>>(2, 3, 0);
    k_mlp<<<dim3(NP / 128, BATCH), 256, mlp_smem>>>(w_mlp, b_mlp, w_end, b_end);
    k_lin<<<DM / 64, 128>>>(w_lin, b_lin);
    k_ln<<<BATCH, 256>>>(ln_g, ln_b, out);
}

// round 4
// speedup vs baseline: 1.6748x; 1.0015x over previous
#include <cuda_runtime.h>
#include <cuda_bf16.h>
#include <math.h>
#include <stdint.h>

// ---------------- problem constants ----------------
#define N_NODE 2000
#define NP     2048          // padded node dim
#define BATCH  64
#define CC     64
#define MROWS  (BATCH*CC)    // 4096
#define DM     2048
#define IN_D   7
#define KW     49
#define ND     40
#define ALPHA_C 0.05f
#define BETA_C  0.95f

// mix GEMM tiling
#define KC      64                    // k-chunk: 64 bf16 = 128B rows (SW128)
#define NCHUNK  (NP / KC)             // 32
#define TILE_M  128
#define TILE_N  128
#define VAR_BYTES (128 * 128)         // one 128-row x 128B tile = 16384 B
#define OFF_AHI 0
#define OFF_ALO (VAR_BYTES)
#define OFF_BHI (2 * VAR_BYTES)
#define OFF_BLO (3 * VAR_BYTES)
#define STAGE_BYTES (4 * VAR_BYTES)   // 65536
#define NSTAGE  3
#define MIX_SMEM (NSTAGE * STAGE_BYTES)  // 196608

// ---------------- scratch ----------------
__device__ float          g_H[4 * MROWS * NP];     // fp32 hops
__device__ __nv_bfloat16  g_Ahi[4 * MROWS * NP];   // bf16 hi of hops
__device__ __nv_bfloat16  g_Alo[4 * MROWS * NP];   // bf16 lo of hops
__device__ __nv_bfloat16  g_Bhi[NP * NP];          // adjacency a[v][w] hi
__device__ __nv_bfloat16  g_Blo[NP * NP];          // adjacency a[v][w] lo
__device__ float          g_S[BATCH * NP];
__device__ float          g_Y[BATCH * DM];

// ---------------- helpers ----------------
__device__ __forceinline__ uint32_t smem_u32(const void* p) {
    uint32_t a;
    asm("{ .reg .u64 t; cvta.to.shared.u64 t, %1; cvt.u32.u64 %0, t; }" : "=r"(a) : "l"(p));
    return a;
}
__device__ __forceinline__ void cpa16(uint32_t s, const void* g) {
    asm volatile("cp.async.cg.shared.global [%0], [%1], 16;" :: "r"(s), "l"(g));
}
#define CPA_COMMIT() asm volatile("cp.async.commit_group;" ::: "memory")
#define CPA_WAIT(n)  asm volatile("cp.async.wait_group %0;" :: "n"(n) : "memory")

__device__ __forceinline__ void ldsm4(uint32_t* r, uint32_t addr) {
    asm volatile("ldmatrix.sync.aligned.m8n8.x4.shared.b16 {%0,%1,%2,%3}, [%4];"
                 : "=r"(r[0]), "=r"(r[1]), "=r"(r[2]), "=r"(r[3]) : "r"(addr));
}
__device__ __forceinline__ void mma16816(float* d, const uint32_t* a, const uint32_t* b) {
    asm volatile("mma.sync.aligned.m16n8k16.row.col.f32.bf16.bf16.f32 "
                 "{%0,%1,%2,%3}, {%4,%5,%6,%7}, {%8,%9}, {%0,%1,%2,%3};"
                 : "+f"(d[0]), "+f"(d[1]), "+f"(d[2]), "+f"(d[3])
                 : "r"(a[0]), "r"(a[1]), "r"(a[2]), "r"(a[3]), "r"(b[0]), "r"(b[1]));
}
__device__ __forceinline__ void bf16_split(float v, __nv_bfloat16& hi, __nv_bfloat16& lo) {
    hi = __float2bfloat16(v);
    lo = __float2bfloat16(v - __bfloat162float(hi));
}

// ---------------- kernel 1: adjacency -> bf16 hi/lo, a[v][w] K-major ----------------
__global__ void k_adj(const float* __restrict__ E1, const float* __restrict__ E2) {
    int v = blockIdx.x;
    int tid = threadIdx.x;
    if (v >= N_NODE) {
        for (int w = tid; w < NP; w += 256) {
            g_Bhi[(size_t)v * NP + w] = __float2bfloat16(0.f);
            g_Blo[(size_t)v * NP + w] = __float2bfloat16(0.f);
        }
        return;
    }
    __shared__ float e1[ND];
    __shared__ float z[N_NODE];
    __shared__ float red[256];
    if (tid < ND) e1[tid] = E1[v * ND + tid];
    __syncthreads();

    float lmax = -1e30f;
    for (int w = tid; w < N_NODE; w += 256) {
        float acc = 0.f;
#pragma unroll
        for (int k = 0; k < ND; k++) acc += e1[k] * E2[k * N_NODE + w];
        acc = fmaxf(acc, 0.f);
        z[w] = acc;
        lmax = fmaxf(lmax, acc);
    }
    red[tid] = lmax; __syncthreads();
    for (int s = 128; s > 0; s >>= 1) { if (tid < s) red[tid] = fmaxf(red[tid], red[tid + s]); __syncthreads(); }
    float smax = red[0];
    __syncthreads();

    float lsum = 0.f;
    for (int w = tid; w < N_NODE; w += 256) { float e = expf(z[w] - smax); z[w] = e; lsum += e; }
    red[tid] = lsum; __syncthreads();
    for (int s = 128; s > 0; s >>= 1) { if (tid < s) red[tid] += red[tid + s]; __syncthreads(); }
    float inv = 0.5f / red[0];   // a = (softmax + I)/2 (adj rows sum to exactly 2)
    for (int w = tid; w < NP; w += 256) {
        float val = (w < N_NODE) ? (z[w] * inv + ((w == v) ? 0.5f : 0.f)) : 0.f;
        __nv_bfloat16 h, l; bf16_split(val, h, l);
        g_Bhi[(size_t)v * NP + w] = h;
        g_Blo[(size_t)v * NP + w] = l;
    }
}

// ---------------- kernel 2: start conv -> hop0 (fp32 + bf16 hi/lo) ----------------
__global__ __launch_bounds__(256) void k_conv(const float* __restrict__ x,
                                              const float* __restrict__ w,
                                              const float* __restrict__ bias) {
    extern __shared__ float sm[];
    float* ws = sm;
    float* xs = sm + CC * IN_D * KW;
    int b  = blockIdx.y;
    int n0 = blockIdx.x * 256;
    int tid = threadIdx.x;
    int ng  = tid & 31;
    int cog = tid >> 5;

    for (int idx = tid; idx < CC * IN_D * KW; idx += 256) ws[idx] = w[idx];
    for (int idx = tid; idx < IN_D * 304; idx += 256) {
        int ci = idx / 304, p = idx % 304;
        int gp = n0 + p;
        xs[idx] = (gp < DM) ? x[(size_t)b * IN_D * DM + ci * DM + gp] : 0.f;
    }
    __syncthreads();

    float acc[8][8];
#pragma unroll
    for (int i = 0; i < 8; i++)
#pragma unroll
        for (int j = 0; j < 8; j++) acc[i][j] = 0.f;

    for (int ci = 0; ci < IN_D; ci++) {
        for (int k = 0; k < KW; k++) {
            float xv[8];
#pragma unroll
            for (int j = 0; j < 8; j++) xv[j] = xs[ci * 304 + ng + j * 32 + k];
#pragma unroll
            for (int i = 0; i < 8; i++) {
                float wv = ws[(cog * 8 + i) * (IN_D * KW) + ci * KW + k];
#pragma unroll
                for (int j = 0; j < 8; j++) acc[i][j] += wv * xv[j];
            }
        }
    }
#pragma unroll
    for (int i = 0; i < 8; i++) {
        int co = cog * 8 + i;
        float bb = bias[co];
        size_t row = (size_t)(b * CC + co) * NP;
#pragma unroll
        for (int j = 0; j < 8; j++) {
            int n = n0 + ng + j * 32;
            float v = (n < N_NODE) ? (acc[i][j] + bb) : 0.f;
            g_H[row + n] = v;
            __nv_bfloat16 h, l; bf16_split(v, h, l);
            g_Ahi[row + n] = h;
            g_Alo[row + n] = l;
        }
    }
}

// ---------------- kernel 3: mixprop GEMM on HMMA (mma.sync bf16, hi/lo split) -----
// D[m][v] = sum_w H_src[m][w] * a[v][w];  C = ALPHA*h0 + BETA*D
// CTA 128x128, K-chunks of 64, 3-stage cp.async pipeline, SW128 xor swizzle.
// 8 warps in 2(m) x 4(n); warp tile 64x32. Products ordered outermost so each
// accumulator is revisited at distance 16 independent MMAs (no RAW stalls).
__global__ __launch_bounds__(256) void k_mix_mma(int src, int dst, int wb) {
    extern __shared__ char smem[];
    const uint32_t sbase = smem_u32(smem);

    const int tid = threadIdx.x;
    const int wid = tid >> 5, lane = tid & 31;
    const int wm = wid >> 2;            // 0..1 -> m offset wm*64
    const int wn = wid & 3;             // 0..3 -> n offset wn*32
    const int m0 = blockIdx.y * TILE_M;
    const int n0 = blockIdx.x * TILE_N;

    const __nv_bfloat16* Ahi = g_Ahi + (size_t)src * MROWS * NP;
    const __nv_bfloat16* Alo = g_Alo + (size_t)src * MROWS * NP;

    // loader mapping: row = tid>>1 (0..127), 16B segs (tid&1)*4 .. +3
    const int lr = tid >> 1;
    const int ls = (tid & 1) * 4;
    const uint32_t lswz = (uint32_t)(lr & 7);
    const char* gAhi = (const char*)(Ahi + (size_t)(m0 + lr) * NP);
    const char* gAlo = (const char*)(Alo + (size_t)(m0 + lr) * NP);
    const char* gBhi = (const char*)(g_Bhi + (size_t)(n0 + lr) * NP);
    const char* gBlo = (const char*)(g_Blo + (size_t)(n0 + lr) * NP);

#define LOAD_CHUNK(cidx, buf) do {                                                   \
    uint32_t sb = sbase + (buf) * STAGE_BYTES + lr * 128;                            \
    size_t go = (size_t)(cidx) * 128 + ls * 16;                                      \
    _Pragma("unroll")                                                                \
    for (int j = 0; j < 4; j++) {                                                    \
        uint32_t so = ((uint32_t)(ls + j) ^ lswz) << 4;                              \
        cpa16(sb + OFF_AHI + so, gAhi + go + j * 16);                                \
        cpa16(sb + OFF_ALO + so, gAlo + go + j * 16);                                \
        cpa16(sb + OFF_BHI + so, gBhi + go + j * 16);                                \
        cpa16(sb + OFF_BLO + so, gBlo + go + j * 16);                                \
    }                                                                                \
} while (0)

    float acc[4][4][4];
#pragma unroll
    for (int im = 0; im < 4; im++)
#pragma unroll
        for (int in = 0; in < 4; in++)
#pragma unroll
            for (int q = 0; q < 4; q++) acc[im][in][q] = 0.f;

    // ldmatrix lane address components
    const int a_row_l = (lane & 15);
    const int a_jl = lane >> 4;
    const int b_row_l = ((lane >> 4) << 3) + (lane & 7);
    const int b_jl = (lane >> 3) & 1;

    // prologue: preload chunks 0 and 1 into stages 0 and 1
    LOAD_CHUNK(0, 0); CPA_COMMIT();
    LOAD_CHUNK(1, 1); CPA_COMMIT();

    int buf = 0;        // stage of chunk c
    int nbuf = 2;       // stage that chunk c+2 will be written to
    for (int c = 0; c < NCHUNK; c++) {
        // wait until chunk c resident (allow the younger group(s) in flight)
        if (c + 1 < NCHUNK) { CPA_WAIT(1); } else { CPA_WAIT(0); }
        __syncthreads();   // chunk c visible to all; all warps done reading stage nbuf (chunk c-1 epoch)
        if (c + 2 < NCHUNK) { LOAD_CHUNK(c + 2, nbuf); CPA_COMMIT(); }

        uint32_t sb = sbase + buf * STAGE_BYTES;
#pragma unroll
        for (int ks = 0; ks < 4; ks++) {
            uint32_t ah[4][4], al[4][4], bh[2][4], bl[2][4];
#pragma unroll
            for (int im = 0; im < 4; im++) {
                int row = wm * 64 + im * 16 + a_row_l;
                uint32_t off = (uint32_t)row * 128 +
                               ((uint32_t)((2 * ks + a_jl) ^ (row & 7)) << 4);
                ldsm4(ah[im], sb + OFF_AHI + off);
                ldsm4(al[im], sb + OFF_ALO + off);
            }
#pragma unroll
            for (int inb = 0; inb < 2; inb++) {
                int row = wn * 32 + inb * 16 + b_row_l;
                uint32_t off = (uint32_t)row * 128 +
                               ((uint32_t)((2 * ks + b_jl) ^ (row & 7)) << 4);
                ldsm4(bh[inb], sb + OFF_BHI + off);
                ldsm4(bl[inb], sb + OFF_BLO + off);
            }
            // product-outermost: 16 independent MMAs between touches of same acc
#pragma unroll
            for (int p = 0; p < 3; p++) {
#pragma unroll
                for (int im = 0; im < 4; im++) {
#pragma unroll
                    for (int in = 0; in < 4; in++) {
                        const uint32_t* af = (p == 2) ? al[im] : ah[im];
                        const uint32_t* bf = (p == 1) ? &bl[in >> 1][(in & 1) * 2]
                                                      : &bh[in >> 1][(in & 1) * 2];
                        mma16816(acc[im][in], af, bf);
                    }
                }
            }
        }
        buf = (buf == NSTAGE - 1) ? 0 : buf + 1;
        nbuf = (nbuf == NSTAGE - 1) ? 0 : nbuf + 1;
    }

    // epilogue: fuse C = ALPHA*h0 + BETA*acc, emit fp32 + bf16 hi/lo
    const float* X = g_H;                                    // hop0
    float* C = g_H + (size_t)dst * MROWS * NP;
    __nv_bfloat16* Hh = g_Ahi + (size_t)dst * MROWS * NP;
    __nv_bfloat16* Hl = g_Alo + (size_t)dst * MROWS * NP;

#pragma unroll
    for (int im = 0; im < 4; im++) {
#pragma unroll
        for (int half = 0; half < 2; half++) {
            int m = m0 + wm * 64 + im * 16 + (lane >> 2) + half * 8;
            size_t rowo = (size_t)m * NP;
#pragma unroll
            for (int in = 0; in < 4; in++) {
                int n = n0 + wn * 32 + in * 8 + (lane & 3) * 2;
                float d0 = acc[im][in][half * 2 + 0];
                float d1 = acc[im][in][half * 2 + 1];
                float2 xv = *(const float2*)(X + rowo + n);
                float o0 = ALPHA_C * xv.x + BETA_C * d0;
                float o1 = ALPHA_C * xv.y + BETA_C * d1;
                *(float2*)(C + rowo + n) = make_float2(o0, o1);
                if (wb) {
                    __nv_bfloat16 h0, l0, h1, l1;
                    bf16_split(o0, h0, l0); bf16_split(o1, h1, l1);
                    *(__nv_bfloat162*)(Hh + rowo + n) = __nv_bfloat162(h0, h1);
                    *(__nv_bfloat162*)(Hl + rowo + n) = __nv_bfloat162(l0, l1);
                }
            }
        }
    }
#undef LOAD_CHUNK
}

// ---------------- kernel 4: MLP(256->64) + GELU + end(64->1) ----------------
__global__ __launch_bounds__(256) void k_mlp(const float* __restrict__ wmlp,
                                             const float* __restrict__ bmlp,
                                             const float* __restrict__ wend,
                                             const float* __restrict__ bend) {
    extern __shared__ float ws[];
    __shared__ float red[8][128];
    int b  = blockIdx.y;
    int n0 = blockIdx.x * 128;
    int tid = threadIdx.x;
    int ng = tid & 31, og = tid >> 5;

    for (int idx = tid; idx < 64 * 256; idx += 256) ws[idx] = wmlp[idx];
    __syncthreads();

    float acc[8][4];
#pragma unroll
    for (int i = 0; i < 8; i++)
#pragma unroll
        for (int jj = 0; jj < 4; jj++) acc[i][jj] = 0.f;

    for (int jc = 0; jc < 256; jc++) {
        int j = jc >> 6, c = jc & 63;
        const float* hp = g_H + ((size_t)j * MROWS + b * CC + c) * NP + n0 + ng;
        float hv[4];
#pragma unroll
        for (int jj = 0; jj < 4; jj++) hv[jj] = hp[jj * 32];
#pragma unroll
        for (int i = 0; i < 8; i++) {
            float wv = ws[(og * 8 + i) * 256 + jc];
#pragma unroll
            for (int jj = 0; jj < 4; jj++) acc[i][jj] += wv * hv[jj];
        }
    }

    float part[4] = {0.f, 0.f, 0.f, 0.f};
#pragma unroll
    for (int i = 0; i < 8; i++) {
        int o = og * 8 + i;
        float bm = bmlp[o], we = wend[o];
#pragma unroll
        for (int jj = 0; jj < 4; jj++) {
            float v = acc[i][jj] + bm;
            float g = 0.5f * v * (1.f + erff(v * 0.70710678118654752f));
            part[jj] += we * g;
        }
    }
#pragma unroll
    for (int jj = 0; jj < 4; jj++) red[og][ng + jj * 32] = part[jj];
    __syncthreads();
    if (og == 0) {
#pragma unroll
        for (int jj = 0; jj < 4; jj++) {
            int nl = ng + jj * 32;
            float s = bend[0];
#pragma unroll
            for (int g = 0; g < 8; g++) s += red[g][nl];
            int n = n0 + nl;
            if (n < N_NODE) g_S[(size_t)b * NP + n] = s;
        }
    }
}

// ---------------- kernel 5: final linear ----------------
__global__ __launch_bounds__(128) void k_lin(const float* __restrict__ wlin,
                                             const float* __restrict__ blin) {
    __shared__ float Ss[64][41];
    __shared__ float Ws[64][41];
    int d0 = blockIdx.x * 64;
    int tid = threadIdx.x;
    int dg = tid >> 3, bg = tid & 7;

    float acc[4][8];
#pragma unroll
    for (int i = 0; i < 4; i++)
#pragma unroll
        for (int j = 0; j < 8; j++) acc[i][j] = 0.f;

    for (int k0 = 0; k0 < N_NODE; k0 += 40) {
        for (int idx = tid; idx < 64 * 40; idx += 128) {
            int bb = idx / 40, kk = idx % 40;
            Ss[bb][kk] = g_S[(size_t)bb * NP + k0 + kk];
        }
        for (int idx = tid; idx < 64 * 40; idx += 128) {
            int dd = idx / 40, kk = idx % 40;
            Ws[dd][kk] = wlin[(size_t)(d0 + dd) * N_NODE + k0 + kk];
        }
        __syncthreads();
#pragma unroll 8
        for (int k = 0; k < 40; k++) {
            float wv[4];
#pragma unroll
            for (int i = 0; i < 4; i++) wv[i] = Ws[dg * 4 + i][k];
#pragma unroll
            for (int j = 0; j < 8; j++) {
                float sv = Ss[bg * 8 + j][k];
#pragma unroll
                for (int i = 0; i < 4; i++) acc[i][j] += wv[i] * sv;
            }
        }
        __syncthreads();
    }
#pragma unroll
    for (int i = 0; i < 4; i++) {
        int d = d0 + dg * 4 + i;
        float bl = blin[d];
#pragma unroll
        for (int j = 0; j < 8; j++) {
            int bb = bg * 8 + j;
            g_Y[(size_t)bb * DM + d] = acc[i][j] + bl;
        }
    }
}

// ---------------- kernel 6: layernorm ----------------
__global__ void k_ln(const float* __restrict__ gam, const float* __restrict__ bet,
                     float* __restrict__ out) {
    int b = blockIdx.x;
    int tid = threadIdx.x;
    __shared__ float red[256];
    const float* y = g_Y + (size_t)b * DM;

    float s = 0.f;
    for (int d = tid; d < DM; d += 256) s += y[d];
    red[tid] = s; __syncthreads();
    for (int st = 128; st > 0; st >>= 1) { if (tid < st) red[tid] += red[tid + st]; __syncthreads(); }
    float mu = red[0] / DM;
    __syncthreads();

    float v = 0.f;
    for (int d = tid; d < DM; d += 256) { float t = y[d] - mu; v += t * t; }
    red[tid] = v; __syncthreads();
    for (int st = 128; st > 0; st >>= 1) { if (tid < st) red[tid] += red[tid + st]; __syncthreads(); }
    float rinv = rsqrtf(red[0] / DM + 1e-5f);

    for (int d = tid; d < DM; d += 256)
        out[(size_t)b * DM + d] = (y[d] - mu) * rinv * gam[d] + bet[d];
}

// ---------------- launch ----------------
extern "C" void kernel_launch(void* const* d_in, const int* in_sizes, int n_in,
                              void* d_out, int out_size) {
    const float* x       = (const float*)d_in[0];
    const float* nv1     = (const float*)d_in[1];
    const float* nv2     = (const float*)d_in[2];
    const float* w_start = (const float*)d_in[3];
    const float* b_start = (const float*)d_in[4];
    const float* w_mlp   = (const float*)d_in[5];
    const float* b_mlp   = (const float*)d_in[6];
    const float* w_end   = (const float*)d_in[7];
    const float* b_end   = (const float*)d_in[8];
    const float* w_lin   = (const float*)d_in[9];
    const float* b_lin   = (const float*)d_in[10];
    const float* ln_g    = (const float*)d_in[11];
    const float* ln_b    = (const float*)d_in[12];
    float* out = (float*)d_out;

    const int conv_smem = (CC * IN_D * KW + IN_D * 304) * sizeof(float);
    const int mlp_smem  = 64 * 256 * sizeof(float);
    cudaFuncSetAttribute(k_conv,    cudaFuncAttributeMaxDynamicSharedMemorySize, conv_smem);
    cudaFuncSetAttribute(k_mlp,     cudaFuncAttributeMaxDynamicSharedMemorySize, mlp_smem);
    cudaFuncSetAttribute(k_mix_mma, cudaFuncAttributeMaxDynamicSharedMemorySize, MIX_SMEM);

    k_adj<<<NP, 256>>>(nv1, nv2);
    k_conv<<<dim3(DM / 256, BATCH), 256, conv_smem>>>(x, w_start, b_start);
    dim3 mixg(NP / TILE_N, MROWS / TILE_M);
    k_mix_mma<<<mixg, 256, MIX_SMEM>>>(0, 1, 1);
    k_mix_mma<<<mixg, 256, MIX_SMEM>>>(1, 2, 1);
    k_mix_mma<<<mixg, 256, MIX_SMEM>>>(2, 3, 0);
    k_mlp<<<dim3(NP / 128, BATCH), 256, mlp_smem>>>(w_mlp, b_mlp, w_end, b_end);
    k_lin<<<DM / 64, 128>>>(w_lin, b_lin);
    k_ln<<<BATCH, 256>>>(ln_g, ln_b, out);
}

// round 5
// speedup vs baseline: 1.8607x; 1.1110x over previous
#include <cuda_runtime.h>
#include <cuda_bf16.h>
#include <math.h>
#include <stdint.h>

// ---------------- problem constants ----------------
#define N_NODE 2000
#define NP     2048          // padded node dim
#define BATCH  64
#define CC     64
#define MROWS  (BATCH*CC)    // 4096
#define DM     2048
#define IN_D   7
#define KW     49
#define ND     40
#define ALPHA_C 0.05f
#define BETA_C  0.95f

// mix GEMM tiling: k-chunk 32 (64B rows) so 3 stages = 96KB -> 2 CTAs/SM
#define KC      32
#define NCHUNK  (NP / KC)             // 64
#define TILE_M  128
#define TILE_N  128
#define VAR_BYTES (128 * 64)          // one 128-row x 64B tile = 8192 B
#define OFF_AHI 0
#define OFF_ALO (VAR_BYTES)
#define OFF_BHI (2 * VAR_BYTES)
#define OFF_BLO (3 * VAR_BYTES)
#define STAGE_BYTES (4 * VAR_BYTES)   // 32768
#define NSTAGE  3
#define MIX_SMEM (NSTAGE * STAGE_BYTES)  // 98304 -> 2 CTAs/SM

// ---------------- scratch ----------------
__device__ float          g_H[4 * MROWS * NP];     // fp32 hops
__device__ __nv_bfloat16  g_Ahi[4 * MROWS * NP];   // bf16 hi of hops
__device__ __nv_bfloat16  g_Alo[4 * MROWS * NP];   // bf16 lo of hops
__device__ __nv_bfloat16  g_Bhi[NP * NP];          // adjacency a[v][w] hi
__device__ __nv_bfloat16  g_Blo[NP * NP];          // adjacency a[v][w] lo
__device__ float          g_S[BATCH * NP];
__device__ float          g_Y[BATCH * DM];

// ---------------- helpers ----------------
__device__ __forceinline__ uint32_t smem_u32(const void* p) {
    uint32_t a;
    asm("{ .reg .u64 t; cvta.to.shared.u64 t, %1; cvt.u32.u64 %0, t; }" : "=r"(a) : "l"(p));
    return a;
}
__device__ __forceinline__ void cpa16(uint32_t s, const void* g) {
    asm volatile("cp.async.cg.shared.global [%0], [%1], 16;" :: "r"(s), "l"(g));
}
#define CPA_COMMIT() asm volatile("cp.async.commit_group;" ::: "memory")
#define CPA_WAIT(n)  asm volatile("cp.async.wait_group %0;" :: "n"(n) : "memory")

__device__ __forceinline__ void ldsm4(uint32_t* r, uint32_t addr) {
    asm volatile("ldmatrix.sync.aligned.m8n8.x4.shared.b16 {%0,%1,%2,%3}, [%4];"
                 : "=r"(r[0]), "=r"(r[1]), "=r"(r[2]), "=r"(r[3]) : "r"(addr));
}
__device__ __forceinline__ void mma16816(float* d, const uint32_t* a, const uint32_t* b) {
    asm volatile("mma.sync.aligned.m16n8k16.row.col.f32.bf16.bf16.f32 "
                 "{%0,%1,%2,%3}, {%4,%5,%6,%7}, {%8,%9}, {%0,%1,%2,%3};"
                 : "+f"(d[0]), "+f"(d[1]), "+f"(d[2]), "+f"(d[3])
                 : "r"(a[0]), "r"(a[1]), "r"(a[2]), "r"(a[3]), "r"(b[0]), "r"(b[1]));
}
__device__ __forceinline__ void bf16_split(float v, __nv_bfloat16& hi, __nv_bfloat16& lo) {
    hi = __float2bfloat16(v);
    lo = __float2bfloat16(v - __bfloat162float(hi));
}

// ---------------- kernel 1: adjacency -> bf16 hi/lo, a[v][w] K-major ----------------
__global__ void k_adj(const float* __restrict__ E1, const float* __restrict__ E2) {
    int v = blockIdx.x;
    int tid = threadIdx.x;
    if (v >= N_NODE) {
        for (int w = tid; w < NP; w += 256) {
            g_Bhi[(size_t)v * NP + w] = __float2bfloat16(0.f);
            g_Blo[(size_t)v * NP + w] = __float2bfloat16(0.f);
        }
        return;
    }
    __shared__ float e1[ND];
    __shared__ float z[N_NODE];
    __shared__ float red[256];
    if (tid < ND) e1[tid] = E1[v * ND + tid];
    __syncthreads();

    float lmax = -1e30f;
    for (int w = tid; w < N_NODE; w += 256) {
        float acc = 0.f;
#pragma unroll
        for (int k = 0; k < ND; k++) acc += e1[k] * E2[k * N_NODE + w];
        acc = fmaxf(acc, 0.f);
        z[w] = acc;
        lmax = fmaxf(lmax, acc);
    }
    red[tid] = lmax; __syncthreads();
    for (int s = 128; s > 0; s >>= 1) { if (tid < s) red[tid] = fmaxf(red[tid], red[tid + s]); __syncthreads(); }
    float smax = red[0];
    __syncthreads();

    float lsum = 0.f;
    for (int w = tid; w < N_NODE; w += 256) { float e = expf(z[w] - smax); z[w] = e; lsum += e; }
    red[tid] = lsum; __syncthreads();
    for (int s = 128; s > 0; s >>= 1) { if (tid < s) red[tid] += red[tid + s]; __syncthreads(); }
    float inv = 0.5f / red[0];   // a = (softmax + I)/2 (adj rows sum to exactly 2)
    for (int w = tid; w < NP; w += 256) {
        float val = (w < N_NODE) ? (z[w] * inv + ((w == v) ? 0.5f : 0.f)) : 0.f;
        __nv_bfloat16 h, l; bf16_split(val, h, l);
        g_Bhi[(size_t)v * NP + w] = h;
        g_Blo[(size_t)v * NP + w] = l;
    }
}

// ---------------- kernel 2: start conv -> hop0 (fp32 + bf16 hi/lo) ----------------
__global__ __launch_bounds__(256) void k_conv(const float* __restrict__ x,
                                              const float* __restrict__ w,
                                              const float* __restrict__ bias) {
    extern __shared__ float sm[];
    float* ws = sm;
    float* xs = sm + CC * IN_D * KW;
    int b  = blockIdx.y;
    int n0 = blockIdx.x * 256;
    int tid = threadIdx.x;
    int ng  = tid & 31;
    int cog = tid >> 5;

    for (int idx = tid; idx < CC * IN_D * KW; idx += 256) ws[idx] = w[idx];
    for (int idx = tid; idx < IN_D * 304; idx += 256) {
        int ci = idx / 304, p = idx % 304;
        int gp = n0 + p;
        xs[idx] = (gp < DM) ? x[(size_t)b * IN_D * DM + ci * DM + gp] : 0.f;
    }
    __syncthreads();

    float acc[8][8];
#pragma unroll
    for (int i = 0; i < 8; i++)
#pragma unroll
        for (int j = 0; j < 8; j++) acc[i][j] = 0.f;

    for (int ci = 0; ci < IN_D; ci++) {
        for (int k = 0; k < KW; k++) {
            float xv[8];
#pragma unroll
            for (int j = 0; j < 8; j++) xv[j] = xs[ci * 304 + ng + j * 32 + k];
#pragma unroll
            for (int i = 0; i < 8; i++) {
                float wv = ws[(cog * 8 + i) * (IN_D * KW) + ci * KW + k];
#pragma unroll
                for (int j = 0; j < 8; j++) acc[i][j] += wv * xv[j];
            }
        }
    }
#pragma unroll
    for (int i = 0; i < 8; i++) {
        int co = cog * 8 + i;
        float bb = bias[co];
        size_t row = (size_t)(b * CC + co) * NP;
#pragma unroll
        for (int j = 0; j < 8; j++) {
            int n = n0 + ng + j * 32;
            float v = (n < N_NODE) ? (acc[i][j] + bb) : 0.f;
            g_H[row + n] = v;
            __nv_bfloat16 h, l; bf16_split(v, h, l);
            g_Ahi[row + n] = h;
            g_Alo[row + n] = l;
        }
    }
}

// ---------------- kernel 3: mixprop GEMM on HMMA (mma.sync bf16, hi/lo split) -----
// D[m][v] = sum_w H_src[m][w] * a[v][w];  C = ALPHA*h0 + BETA*D
// CTA 128x128, K-chunks of 32 (64B rows, SW64 swizzle), 3-stage cp.async pipeline,
// 96KB smem -> 2 CTAs/SM (regs 128 x 256thr x 2 = full RF).
// 8 warps 2(m) x 4(n); warp tile 64x32.
__global__ __launch_bounds__(256, 2) void k_mix_mma(int src, int dst, int wb) {
    extern __shared__ char smem[];
    const uint32_t sbase = smem_u32(smem);

    const int tid = threadIdx.x;
    const int wid = tid >> 5, lane = tid & 31;
    const int wm = wid >> 2;            // 0..1 -> m offset wm*64
    const int wn = wid & 3;             // 0..3 -> n offset wn*32
    const int m0 = blockIdx.y * TILE_M;
    const int n0 = blockIdx.x * TILE_N;

    const __nv_bfloat16* Ahi = g_Ahi + (size_t)src * MROWS * NP;
    const __nv_bfloat16* Alo = g_Alo + (size_t)src * MROWS * NP;

    // loader mapping: row = tid>>1 (0..127), two 16B segs per variant: (tid&1)*2, +1
    const int lr = tid >> 1;
    const int ls = (tid & 1) * 2;
    const uint32_t lswz = (uint32_t)((lr >> 1) & 3);   // SW64: seg ^= (row>>1)&3
    const char* gAhi = (const char*)(Ahi + (size_t)(m0 + lr) * NP);
    const char* gAlo = (const char*)(Alo + (size_t)(m0 + lr) * NP);
    const char* gBhi = (const char*)(g_Bhi + (size_t)(n0 + lr) * NP);
    const char* gBlo = (const char*)(g_Blo + (size_t)(n0 + lr) * NP);

#define LOAD_CHUNK(cidx, buf) do {                                                   \
    uint32_t sb = sbase + (buf) * STAGE_BYTES + lr * 64;                             \
    size_t go = (size_t)(cidx) * 64 + ls * 16;                                       \
    _Pragma("unroll")                                                                \
    for (int j = 0; j < 2; j++) {                                                    \
        uint32_t so = ((uint32_t)(ls + j) ^ lswz) << 4;                              \
        cpa16(sb + OFF_AHI + so, gAhi + go + j * 16);                                \
        cpa16(sb + OFF_ALO + so, gAlo + go + j * 16);                                \
        cpa16(sb + OFF_BHI + so, gBhi + go + j * 16);                                \
        cpa16(sb + OFF_BLO + so, gBlo + go + j * 16);                                \
    }                                                                                \
} while (0)

    float acc[4][4][4];
#pragma unroll
    for (int im = 0; im < 4; im++)
#pragma unroll
        for (int in = 0; in < 4; in++)
#pragma unroll
            for (int q = 0; q < 4; q++) acc[im][in][q] = 0.f;

    // ldmatrix lane address components
    const int a_row_l = (lane & 15);
    const int a_jl = lane >> 4;               // seg j = 2*ks + a_jl
    const int b_row_l = ((lane >> 4) << 3) + (lane & 7);
    const int b_jl = (lane >> 3) & 1;

    // prologue: preload chunks 0 and 1 into stages 0 and 1
    LOAD_CHUNK(0, 0); CPA_COMMIT();
    LOAD_CHUNK(1, 1); CPA_COMMIT();

    int buf = 0;        // stage of chunk c
    int nbuf = 2;       // stage chunk c+2 goes to
    for (int c = 0; c < NCHUNK; c++) {
        if (c + 1 < NCHUNK) { CPA_WAIT(1); } else { CPA_WAIT(0); }
        __syncthreads();
        if (c + 2 < NCHUNK) { LOAD_CHUNK(c + 2, nbuf); CPA_COMMIT(); }

        uint32_t sb = sbase + buf * STAGE_BYTES;
#pragma unroll
        for (int ks = 0; ks < 2; ks++) {
            uint32_t ah[4][4], al[4][4], bh[2][4], bl[2][4];
#pragma unroll
            for (int im = 0; im < 4; im++) {
                int row = wm * 64 + im * 16 + a_row_l;
                uint32_t off = (uint32_t)row * 64 +
                               ((uint32_t)((2 * ks + a_jl) ^ ((row >> 1) & 3)) << 4);
                ldsm4(ah[im], sb + OFF_AHI + off);
                ldsm4(al[im], sb + OFF_ALO + off);
            }
#pragma unroll
            for (int inb = 0; inb < 2; inb++) {
                int row = wn * 32 + inb * 16 + b_row_l;
                uint32_t off = (uint32_t)row * 64 +
                               ((uint32_t)((2 * ks + b_jl) ^ ((row >> 1) & 3)) << 4);
                ldsm4(bh[inb], sb + OFF_BHI + off);
                ldsm4(bl[inb], sb + OFF_BLO + off);
            }
#pragma unroll
            for (int p = 0; p < 3; p++) {
#pragma unroll
                for (int im = 0; im < 4; im++) {
#pragma unroll
                    for (int in = 0; in < 4; in++) {
                        const uint32_t* af = (p == 2) ? al[im] : ah[im];
                        const uint32_t* bf = (p == 1) ? &bl[in >> 1][(in & 1) * 2]
                                                      : &bh[in >> 1][(in & 1) * 2];
                        mma16816(acc[im][in], af, bf);
                    }
                }
            }
        }
        buf = (buf == NSTAGE - 1) ? 0 : buf + 1;
        nbuf = (nbuf == NSTAGE - 1) ? 0 : nbuf + 1;
    }

    // epilogue: fuse C = ALPHA*h0 + BETA*acc, emit fp32 + bf16 hi/lo
    const float* X = g_H;                                    // hop0
    float* C = g_H + (size_t)dst * MROWS * NP;
    __nv_bfloat16* Hh = g_Ahi + (size_t)dst * MROWS * NP;
    __nv_bfloat16* Hl = g_Alo + (size_t)dst * MROWS * NP;

#pragma unroll
    for (int im = 0; im < 4; im++) {
#pragma unroll
        for (int half = 0; half < 2; half++) {
            int m = m0 + wm * 64 + im * 16 + (lane >> 2) + half * 8;
            size_t rowo = (size_t)m * NP;
#pragma unroll
            for (int in = 0; in < 4; in++) {
                int n = n0 + wn * 32 + in * 8 + (lane & 3) * 2;
                float d0 = acc[im][in][half * 2 + 0];
                float d1 = acc[im][in][half * 2 + 1];
                float2 xv = *(const float2*)(X + rowo + n);
                float o0 = ALPHA_C * xv.x + BETA_C * d0;
                float o1 = ALPHA_C * xv.y + BETA_C * d1;
                *(float2*)(C + rowo + n) = make_float2(o0, o1);
                if (wb) {
                    __nv_bfloat16 h0, l0, h1, l1;
                    bf16_split(o0, h0, l0); bf16_split(o1, h1, l1);
                    *(__nv_bfloat162*)(Hh + rowo + n) = __nv_bfloat162(h0, h1);
                    *(__nv_bfloat162*)(Hl + rowo + n) = __nv_bfloat162(l0, l1);
                }
            }
        }
    }
#undef LOAD_CHUNK
}

// ---------------- kernel 4: MLP(256->64) + GELU + end(64->1) ----------------
__global__ __launch_bounds__(256) void k_mlp(const float* __restrict__ wmlp,
                                             const float* __restrict__ bmlp,
                                             const float* __restrict__ wend,
                                             const float* __restrict__ bend) {
    extern __shared__ float ws[];
    __shared__ float red[8][128];
    int b  = blockIdx.y;
    int n0 = blockIdx.x * 128;
    int tid = threadIdx.x;
    int ng = tid & 31, og = tid >> 5;

    for (int idx = tid; idx < 64 * 256; idx += 256) ws[idx] = wmlp[idx];
    __syncthreads();

    float acc[8][4];
#pragma unroll
    for (int i = 0; i < 8; i++)
#pragma unroll
        for (int jj = 0; jj < 4; jj++) acc[i][jj] = 0.f;

    for (int jc = 0; jc < 256; jc++) {
        int j = jc >> 6, c = jc & 63;
        const float* hp = g_H + ((size_t)j * MROWS + b * CC + c) * NP + n0 + ng;
        float hv[4];
#pragma unroll
        for (int jj = 0; jj < 4; jj++) hv[jj] = hp[jj * 32];
#pragma unroll
        for (int i = 0; i < 8; i++) {
            float wv = ws[(og * 8 + i) * 256 + jc];
#pragma unroll
            for (int jj = 0; jj < 4; jj++) acc[i][jj] += wv * hv[jj];
        }
    }

    float part[4] = {0.f, 0.f, 0.f, 0.f};
#pragma unroll
    for (int i = 0; i < 8; i++) {
        int o = og * 8 + i;
        float bm = bmlp[o], we = wend[o];
#pragma unroll
        for (int jj = 0; jj < 4; jj++) {
            float v = acc[i][jj] + bm;
            float g = 0.5f * v * (1.f + erff(v * 0.70710678118654752f));
            part[jj] += we * g;
        }
    }
#pragma unroll
    for (int jj = 0; jj < 4; jj++) red[og][ng + jj * 32] = part[jj];
    __syncthreads();
    if (og == 0) {
#pragma unroll
        for (int jj = 0; jj < 4; jj++) {
            int nl = ng + jj * 32;
            float s = bend[0];
#pragma unroll
            for (int g = 0; g < 8; g++) s += red[g][nl];
            int n = n0 + nl;
            if (n < N_NODE) g_S[(size_t)b * NP + n] = s;
        }
    }
}

// ---------------- kernel 5: final linear ----------------
__global__ __launch_bounds__(128) void k_lin(const float* __restrict__ wlin,
                                             const float* __restrict__ blin) {
    __shared__ float Ss[64][41];
    __shared__ float Ws[64][41];
    int d0 = blockIdx.x * 64;
    int tid = threadIdx.x;
    int dg = tid >> 3, bg = tid & 7;

    float acc[4][8];
#pragma unroll
    for (int i = 0; i < 4; i++)
#pragma unroll
        for (int j = 0; j < 8; j++) acc[i][j] = 0.f;

    for (int k0 = 0; k0 < N_NODE; k0 += 40) {
        for (int idx = tid; idx < 64 * 40; idx += 128) {
            int bb = idx / 40, kk = idx % 40;
            Ss[bb][kk] = g_S[(size_t)bb * NP + k0 + kk];
        }
        for (int idx = tid; idx < 64 * 40; idx += 128) {
            int dd = idx / 40, kk = idx % 40;
            Ws[dd][kk] = wlin[(size_t)(d0 + dd) * N_NODE + k0 + kk];
        }
        __syncthreads();
#pragma unroll 8
        for (int k = 0; k < 40; k++) {
            float wv[4];
#pragma unroll
            for (int i = 0; i < 4; i++) wv[i] = Ws[dg * 4 + i][k];
#pragma unroll
            for (int j = 0; j < 8; j++) {
                float sv = Ss[bg * 8 + j][k];
#pragma unroll
                for (int i = 0; i < 4; i++) acc[i][j] += wv[i] * sv;
            }
        }
        __syncthreads();
    }
#pragma unroll
    for (int i = 0; i < 4; i++) {
        int d = d0 + dg * 4 + i;
        float bl = blin[d];
#pragma unroll
        for (int j = 0; j < 8; j++) {
            int bb = bg * 8 + j;
            g_Y[(size_t)bb * DM + d] = acc[i][j] + bl;
        }
    }
}

// ---------------- kernel 6: layernorm ----------------
__global__ void k_ln(const float* __restrict__ gam, const float* __restrict__ bet,
                     float* __restrict__ out) {
    int b = blockIdx.x;
    int tid = threadIdx.x;
    __shared__ float red[256];
    const float* y = g_Y + (size_t)b * DM;

    float s = 0.f;
    for (int d = tid; d < DM; d += 256) s += y[d];
    red[tid] = s; __syncthreads();
    for (int st = 128; st > 0; st >>= 1) { if (tid < st) red[tid] += red[tid + st]; __syncthreads(); }
    float mu = red[0] / DM;
    __syncthreads();

    float v = 0.f;
    for (int d = tid; d < DM; d += 256) { float t = y[d] - mu; v += t * t; }
    red[tid] = v; __syncthreads();
    for (int st = 128; st > 0; st >>= 1) { if (tid < st) red[tid] += red[tid + st]; __syncthreads(); }
    float rinv = rsqrtf(red[0] / DM + 1e-5f);

    for (int d = tid; d < DM; d += 256)
        out[(size_t)b * DM + d] = (y[d] - mu) * rinv * gam[d] + bet[d];
}

// ---------------- launch ----------------
extern "C" void kernel_launch(void* const* d_in, const int* in_sizes, int n_in,
                              void* d_out, int out_size) {
    const float* x       = (const float*)d_in[0];
    const float* nv1     = (const float*)d_in[1];
    const float* nv2     = (const float*)d_in[2];
    const float* w_start = (const float*)d_in[3];
    const float* b_start = (const float*)d_in[4];
    const float* w_mlp   = (const float*)d_in[5];
    const float* b_mlp   = (const float*)d_in[6];
    const float* w_end   = (const float*)d_in[7];
    const float* b_end   = (const float*)d_in[8];
    const float* w_lin   = (const float*)d_in[9];
    const float* b_lin   = (const float*)d_in[10];
    const float* ln_g    = (const float*)d_in[11];
    const float* ln_b    = (const float*)d_in[12];
    float* out = (float*)d_out;

    const int conv_smem = (CC * IN_D * KW + IN_D * 304) * sizeof(float);
    const int mlp_smem  = 64 * 256 * sizeof(float);
    cudaFuncSetAttribute(k_conv,    cudaFuncAttributeMaxDynamicSharedMemorySize, conv_smem);
    cudaFuncSetAttribute(k_mlp,     cudaFuncAttributeMaxDynamicSharedMemorySize, mlp_smem);
    cudaFuncSetAttribute(k_mix_mma, cudaFuncAttributeMaxDynamicSharedMemorySize, MIX_SMEM);

    k_adj<<<NP, 256>>>(nv1, nv2);
    k_conv<<<dim3(DM / 256, BATCH), 256, conv_smem>>>(x, w_start, b_start);
    dim3 mixg(NP / TILE_N, MROWS / TILE_M);
    k_mix_mma<<<mixg, 256, MIX_SMEM>>>(0, 1, 1);
    k_mix_mma<<<mixg, 256, MIX_SMEM>>>(1, 2, 1);
    k_mix_mma<<<mixg, 256, MIX_SMEM>>>(2, 3, 0);
    k_mlp<<<dim3(NP / 128, BATCH), 256, mlp_smem>>>(w_mlp, b_mlp, w_end, b_end);
    k_lin<<<DM / 64, 128>>>(w_lin, b_lin);
    k_ln<<<BATCH, 256>>>(ln_g, ln_b, out);
}

// round 6
// speedup vs baseline: 2.3427x; 1.2591x over previous
#include <cuda_runtime.h>
#include <cuda_bf16.h>
#include <math.h>
#include <stdint.h>

// ---------------- problem constants ----------------
#define N_NODE 2000
#define NP     2048          // padded node dim
#define BATCH  64
#define CC     64
#define MROWS  (BATCH*CC)    // 4096
#define DM     2048
#define IN_D   7
#define KW     49
#define ND     40
#define ALPHA_C 0.05f
#define BETA_C  0.95f

// mix GEMM tiling: k-chunk 32 (64B rows) so 3 stages = 96KB -> 2 CTAs/SM
#define KC      32
#define NCHUNK  (NP / KC)             // 64
#define TILE_M  128
#define TILE_N  128
#define VAR_BYTES (128 * 64)          // one 128-row x 64B tile = 8192 B
#define OFF_AHI 0
#define OFF_ALO (VAR_BYTES)
#define OFF_BHI (2 * VAR_BYTES)
#define OFF_BLO (3 * VAR_BYTES)
#define STAGE_BYTES (4 * VAR_BYTES)   // 32768
#define NSTAGE  3
#define MIX_SMEM (NSTAGE * STAGE_BYTES)  // 98304 -> 2 CTAs/SM

// mlp GEMM smem layout
#define MLP_A_HI   0
#define MLP_A_LO   32768
#define MLP_B_BASE 65536
#define MLP_B_STG  32768     // per stage (hi 16KB + lo 16KB)
#define MLP_B_VAR  16384
#define MLP_SMEM   131072

// ---------------- scratch ----------------
__device__ float          g_H[MROWS * NP];         // fp32 hop0 only (mix epilogue X)
__device__ __nv_bfloat16  g_Ahi[4 * MROWS * NP];   // bf16 hi of hops
__device__ __nv_bfloat16  g_Alo[4 * MROWS * NP];   // bf16 lo of hops
__device__ __nv_bfloat16  g_Bhi[NP * NP];          // adjacency a[v][w] hi
__device__ __nv_bfloat16  g_Blo[NP * NP];          // adjacency a[v][w] lo
__device__ float          g_S[BATCH * NP];
__device__ float          g_Y[BATCH * DM];

// ---------------- helpers ----------------
__device__ __forceinline__ uint32_t smem_u32(const void* p) {
    uint32_t a;
    asm("{ .reg .u64 t; cvta.to.shared.u64 t, %1; cvt.u32.u64 %0, t; }" : "=r"(a) : "l"(p));
    return a;
}
__device__ __forceinline__ void cpa16(uint32_t s, const void* g) {
    asm volatile("cp.async.cg.shared.global [%0], [%1], 16;" :: "r"(s), "l"(g));
}
#define CPA_COMMIT() asm volatile("cp.async.commit_group;" ::: "memory")
#define CPA_WAIT(n)  asm volatile("cp.async.wait_group %0;" :: "n"(n) : "memory")

__device__ __forceinline__ void ldsm4(uint32_t* r, uint32_t addr) {
    asm volatile("ldmatrix.sync.aligned.m8n8.x4.shared.b16 {%0,%1,%2,%3}, [%4];"
                 : "=r"(r[0]), "=r"(r[1]), "=r"(r[2]), "=r"(r[3]) : "r"(addr));
}
__device__ __forceinline__ void ldsm4t(uint32_t* r, uint32_t addr) {
    asm volatile("ldmatrix.sync.aligned.m8n8.x4.trans.shared.b16 {%0,%1,%2,%3}, [%4];"
                 : "=r"(r[0]), "=r"(r[1]), "=r"(r[2]), "=r"(r[3]) : "r"(addr));
}
__device__ __forceinline__ void mma16816(float* d, const uint32_t* a, const uint32_t* b) {
    asm volatile("mma.sync.aligned.m16n8k16.row.col.f32.bf16.bf16.f32 "
                 "{%0,%1,%2,%3}, {%4,%5,%6,%7}, {%8,%9}, {%0,%1,%2,%3};"
                 : "+f"(d[0]), "+f"(d[1]), "+f"(d[2]), "+f"(d[3])
                 : "r"(a[0]), "r"(a[1]), "r"(a[2]), "r"(a[3]), "r"(b[0]), "r"(b[1]));
}
__device__ __forceinline__ void bf16_split(float v, __nv_bfloat16& hi, __nv_bfloat16& lo) {
    hi = __float2bfloat16(v);
    lo = __float2bfloat16(v - __bfloat162float(hi));
}
__device__ __forceinline__ uint32_t pack_bf2(float a, float b) {
    __nv_bfloat162 t = __floats2bfloat162_rn(a, b);
    return *reinterpret_cast<uint32_t*>(&t);
}
__device__ __forceinline__ float gelu_exact(float v) {
    return 0.5f * v * (1.f + erff(v * 0.70710678118654752f));
}

// ---------------- kernel 1: adjacency -> bf16 hi/lo, a[v][w] K-major ----------------
__global__ void k_adj(const float* __restrict__ E1, const float* __restrict__ E2) {
    int v = blockIdx.x;
    int tid = threadIdx.x;
    if (v >= N_NODE) {
        for (int w = tid; w < NP; w += 256) {
            g_Bhi[(size_t)v * NP + w] = __float2bfloat16(0.f);
            g_Blo[(size_t)v * NP + w] = __float2bfloat16(0.f);
        }
        return;
    }
    __shared__ float e1[ND];
    __shared__ float z[N_NODE];
    __shared__ float red[256];
    if (tid < ND) e1[tid] = E1[v * ND + tid];
    __syncthreads();

    float lmax = -1e30f;
    for (int w = tid; w < N_NODE; w += 256) {
        float acc = 0.f;
#pragma unroll
        for (int k = 0; k < ND; k++) acc += e1[k] * E2[k * N_NODE + w];
        acc = fmaxf(acc, 0.f);
        z[w] = acc;
        lmax = fmaxf(lmax, acc);
    }
    red[tid] = lmax; __syncthreads();
    for (int s = 128; s > 0; s >>= 1) { if (tid < s) red[tid] = fmaxf(red[tid], red[tid + s]); __syncthreads(); }
    float smax = red[0];
    __syncthreads();

    float lsum = 0.f;
    for (int w = tid; w < N_NODE; w += 256) { float e = expf(z[w] - smax); z[w] = e; lsum += e; }
    red[tid] = lsum; __syncthreads();
    for (int s = 128; s > 0; s >>= 1) { if (tid < s) red[tid] += red[tid + s]; __syncthreads(); }
    float inv = 0.5f / red[0];   // a = (softmax + I)/2 (adj rows sum to exactly 2)
    for (int w = tid; w < NP; w += 256) {
        float val = (w < N_NODE) ? (z[w] * inv + ((w == v) ? 0.5f : 0.f)) : 0.f;
        __nv_bfloat16 h, l; bf16_split(val, h, l);
        g_Bhi[(size_t)v * NP + w] = h;
        g_Blo[(size_t)v * NP + w] = l;
    }
}

// ---------------- kernel 2: start conv -> hop0 (fp32 + bf16 hi/lo) ----------------
__global__ __launch_bounds__(256) void k_conv(const float* __restrict__ x,
                                              const float* __restrict__ w,
                                              const float* __restrict__ bias) {
    extern __shared__ float sm[];
    float* ws = sm;
    float* xs = sm + CC * IN_D * KW;
    int b  = blockIdx.y;
    int n0 = blockIdx.x * 256;
    int tid = threadIdx.x;
    int ng  = tid & 31;
    int cog = tid >> 5;

    for (int idx = tid; idx < CC * IN_D * KW; idx += 256) ws[idx] = w[idx];
    for (int idx = tid; idx < IN_D * 304; idx += 256) {
        int ci = idx / 304, p = idx % 304;
        int gp = n0 + p;
        xs[idx] = (gp < DM) ? x[(size_t)b * IN_D * DM + ci * DM + gp] : 0.f;
    }
    __syncthreads();

    float acc[8][8];
#pragma unroll
    for (int i = 0; i < 8; i++)
#pragma unroll
        for (int j = 0; j < 8; j++) acc[i][j] = 0.f;

    for (int ci = 0; ci < IN_D; ci++) {
        for (int k = 0; k < KW; k++) {
            float xv[8];
#pragma unroll
            for (int j = 0; j < 8; j++) xv[j] = xs[ci * 304 + ng + j * 32 + k];
#pragma unroll
            for (int i = 0; i < 8; i++) {
                float wv = ws[(cog * 8 + i) * (IN_D * KW) + ci * KW + k];
#pragma unroll
                for (int j = 0; j < 8; j++) acc[i][j] += wv * xv[j];
            }
        }
    }
#pragma unroll
    for (int i = 0; i < 8; i++) {
        int co = cog * 8 + i;
        float bb = bias[co];
        size_t row = (size_t)(b * CC + co) * NP;
#pragma unroll
        for (int j = 0; j < 8; j++) {
            int n = n0 + ng + j * 32;
            float v = (n < N_NODE) ? (acc[i][j] + bb) : 0.f;
            g_H[row + n] = v;
            __nv_bfloat16 h, l; bf16_split(v, h, l);
            g_Ahi[row + n] = h;
            g_Alo[row + n] = l;
        }
    }
}

// ---------------- kernel 3: mixprop GEMM on HMMA (mma.sync bf16, hi/lo split) -----
// D[m][v] = sum_w H_src[m][w] * a[v][w];  C = ALPHA*h0 + BETA*D  (stored bf16 hi/lo)
__global__ __launch_bounds__(256, 2) void k_mix_mma(int src, int dst) {
    extern __shared__ char smem[];
    const uint32_t sbase = smem_u32(smem);

    const int tid = threadIdx.x;
    const int wid = tid >> 5, lane = tid & 31;
    const int wm = wid >> 2;
    const int wn = wid & 3;
    const int m0 = blockIdx.y * TILE_M;
    const int n0 = blockIdx.x * TILE_N;

    const __nv_bfloat16* Ahi = g_Ahi + (size_t)src * MROWS * NP;
    const __nv_bfloat16* Alo = g_Alo + (size_t)src * MROWS * NP;

    const int lr = tid >> 1;
    const int ls = (tid & 1) * 2;
    const uint32_t lswz = (uint32_t)((lr >> 1) & 3);   // SW64: seg ^= (row>>1)&3
    const char* gAhi = (const char*)(Ahi + (size_t)(m0 + lr) * NP);
    const char* gAlo = (const char*)(Alo + (size_t)(m0 + lr) * NP);
    const char* gBhi = (const char*)(g_Bhi + (size_t)(n0 + lr) * NP);
    const char* gBlo = (const char*)(g_Blo + (size_t)(n0 + lr) * NP);

#define LOAD_CHUNK(cidx, buf) do {                                                   \
    uint32_t sb = sbase + (buf) * STAGE_BYTES + lr * 64;                             \
    size_t go = (size_t)(cidx) * 64 + ls * 16;                                       \
    _Pragma("unroll")                                                                \
    for (int j = 0; j < 2; j++) {                                                    \
        uint32_t so = ((uint32_t)(ls + j) ^ lswz) << 4;                              \
        cpa16(sb + OFF_AHI + so, gAhi + go + j * 16);                                \
        cpa16(sb + OFF_ALO + so, gAlo + go + j * 16);                                \
        cpa16(sb + OFF_BHI + so, gBhi + go + j * 16);                                \
        cpa16(sb + OFF_BLO + so, gBlo + go + j * 16);                                \
    }                                                                                \
} while (0)

    float acc[4][4][4];
#pragma unroll
    for (int im = 0; im < 4; im++)
#pragma unroll
        for (int in = 0; in < 4; in++)
#pragma unroll
            for (int q = 0; q < 4; q++) acc[im][in][q] = 0.f;

    const int a_row_l = (lane & 15);
    const int a_jl = lane >> 4;
    const int b_row_l = ((lane >> 4) << 3) + (lane & 7);
    const int b_jl = (lane >> 3) & 1;

    LOAD_CHUNK(0, 0); CPA_COMMIT();
    LOAD_CHUNK(1, 1); CPA_COMMIT();

    int buf = 0, nbuf = 2;
    for (int c = 0; c < NCHUNK; c++) {
        if (c + 1 < NCHUNK) { CPA_WAIT(1); } else { CPA_WAIT(0); }
        __syncthreads();
        if (c + 2 < NCHUNK) { LOAD_CHUNK(c + 2, nbuf); CPA_COMMIT(); }

        uint32_t sb = sbase + buf * STAGE_BYTES;
#pragma unroll
        for (int ks = 0; ks < 2; ks++) {
            uint32_t ah[4][4], al[4][4], bh[2][4], bl[2][4];
#pragma unroll
            for (int im = 0; im < 4; im++) {
                int row = wm * 64 + im * 16 + a_row_l;
                uint32_t off = (uint32_t)row * 64 +
                               ((uint32_t)((2 * ks + a_jl) ^ ((row >> 1) & 3)) << 4);
                ldsm4(ah[im], sb + OFF_AHI + off);
                ldsm4(al[im], sb + OFF_ALO + off);
            }
#pragma unroll
            for (int inb = 0; inb < 2; inb++) {
                int row = wn * 32 + inb * 16 + b_row_l;
                uint32_t off = (uint32_t)row * 64 +
                               ((uint32_t)((2 * ks + b_jl) ^ ((row >> 1) & 3)) << 4);
                ldsm4(bh[inb], sb + OFF_BHI + off);
                ldsm4(bl[inb], sb + OFF_BLO + off);
            }
#pragma unroll
            for (int p = 0; p < 3; p++) {
#pragma unroll
                for (int im = 0; im < 4; im++) {
#pragma unroll
                    for (int in = 0; in < 4; in++) {
                        const uint32_t* af = (p == 2) ? al[im] : ah[im];
                        const uint32_t* bf = (p == 1) ? &bl[in >> 1][(in & 1) * 2]
                                                      : &bh[in >> 1][(in & 1) * 2];
                        mma16816(acc[im][in], af, bf);
                    }
                }
            }
        }
        buf = (buf == NSTAGE - 1) ? 0 : buf + 1;
        nbuf = (nbuf == NSTAGE - 1) ? 0 : nbuf + 1;
    }

    // epilogue: C = ALPHA*h0 + BETA*acc -> bf16 hi/lo only
    const float* X = g_H;
    __nv_bfloat16* Hh = g_Ahi + (size_t)dst * MROWS * NP;
    __nv_bfloat16* Hl = g_Alo + (size_t)dst * MROWS * NP;

#pragma unroll
    for (int im = 0; im < 4; im++) {
#pragma unroll
        for (int half = 0; half < 2; half++) {
            int m = m0 + wm * 64 + im * 16 + (lane >> 2) + half * 8;
            size_t rowo = (size_t)m * NP;
#pragma unroll
            for (int in = 0; in < 4; in++) {
                int n = n0 + wn * 32 + in * 8 + (lane & 3) * 2;
                float d0 = acc[im][in][half * 2 + 0];
                float d1 = acc[im][in][half * 2 + 1];
                float2 xv = *(const float2*)(X + rowo + n);
                float o0 = ALPHA_C * xv.x + BETA_C * d0;
                float o1 = ALPHA_C * xv.y + BETA_C * d1;
                __nv_bfloat16 h0, l0, h1, l1;
                bf16_split(o0, h0, l0); bf16_split(o1, h1, l1);
                *(__nv_bfloat162*)(Hh + rowo + n) = __nv_bfloat162(h0, h1);
                *(__nv_bfloat162*)(Hl + rowo + n) = __nv_bfloat162(l0, l1);
            }
        }
    }
#undef LOAD_CHUNK
}

// ---------------- kernel 4: MLP on HMMA + fused GELU + end dot ----------------
// s[b][n] = bend + sum_o wend[o] * gelu( sum_k w[o][k] * H[k][b][n] + bmlp[o] )
// K = 256 (hop*64 + c).  A = w hi/lo in smem [m=64][k=256], B = H hi/lo tiles
// [k=64][n=128] per chunk (chunk == hop), read via ldmatrix.trans.
// 8 warps = 4(m16) x 2(n64); acc[8 nfrag][4].
__global__ __launch_bounds__(256) void k_mlp_mma(const float* __restrict__ wmlp,
                                                 const float* __restrict__ bmlp,
                                                 const float* __restrict__ wend,
                                                 const float* __restrict__ bend) {
    extern __shared__ char smem[];
    __shared__ float red[4][128];
    const uint32_t sbase = smem_u32(smem);
    const int tid = threadIdx.x;
    const int wid = tid >> 5, lane = tid & 31;
    const int wm = wid >> 1;          // 0..3 -> o offset wm*16
    const int wn = wid & 1;           // 0..1 -> n offset wn*64
    const int b  = blockIdx.y;
    const int n0 = blockIdx.x * 128;

    // ---- A: convert w_mlp (64x256 fp32) to bf16 hi/lo in smem, swizzled ----
    // rows 512B (32 segs of 16B); phys seg = s ^ (row & 15)
#pragma unroll
    for (int i = 0; i < 8; i++) {
        int idx = tid + i * 256;            // (o, s)
        int o = idx >> 5, s = idx & 31;
        const float* wp = wmlp + o * 256 + s * 8;
        float4 v0 = *(const float4*)wp;
        float4 v1 = *(const float4*)(wp + 4);
        float vv[8] = {v0.x, v0.y, v0.z, v0.w, v1.x, v1.y, v1.z, v1.w};
        uint32_t hp[4], lp[4];
#pragma unroll
        for (int j = 0; j < 4; j++) {
            __nv_bfloat16 h0, l0, h1, l1;
            bf16_split(vv[2 * j], h0, l0);
            bf16_split(vv[2 * j + 1], h1, l1);
            __nv_bfloat162 hh(h0, h1), ll(l0, l1);
            hp[j] = *reinterpret_cast<uint32_t*>(&hh);
            lp[j] = *reinterpret_cast<uint32_t*>(&ll);
        }
        uint32_t phys = (uint32_t)(s ^ (o & 15));
        *(uint4*)(smem + MLP_A_HI + o * 512 + phys * 16) = make_uint4(hp[0], hp[1], hp[2], hp[3]);
        *(uint4*)(smem + MLP_A_LO + o * 512 + phys * 16) = make_uint4(lp[0], lp[1], lp[2], lp[3]);
    }

    // ---- B loader: chunk == hop; rows k=c (64), 256B rows (16 segs), phys = s^(k&7) ----
#define LOAD_BCH(chunk, stg) do {                                                        \
    const __nv_bfloat16* HBh = g_Ahi + ((size_t)(chunk) * MROWS + b * 64) * NP + n0;     \
    const __nv_bfloat16* HBl = g_Alo + ((size_t)(chunk) * MROWS + b * 64) * NP + n0;     \
    _Pragma("unroll")                                                                    \
    for (int i = 0; i < 4; i++) {                                                        \
        int idx = tid + i * 256;                                                         \
        int k = idx >> 4, s = idx & 15;                                                  \
        uint32_t phys = (uint32_t)(s ^ (k & 7));                                         \
        uint32_t dst = sbase + MLP_B_BASE + (stg) * MLP_B_STG + k * 256 + phys * 16;     \
        cpa16(dst,             (const char*)HBh + (size_t)k * NP * 2 + s * 16);          \
        cpa16(dst + MLP_B_VAR, (const char*)HBl + (size_t)k * NP * 2 + s * 16);          \
    }                                                                                    \
} while (0)

    float acc[8][4];
#pragma unroll
    for (int in = 0; in < 8; in++)
#pragma unroll
        for (int q = 0; q < 4; q++) acc[in][q] = 0.f;

    const int a_row = wm * 16 + (lane & 15);
    const int a_jl  = lane >> 4;
    const int b_kl  = ((lane >> 3) & 1) * 8 + (lane & 7);   // k within 16
    const int b_nl  = lane >> 4;                            // nseg parity

    LOAD_BCH(0, 0); CPA_COMMIT();

    for (int chunk = 0; chunk < 4; chunk++) {
        CPA_WAIT(0);
        __syncthreads();
        if (chunk < 3) { LOAD_BCH(chunk + 1, (chunk + 1) & 1); CPA_COMMIT(); }
        uint32_t bstg = sbase + MLP_B_BASE + (chunk & 1) * MLP_B_STG;

#pragma unroll
        for (int ks = 0; ks < 4; ks++) {
            int ksg = chunk * 4 + ks;
            uint32_t ah[4], al[4], bh[4][4], bl[4][4];
            {
                int s = 2 * ksg + a_jl;
                uint32_t off = (uint32_t)a_row * 512 + ((uint32_t)(s ^ (a_row & 15)) << 4);
                ldsm4(ah, sbase + MLP_A_HI + off);
                ldsm4(al, sbase + MLP_A_LO + off);
            }
            int krow = ks * 16 + b_kl;
            uint32_t koff = (uint32_t)krow * 256;
            uint32_t kx = (uint32_t)(krow & 7);
#pragma unroll
            for (int q = 0; q < 4; q++) {
                int ns = wn * 8 + 2 * q + b_nl;
                uint32_t off = koff + ((uint32_t)(ns ^ kx) << 4);
                ldsm4t(bh[q], bstg + off);
                ldsm4t(bl[q], bstg + MLP_B_VAR + off);
            }
#pragma unroll
            for (int p = 0; p < 3; p++) {
#pragma unroll
                for (int in = 0; in < 8; in++) {
                    const uint32_t* af = (p == 2) ? al : ah;
                    const uint32_t* bf = (p == 1) ? &bl[in >> 1][(in & 1) * 2]
                                                  : &bh[in >> 1][(in & 1) * 2];
                    mma16816(acc[in], af, bf);
                }
            }
        }
        __syncthreads();   // all warps done with stage before next overwrite epoch
    }

    // ---- epilogue: bias + gelu + wend dot + reductions ----
    const int o0 = wm * 16 + (lane >> 2);
    const int o1 = o0 + 8;
    const float bm0 = bmlp[o0], bm1 = bmlp[o1];
    const float we0 = wend[o0], we1 = wend[o1];

#pragma unroll
    for (int in = 0; in < 8; in++) {
        float g00 = gelu_exact(acc[in][0] + bm0);
        float g01 = gelu_exact(acc[in][1] + bm0);
        float g10 = gelu_exact(acc[in][2] + bm1);
        float g11 = gelu_exact(acc[in][3] + bm1);
        float p0 = we0 * g00 + we1 * g10;
        float p1 = we0 * g01 + we1 * g11;
#pragma unroll
        for (int d = 4; d <= 16; d <<= 1) {
            p0 += __shfl_xor_sync(0xFFFFFFFF, p0, d);
            p1 += __shfl_xor_sync(0xFFFFFFFF, p1, d);
        }
        if (lane < 4) {
            red[wm][wn * 64 + in * 8 + lane * 2 + 0] = p0;
            red[wm][wn * 64 + in * 8 + lane * 2 + 1] = p1;
        }
    }
    __syncthreads();
    if (tid < 128) {
        int n = n0 + tid;
        if (n < N_NODE) {
            float s = bend[0] + red[0][tid] + red[1][tid] + red[2][tid] + red[3][tid];
            g_S[(size_t)b * NP + n] = s;
        }
    }
#undef LOAD_BCH
}

// ---------------- kernel 5: final linear (d-tile 32, 64 CTAs) ----------------
__global__ __launch_bounds__(128) void k_lin(const float* __restrict__ wlin,
                                             const float* __restrict__ blin) {
    __shared__ float Ss[64][41];
    __shared__ float Ws[32][41];
    int d0 = blockIdx.x * 32;
    int tid = threadIdx.x;
    int dg = tid >> 3, bg = tid & 7;

    float acc[2][8];
#pragma unroll
    for (int i = 0; i < 2; i++)
#pragma unroll
        for (int j = 0; j < 8; j++) acc[i][j] = 0.f;

    for (int k0 = 0; k0 < N_NODE; k0 += 40) {
        for (int idx = tid; idx < 64 * 40; idx += 128) {
            int bb = idx / 40, kk = idx % 40;
            Ss[bb][kk] = g_S[(size_t)bb * NP + k0 + kk];
        }
        for (int idx = tid; idx < 32 * 40; idx += 128) {
            int dd = idx / 40, kk = idx % 40;
            Ws[dd][kk] = wlin[(size_t)(d0 + dd) * N_NODE + k0 + kk];
        }
        __syncthreads();
#pragma unroll 8
        for (int k = 0; k < 40; k++) {
            float wv[2];
#pragma unroll
            for (int i = 0; i < 2; i++) wv[i] = Ws[dg * 2 + i][k];
#pragma unroll
            for (int j = 0; j < 8; j++) {
                float sv = Ss[bg * 8 + j][k];
#pragma unroll
                for (int i = 0; i < 2; i++) acc[i][j] += wv[i] * sv;
            }
        }
        __syncthreads();
    }
#pragma unroll
    for (int i = 0; i < 2; i++) {
        int d = d0 + dg * 2 + i;
        float bl = blin[d];
#pragma unroll
        for (int j = 0; j < 8; j++) {
            int bb = bg * 8 + j;
            g_Y[(size_t)bb * DM + d] = acc[i][j] + bl;
        }
    }
}

// ---------------- kernel 6: layernorm ----------------
__global__ void k_ln(const float* __restrict__ gam, const float* __restrict__ bet,
                     float* __restrict__ out) {
    int b = blockIdx.x;
    int tid = threadIdx.x;
    __shared__ float red[256];
    const float* y = g_Y + (size_t)b * DM;

    float s = 0.f;
    for (int d = tid; d < DM; d += 256) s += y[d];
    red[tid] = s; __syncthreads();
    for (int st = 128; st > 0; st >>= 1) { if (tid < st) red[tid] += red[tid + st]; __syncthreads(); }
    float mu = red[0] / DM;
    __syncthreads();

    float v = 0.f;
    for (int d = tid; d < DM; d += 256) { float t = y[d] - mu; v += t * t; }
    red[tid] = v; __syncthreads();
    for (int st = 128; st > 0; st >>= 1) { if (tid < st) red[tid] += red[tid + st]; __syncthreads(); }
    float rinv = rsqrtf(red[0] / DM + 1e-5f);

    for (int d = tid; d < DM; d += 256)
        out[(size_t)b * DM + d] = (y[d] - mu) * rinv * gam[d] + bet[d];
}

// ---------------- launch ----------------
extern "C" void kernel_launch(void* const* d_in, const int* in_sizes, int n_in,
                              void* d_out, int out_size) {
    const float* x       = (const float*)d_in[0];
    const float* nv1     = (const float*)d_in[1];
    const float* nv2     = (const float*)d_in[2];
    const float* w_start = (const float*)d_in[3];
    const float* b_start = (const float*)d_in[4];
    const float* w_mlp   = (const float*)d_in[5];
    const float* b_mlp   = (const float*)d_in[6];
    const float* w_end   = (const float*)d_in[7];
    const float* b_end   = (const float*)d_in[8];
    const float* w_lin   = (const float*)d_in[9];
    const float* b_lin   = (const float*)d_in[10];
    const float* ln_g    = (const float*)d_in[11];
    const float* ln_b    = (const float*)d_in[12];
    float* out = (float*)d_out;

    const int conv_smem = (CC * IN_D * KW + IN_D * 304) * sizeof(float);
    cudaFuncSetAttribute(k_conv,    cudaFuncAttributeMaxDynamicSharedMemorySize, conv_smem);
    cudaFuncSetAttribute(k_mix_mma, cudaFuncAttributeMaxDynamicSharedMemorySize, MIX_SMEM);
    cudaFuncSetAttribute(k_mlp_mma, cudaFuncAttributeMaxDynamicSharedMemorySize, MLP_SMEM);

    k_adj<<<NP, 256>>>(nv1, nv2);
    k_conv<<<dim3(DM / 256, BATCH), 256, conv_smem>>>(x, w_start, b_start);
    dim3 mixg(NP / TILE_N, MROWS / TILE_M);
    k_mix_mma<<<mixg, 256, MIX_SMEM>>>(0, 1);
    k_mix_mma<<<mixg, 256, MIX_SMEM>>>(1, 2);
    k_mix_mma<<<mixg, 256, MIX_SMEM>>>(2, 3);
    k_mlp_mma<<<dim3(NP / 128, BATCH), 256, MLP_SMEM>>>(w_mlp, b_mlp, w_end, b_end);
    k_lin<<<DM / 32, 128>>>(w_lin, b_lin);
    k_ln<<<BATCH, 256>>>(ln_g, ln_b, out);
}

// round 7
// speedup vs baseline: 2.4274x; 1.0362x over previous
#include <cuda_runtime.h>
#include <cuda_bf16.h>
#include <math.h>
#include <stdint.h>

// ---------------- problem constants ----------------
#define N_NODE 2000
#define NP     2048          // padded node dim
#define BATCH  64
#define CC     64
#define MROWS  (BATCH*CC)    // 4096
#define DM     2048
#define IN_D   7
#define KW     49
#define ND     40
#define ALPHA_C 0.05f
#define BETA_C  0.95f

// mix GEMM tiling: k-chunk 32 (64B rows) so 3 stages = 96KB -> 2 CTAs/SM
#define KC      32
#define NCHUNK_IT 63                  // chunks 0..62 cover k=0..2015 (>=2000); 63 all-zero
#define TILE_M  128
#define TILE_N  128
#define VAR_BYTES (128 * 64)          // one 128-row x 64B tile = 8192 B
#define OFF_AHI 0
#define OFF_ALO (VAR_BYTES)
#define OFF_BHI (2 * VAR_BYTES)
#define OFF_BLO (3 * VAR_BYTES)
#define STAGE_BYTES (4 * VAR_BYTES)   // 32768
#define NSTAGE  3
#define MIX_SMEM (NSTAGE * STAGE_BYTES)  // 98304 -> 2 CTAs/SM

// mlp GEMM smem layout
#define MLP_A_HI   0
#define MLP_A_LO   32768
#define MLP_B_BASE 65536
#define MLP_B_STG  32768     // per stage (hi 16KB + lo 16KB)
#define MLP_B_VAR  16384
#define MLP_SMEM   131072

// conv GEMM smem layout
#define CV_A_STG   16384     // per stage: hi 8KB + lo 8KB
#define CV_A_VAR   8192
#define CV_B_STG   32768     // per stage: hi 16KB + lo 16KB
#define CV_B_VAR   16384
#define CV_A0      0
#define CV_B0      (2 * CV_A_STG)              // 32768
#define CV_XW      (CV_B0 + 2 * CV_B_STG)      // 98304
#define CV_SMEM    (CV_XW + 2 * 768)           // 99840 -> 2 CTAs/SM

// ---------------- scratch ----------------
__device__ float          g_H[MROWS * NP];         // fp32 hop0 only (mix epilogue X)
__device__ __nv_bfloat16  g_Ahi[4 * MROWS * NP];   // bf16 hi of hops
__device__ __nv_bfloat16  g_Alo[4 * MROWS * NP];   // bf16 lo of hops
__device__ __nv_bfloat16  g_Bhi[NP * NP];          // adjacency a[v][w] hi
__device__ __nv_bfloat16  g_Blo[NP * NP];          // adjacency a[v][w] lo
__device__ __nv_bfloat16  g_Whi[IN_D * CC * 64];   // conv weights hi [ci][co][64]
__device__ __nv_bfloat16  g_Wlo[IN_D * CC * 64];   // conv weights lo
__device__ float          g_S[BATCH * NP];
__device__ float          g_Y[BATCH * DM];

// ---------------- helpers ----------------
__device__ __forceinline__ uint32_t smem_u32(const void* p) {
    uint32_t a;
    asm("{ .reg .u64 t; cvta.to.shared.u64 t, %1; cvt.u32.u64 %0, t; }" : "=r"(a) : "l"(p));
    return a;
}
__device__ __forceinline__ void cpa16(uint32_t s, const void* g) {
    asm volatile("cp.async.cg.shared.global [%0], [%1], 16;" :: "r"(s), "l"(g));
}
#define CPA_COMMIT() asm volatile("cp.async.commit_group;" ::: "memory")
#define CPA_WAIT(n)  asm volatile("cp.async.wait_group %0;" :: "n"(n) : "memory")

__device__ __forceinline__ void ldsm4(uint32_t* r, uint32_t addr) {
    asm volatile("ldmatrix.sync.aligned.m8n8.x4.shared.b16 {%0,%1,%2,%3}, [%4];"
                 : "=r"(r[0]), "=r"(r[1]), "=r"(r[2]), "=r"(r[3]) : "r"(addr));
}
__device__ __forceinline__ void ldsm4t(uint32_t* r, uint32_t addr) {
    asm volatile("ldmatrix.sync.aligned.m8n8.x4.trans.shared.b16 {%0,%1,%2,%3}, [%4];"
                 : "=r"(r[0]), "=r"(r[1]), "=r"(r[2]), "=r"(r[3]) : "r"(addr));
}
__device__ __forceinline__ void mma16816(float* d, const uint32_t* a, const uint32_t* b) {
    asm volatile("mma.sync.aligned.m16n8k16.row.col.f32.bf16.bf16.f32 "
                 "{%0,%1,%2,%3}, {%4,%5,%6,%7}, {%8,%9}, {%0,%1,%2,%3};"
                 : "+f"(d[0]), "+f"(d[1]), "+f"(d[2]), "+f"(d[3])
                 : "r"(a[0]), "r"(a[1]), "r"(a[2]), "r"(a[3]), "r"(b[0]), "r"(b[1]));
}
__device__ __forceinline__ void bf16_split(float v, __nv_bfloat16& hi, __nv_bfloat16& lo) {
    hi = __float2bfloat16(v);
    lo = __float2bfloat16(v - __bfloat162float(hi));
}
__device__ __forceinline__ float gelu_exact(float v) {
    return 0.5f * v * (1.f + erff(v * 0.70710678118654752f));
}

// ---------------- kernel 0: prep conv weights -> bf16 hi/lo [ci][co][64] ----------------
__global__ void k_prepw(const float* __restrict__ w) {
    int ci = blockIdx.x;
    for (int idx = threadIdx.x; idx < CC * 64; idx += 256) {
        int co = idx >> 6, t = idx & 63;
        float v = (t < KW) ? w[co * (IN_D * KW) + ci * KW + t] : 0.f;
        __nv_bfloat16 h, l; bf16_split(v, h, l);
        g_Whi[ci * CC * 64 + idx] = h;
        g_Wlo[ci * CC * 64 + idx] = l;
    }
}

// ---------------- kernel 1: adjacency -> bf16 hi/lo, a[v][w] K-major ----------------
__global__ void k_adj(const float* __restrict__ E1, const float* __restrict__ E2) {
    int v = blockIdx.x;
    int tid = threadIdx.x;
    if (v >= N_NODE) {
        for (int w = tid; w < NP; w += 256) {
            g_Bhi[(size_t)v * NP + w] = __float2bfloat16(0.f);
            g_Blo[(size_t)v * NP + w] = __float2bfloat16(0.f);
        }
        return;
    }
    __shared__ float e1[ND];
    __shared__ float z[N_NODE];
    __shared__ float red[256];
    if (tid < ND) e1[tid] = E1[v * ND + tid];
    __syncthreads();

    float lmax = -1e30f;
    for (int w = tid; w < N_NODE; w += 256) {
        float acc = 0.f;
#pragma unroll
        for (int k = 0; k < ND; k++) acc += e1[k] * E2[k * N_NODE + w];
        acc = fmaxf(acc, 0.f);
        z[w] = acc;
        lmax = fmaxf(lmax, acc);
    }
    red[tid] = lmax; __syncthreads();
    for (int s = 128; s > 0; s >>= 1) { if (tid < s) red[tid] = fmaxf(red[tid], red[tid + s]); __syncthreads(); }
    float smax = red[0];
    __syncthreads();

    float lsum = 0.f;
    for (int w = tid; w < N_NODE; w += 256) { float e = expf(z[w] - smax); z[w] = e; lsum += e; }
    red[tid] = lsum; __syncthreads();
    for (int s = 128; s > 0; s >>= 1) { if (tid < s) red[tid] += red[tid + s]; __syncthreads(); }
    float inv = 0.5f / red[0];   // a = (softmax + I)/2 (adj rows sum to exactly 2)
    for (int w = tid; w < NP; w += 256) {
        float val = (w < N_NODE) ? (z[w] * inv + ((w == v) ? 0.5f : 0.f)) : 0.f;
        __nv_bfloat16 h, l; bf16_split(val, h, l);
        g_Bhi[(size_t)v * NP + w] = h;
        g_Blo[(size_t)v * NP + w] = l;
    }
}

// ---------------- kernel 2: start conv on HMMA (im2col in smem) ----------------
// out[b,co,n] = sum_{ci,t} w[co,ci,t] * x[b, ci*2048 + n + t] + bias[co]
// M=64(co) x N=128(n) per CTA, K = 7 chunks of 64 taps (taps>=49 have zero weights).
// 8 warps = 4(m16) x 2(n64), bf16 hi/lo 3-product.
__global__ __launch_bounds__(256, 2) void k_conv_mma(const float* __restrict__ x,
                                                     const float* __restrict__ bias) {
    extern __shared__ char smem[];
    const uint32_t sbase = smem_u32(smem);
    float* xw = (float*)(smem + CV_XW);            // [2][192] fp32 windows
    const int tid = threadIdx.x;
    const int wid = tid >> 5, lane = tid & 31;
    const int wm = wid >> 1;          // 0..3 -> co offset wm*16
    const int wn = wid & 1;           // 0..1 -> n offset wn*64
    const int b  = blockIdx.y;
    const int n0 = blockIdx.x * 128;

    // A chunk loader: rows co (64), 128B rows (8 segs), phys seg = s ^ (co&7)
#define CV_LOAD_A(ci, stg) do {                                                      \
    _Pragma("unroll")                                                                \
    for (int i = 0; i < 2; i++) {                                                    \
        int idx = tid + i * 256;            /* 512 entries (co, s) */                \
        int co = idx >> 3, s = idx & 7;                                              \
        uint32_t dst = sbase + CV_A0 + (stg) * CV_A_STG + co * 128 +                 \
                       ((uint32_t)(s ^ (co & 7)) << 4);                              \
        const char* src = (const char*)(g_Whi + (ci) * CC * 64 + co * 64 + s * 8);   \
        const char* srl = (const char*)(g_Wlo + (ci) * CC * 64 + co * 64 + s * 8);   \
        cpa16(dst, src);                                                             \
        cpa16(dst + CV_A_VAR, srl);                                                  \
    }                                                                                \
} while (0)

    // x window loader: 191 floats (t+n up to 190), zero-fill past row end
#define CV_LOAD_XW(ci, stg) do {                                                     \
    if (tid < 192) {                                                                 \
        int p = n0 + tid;                                                            \
        xw[(stg) * 192 + tid] = (p < DM) ? x[(size_t)b * IN_D * DM + (ci) * DM + p] : 0.f; \
    }                                                                                \
} while (0)

    // build B tile [t=64][n=128] bf16 hi/lo, 256B rows (16 segs), phys = s ^ (t&7)
#define CV_BUILD_B(stg) do {                                                         \
    const float* xwp = xw + (stg) * 192;                                             \
    uint32_t bb = sbase + CV_B0 + (stg) * CV_B_STG;                                  \
    _Pragma("unroll")                                                                \
    for (int i = 0; i < 16; i++) {                                                   \
        int idx = tid + i * 256;            /* 4096 pair entries */                  \
        int t = idx >> 6, j2 = idx & 63;    /* n = j2*2 */                           \
        int n = j2 * 2;                                                              \
        float v0 = xwp[t + n], v1 = xwp[t + n + 1];                                  \
        __nv_bfloat16 h0, l0, h1, l1;                                                \
        bf16_split(v0, h0, l0); bf16_split(v1, h1, l1);                              \
        __nv_bfloat162 hh(h0, h1), ll(l0, l1);                                       \
        int s = n >> 3;                                                              \
        uint32_t addr = bb + t * 256 + ((uint32_t)(s ^ (t & 7)) << 4) + (j2 & 3) * 4;\
        *(uint32_t*)(smem + (addr - sbase)) = *reinterpret_cast<uint32_t*>(&hh);     \
        *(uint32_t*)(smem + (addr - sbase) + CV_B_VAR) = *reinterpret_cast<uint32_t*>(&ll); \
    }                                                                                \
} while (0)

    float acc[8][4];
#pragma unroll
    for (int in = 0; in < 8; in++)
#pragma unroll
        for (int q = 0; q < 4; q++) acc[in][q] = 0.f;

    const int a_row = wm * 16 + (lane & 15);
    const int a_jl  = lane >> 4;
    const int b_kl  = ((lane >> 3) & 1) * 8 + (lane & 7);
    const int b_nl  = lane >> 4;

    CV_LOAD_A(0, 0); CPA_COMMIT();
    CV_LOAD_XW(0, 0);
    CPA_WAIT(0);
    __syncthreads();
    CV_BUILD_B(0);
    __syncthreads();

    for (int c = 0; c < IN_D; c++) {
        int stg = c & 1, nstg = (c + 1) & 1;
        if (c + 1 < IN_D) { CV_LOAD_A(c + 1, nstg); CPA_COMMIT(); CV_LOAD_XW(c + 1, nstg); }

        uint32_t astg = sbase + CV_A0 + stg * CV_A_STG;
        uint32_t bstg = sbase + CV_B0 + stg * CV_B_STG;
#pragma unroll
        for (int ks = 0; ks < 4; ks++) {
            uint32_t ah[4], al[4], bh[4][4], bl[4][4];
            {
                int s = 2 * ks + a_jl;
                uint32_t off = (uint32_t)a_row * 128 + ((uint32_t)(s ^ (a_row & 7)) << 4);
                ldsm4(ah, astg + off);
                ldsm4(al, astg + CV_A_VAR + off);
            }
            int krow = ks * 16 + b_kl;
            uint32_t koff = (uint32_t)krow * 256;
            uint32_t kx = (uint32_t)(krow & 7);
#pragma unroll
            for (int q = 0; q < 4; q++) {
                int ns = wn * 8 + 2 * q + b_nl;
                uint32_t off = koff + ((uint32_t)(ns ^ kx) << 4);
                ldsm4t(bh[q], bstg + off);
                ldsm4t(bl[q], bstg + CV_B_VAR + off);
            }
#pragma unroll
            for (int p = 0; p < 3; p++) {
#pragma unroll
                for (int in = 0; in < 8; in++) {
                    const uint32_t* af = (p == 2) ? al : ah;
                    const uint32_t* bf = (p == 1) ? &bl[in >> 1][(in & 1) * 2]
                                                  : &bh[in >> 1][(in & 1) * 2];
                    mma16816(acc[in], af, bf);
                }
            }
        }
        if (c + 1 < IN_D) {
            CPA_WAIT(0);
            __syncthreads();       // all warps done with MMA(c) + loads landed
            CV_BUILD_B(nstg);
            __syncthreads();
        }
    }

    // epilogue: bias add, write fp32 hop0 + bf16 hi/lo, zero pad n>=2000
    const int o0 = wm * 16 + (lane >> 2);
    const int o1 = o0 + 8;
    const float b0v = bias[o0], b1v = bias[o1];
#pragma unroll
    for (int in = 0; in < 8; in++) {
        int n = n0 + wn * 64 + in * 8 + (lane & 3) * 2;
        bool ok = (n < N_NODE);
        float v00 = ok ? (acc[in][0] + b0v) : 0.f;
        float v01 = ok ? (acc[in][1] + b0v) : 0.f;
        float v10 = ok ? (acc[in][2] + b1v) : 0.f;
        float v11 = ok ? (acc[in][3] + b1v) : 0.f;
        size_t r0 = (size_t)(b * CC + o0) * NP + n;
        size_t r1 = (size_t)(b * CC + o1) * NP + n;
        *(float2*)(g_H + r0) = make_float2(v00, v01);
        *(float2*)(g_H + r1) = make_float2(v10, v11);
        __nv_bfloat16 h0, l0, h1, l1;
        bf16_split(v00, h0, l0); bf16_split(v01, h1, l1);
        *(__nv_bfloat162*)(g_Ahi + r0) = __nv_bfloat162(h0, h1);
        *(__nv_bfloat162*)(g_Alo + r0) = __nv_bfloat162(l0, l1);
        bf16_split(v10, h0, l0); bf16_split(v11, h1, l1);
        *(__nv_bfloat162*)(g_Ahi + r1) = __nv_bfloat162(h0, h1);
        *(__nv_bfloat162*)(g_Alo + r1) = __nv_bfloat162(l0, l1);
    }
#undef CV_LOAD_A
#undef CV_LOAD_XW
#undef CV_BUILD_B
}

// ---------------- kernel 3: mixprop GEMM on HMMA (mma.sync bf16, hi/lo split) -----
__global__ __launch_bounds__(256, 2) void k_mix_mma(int src, int dst) {
    extern __shared__ char smem[];
    const uint32_t sbase = smem_u32(smem);

    const int tid = threadIdx.x;
    const int wid = tid >> 5, lane = tid & 31;
    const int wm = wid >> 2;
    const int wn = wid & 3;
    const int m0 = blockIdx.y * TILE_M;
    const int n0 = blockIdx.x * TILE_N;

    const __nv_bfloat16* Ahi = g_Ahi + (size_t)src * MROWS * NP;
    const __nv_bfloat16* Alo = g_Alo + (size_t)src * MROWS * NP;

    const int lr = tid >> 1;
    const int ls = (tid & 1) * 2;
    const uint32_t lswz = (uint32_t)((lr >> 1) & 3);   // SW64: seg ^= (row>>1)&3
    const char* gAhi = (const char*)(Ahi + (size_t)(m0 + lr) * NP);
    const char* gAlo = (const char*)(Alo + (size_t)(m0 + lr) * NP);
    const char* gBhi = (const char*)(g_Bhi + (size_t)(n0 + lr) * NP);
    const char* gBlo = (const char*)(g_Blo + (size_t)(n0 + lr) * NP);

#define LOAD_CHUNK(cidx, buf) do {                                                   \
    uint32_t sb = sbase + (buf) * STAGE_BYTES + lr * 64;                             \
    size_t go = (size_t)(cidx) * 64 + ls * 16;                                       \
    _Pragma("unroll")                                                                \
    for (int j = 0; j < 2; j++) {                                                    \
        uint32_t so = ((uint32_t)(ls + j) ^ lswz) << 4;                              \
        cpa16(sb + OFF_AHI + so, gAhi + go + j * 16);                                \
        cpa16(sb + OFF_ALO + so, gAlo + go + j * 16);                                \
        cpa16(sb + OFF_BHI + so, gBhi + go + j * 16);                                \
        cpa16(sb + OFF_BLO + so, gBlo + go + j * 16);                                \
    }                                                                                \
} while (0)

    float acc[4][4][4];
#pragma unroll
    for (int im = 0; im < 4; im++)
#pragma unroll
        for (int in = 0; in < 4; in++)
#pragma unroll
            for (int q = 0; q < 4; q++) acc[im][in][q] = 0.f;

    const int a_row_l = (lane & 15);
    const int a_jl = lane >> 4;
    const int b_row_l = ((lane >> 4) << 3) + (lane & 7);
    const int b_jl = (lane >> 3) & 1;

    LOAD_CHUNK(0, 0); CPA_COMMIT();
    LOAD_CHUNK(1, 1); CPA_COMMIT();

    int buf = 0, nbuf = 2;
    for (int c = 0; c < NCHUNK_IT; c++) {
        if (c + 1 < NCHUNK_IT) { CPA_WAIT(1); } else { CPA_WAIT(0); }
        __syncthreads();
        if (c + 2 < NCHUNK_IT) { LOAD_CHUNK(c + 2, nbuf); CPA_COMMIT(); }

        uint32_t sb = sbase + buf * STAGE_BYTES;
#pragma unroll
        for (int ks = 0; ks < 2; ks++) {
            uint32_t ah[4][4], al[4][4], bh[2][4], bl[2][4];
#pragma unroll
            for (int im = 0; im < 4; im++) {
                int row = wm * 64 + im * 16 + a_row_l;
                uint32_t off = (uint32_t)row * 64 +
                               ((uint32_t)((2 * ks + a_jl) ^ ((row >> 1) & 3)) << 4);
                ldsm4(ah[im], sb + OFF_AHI + off);
                ldsm4(al[im], sb + OFF_ALO + off);
            }
#pragma unroll
            for (int inb = 0; inb < 2; inb++) {
                int row = wn * 32 + inb * 16 + b_row_l;
                uint32_t off = (uint32_t)row * 64 +
                               ((uint32_t)((2 * ks + b_jl) ^ ((row >> 1) & 3)) << 4);
                ldsm4(bh[inb], sb + OFF_BHI + off);
                ldsm4(bl[inb], sb + OFF_BLO + off);
            }
#pragma unroll
            for (int p = 0; p < 3; p++) {
#pragma unroll
                for (int im = 0; im < 4; im++) {
#pragma unroll
                    for (int in = 0; in < 4; in++) {
                        const uint32_t* af = (p == 2) ? al[im] : ah[im];
                        const uint32_t* bf = (p == 1) ? &bl[in >> 1][(in & 1) * 2]
                                                      : &bh[in >> 1][(in & 1) * 2];
                        mma16816(acc[im][in], af, bf);
                    }
                }
            }
        }
        buf = (buf == NSTAGE - 1) ? 0 : buf + 1;
        nbuf = (nbuf == NSTAGE - 1) ? 0 : nbuf + 1;
    }

    // epilogue: C = ALPHA*h0 + BETA*acc -> bf16 hi/lo only
    const float* X = g_H;
    __nv_bfloat16* Hh = g_Ahi + (size_t)dst * MROWS * NP;
    __nv_bfloat16* Hl = g_Alo + (size_t)dst * MROWS * NP;

#pragma unroll
    for (int im = 0; im < 4; im++) {
#pragma unroll
        for (int half = 0; half < 2; half++) {
            int m = m0 + wm * 64 + im * 16 + (lane >> 2) + half * 8;
            size_t rowo = (size_t)m * NP;
#pragma unroll
            for (int in = 0; in < 4; in++) {
                int n = n0 + wn * 32 + in * 8 + (lane & 3) * 2;
                float d0 = acc[im][in][half * 2 + 0];
                float d1 = acc[im][in][half * 2 + 1];
                float2 xv = *(const float2*)(X + rowo + n);
                float o0 = ALPHA_C * xv.x + BETA_C * d0;
                float o1 = ALPHA_C * xv.y + BETA_C * d1;
                __nv_bfloat16 h0, l0, h1, l1;
                bf16_split(o0, h0, l0); bf16_split(o1, h1, l1);
                *(__nv_bfloat162*)(Hh + rowo + n) = __nv_bfloat162(h0, h1);
                *(__nv_bfloat162*)(Hl + rowo + n) = __nv_bfloat162(l0, l1);
            }
        }
    }
#undef LOAD_CHUNK
}

// ---------------- kernel 4: MLP on HMMA + fused GELU + end dot ----------------
__global__ __launch_bounds__(256) void k_mlp_mma(const float* __restrict__ wmlp,
                                                 const float* __restrict__ bmlp,
                                                 const float* __restrict__ wend,
                                                 const float* __restrict__ bend) {
    extern __shared__ char smem[];
    __shared__ float red[4][128];
    const uint32_t sbase = smem_u32(smem);
    const int tid = threadIdx.x;
    const int wid = tid >> 5, lane = tid & 31;
    const int wm = wid >> 1;
    const int wn = wid & 1;
    const int b  = blockIdx.y;
    const int n0 = blockIdx.x * 128;

#pragma unroll
    for (int i = 0; i < 8; i++) {
        int idx = tid + i * 256;
        int o = idx >> 5, s = idx & 31;
        const float* wp = wmlp + o * 256 + s * 8;
        float4 v0 = *(const float4*)wp;
        float4 v1 = *(const float4*)(wp + 4);
        float vv[8] = {v0.x, v0.y, v0.z, v0.w, v1.x, v1.y, v1.z, v1.w};
        uint32_t hp[4], lp[4];
#pragma unroll
        for (int j = 0; j < 4; j++) {
            __nv_bfloat16 h0, l0, h1, l1;
            bf16_split(vv[2 * j], h0, l0);
            bf16_split(vv[2 * j + 1], h1, l1);
            __nv_bfloat162 hh(h0, h1), ll(l0, l1);
            hp[j] = *reinterpret_cast<uint32_t*>(&hh);
            lp[j] = *reinterpret_cast<uint32_t*>(&ll);
        }
        uint32_t phys = (uint32_t)(s ^ (o & 15));
        *(uint4*)(smem + MLP_A_HI + o * 512 + phys * 16) = make_uint4(hp[0], hp[1], hp[2], hp[3]);
        *(uint4*)(smem + MLP_A_LO + o * 512 + phys * 16) = make_uint4(lp[0], lp[1], lp[2], lp[3]);
    }

#define LOAD_BCH(chunk, stg) do {                                                        \
    const __nv_bfloat16* HBh = g_Ahi + ((size_t)(chunk) * MROWS + b * 64) * NP + n0;     \
    const __nv_bfloat16* HBl = g_Alo + ((size_t)(chunk) * MROWS + b * 64) * NP + n0;     \
    _Pragma("unroll")                                                                    \
    for (int i = 0; i < 4; i++) {                                                        \
        int idx = tid + i * 256;                                                         \
        int k = idx >> 4, s = idx & 15;                                                  \
        uint32_t phys = (uint32_t)(s ^ (k & 7));                                         \
        uint32_t dst = sbase + MLP_B_BASE + (stg) * MLP_B_STG + k * 256 + phys * 16;     \
        cpa16(dst,             (const char*)HBh + (size_t)k * NP * 2 + s * 16);          \
        cpa16(dst + MLP_B_VAR, (const char*)HBl + (size_t)k * NP * 2 + s * 16);          \
    }                                                                                    \
} while (0)

    float acc[8][4];
#pragma unroll
    for (int in = 0; in < 8; in++)
#pragma unroll
        for (int q = 0; q < 4; q++) acc[in][q] = 0.f;

    const int a_row = wm * 16 + (lane & 15);
    const int a_jl  = lane >> 4;
    const int b_kl  = ((lane >> 3) & 1) * 8 + (lane & 7);
    const int b_nl  = lane >> 4;

    LOAD_BCH(0, 0); CPA_COMMIT();

    for (int chunk = 0; chunk < 4; chunk++) {
        CPA_WAIT(0);
        __syncthreads();
        if (chunk < 3) { LOAD_BCH(chunk + 1, (chunk + 1) & 1); CPA_COMMIT(); }
        uint32_t bstg = sbase + MLP_B_BASE + (chunk & 1) * MLP_B_STG;

#pragma unroll
        for (int ks = 0; ks < 4; ks++) {
            int ksg = chunk * 4 + ks;
            uint32_t ah[4], al[4], bh[4][4], bl[4][4];
            {
                int s = 2 * ksg + a_jl;
                uint32_t off = (uint32_t)a_row * 512 + ((uint32_t)(s ^ (a_row & 15)) << 4);
                ldsm4(ah, sbase + MLP_A_HI + off);
                ldsm4(al, sbase + MLP_A_LO + off);
            }
            int krow = ks * 16 + b_kl;
            uint32_t koff = (uint32_t)krow * 256;
            uint32_t kx = (uint32_t)(krow & 7);
#pragma unroll
            for (int q = 0; q < 4; q++) {
                int ns = wn * 8 + 2 * q + b_nl;
                uint32_t off = koff + ((uint32_t)(ns ^ kx) << 4);
                ldsm4t(bh[q], bstg + off);
                ldsm4t(bl[q], bstg + MLP_B_VAR + off);
            }
#pragma unroll
            for (int p = 0; p < 3; p++) {
#pragma unroll
                for (int in = 0; in < 8; in++) {
                    const uint32_t* af = (p == 2) ? al : ah;
                    const uint32_t* bf = (p == 1) ? &bl[in >> 1][(in & 1) * 2]
                                                  : &bh[in >> 1][(in & 1) * 2];
                    mma16816(acc[in], af, bf);
                }
            }
        }
        __syncthreads();
    }

    const int o0 = wm * 16 + (lane >> 2);
    const int o1 = o0 + 8;
    const float bm0 = bmlp[o0], bm1 = bmlp[o1];
    const float we0 = wend[o0], we1 = wend[o1];

#pragma unroll
    for (int in = 0; in < 8; in++) {
        float g00 = gelu_exact(acc[in][0] + bm0);
        float g01 = gelu_exact(acc[in][1] + bm0);
        float g10 = gelu_exact(acc[in][2] + bm1);
        float g11 = gelu_exact(acc[in][3] + bm1);
        float p0 = we0 * g00 + we1 * g10;
        float p1 = we0 * g01 + we1 * g11;
#pragma unroll
        for (int d = 4; d <= 16; d <<= 1) {
            p0 += __shfl_xor_sync(0xFFFFFFFF, p0, d);
            p1 += __shfl_xor_sync(0xFFFFFFFF, p1, d);
        }
        if (lane < 4) {
            red[wm][wn * 64 + in * 8 + lane * 2 + 0] = p0;
            red[wm][wn * 64 + in * 8 + lane * 2 + 1] = p1;
        }
    }
    __syncthreads();
    if (tid < 128) {
        int n = n0 + tid;
        if (n < N_NODE) {
            float s = bend[0] + red[0][tid] + red[1][tid] + red[2][tid] + red[3][tid];
            g_S[(size_t)b * NP + n] = s;
        }
    }
#undef LOAD_BCH
}

// ---------------- kernel 5: final linear (d-tile 32, 64 CTAs) ----------------
__global__ __launch_bounds__(128) void k_lin(const float* __restrict__ wlin,
                                             const float* __restrict__ blin) {
    __shared__ float Ss[64][41];
    __shared__ float Ws[32][41];
    int d0 = blockIdx.x * 32;
    int tid = threadIdx.x;
    int dg = tid >> 3, bg = tid & 7;

    float acc[2][8];
#pragma unroll
    for (int i = 0; i < 2; i++)
#pragma unroll
        for (int j = 0; j < 8; j++) acc[i][j] = 0.f;

    for (int k0 = 0; k0 < N_NODE; k0 += 40) {
        for (int idx = tid; idx < 64 * 40; idx += 128) {
            int bb = idx / 40, kk = idx % 40;
            Ss[bb][kk] = g_S[(size_t)bb * NP + k0 + kk];
        }
        for (int idx = tid; idx < 32 * 40; idx += 128) {
            int dd = idx / 40, kk = idx % 40;
            Ws[dd][kk] = wlin[(size_t)(d0 + dd) * N_NODE + k0 + kk];
        }
        __syncthreads();
#pragma unroll 8
        for (int k = 0; k < 40; k++) {
            float wv[2];
#pragma unroll
            for (int i = 0; i < 2; i++) wv[i] = Ws[dg * 2 + i][k];
#pragma unroll
            for (int j = 0; j < 8; j++) {
                float sv = Ss[bg * 8 + j][k];
#pragma unroll
                for (int i = 0; i < 2; i++) acc[i][j] += wv[i] * sv;
            }
        }
        __syncthreads();
    }
#pragma unroll
    for (int i = 0; i < 2; i++) {
        int d = d0 + dg * 2 + i;
        float bl = blin[d];
#pragma unroll
        for (int j = 0; j < 8; j++) {
            int bb = bg * 8 + j;
            g_Y[(size_t)bb * DM + d] = acc[i][j] + bl;
        }
    }
}

// ---------------- kernel 6: layernorm ----------------
__global__ void k_ln(const float* __restrict__ gam, const float* __restrict__ bet,
                     float* __restrict__ out) {
    int b = blockIdx.x;
    int tid = threadIdx.x;
    __shared__ float red[256];
    const float* y = g_Y + (size_t)b * DM;

    float s = 0.f;
    for (int d = tid; d < DM; d += 256) s += y[d];
    red[tid] = s; __syncthreads();
    for (int st = 128; st > 0; st >>= 1) { if (tid < st) red[tid] += red[tid + st]; __syncthreads(); }
    float mu = red[0] / DM;
    __syncthreads();

    float v = 0.f;
    for (int d = tid; d < DM; d += 256) { float t = y[d] - mu; v += t * t; }
    red[tid] = v; __syncthreads();
    for (int st = 128; st > 0; st >>= 1) { if (tid < st) red[tid] += red[tid + st]; __syncthreads(); }
    float rinv = rsqrtf(red[0] / DM + 1e-5f);

    for (int d = tid; d < DM; d += 256)
        out[(size_t)b * DM + d] = (y[d] - mu) * rinv * gam[d] + bet[d];
}

// ---------------- launch ----------------
extern "C" void kernel_launch(void* const* d_in, const int* in_sizes, int n_in,
                              void* d_out, int out_size) {
    const float* x       = (const float*)d_in[0];
    const float* nv1     = (const float*)d_in[1];
    const float* nv2     = (const float*)d_in[2];
    const float* w_start = (const float*)d_in[3];
    const float* b_start = (const float*)d_in[4];
    const float* w_mlp   = (const float*)d_in[5];
    const float* b_mlp   = (const float*)d_in[6];
    const float* w_end   = (const float*)d_in[7];
    const float* b_end   = (const float*)d_in[8];
    const float* w_lin   = (const float*)d_in[9];
    const float* b_lin   = (const float*)d_in[10];
    const float* ln_g    = (const float*)d_in[11];
    const float* ln_b    = (const float*)d_in[12];
    float* out = (float*)d_out;

    cudaFuncSetAttribute(k_mix_mma,  cudaFuncAttributeMaxDynamicSharedMemorySize, MIX_SMEM);
    cudaFuncSetAttribute(k_mlp_mma,  cudaFuncAttributeMaxDynamicSharedMemorySize, MLP_SMEM);
    cudaFuncSetAttribute(k_conv_mma, cudaFuncAttributeMaxDynamicSharedMemorySize, CV_SMEM);

    k_prepw<<<IN_D, 256>>>(w_start);
    k_adj<<<NP, 256>>>(nv1, nv2);
    k_conv_mma<<<dim3(NP / 128, BATCH), 256, CV_SMEM>>>(x, b_start);
    dim3 mixg(NP / TILE_N, MROWS / TILE_M);
    k_mix_mma<<<mixg, 256, MIX_SMEM>>>(0, 1);
    k_mix_mma<<<mixg, 256, MIX_SMEM>>>(1, 2);
    k_mix_mma<<<mixg, 256, MIX_SMEM>>>(2, 3);
    k_mlp_mma<<<dim3(NP / 128, BATCH), 256, MLP_SMEM>>>(w_mlp, b_mlp, w_end, b_end);
    k_lin<<<DM / 32, 128>>>(w_lin, b_lin);
    k_ln<<<BATCH, 256>>>(ln_g, ln_b, out);
}

// round 8
// speedup vs baseline: 3.0252x; 1.2462x over previous
#include <cuda_runtime.h>
#include <cuda_fp16.h>
#include <math.h>
#include <stdint.h>

// ---------------- problem constants ----------------
#define N_NODE 2000
#define NP     2048
#define BATCH  64
#define CC     64
#define MROWS  (BATCH*CC)    // 4096
#define DM     2048
#define IN_D   7
#define KW     49
#define ND     40
#define ALPHA_C 0.05f
#define BETA_C  0.95f

// mix GEMM tiling: k-chunk 32 (64B rows), 3 tiles (Ahi, Alo, Bh) per stage
#define KC      32
#define NCHUNK_IT 63                  // chunks 0..62 cover k=0..2015; 63 all-zero
#define TILE_M  128
#define TILE_N  128
#define VAR_BYTES (128 * 64)          // 8192 B
#define OFF_AHI 0
#define OFF_ALO (VAR_BYTES)
#define OFF_BH  (2 * VAR_BYTES)
#define STAGE_BYTES (3 * VAR_BYTES)   // 24576
#define NSTAGE  3
#define MIX_SMEM (NSTAGE * STAGE_BYTES)  // 73728 -> 2 CTAs/SM

// mlp GEMM smem layout
#define MLP_A_HI   0
#define MLP_A_LO   32768
#define MLP_B_BASE 65536
#define MLP_B_STG  32768
#define MLP_B_VAR  16384
#define MLP_SMEM   131072

// conv GEMM smem layout
#define CV_A_STG   16384
#define CV_A_VAR   8192
#define CV_B_STG   32768
#define CV_B_VAR   16384
#define CV_A0      0
#define CV_B0      (2 * CV_A_STG)
#define CV_XW      (CV_B0 + 2 * CV_B_STG)
#define CV_SMEM    (CV_XW + 2 * 768)

// ---------------- scratch ----------------
__device__ __half  g_Ahi[4 * MROWS * NP];   // fp16 hi of hops
__device__ __half  g_Alo[4 * MROWS * NP];   // fp16 lo of hops
__device__ __half  g_Bh[NP * NP];           // adjacency a[v][w], fp16 single
__device__ __half  g_Whi[IN_D * CC * 64];   // conv weights hi [ci][co][64]
__device__ __half  g_Wlo[IN_D * CC * 64];
__device__ float   g_S[BATCH * NP];
__device__ float   g_Y[BATCH * DM];

// ---------------- helpers ----------------
__device__ __forceinline__ uint32_t smem_u32(const void* p) {
    uint32_t a;
    asm("{ .reg .u64 t; cvta.to.shared.u64 t, %1; cvt.u32.u64 %0, t; }" : "=r"(a) : "l"(p));
    return a;
}
__device__ __forceinline__ void cpa16(uint32_t s, const void* g) {
    asm volatile("cp.async.cg.shared.global [%0], [%1], 16;" :: "r"(s), "l"(g));
}
#define CPA_COMMIT() asm volatile("cp.async.commit_group;" ::: "memory")
#define CPA_WAIT(n)  asm volatile("cp.async.wait_group %0;" :: "n"(n) : "memory")

__device__ __forceinline__ void ldsm4(uint32_t* r, uint32_t addr) {
    asm volatile("ldmatrix.sync.aligned.m8n8.x4.shared.b16 {%0,%1,%2,%3}, [%4];"
                 : "=r"(r[0]), "=r"(r[1]), "=r"(r[2]), "=r"(r[3]) : "r"(addr));
}
__device__ __forceinline__ void ldsm4t(uint32_t* r, uint32_t addr) {
    asm volatile("ldmatrix.sync.aligned.m8n8.x4.trans.shared.b16 {%0,%1,%2,%3}, [%4];"
                 : "=r"(r[0]), "=r"(r[1]), "=r"(r[2]), "=r"(r[3]) : "r"(addr));
}
__device__ __forceinline__ void mma16816(float* d, const uint32_t* a, const uint32_t* b) {
    asm volatile("mma.sync.aligned.m16n8k16.row.col.f32.f16.f16.f32 "
                 "{%0,%1,%2,%3}, {%4,%5,%6,%7}, {%8,%9}, {%0,%1,%2,%3};"
                 : "+f"(d[0]), "+f"(d[1]), "+f"(d[2]), "+f"(d[3])
                 : "r"(a[0]), "r"(a[1]), "r"(a[2]), "r"(a[3]), "r"(b[0]), "r"(b[1]));
}
__device__ __forceinline__ void fp16_split(float v, __half& hi, __half& lo) {
    hi = __float2half_rn(v);
    lo = __float2half_rn(v - __half2float(hi));
}
__device__ __forceinline__ float gelu_exact(float v) {
    return 0.5f * v * (1.f + erff(v * 0.70710678118654752f));
}

// ---------------- kernel 0: prep conv weights -> fp16 hi/lo [ci][co][64] ----------------
__global__ void k_prepw(const float* __restrict__ w) {
    int ci = blockIdx.x;
    for (int idx = threadIdx.x; idx < CC * 64; idx += 256) {
        int co = idx >> 6, t = idx & 63;
        float v = (t < KW) ? w[co * (IN_D * KW) + ci * KW + t] : 0.f;
        __half h, l; fp16_split(v, h, l);
        g_Whi[ci * CC * 64 + idx] = h;
        g_Wlo[ci * CC * 64 + idx] = l;
    }
}

// ---------------- kernel 1: adjacency -> fp16 single, a[v][w] K-major ----------------
__global__ void k_adj(const float* __restrict__ E1, const float* __restrict__ E2) {
    int v = blockIdx.x;
    int tid = threadIdx.x;
    if (v >= N_NODE) {
        for (int w = tid; w < NP; w += 256) g_Bh[(size_t)v * NP + w] = __float2half(0.f);
        return;
    }
    __shared__ float e1[ND];
    __shared__ float z[N_NODE];
    __shared__ float red[256];
    if (tid < ND) e1[tid] = E1[v * ND + tid];
    __syncthreads();

    float lmax = -1e30f;
    for (int w = tid; w < N_NODE; w += 256) {
        float acc = 0.f;
#pragma unroll
        for (int k = 0; k < ND; k++) acc += e1[k] * E2[k * N_NODE + w];
        acc = fmaxf(acc, 0.f);
        z[w] = acc;
        lmax = fmaxf(lmax, acc);
    }
    red[tid] = lmax; __syncthreads();
    for (int s = 128; s > 0; s >>= 1) { if (tid < s) red[tid] = fmaxf(red[tid], red[tid + s]); __syncthreads(); }
    float smax = red[0];
    __syncthreads();

    float lsum = 0.f;
    for (int w = tid; w < N_NODE; w += 256) { float e = expf(z[w] - smax); z[w] = e; lsum += e; }
    red[tid] = lsum; __syncthreads();
    for (int s = 128; s > 0; s >>= 1) { if (tid < s) red[tid] += red[tid + s]; __syncthreads(); }
    float inv = 0.5f / red[0];   // a = (softmax + I)/2
    for (int w = tid; w < NP; w += 256) {
        float val = (w < N_NODE) ? (z[w] * inv + ((w == v) ? 0.5f : 0.f)) : 0.f;
        g_Bh[(size_t)v * NP + w] = __float2half_rn(val);
    }
}

// ---------------- kernel 2: start conv on HMMA (im2col in smem, fp16 hi/lo) ----------------
__global__ __launch_bounds__(256, 2) void k_conv_mma(const float* __restrict__ x,
                                                     const float* __restrict__ bias) {
    extern __shared__ char smem[];
    const uint32_t sbase = smem_u32(smem);
    float* xw = (float*)(smem + CV_XW);
    const int tid = threadIdx.x;
    const int wid = tid >> 5, lane = tid & 31;
    const int wm = wid >> 1;
    const int wn = wid & 1;
    const int b  = blockIdx.y;
    const int n0 = blockIdx.x * 128;

#define CV_LOAD_A(ci, stg) do {                                                      \
    _Pragma("unroll")                                                                \
    for (int i = 0; i < 2; i++) {                                                    \
        int idx = tid + i * 256;                                                     \
        int co = idx >> 3, s = idx & 7;                                              \
        uint32_t dst = sbase + CV_A0 + (stg) * CV_A_STG + co * 128 +                 \
                       ((uint32_t)(s ^ (co & 7)) << 4);                              \
        cpa16(dst,            (const char*)(g_Whi + (ci) * CC * 64 + co * 64 + s * 8)); \
        cpa16(dst + CV_A_VAR, (const char*)(g_Wlo + (ci) * CC * 64 + co * 64 + s * 8)); \
    }                                                                                \
} while (0)

#define CV_LOAD_XW(ci, stg) do {                                                     \
    if (tid < 192) {                                                                 \
        int p = n0 + tid;                                                            \
        xw[(stg) * 192 + tid] = (p < DM) ? x[(size_t)b * IN_D * DM + (ci) * DM + p] : 0.f; \
    }                                                                                \
} while (0)

#define CV_BUILD_B(stg) do {                                                         \
    const float* xwp = xw + (stg) * 192;                                             \
    uint32_t bb = sbase + CV_B0 + (stg) * CV_B_STG;                                  \
    _Pragma("unroll")                                                                \
    for (int i = 0; i < 16; i++) {                                                   \
        int idx = tid + i * 256;                                                     \
        int t = idx >> 6, j2 = idx & 63;                                             \
        int n = j2 * 2;                                                              \
        float v0 = xwp[t + n], v1 = xwp[t + n + 1];                                  \
        __half h0, l0, h1, l1;                                                       \
        fp16_split(v0, h0, l0); fp16_split(v1, h1, l1);                              \
        __half2 hh(h0, h1), ll(l0, l1);                                              \
        int s = n >> 3;                                                              \
        uint32_t off = t * 256 + ((uint32_t)(s ^ (t & 7)) << 4) + (j2 & 3) * 4;      \
        *(uint32_t*)(smem + CV_B0 + (stg) * CV_B_STG + off) = *reinterpret_cast<uint32_t*>(&hh); \
        *(uint32_t*)(smem + CV_B0 + (stg) * CV_B_STG + off + CV_B_VAR) = *reinterpret_cast<uint32_t*>(&ll); \
    }                                                                                \
    (void)bb;                                                                        \
} while (0)

    float acc[8][4];
#pragma unroll
    for (int in = 0; in < 8; in++)
#pragma unroll
        for (int q = 0; q < 4; q++) acc[in][q] = 0.f;

    const int a_row = wm * 16 + (lane & 15);
    const int a_jl  = lane >> 4;
    const int b_kl  = ((lane >> 3) & 1) * 8 + (lane & 7);
    const int b_nl  = lane >> 4;

    CV_LOAD_A(0, 0); CPA_COMMIT();
    CV_LOAD_XW(0, 0);
    CPA_WAIT(0);
    __syncthreads();
    CV_BUILD_B(0);
    __syncthreads();

    for (int c = 0; c < IN_D; c++) {
        int stg = c & 1, nstg = (c + 1) & 1;
        if (c + 1 < IN_D) { CV_LOAD_A(c + 1, nstg); CPA_COMMIT(); CV_LOAD_XW(c + 1, nstg); }

        uint32_t astg = sbase + CV_A0 + stg * CV_A_STG;
        uint32_t bstg = sbase + CV_B0 + stg * CV_B_STG;
#pragma unroll
        for (int ks = 0; ks < 4; ks++) {
            uint32_t ah[4], al[4], bh[4][4], bl[4][4];
            {
                int s = 2 * ks + a_jl;
                uint32_t off = (uint32_t)a_row * 128 + ((uint32_t)(s ^ (a_row & 7)) << 4);
                ldsm4(ah, astg + off);
                ldsm4(al, astg + CV_A_VAR + off);
            }
            int krow = ks * 16 + b_kl;
            uint32_t koff = (uint32_t)krow * 256;
            uint32_t kx = (uint32_t)(krow & 7);
#pragma unroll
            for (int q = 0; q < 4; q++) {
                int ns = wn * 8 + 2 * q + b_nl;
                uint32_t off = koff + ((uint32_t)(ns ^ kx) << 4);
                ldsm4t(bh[q], bstg + off);
                ldsm4t(bl[q], bstg + CV_B_VAR + off);
            }
#pragma unroll
            for (int p = 0; p < 3; p++) {
#pragma unroll
                for (int in = 0; in < 8; in++) {
                    const uint32_t* af = (p == 2) ? al : ah;
                    const uint32_t* bf = (p == 1) ? &bl[in >> 1][(in & 1) * 2]
                                                  : &bh[in >> 1][(in & 1) * 2];
                    mma16816(acc[in], af, bf);
                }
            }
        }
        if (c + 1 < IN_D) {
            CPA_WAIT(0);
            __syncthreads();
            CV_BUILD_B(nstg);
            __syncthreads();
        }
    }

    // epilogue: bias add, write fp16 hi/lo hop0, zero pad n>=2000
    const int o0 = wm * 16 + (lane >> 2);
    const int o1 = o0 + 8;
    const float b0v = bias[o0], b1v = bias[o1];
#pragma unroll
    for (int in = 0; in < 8; in++) {
        int n = n0 + wn * 64 + in * 8 + (lane & 3) * 2;
        bool ok = (n < N_NODE);
        float v00 = ok ? (acc[in][0] + b0v) : 0.f;
        float v01 = ok ? (acc[in][1] + b0v) : 0.f;
        float v10 = ok ? (acc[in][2] + b1v) : 0.f;
        float v11 = ok ? (acc[in][3] + b1v) : 0.f;
        size_t r0 = (size_t)(b * CC + o0) * NP + n;
        size_t r1 = (size_t)(b * CC + o1) * NP + n;
        __half h0, l0, h1, l1;
        fp16_split(v00, h0, l0); fp16_split(v01, h1, l1);
        *(__half2*)(g_Ahi + r0) = __half2(h0, h1);
        *(__half2*)(g_Alo + r0) = __half2(l0, l1);
        fp16_split(v10, h0, l0); fp16_split(v11, h1, l1);
        *(__half2*)(g_Ahi + r1) = __half2(h0, h1);
        *(__half2*)(g_Alo + r1) = __half2(l0, l1);
    }
#undef CV_LOAD_A
#undef CV_LOAD_XW
#undef CV_BUILD_B
}

// ---------------- kernel 3: mixprop GEMM on HMMA (fp16, 2-product) ----------------
// D[m][v] = sum_w H_src[m][w] * a[v][w];  C = ALPHA*h0 + BETA*D  (fp16 hi/lo)
__global__ __launch_bounds__(256, 2) void k_mix_mma(int src, int dst) {
    extern __shared__ char smem[];
    const uint32_t sbase = smem_u32(smem);

    const int tid = threadIdx.x;
    const int wid = tid >> 5, lane = tid & 31;
    const int wm = wid >> 2;
    const int wn = wid & 3;
    const int m0 = blockIdx.y * TILE_M;
    const int n0 = blockIdx.x * TILE_N;

    const __half* Ahi = g_Ahi + (size_t)src * MROWS * NP;
    const __half* Alo = g_Alo + (size_t)src * MROWS * NP;

    const int lr = tid >> 1;
    const int ls = (tid & 1) * 2;
    const uint32_t lswz = (uint32_t)((lr >> 1) & 3);   // SW64
    const char* gAhi = (const char*)(Ahi + (size_t)(m0 + lr) * NP);
    const char* gAlo = (const char*)(Alo + (size_t)(m0 + lr) * NP);
    const char* gBh  = (const char*)(g_Bh + (size_t)(n0 + lr) * NP);

#define LOAD_CHUNK(cidx, buf) do {                                                   \
    uint32_t sb = sbase + (buf) * STAGE_BYTES + lr * 64;                             \
    size_t go = (size_t)(cidx) * 64 + ls * 16;                                       \
    _Pragma("unroll")                                                                \
    for (int j = 0; j < 2; j++) {                                                    \
        uint32_t so = ((uint32_t)(ls + j) ^ lswz) << 4;                              \
        cpa16(sb + OFF_AHI + so, gAhi + go + j * 16);                                \
        cpa16(sb + OFF_ALO + so, gAlo + go + j * 16);                                \
        cpa16(sb + OFF_BH  + so, gBh  + go + j * 16);                                \
    }                                                                                \
} while (0)

    float acc[4][4][4];
#pragma unroll
    for (int im = 0; im < 4; im++)
#pragma unroll
        for (int in = 0; in < 4; in++)
#pragma unroll
            for (int q = 0; q < 4; q++) acc[im][in][q] = 0.f;

    const int a_row_l = (lane & 15);
    const int a_jl = lane >> 4;
    const int b_row_l = ((lane >> 4) << 3) + (lane & 7);
    const int b_jl = (lane >> 3) & 1;

    LOAD_CHUNK(0, 0); CPA_COMMIT();
    LOAD_CHUNK(1, 1); CPA_COMMIT();

    int buf = 0, nbuf = 2;
    for (int c = 0; c < NCHUNK_IT; c++) {
        if (c + 1 < NCHUNK_IT) { CPA_WAIT(1); } else { CPA_WAIT(0); }
        __syncthreads();
        if (c + 2 < NCHUNK_IT) { LOAD_CHUNK(c + 2, nbuf); CPA_COMMIT(); }

        uint32_t sb = sbase + buf * STAGE_BYTES;
#pragma unroll
        for (int ks = 0; ks < 2; ks++) {
            uint32_t ah[4][4], al[4][4], bh[2][4];
#pragma unroll
            for (int im = 0; im < 4; im++) {
                int row = wm * 64 + im * 16 + a_row_l;
                uint32_t off = (uint32_t)row * 64 +
                               ((uint32_t)((2 * ks + a_jl) ^ ((row >> 1) & 3)) << 4);
                ldsm4(ah[im], sb + OFF_AHI + off);
                ldsm4(al[im], sb + OFF_ALO + off);
            }
#pragma unroll
            for (int inb = 0; inb < 2; inb++) {
                int row = wn * 32 + inb * 16 + b_row_l;
                uint32_t off = (uint32_t)row * 64 +
                               ((uint32_t)((2 * ks + b_jl) ^ ((row >> 1) & 3)) << 4);
                ldsm4(bh[inb], sb + OFF_BH + off);
            }
#pragma unroll
            for (int p = 0; p < 2; p++) {
#pragma unroll
                for (int im = 0; im < 4; im++) {
#pragma unroll
                    for (int in = 0; in < 4; in++) {
                        const uint32_t* af = (p == 1) ? al[im] : ah[im];
                        mma16816(acc[im][in], af, &bh[in >> 1][(in & 1) * 2]);
                    }
                }
            }
        }
        buf = (buf == NSTAGE - 1) ? 0 : buf + 1;
        nbuf = (nbuf == NSTAGE - 1) ? 0 : nbuf + 1;
    }

    // epilogue: C = ALPHA*(h0 hi+lo) + BETA*acc -> fp16 hi/lo
    const __half* Xh = g_Ahi;
    const __half* Xl = g_Alo;
    __half* Hh = g_Ahi + (size_t)dst * MROWS * NP;
    __half* Hl = g_Alo + (size_t)dst * MROWS * NP;

#pragma unroll
    for (int im = 0; im < 4; im++) {
#pragma unroll
        for (int half = 0; half < 2; half++) {
            int m = m0 + wm * 64 + im * 16 + (lane >> 2) + half * 8;
            size_t rowo = (size_t)m * NP;
#pragma unroll
            for (int in = 0; in < 4; in++) {
                int n = n0 + wn * 32 + in * 8 + (lane & 3) * 2;
                float d0 = acc[im][in][half * 2 + 0];
                float d1 = acc[im][in][half * 2 + 1];
                __half2 xh = *(const __half2*)(Xh + rowo + n);
                __half2 xl = *(const __half2*)(Xl + rowo + n);
                float x0 = __half2float(xh.x) + __half2float(xl.x);
                float x1 = __half2float(xh.y) + __half2float(xl.y);
                float o0 = ALPHA_C * x0 + BETA_C * d0;
                float o1 = ALPHA_C * x1 + BETA_C * d1;
                __half h0, l0, h1, l1;
                fp16_split(o0, h0, l0); fp16_split(o1, h1, l1);
                *(__half2*)(Hh + rowo + n) = __half2(h0, h1);
                *(__half2*)(Hl + rowo + n) = __half2(l0, l1);
            }
        }
    }
#undef LOAD_CHUNK
}

// ---------------- kernel 4: MLP on HMMA + fused GELU + end dot (fp16) ----------------
__global__ __launch_bounds__(256) void k_mlp_mma(const float* __restrict__ wmlp,
                                                 const float* __restrict__ bmlp,
                                                 const float* __restrict__ wend,
                                                 const float* __restrict__ bend) {
    extern __shared__ char smem[];
    __shared__ float red[4][128];
    const uint32_t sbase = smem_u32(smem);
    const int tid = threadIdx.x;
    const int wid = tid >> 5, lane = tid & 31;
    const int wm = wid >> 1;
    const int wn = wid & 1;
    const int b  = blockIdx.y;
    const int n0 = blockIdx.x * 128;

#pragma unroll
    for (int i = 0; i < 8; i++) {
        int idx = tid + i * 256;
        int o = idx >> 5, s = idx & 31;
        const float* wp = wmlp + o * 256 + s * 8;
        float4 v0 = *(const float4*)wp;
        float4 v1 = *(const float4*)(wp + 4);
        float vv[8] = {v0.x, v0.y, v0.z, v0.w, v1.x, v1.y, v1.z, v1.w};
        uint32_t hp[4], lp[4];
#pragma unroll
        for (int j = 0; j < 4; j++) {
            __half h0, l0, h1, l1;
            fp16_split(vv[2 * j], h0, l0);
            fp16_split(vv[2 * j + 1], h1, l1);
            __half2 hh(h0, h1), ll(l0, l1);
            hp[j] = *reinterpret_cast<uint32_t*>(&hh);
            lp[j] = *reinterpret_cast<uint32_t*>(&ll);
        }
        uint32_t phys = (uint32_t)(s ^ (o & 15));
        *(uint4*)(smem + MLP_A_HI + o * 512 + phys * 16) = make_uint4(hp[0], hp[1], hp[2], hp[3]);
        *(uint4*)(smem + MLP_A_LO + o * 512 + phys * 16) = make_uint4(lp[0], lp[1], lp[2], lp[3]);
    }

#define LOAD_BCH(chunk, stg) do {                                                        \
    const __half* HBh = g_Ahi + ((size_t)(chunk) * MROWS + b * 64) * NP + n0;            \
    const __half* HBl = g_Alo + ((size_t)(chunk) * MROWS + b * 64) * NP + n0;            \
    _Pragma("unroll")                                                                    \
    for (int i = 0; i < 4; i++) {                                                        \
        int idx = tid + i * 256;                                                         \
        int k = idx >> 4, s = idx & 15;                                                  \
        uint32_t phys = (uint32_t)(s ^ (k & 7));                                         \
        uint32_t dst = sbase + MLP_B_BASE + (stg) * MLP_B_STG + k * 256 + phys * 16;     \
        cpa16(dst,             (const char*)HBh + (size_t)k * NP * 2 + s * 16);          \
        cpa16(dst + MLP_B_VAR, (const char*)HBl + (size_t)k * NP * 2 + s * 16);          \
    }                                                                                    \
} while (0)

    float acc[8][4];
#pragma unroll
    for (int in = 0; in < 8; in++)
#pragma unroll
        for (int q = 0; q < 4; q++) acc[in][q] = 0.f;

    const int a_row = wm * 16 + (lane & 15);
    const int a_jl  = lane >> 4;
    const int b_kl  = ((lane >> 3) & 1) * 8 + (lane & 7);
    const int b_nl  = lane >> 4;

    LOAD_BCH(0, 0); CPA_COMMIT();

    for (int chunk = 0; chunk < 4; chunk++) {
        CPA_WAIT(0);
        __syncthreads();
        if (chunk < 3) { LOAD_BCH(chunk + 1, (chunk + 1) & 1); CPA_COMMIT(); }
        uint32_t bstg = sbase + MLP_B_BASE + (chunk & 1) * MLP_B_STG;

#pragma unroll
        for (int ks = 0; ks < 4; ks++) {
            int ksg = chunk * 4 + ks;
            uint32_t ah[4], al[4], bh[4][4], bl[4][4];
            {
                int s = 2 * ksg + a_jl;
                uint32_t off = (uint32_t)a_row * 512 + ((uint32_t)(s ^ (a_row & 15)) << 4);
                ldsm4(ah, sbase + MLP_A_HI + off);
                ldsm4(al, sbase + MLP_A_LO + off);
            }
            int krow = ks * 16 + b_kl;
            uint32_t koff = (uint32_t)krow * 256;
            uint32_t kx = (uint32_t)(krow & 7);
#pragma unroll
            for (int q = 0; q < 4; q++) {
                int ns = wn * 8 + 2 * q + b_nl;
                uint32_t off = koff + ((uint32_t)(ns ^ kx) << 4);
                ldsm4t(bh[q], bstg + off);
                ldsm4t(bl[q], bstg + MLP_B_VAR + off);
            }
#pragma unroll
            for (int p = 0; p < 3; p++) {
#pragma unroll
                for (int in = 0; in < 8; in++) {
                    const uint32_t* af = (p == 2) ? al : ah;
                    const uint32_t* bf = (p == 1) ? &bl[in >> 1][(in & 1) * 2]
                                                  : &bh[in >> 1][(in & 1) * 2];
                    mma16816(acc[in], af, bf);
                }
            }
        }
        __syncthreads();
    }

    const int o0 = wm * 16 + (lane >> 2);
    const int o1 = o0 + 8;
    const float bm0 = bmlp[o0], bm1 = bmlp[o1];
    const float we0 = wend[o0], we1 = wend[o1];

#pragma unroll
    for (int in = 0; in < 8; in++) {
        float g00 = gelu_exact(acc[in][0] + bm0);
        float g01 = gelu_exact(acc[in][1] + bm0);
        float g10 = gelu_exact(acc[in][2] + bm1);
        float g11 = gelu_exact(acc[in][3] + bm1);
        float p0 = we0 * g00 + we1 * g10;
        float p1 = we0 * g01 + we1 * g11;
#pragma unroll
        for (int d = 4; d <= 16; d <<= 1) {
            p0 += __shfl_xor_sync(0xFFFFFFFF, p0, d);
            p1 += __shfl_xor_sync(0xFFFFFFFF, p1, d);
        }
        if (lane < 4) {
            red[wm][wn * 64 + in * 8 + lane * 2 + 0] = p0;
            red[wm][wn * 64 + in * 8 + lane * 2 + 1] = p1;
        }
    }
    __syncthreads();
    if (tid < 128) {
        int n = n0 + tid;
        if (n < N_NODE) {
            float s = bend[0] + red[0][tid] + red[1][tid] + red[2][tid] + red[3][tid];
            g_S[(size_t)b * NP + n] = s;
        }
    }
#undef LOAD_BCH
}

// ---------------- kernel 5: final linear (d-tile 32, 64 CTAs) ----------------
__global__ __launch_bounds__(128) void k_lin(const float* __restrict__ wlin,
                                             const float* __restrict__ blin) {
    __shared__ float Ss[64][41];
    __shared__ float Ws[32][41];
    int d0 = blockIdx.x * 32;
    int tid = threadIdx.x;
    int dg = tid >> 3, bg = tid & 7;

    float acc[2][8];
#pragma unroll
    for (int i = 0; i < 2; i++)
#pragma unroll
        for (int j = 0; j < 8; j++) acc[i][j] = 0.f;

    for (int k0 = 0; k0 < N_NODE; k0 += 40) {
        for (int idx = tid; idx < 64 * 40; idx += 128) {
            int bb = idx / 40, kk = idx % 40;
            Ss[bb][kk] = g_S[(size_t)bb * NP + k0 + kk];
        }
        for (int idx = tid; idx < 32 * 40; idx += 128) {
            int dd = idx / 40, kk = idx % 40;
            Ws[dd][kk] = wlin[(size_t)(d0 + dd) * N_NODE + k0 + kk];
        }
        __syncthreads();
#pragma unroll 8
        for (int k = 0; k < 40; k++) {
            float wv[2];
#pragma unroll
            for (int i = 0; i < 2; i++) wv[i] = Ws[dg * 2 + i][k];
#pragma unroll
            for (int j = 0; j < 8; j++) {
                float sv = Ss[bg * 8 + j][k];
#pragma unroll
                for (int i = 0; i < 2; i++) acc[i][j] += wv[i] * sv;
            }
        }
        __syncthreads();
    }
#pragma unroll
    for (int i = 0; i < 2; i++) {
        int d = d0 + dg * 2 + i;
        float bl = blin[d];
#pragma unroll
        for (int j = 0; j < 8; j++) {
            int bb = bg * 8 + j;
            g_Y[(size_t)bb * DM + d] = acc[i][j] + bl;
        }
    }
}

// ---------------- kernel 6: layernorm ----------------
__global__ void k_ln(const float* __restrict__ gam, const float* __restrict__ bet,
                     float* __restrict__ out) {
    int b = blockIdx.x;
    int tid = threadIdx.x;
    __shared__ float red[256];
    const float* y = g_Y + (size_t)b * DM;

    float s = 0.f;
    for (int d = tid; d < DM; d += 256) s += y[d];
    red[tid] = s; __syncthreads();
    for (int st = 128; st > 0; st >>= 1) { if (tid < st) red[tid] += red[tid + st]; __syncthreads(); }
    float mu = red[0] / DM;
    __syncthreads();

    float v = 0.f;
    for (int d = tid; d < DM; d += 256) { float t = y[d] - mu; v += t * t; }
    red[tid] = v; __syncthreads();
    for (int st = 128; st > 0; st >>= 1) { if (tid < st) red[tid] += red[tid + st]; __syncthreads(); }
    float rinv = rsqrtf(red[0] / DM + 1e-5f);

    for (int d = tid; d < DM; d += 256)
        out[(size_t)b * DM + d] = (y[d] - mu) * rinv * gam[d] + bet[d];
}

// ---------------- launch ----------------
extern "C" void kernel_launch(void* const* d_in, const int* in_sizes, int n_in,
                              void* d_out, int out_size) {
    const float* x       = (const float*)d_in[0];
    const float* nv1     = (const float*)d_in[1];
    const float* nv2     = (const float*)d_in[2];
    const float* w_start = (const float*)d_in[3];
    const float* b_start = (const float*)d_in[4];
    const float* w_mlp   = (const float*)d_in[5];
    const float* b_mlp   = (const float*)d_in[6];
    const float* w_end   = (const float*)d_in[7];
    const float* b_end   = (const float*)d_in[8];
    const float* w_lin   = (const float*)d_in[9];
    const float* b_lin   = (const float*)d_in[10];
    const float* ln_g    = (const float*)d_in[11];
    const float* ln_b    = (const float*)d_in[12];
    float* out = (float*)d_out;

    cudaFuncSetAttribute(k_mix_mma,  cudaFuncAttributeMaxDynamicSharedMemorySize, MIX_SMEM);
    cudaFuncSetAttribute(k_mlp_mma,  cudaFuncAttributeMaxDynamicSharedMemorySize, MLP_SMEM);
    cudaFuncSetAttribute(k_conv_mma, cudaFuncAttributeMaxDynamicSharedMemorySize, CV_SMEM);

    k_prepw<<<IN_D, 256>>>(w_start);
    k_adj<<<NP, 256>>>(nv1, nv2);
    k_conv_mma<<<dim3(NP / 128, BATCH), 256, CV_SMEM>>>(x, b_start);
    dim3 mixg(NP / TILE_N, MROWS / TILE_M);
    k_mix_mma<<<mixg, 256, MIX_SMEM>>>(0, 1);
    k_mix_mma<<<mixg, 256, MIX_SMEM>>>(1, 2);
    k_mix_mma<<<mixg, 256, MIX_SMEM>>>(2, 3);
    k_mlp_mma<<<dim3(NP / 128, BATCH), 256, MLP_SMEM>>>(w_mlp, b_mlp, w_end, b_end);
    k_lin<<<DM / 32, 128>>>(w_lin, b_lin);
    k_ln<<<BATCH, 256>>>(ln_g, ln_b, out);
}

// round 9
// speedup vs baseline: 3.8383x; 1.2688x over previous
#include <cuda_runtime.h>
#include <cuda_fp16.h>
#include <math.h>
#include <stdint.h>

// ---------------- problem constants ----------------
#define N_NODE 2000
#define NP     2048
#define BATCH  64
#define CC     64
#define MROWS  (BATCH*CC)    // 4096
#define DM     2048
#define IN_D   7
#define KW     49
#define ND     40
#define ALPHA_C 0.05f
#define BETA_C  0.95f

// mix GEMM tiling: k-chunk 32 (64B rows), 2 tiles (Ah, Bh) per stage
#define KC      32
#define NCHUNK_IT 63                  // chunks 0..62 cover k=0..2015; 63 all-zero
#define TILE_M  128
#define TILE_N  128
#define VAR_BYTES (128 * 64)          // 8192 B
#define OFF_AH  0
#define OFF_BH  (VAR_BYTES)
#define STAGE_BYTES (2 * VAR_BYTES)   // 16384
#define NSTAGE  3
#define MIX_SMEM (NSTAGE * STAGE_BYTES)  // 49152 -> 2 CTAs/SM (regs bind)

// mlp GEMM smem layout
#define MLP_A_HI   0
#define MLP_A_LO   32768
#define MLP_B_BASE 65536
#define MLP_B_STG  32768
#define MLP_B_VAR  16384
#define MLP_SMEM   131072

// conv GEMM smem layout
#define CV_A_STG   16384
#define CV_A_VAR   8192
#define CV_B_STG   32768
#define CV_B_VAR   16384
#define CV_A0      0
#define CV_B0      (2 * CV_A_STG)
#define CV_XW      (CV_B0 + 2 * CV_B_STG)
#define CV_SMEM    (CV_XW + 2 * 768)

// ---------------- scratch ----------------
__device__ __half  g_Ahi[4 * MROWS * NP];   // fp16 hi of hops
__device__ __half  g_Alo[4 * MROWS * NP];   // fp16 lo of hops
__device__ __half  g_Bh[NP * NP];           // adjacency a[v][w], fp16 single
__device__ __half  g_Whi[IN_D * CC * 64];   // conv weights hi [ci][co][64]
__device__ __half  g_Wlo[IN_D * CC * 64];
__device__ float   g_S[BATCH * NP];
__device__ float   g_Y[BATCH * DM];

// ---------------- helpers ----------------
__device__ __forceinline__ uint32_t smem_u32(const void* p) {
    uint32_t a;
    asm("{ .reg .u64 t; cvta.to.shared.u64 t, %1; cvt.u32.u64 %0, t; }" : "=r"(a) : "l"(p));
    return a;
}
__device__ __forceinline__ void cpa16(uint32_t s, const void* g) {
    asm volatile("cp.async.cg.shared.global [%0], [%1], 16;" :: "r"(s), "l"(g));
}
#define CPA_COMMIT() asm volatile("cp.async.commit_group;" ::: "memory")
#define CPA_WAIT(n)  asm volatile("cp.async.wait_group %0;" :: "n"(n) : "memory")

__device__ __forceinline__ void ldsm4(uint32_t* r, uint32_t addr) {
    asm volatile("ldmatrix.sync.aligned.m8n8.x4.shared.b16 {%0,%1,%2,%3}, [%4];"
                 : "=r"(r[0]), "=r"(r[1]), "=r"(r[2]), "=r"(r[3]) : "r"(addr));
}
__device__ __forceinline__ void ldsm4t(uint32_t* r, uint32_t addr) {
    asm volatile("ldmatrix.sync.aligned.m8n8.x4.trans.shared.b16 {%0,%1,%2,%3}, [%4];"
                 : "=r"(r[0]), "=r"(r[1]), "=r"(r[2]), "=r"(r[3]) : "r"(addr));
}
__device__ __forceinline__ void mma16816(float* d, const uint32_t* a, const uint32_t* b) {
    asm volatile("mma.sync.aligned.m16n8k16.row.col.f32.f16.f16.f32 "
                 "{%0,%1,%2,%3}, {%4,%5,%6,%7}, {%8,%9}, {%0,%1,%2,%3};"
                 : "+f"(d[0]), "+f"(d[1]), "+f"(d[2]), "+f"(d[3])
                 : "r"(a[0]), "r"(a[1]), "r"(a[2]), "r"(a[3]), "r"(b[0]), "r"(b[1]));
}
__device__ __forceinline__ void fp16_split(float v, __half& hi, __half& lo) {
    hi = __float2half_rn(v);
    lo = __float2half_rn(v - __half2float(hi));
}
__device__ __forceinline__ float gelu_exact(float v) {
    return 0.5f * v * (1.f + erff(v * 0.70710678118654752f));
}

// ---------------- kernel 0: prep conv weights -> fp16 hi/lo [ci][co][64] ----------------
__global__ void k_prepw(const float* __restrict__ w) {
    int ci = blockIdx.x;
    for (int idx = threadIdx.x; idx < CC * 64; idx += 256) {
        int co = idx >> 6, t = idx & 63;
        float v = (t < KW) ? w[co * (IN_D * KW) + ci * KW + t] : 0.f;
        __half h, l; fp16_split(v, h, l);
        g_Whi[ci * CC * 64 + idx] = h;
        g_Wlo[ci * CC * 64 + idx] = l;
    }
}

// ---------------- kernel 1: adjacency -> fp16 single, a[v][w] K-major ----------------
__global__ void k_adj(const float* __restrict__ E1, const float* __restrict__ E2) {
    int v = blockIdx.x;
    int tid = threadIdx.x;
    if (v >= N_NODE) {
        for (int w = tid; w < NP; w += 256) g_Bh[(size_t)v * NP + w] = __float2half(0.f);
        return;
    }
    __shared__ float e1[ND];
    __shared__ float z[N_NODE];
    __shared__ float red[256];
    if (tid < ND) e1[tid] = E1[v * ND + tid];
    __syncthreads();

    float lmax = -1e30f;
    for (int w = tid; w < N_NODE; w += 256) {
        float acc = 0.f;
#pragma unroll
        for (int k = 0; k < ND; k++) acc += e1[k] * E2[k * N_NODE + w];
        acc = fmaxf(acc, 0.f);
        z[w] = acc;
        lmax = fmaxf(lmax, acc);
    }
    red[tid] = lmax; __syncthreads();
    for (int s = 128; s > 0; s >>= 1) { if (tid < s) red[tid] = fmaxf(red[tid], red[tid + s]); __syncthreads(); }
    float smax = red[0];
    __syncthreads();

    float lsum = 0.f;
    for (int w = tid; w < N_NODE; w += 256) { float e = expf(z[w] - smax); z[w] = e; lsum += e; }
    red[tid] = lsum; __syncthreads();
    for (int s = 128; s > 0; s >>= 1) { if (tid < s) red[tid] += red[tid + s]; __syncthreads(); }
    float inv = 0.5f / red[0];   // a = (softmax + I)/2
    for (int w = tid; w < NP; w += 256) {
        float val = (w < N_NODE) ? (z[w] * inv + ((w == v) ? 0.5f : 0.f)) : 0.f;
        g_Bh[(size_t)v * NP + w] = __float2half_rn(val);
    }
}

// ---------------- kernel 2: start conv on HMMA (im2col in smem, fp16 hi/lo) ----------------
__global__ __launch_bounds__(256, 2) void k_conv_mma(const float* __restrict__ x,
                                                     const float* __restrict__ bias) {
    extern __shared__ char smem[];
    const uint32_t sbase = smem_u32(smem);
    float* xw = (float*)(smem + CV_XW);
    const int tid = threadIdx.x;
    const int wid = tid >> 5, lane = tid & 31;
    const int wm = wid >> 1;
    const int wn = wid & 1;
    const int b  = blockIdx.y;
    const int n0 = blockIdx.x * 128;

#define CV_LOAD_A(ci, stg) do {                                                      \
    _Pragma("unroll")                                                                \
    for (int i = 0; i < 2; i++) {                                                    \
        int idx = tid + i * 256;                                                     \
        int co = idx >> 3, s = idx & 7;                                              \
        uint32_t dst = sbase + CV_A0 + (stg) * CV_A_STG + co * 128 +                 \
                       ((uint32_t)(s ^ (co & 7)) << 4);                              \
        cpa16(dst,            (const char*)(g_Whi + (ci) * CC * 64 + co * 64 + s * 8)); \
        cpa16(dst + CV_A_VAR, (const char*)(g_Wlo + (ci) * CC * 64 + co * 64 + s * 8)); \
    }                                                                                \
} while (0)

#define CV_LOAD_XW(ci, stg) do {                                                     \
    if (tid < 192) {                                                                 \
        int p = n0 + tid;                                                            \
        xw[(stg) * 192 + tid] = (p < DM) ? x[(size_t)b * IN_D * DM + (ci) * DM + p] : 0.f; \
    }                                                                                \
} while (0)

#define CV_BUILD_B(stg) do {                                                         \
    const float* xwp = xw + (stg) * 192;                                             \
    _Pragma("unroll")                                                                \
    for (int i = 0; i < 16; i++) {                                                   \
        int idx = tid + i * 256;                                                     \
        int t = idx >> 6, j2 = idx & 63;                                             \
        int n = j2 * 2;                                                              \
        float v0 = xwp[t + n], v1 = xwp[t + n + 1];                                  \
        __half h0, l0, h1, l1;                                                       \
        fp16_split(v0, h0, l0); fp16_split(v1, h1, l1);                              \
        __half2 hh(h0, h1), ll(l0, l1);                                              \
        int s = n >> 3;                                                              \
        uint32_t off = t * 256 + ((uint32_t)(s ^ (t & 7)) << 4) + (j2 & 3) * 4;      \
        *(uint32_t*)(smem + CV_B0 + (stg) * CV_B_STG + off) = *reinterpret_cast<uint32_t*>(&hh); \
        *(uint32_t*)(smem + CV_B0 + (stg) * CV_B_STG + off + CV_B_VAR) = *reinterpret_cast<uint32_t*>(&ll); \
    }                                                                                \
} while (0)

    float acc[8][4];
#pragma unroll
    for (int in = 0; in < 8; in++)
#pragma unroll
        for (int q = 0; q < 4; q++) acc[in][q] = 0.f;

    const int a_row = wm * 16 + (lane & 15);
    const int a_jl  = lane >> 4;
    const int b_kl  = ((lane >> 3) & 1) * 8 + (lane & 7);
    const int b_nl  = lane >> 4;

    CV_LOAD_A(0, 0); CPA_COMMIT();
    CV_LOAD_XW(0, 0);
    CPA_WAIT(0);
    __syncthreads();
    CV_BUILD_B(0);
    __syncthreads();

    for (int c = 0; c < IN_D; c++) {
        int stg = c & 1, nstg = (c + 1) & 1;
        if (c + 1 < IN_D) { CV_LOAD_A(c + 1, nstg); CPA_COMMIT(); CV_LOAD_XW(c + 1, nstg); }

        uint32_t astg = sbase + CV_A0 + stg * CV_A_STG;
        uint32_t bstg = sbase + CV_B0 + stg * CV_B_STG;
#pragma unroll
        for (int ks = 0; ks < 4; ks++) {
            uint32_t ah[4], al[4], bh[4][4], bl[4][4];
            {
                int s = 2 * ks + a_jl;
                uint32_t off = (uint32_t)a_row * 128 + ((uint32_t)(s ^ (a_row & 7)) << 4);
                ldsm4(ah, astg + off);
                ldsm4(al, astg + CV_A_VAR + off);
            }
            int krow = ks * 16 + b_kl;
            uint32_t koff = (uint32_t)krow * 256;
            uint32_t kx = (uint32_t)(krow & 7);
#pragma unroll
            for (int q = 0; q < 4; q++) {
                int ns = wn * 8 + 2 * q + b_nl;
                uint32_t off = koff + ((uint32_t)(ns ^ kx) << 4);
                ldsm4t(bh[q], bstg + off);
                ldsm4t(bl[q], bstg + CV_B_VAR + off);
            }
#pragma unroll
            for (int p = 0; p < 3; p++) {
#pragma unroll
                for (int in = 0; in < 8; in++) {
                    const uint32_t* af = (p == 2) ? al : ah;
                    const uint32_t* bf = (p == 1) ? &bl[in >> 1][(in & 1) * 2]
                                                  : &bh[in >> 1][(in & 1) * 2];
                    mma16816(acc[in], af, bf);
                }
            }
        }
        if (c + 1 < IN_D) {
            CPA_WAIT(0);
            __syncthreads();
            CV_BUILD_B(nstg);
            __syncthreads();
        }
    }

    // epilogue: bias add, write fp16 hi/lo hop0, zero pad n>=2000
    const int o0 = wm * 16 + (lane >> 2);
    const int o1 = o0 + 8;
    const float b0v = bias[o0], b1v = bias[o1];
#pragma unroll
    for (int in = 0; in < 8; in++) {
        int n = n0 + wn * 64 + in * 8 + (lane & 3) * 2;
        bool ok = (n < N_NODE);
        float v00 = ok ? (acc[in][0] + b0v) : 0.f;
        float v01 = ok ? (acc[in][1] + b0v) : 0.f;
        float v10 = ok ? (acc[in][2] + b1v) : 0.f;
        float v11 = ok ? (acc[in][3] + b1v) : 0.f;
        size_t r0 = (size_t)(b * CC + o0) * NP + n;
        size_t r1 = (size_t)(b * CC + o1) * NP + n;
        __half h0, l0, h1, l1;
        fp16_split(v00, h0, l0); fp16_split(v01, h1, l1);
        *(__half2*)(g_Ahi + r0) = __half2(h0, h1);
        *(__half2*)(g_Alo + r0) = __half2(l0, l1);
        fp16_split(v10, h0, l0); fp16_split(v11, h1, l1);
        *(__half2*)(g_Ahi + r1) = __half2(h0, h1);
        *(__half2*)(g_Alo + r1) = __half2(l0, l1);
    }
#undef CV_LOAD_A
#undef CV_LOAD_XW
#undef CV_BUILD_B
}

// ---------------- kernel 3: mixprop GEMM on HMMA (fp16 single-product) ----------------
// D[m][v] = sum_w Hhi_src[m][w] * a[v][w];  C = ALPHA*h0 + BETA*D  (fp16 hi/lo)
__global__ __launch_bounds__(256, 2) void k_mix_mma(int src, int dst) {
    extern __shared__ char smem[];
    const uint32_t sbase = smem_u32(smem);

    const int tid = threadIdx.x;
    const int wid = tid >> 5, lane = tid & 31;
    const int wm = wid >> 2;
    const int wn = wid & 3;
    const int m0 = blockIdx.y * TILE_M;
    const int n0 = blockIdx.x * TILE_N;

    const __half* Ahi = g_Ahi + (size_t)src * MROWS * NP;

    const int lr = tid >> 1;
    const int ls = (tid & 1) * 2;
    const uint32_t lswz = (uint32_t)((lr >> 1) & 3);   // SW64
    const char* gAhi = (const char*)(Ahi + (size_t)(m0 + lr) * NP);
    const char* gBh  = (const char*)(g_Bh + (size_t)(n0 + lr) * NP);

#define LOAD_CHUNK(cidx, buf) do {                                                   \
    uint32_t sb = sbase + (buf) * STAGE_BYTES + lr * 64;                             \
    size_t go = (size_t)(cidx) * 64 + ls * 16;                                       \
    _Pragma("unroll")                                                                \
    for (int j = 0; j < 2; j++) {                                                    \
        uint32_t so = ((uint32_t)(ls + j) ^ lswz) << 4;                              \
        cpa16(sb + OFF_AH + so, gAhi + go + j * 16);                                 \
        cpa16(sb + OFF_BH + so, gBh  + go + j * 16);                                 \
    }                                                                                \
} while (0)

    float acc[4][4][4];
#pragma unroll
    for (int im = 0; im < 4; im++)
#pragma unroll
        for (int in = 0; in < 4; in++)
#pragma unroll
            for (int q = 0; q < 4; q++) acc[im][in][q] = 0.f;

    const int a_row_l = (lane & 15);
    const int a_jl = lane >> 4;
    const int b_row_l = ((lane >> 4) << 3) + (lane & 7);
    const int b_jl = (lane >> 3) & 1;

    LOAD_CHUNK(0, 0); CPA_COMMIT();
    LOAD_CHUNK(1, 1); CPA_COMMIT();

    int buf = 0, nbuf = 2;
    for (int c = 0; c < NCHUNK_IT; c++) {
        if (c + 1 < NCHUNK_IT) { CPA_WAIT(1); } else { CPA_WAIT(0); }
        __syncthreads();
        if (c + 2 < NCHUNK_IT) { LOAD_CHUNK(c + 2, nbuf); CPA_COMMIT(); }

        uint32_t sb = sbase + buf * STAGE_BYTES;
#pragma unroll
        for (int ks = 0; ks < 2; ks++) {
            uint32_t ah[4][4], bh[2][4];
#pragma unroll
            for (int im = 0; im < 4; im++) {
                int row = wm * 64 + im * 16 + a_row_l;
                uint32_t off = (uint32_t)row * 64 +
                               ((uint32_t)((2 * ks + a_jl) ^ ((row >> 1) & 3)) << 4);
                ldsm4(ah[im], sb + OFF_AH + off);
            }
#pragma unroll
            for (int inb = 0; inb < 2; inb++) {
                int row = wn * 32 + inb * 16 + b_row_l;
                uint32_t off = (uint32_t)row * 64 +
                               ((uint32_t)((2 * ks + b_jl) ^ ((row >> 1) & 3)) << 4);
                ldsm4(bh[inb], sb + OFF_BH + off);
            }
#pragma unroll
            for (int im = 0; im < 4; im++) {
#pragma unroll
                for (int in = 0; in < 4; in++) {
                    mma16816(acc[im][in], ah[im], &bh[in >> 1][(in & 1) * 2]);
                }
            }
        }
        buf = (buf == NSTAGE - 1) ? 0 : buf + 1;
        nbuf = (nbuf == NSTAGE - 1) ? 0 : nbuf + 1;
    }

    // epilogue: C = ALPHA*(h0 hi+lo) + BETA*acc -> fp16 hi/lo
    const __half* Xh = g_Ahi;
    const __half* Xl = g_Alo;
    __half* Hh = g_Ahi + (size_t)dst * MROWS * NP;
    __half* Hl = g_Alo + (size_t)dst * MROWS * NP;

#pragma unroll
    for (int im = 0; im < 4; im++) {
#pragma unroll
        for (int half = 0; half < 2; half++) {
            int m = m0 + wm * 64 + im * 16 + (lane >> 2) + half * 8;
            size_t rowo = (size_t)m * NP;
#pragma unroll
            for (int in = 0; in < 4; in++) {
                int n = n0 + wn * 32 + in * 8 + (lane & 3) * 2;
                float d0 = acc[im][in][half * 2 + 0];
                float d1 = acc[im][in][half * 2 + 1];
                __half2 xh = *(const __half2*)(Xh + rowo + n);
                __half2 xl = *(const __half2*)(Xl + rowo + n);
                float x0 = __half2float(xh.x) + __half2float(xl.x);
                float x1 = __half2float(xh.y) + __half2float(xl.y);
                float o0 = ALPHA_C * x0 + BETA_C * d0;
                float o1 = ALPHA_C * x1 + BETA_C * d1;
                __half h0, l0, h1, l1;
                fp16_split(o0, h0, l0); fp16_split(o1, h1, l1);
                *(__half2*)(Hh + rowo + n) = __half2(h0, h1);
                *(__half2*)(Hl + rowo + n) = __half2(l0, l1);
            }
        }
    }
#undef LOAD_CHUNK
}

// ---------------- kernel 4: MLP on HMMA + fused GELU + end dot (fp16) ----------------
__global__ __launch_bounds__(256) void k_mlp_mma(const float* __restrict__ wmlp,
                                                 const float* __restrict__ bmlp,
                                                 const float* __restrict__ wend,
                                                 const float* __restrict__ bend) {
    extern __shared__ char smem[];
    __shared__ float red[4][128];
    const uint32_t sbase = smem_u32(smem);
    const int tid = threadIdx.x;
    const int wid = tid >> 5, lane = tid & 31;
    const int wm = wid >> 1;
    const int wn = wid & 1;
    const int b  = blockIdx.y;
    const int n0 = blockIdx.x * 128;

#pragma unroll
    for (int i = 0; i < 8; i++) {
        int idx = tid + i * 256;
        int o = idx >> 5, s = idx & 31;
        const float* wp = wmlp + o * 256 + s * 8;
        float4 v0 = *(const float4*)wp;
        float4 v1 = *(const float4*)(wp + 4);
        float vv[8] = {v0.x, v0.y, v0.z, v0.w, v1.x, v1.y, v1.z, v1.w};
        uint32_t hp[4], lp[4];
#pragma unroll
        for (int j = 0; j < 4; j++) {
            __half h0, l0, h1, l1;
            fp16_split(vv[2 * j], h0, l0);
            fp16_split(vv[2 * j + 1], h1, l1);
            __half2 hh(h0, h1), ll(l0, l1);
            hp[j] = *reinterpret_cast<uint32_t*>(&hh);
            lp[j] = *reinterpret_cast<uint32_t*>(&ll);
        }
        uint32_t phys = (uint32_t)(s ^ (o & 15));
        *(uint4*)(smem + MLP_A_HI + o * 512 + phys * 16) = make_uint4(hp[0], hp[1], hp[2], hp[3]);
        *(uint4*)(smem + MLP_A_LO + o * 512 + phys * 16) = make_uint4(lp[0], lp[1], lp[2], lp[3]);
    }

#define LOAD_BCH(chunk, stg) do {                                                        \
    const __half* HBh = g_Ahi + ((size_t)(chunk) * MROWS + b * 64) * NP + n0;            \
    const __half* HBl = g_Alo + ((size_t)(chunk) * MROWS + b * 64) * NP + n0;            \
    _Pragma("unroll")                                                                    \
    for (int i = 0; i < 4; i++) {                                                        \
        int idx = tid + i * 256;                                                         \
        int k = idx >> 4, s = idx & 15;                                                  \
        uint32_t phys = (uint32_t)(s ^ (k & 7));                                         \
        uint32_t dst = sbase + MLP_B_BASE + (stg) * MLP_B_STG + k * 256 + phys * 16;     \
        cpa16(dst,             (const char*)HBh + (size_t)k * NP * 2 + s * 16);          \
        cpa16(dst + MLP_B_VAR, (const char*)HBl + (size_t)k * NP * 2 + s * 16);          \
    }                                                                                    \
} while (0)

    float acc[8][4];
#pragma unroll
    for (int in = 0; in < 8; in++)
#pragma unroll
        for (int q = 0; q < 4; q++) acc[in][q] = 0.f;

    const int a_row = wm * 16 + (lane & 15);
    const int a_jl  = lane >> 4;
    const int b_kl  = ((lane >> 3) & 1) * 8 + (lane & 7);
    const int b_nl  = lane >> 4;

    LOAD_BCH(0, 0); CPA_COMMIT();

    for (int chunk = 0; chunk < 4; chunk++) {
        CPA_WAIT(0);
        __syncthreads();
        if (chunk < 3) { LOAD_BCH(chunk + 1, (chunk + 1) & 1); CPA_COMMIT(); }
        uint32_t bstg = sbase + MLP_B_BASE + (chunk & 1) * MLP_B_STG;

#pragma unroll
        for (int ks = 0; ks < 4; ks++) {
            int ksg = chunk * 4 + ks;
            uint32_t ah[4], al[4], bh[4][4], bl[4][4];
            {
                int s = 2 * ksg + a_jl;
                uint32_t off = (uint32_t)a_row * 512 + ((uint32_t)(s ^ (a_row & 15)) << 4);
                ldsm4(ah, sbase + MLP_A_HI + off);
                ldsm4(al, sbase + MLP_A_LO + off);
            }
            int krow = ks * 16 + b_kl;
            uint32_t koff = (uint32_t)krow * 256;
            uint32_t kx = (uint32_t)(krow & 7);
#pragma unroll
            for (int q = 0; q < 4; q++) {
                int ns = wn * 8 + 2 * q + b_nl;
                uint32_t off = koff + ((uint32_t)(ns ^ kx) << 4);
                ldsm4t(bh[q], bstg + off);
                ldsm4t(bl[q], bstg + MLP_B_VAR + off);
            }
#pragma unroll
            for (int p = 0; p < 3; p++) {
#pragma unroll
                for (int in = 0; in < 8; in++) {
                    const uint32_t* af = (p == 2) ? al : ah;
                    const uint32_t* bf = (p == 1) ? &bl[in >> 1][(in & 1) * 2]
                                                  : &bh[in >> 1][(in & 1) * 2];
                    mma16816(acc[in], af, bf);
                }
            }
        }
        __syncthreads();
    }

    const int o0 = wm * 16 + (lane >> 2);
    const int o1 = o0 + 8;
    const float bm0 = bmlp[o0], bm1 = bmlp[o1];
    const float we0 = wend[o0], we1 = wend[o1];

#pragma unroll
    for (int in = 0; in < 8; in++) {
        float g00 = gelu_exact(acc[in][0] + bm0);
        float g01 = gelu_exact(acc[in][1] + bm0);
        float g10 = gelu_exact(acc[in][2] + bm1);
        float g11 = gelu_exact(acc[in][3] + bm1);
        float p0 = we0 * g00 + we1 * g10;
        float p1 = we0 * g01 + we1 * g11;
#pragma unroll
        for (int d = 4; d <= 16; d <<= 1) {
            p0 += __shfl_xor_sync(0xFFFFFFFF, p0, d);
            p1 += __shfl_xor_sync(0xFFFFFFFF, p1, d);
        }
        if (lane < 4) {
            red[wm][wn * 64 + in * 8 + lane * 2 + 0] = p0;
            red[wm][wn * 64 + in * 8 + lane * 2 + 1] = p1;
        }
    }
    __syncthreads();
    if (tid < 128) {
        int n = n0 + tid;
        if (n < N_NODE) {
            float s = bend[0] + red[0][tid] + red[1][tid] + red[2][tid] + red[3][tid];
            g_S[(size_t)b * NP + n] = s;
        }
    }
#undef LOAD_BCH
}

// ---------------- kernel 5: final linear (d-tile 32, 64 CTAs) ----------------
__global__ __launch_bounds__(128) void k_lin(const float* __restrict__ wlin,
                                             const float* __restrict__ blin) {
    __shared__ float Ss[64][41];
    __shared__ float Ws[32][41];
    int d0 = blockIdx.x * 32;
    int tid = threadIdx.x;
    int dg = tid >> 3, bg = tid & 7;

    float acc[2][8];
#pragma unroll
    for (int i = 0; i < 2; i++)
#pragma unroll
        for (int j = 0; j < 8; j++) acc[i][j] = 0.f;

    for (int k0 = 0; k0 < N_NODE; k0 += 40) {
        for (int idx = tid; idx < 64 * 40; idx += 128) {
            int bb = idx / 40, kk = idx % 40;
            Ss[bb][kk] = g_S[(size_t)bb * NP + k0 + kk];
        }
        for (int idx = tid; idx < 32 * 40; idx += 128) {
            int dd = idx / 40, kk = idx % 40;
            Ws[dd][kk] = wlin[(size_t)(d0 + dd) * N_NODE + k0 + kk];
        }
        __syncthreads();
#pragma unroll 8
        for (int k = 0; k < 40; k++) {
            float wv[2];
#pragma unroll
            for (int i = 0; i < 2; i++) wv[i] = Ws[dg * 2 + i][k];
#pragma unroll
            for (int j = 0; j < 8; j++) {
                float sv = Ss[bg * 8 + j][k];
#pragma unroll
                for (int i = 0; i < 2; i++) acc[i][j] += wv[i] * sv;
            }
        }
        __syncthreads();
    }
#pragma unroll
    for (int i = 0; i < 2; i++) {
        int d = d0 + dg * 2 + i;
        float bl = blin[d];
#pragma unroll
        for (int j = 0; j < 8; j++) {
            int bb = bg * 8 + j;
            g_Y[(size_t)bb * DM + d] = acc[i][j] + bl;
        }
    }
}

// ---------------- kernel 6: layernorm ----------------
__global__ void k_ln(const float* __restrict__ gam, const float* __restrict__ bet,
                     float* __restrict__ out) {
    int b = blockIdx.x;
    int tid = threadIdx.x;
    __shared__ float red[256];
    const float* y = g_Y + (size_t)b * DM;

    float s = 0.f;
    for (int d = tid; d < DM; d += 256) s += y[d];
    red[tid] = s; __syncthreads();
    for (int st = 128; st > 0; st >>= 1) { if (tid < st) red[tid] += red[tid + st]; __syncthreads(); }
    float mu = red[0] / DM;
    __syncthreads();

    float v = 0.f;
    for (int d = tid; d < DM; d += 256) { float t = y[d] - mu; v += t * t; }
    red[tid] = v; __syncthreads();
    for (int st = 128; st > 0; st >>= 1) { if (tid < st) red[tid] += red[tid + st]; __syncthreads(); }
    float rinv = rsqrtf(red[0] / DM + 1e-5f);

    for (int d = tid; d < DM; d += 256)
        out[(size_t)b * DM + d] = (y[d] - mu) * rinv * gam[d] + bet[d];
}

// ---------------- launch ----------------
extern "C" void kernel_launch(void* const* d_in, const int* in_sizes, int n_in,
                              void* d_out, int out_size) {
    const float* x       = (const float*)d_in[0];
    const float* nv1     = (const float*)d_in[1];
    const float* nv2     = (const float*)d_in[2];
    const float* w_start = (const float*)d_in[3];
    const float* b_start = (const float*)d_in[4];
    const float* w_mlp   = (const float*)d_in[5];
    const float* b_mlp   = (const float*)d_in[6];
    const float* w_end   = (const float*)d_in[7];
    const float* b_end   = (const float*)d_in[8];
    const float* w_lin   = (const float*)d_in[9];
    const float* b_lin   = (const float*)d_in[10];
    const float* ln_g    = (const float*)d_in[11];
    const float* ln_b    = (const float*)d_in[12];
    float* out = (float*)d_out;

    cudaFuncSetAttribute(k_mix_mma,  cudaFuncAttributeMaxDynamicSharedMemorySize, MIX_SMEM);
    cudaFuncSetAttribute(k_mlp_mma,  cudaFuncAttributeMaxDynamicSharedMemorySize, MLP_SMEM);
    cudaFuncSetAttribute(k_conv_mma, cudaFuncAttributeMaxDynamicSharedMemorySize, CV_SMEM);

    k_prepw<<<IN_D, 256>>>(w_start);
    k_adj<<<NP, 256>>>(nv1, nv2);
    k_conv_mma<<<dim3(NP / 128, BATCH), 256, CV_SMEM>>>(x, b_start);
    dim3 mixg(NP / TILE_N, MROWS / TILE_M);
    k_mix_mma<<<mixg, 256, MIX_SMEM>>>(0, 1);
    k_mix_mma<<<mixg, 256, MIX_SMEM>>>(1, 2);
    k_mix_mma<<<mixg, 256, MIX_SMEM>>>(2, 3);
    k_mlp_mma<<<dim3(NP / 128, BATCH), 256, MLP_SMEM>>>(w_mlp, b_mlp, w_end, b_end);
    k_lin<<<DM / 32, 128>>>(w_lin, b_lin);
    k_ln<<<BATCH, 256>>>(ln_g, ln_b, out);
}

// round 10
// speedup vs baseline: 5.3427x; 1.3919x over previous
#include <cuda_runtime.h>
#include <cuda_fp16.h>
#include <math.h>
#include <stdint.h>

// ---------------- problem constants ----------------
#define N_NODE 2000
#define NP     2048
#define BATCH  64
#define CC     64
#define MROWS  (BATCH*CC)    // 4096
#define DM     2048
#define IN_D   7
#define KW     49
#define ND     40
#define ALPHA_C 0.05f
#define BETA_C  0.95f

// mix GEMM tiling: k-chunk 64 (128B rows, SW128), 2 tiles (Ah, Bh) per stage
#define NCHUNK  32
#define TILE_M  128
#define TILE_N  128
#define VAR_BYTES (128 * 128)         // 16384 B
#define OFF_AH  0
#define OFF_BH  (VAR_BYTES)
#define STAGE_BYTES (2 * VAR_BYTES)   // 32768
#define NSTAGE  3
#define MIX_SMEM (NSTAGE * STAGE_BYTES)  // 98304 -> 2 CTAs/SM

// mlp GEMM smem layout
#define MLP_A_HI   0
#define MLP_A_LO   32768
#define MLP_B_BASE 65536
#define MLP_B_STG  32768
#define MLP_B_VAR  16384
#define MLP_SMEM   131072

// conv GEMM smem layout
#define CV_A_STG   16384
#define CV_A_VAR   8192
#define CV_B_STG   32768
#define CV_B_VAR   16384
#define CV_A0      0
#define CV_B0      (2 * CV_A_STG)
#define CV_XW      (CV_B0 + 2 * CV_B_STG)
#define CV_SMEM    (CV_XW + 2 * 768)

// adj
#define ADJ_R   8
#define ADJ_SMEM (ADJ_R * NP * 4)     // 65536

// lin GEMM
#define LIN_TN  64
#define LIN_A_BYTES (64 * 128)        // 8192
#define LIN_B_BYTES (LIN_TN * 128)    // 8192
#define LIN_STG (LIN_A_BYTES + LIN_B_BYTES)  // 16384
#define LIN_SMEM (2 * LIN_STG)        // 32768

// ---------------- scratch ----------------
__device__ __half  g_Ahi[4 * MROWS * NP];   // fp16 hi of hops
__device__ __half  g_Alo[4 * MROWS * NP];   // fp16 lo of hops
__device__ __half  g_Bh[NP * NP];           // adjacency a[v][w], fp16
__device__ __half  g_Whi[IN_D * CC * 64];   // conv weights hi [ci][co][64]
__device__ __half  g_Wlo[IN_D * CC * 64];
__device__ __half  g_Wl[NP * NP];           // w_lin fp16 [d][node], padded
__device__ __half  g_Sh[BATCH * NP];        // skip output fp16
__device__ float   g_Y[BATCH * DM];

// ---------------- helpers ----------------
__device__ __forceinline__ uint32_t smem_u32(const void* p) {
    uint32_t a;
    asm("{ .reg .u64 t; cvta.to.shared.u64 t, %1; cvt.u32.u64 %0, t; }" : "=r"(a) : "l"(p));
    return a;
}
__device__ __forceinline__ void cpa16(uint32_t s, const void* g) {
    asm volatile("cp.async.cg.shared.global [%0], [%1], 16;" :: "r"(s), "l"(g));
}
#define CPA_COMMIT() asm volatile("cp.async.commit_group;" ::: "memory")
#define CPA_WAIT(n)  asm volatile("cp.async.wait_group %0;" :: "n"(n) : "memory")

__device__ __forceinline__ void ldsm4(uint32_t* r, uint32_t addr) {
    asm volatile("ldmatrix.sync.aligned.m8n8.x4.shared.b16 {%0,%1,%2,%3}, [%4];"
                 : "=r"(r[0]), "=r"(r[1]), "=r"(r[2]), "=r"(r[3]) : "r"(addr));
}
__device__ __forceinline__ void ldsm4t(uint32_t* r, uint32_t addr) {
    asm volatile("ldmatrix.sync.aligned.m8n8.x4.trans.shared.b16 {%0,%1,%2,%3}, [%4];"
                 : "=r"(r[0]), "=r"(r[1]), "=r"(r[2]), "=r"(r[3]) : "r"(addr));
}
__device__ __forceinline__ void mma16816(float* d, const uint32_t* a, const uint32_t* b) {
    asm volatile("mma.sync.aligned.m16n8k16.row.col.f32.f16.f16.f32 "
                 "{%0,%1,%2,%3}, {%4,%5,%6,%7}, {%8,%9}, {%0,%1,%2,%3};"
                 : "+f"(d[0]), "+f"(d[1]), "+f"(d[2]), "+f"(d[3])
                 : "r"(a[0]), "r"(a[1]), "r"(a[2]), "r"(a[3]), "r"(b[0]), "r"(b[1]));
}
__device__ __forceinline__ void fp16_split(float v, __half& hi, __half& lo) {
    hi = __float2half_rn(v);
    lo = __float2half_rn(v - __half2float(hi));
}
__device__ __forceinline__ float gelu_exact(float v) {
    return 0.5f * v * (1.f + erff(v * 0.70710678118654752f));
}

// ---------------- kernel 0a: prep conv weights ----------------
__global__ void k_prepw(const float* __restrict__ w) {
    int ci = blockIdx.x;
    for (int idx = threadIdx.x; idx < CC * 64; idx += 256) {
        int co = idx >> 6, t = idx & 63;
        float v = (t < KW) ? w[co * (IN_D * KW) + ci * KW + t] : 0.f;
        __half h, l; fp16_split(v, h, l);
        g_Whi[ci * CC * 64 + idx] = h;
        g_Wlo[ci * CC * 64 + idx] = l;
    }
}

// ---------------- kernel 0b: prep w_lin -> fp16 padded [d][2048] ----------------
__global__ void k_prepl(const float* __restrict__ wlin) {
    int d = blockIdx.x;
    for (int w = threadIdx.x; w < NP; w += 256) {
        float v = (w < N_NODE) ? wlin[(size_t)d * N_NODE + w] : 0.f;
        g_Wl[(size_t)d * NP + w] = __float2half_rn(v);
    }
}

// ---------------- kernel 1: adjacency, 8 rows per CTA ----------------
__global__ void k_adj(const float* __restrict__ E1, const float* __restrict__ E2) {
    extern __shared__ float z[];             // [ADJ_R][NP]
    __shared__ float e1s[ADJ_R][ND];
    __shared__ float red[256];
    __shared__ float srow[ADJ_R];
    int tid = threadIdx.x;
    int r0 = blockIdx.x * ADJ_R;

    if (r0 >= N_NODE) {                      // zero pad rows 2000..2047
        for (int r = 0; r < ADJ_R; r++) {
            int v = r0 + r;
            if (v < NP)
                for (int w = tid; w < NP; w += 256) g_Bh[(size_t)v * NP + w] = __float2half(0.f);
        }
        return;
    }

    for (int idx = tid; idx < ADJ_R * ND; idx += 256)
        e1s[idx / ND][idx % ND] = E1[(r0 + idx / ND) * ND + idx % ND];
    __syncthreads();

    float lmax[ADJ_R];
#pragma unroll
    for (int r = 0; r < ADJ_R; r++) lmax[r] = -1e30f;

    for (int w = tid; w < N_NODE; w += 256) {
        float acc[ADJ_R];
#pragma unroll
        for (int r = 0; r < ADJ_R; r++) acc[r] = 0.f;
#pragma unroll 8
        for (int k = 0; k < ND; k++) {
            float e2 = E2[k * N_NODE + w];
#pragma unroll
            for (int r = 0; r < ADJ_R; r++) acc[r] += e1s[r][k] * e2;
        }
#pragma unroll
        for (int r = 0; r < ADJ_R; r++) {
            float v = fmaxf(acc[r], 0.f);
            z[r * NP + w] = v;
            lmax[r] = fmaxf(lmax[r], v);
        }
    }
    // reduce maxes
#pragma unroll
    for (int r = 0; r < ADJ_R; r++) {
        red[tid] = lmax[r]; __syncthreads();
        for (int s = 128; s > 0; s >>= 1) { if (tid < s) red[tid] = fmaxf(red[tid], red[tid + s]); __syncthreads(); }
        if (tid == 0) srow[r] = red[0];
        __syncthreads();
    }
    float lsum[ADJ_R];
#pragma unroll
    for (int r = 0; r < ADJ_R; r++) lsum[r] = 0.f;
    for (int w = tid; w < N_NODE; w += 256) {
#pragma unroll
        for (int r = 0; r < ADJ_R; r++) {
            float e = expf(z[r * NP + w] - srow[r]);
            z[r * NP + w] = e;
            lsum[r] += e;
        }
    }
#pragma unroll
    for (int r = 0; r < ADJ_R; r++) {
        red[tid] = lsum[r]; __syncthreads();
        for (int s = 128; s > 0; s >>= 1) { if (tid < s) red[tid] += red[tid + s]; __syncthreads(); }
        if (tid == 0) srow[r] = 0.5f / red[0];   // a = (softmax + I)/2
        __syncthreads();
    }
    for (int w = tid; w < NP; w += 256) {
#pragma unroll
        for (int r = 0; r < ADJ_R; r++) {
            int v = r0 + r;
            float val = (w < N_NODE) ? (z[r * NP + w] * srow[r] + ((w == v) ? 0.5f : 0.f)) : 0.f;
            g_Bh[(size_t)v * NP + w] = __float2half_rn(val);
        }
    }
}

// ---------------- kernel 2: start conv on HMMA (im2col in smem, fp16 hi/lo) ----------------
__global__ __launch_bounds__(256, 2) void k_conv_mma(const float* __restrict__ x,
                                                     const float* __restrict__ bias) {
    extern __shared__ char smem[];
    const uint32_t sbase = smem_u32(smem);
    float* xw = (float*)(smem + CV_XW);
    const int tid = threadIdx.x;
    const int wid = tid >> 5, lane = tid & 31;
    const int wm = wid >> 1;
    const int wn = wid & 1;
    const int b  = blockIdx.y;
    const int n0 = blockIdx.x * 128;

#define CV_LOAD_A(ci, stg) do {                                                      \
    _Pragma("unroll")                                                                \
    for (int i = 0; i < 2; i++) {                                                    \
        int idx = tid + i * 256;                                                     \
        int co = idx >> 3, s = idx & 7;                                              \
        uint32_t dst = sbase + CV_A0 + (stg) * CV_A_STG + co * 128 +                 \
                       ((uint32_t)(s ^ (co & 7)) << 4);                              \
        cpa16(dst,            (const char*)(g_Whi + (ci) * CC * 64 + co * 64 + s * 8)); \
        cpa16(dst + CV_A_VAR, (const char*)(g_Wlo + (ci) * CC * 64 + co * 64 + s * 8)); \
    }                                                                                \
} while (0)

#define CV_LOAD_XW(ci, stg) do {                                                     \
    if (tid < 192) {                                                                 \
        int p = n0 + tid;                                                            \
        xw[(stg) * 192 + tid] = (p < DM) ? x[(size_t)b * IN_D * DM + (ci) * DM + p] : 0.f; \
    }                                                                                \
} while (0)

#define CV_BUILD_B(stg) do {                                                         \
    const float* xwp = xw + (stg) * 192;                                             \
    _Pragma("unroll")                                                                \
    for (int i = 0; i < 16; i++) {                                                   \
        int idx = tid + i * 256;                                                     \
        int t = idx >> 6, j2 = idx & 63;                                             \
        int n = j2 * 2;                                                              \
        float v0 = xwp[t + n], v1 = xwp[t + n + 1];                                  \
        __half h0, l0, h1, l1;                                                       \
        fp16_split(v0, h0, l0); fp16_split(v1, h1, l1);                              \
        __half2 hh(h0, h1), ll(l0, l1);                                              \
        int s = n >> 3;                                                              \
        uint32_t off = t * 256 + ((uint32_t)(s ^ (t & 7)) << 4) + (j2 & 3) * 4;      \
        *(uint32_t*)(smem + CV_B0 + (stg) * CV_B_STG + off) = *reinterpret_cast<uint32_t*>(&hh); \
        *(uint32_t*)(smem + CV_B0 + (stg) * CV_B_STG + off + CV_B_VAR) = *reinterpret_cast<uint32_t*>(&ll); \
    }                                                                                \
} while (0)

    float acc[8][4];
#pragma unroll
    for (int in = 0; in < 8; in++)
#pragma unroll
        for (int q = 0; q < 4; q++) acc[in][q] = 0.f;

    const int a_row = wm * 16 + (lane & 15);
    const int a_jl  = lane >> 4;
    const int b_kl  = ((lane >> 3) & 1) * 8 + (lane & 7);
    const int b_nl  = lane >> 4;

    CV_LOAD_A(0, 0); CPA_COMMIT();
    CV_LOAD_XW(0, 0);
    CPA_WAIT(0);
    __syncthreads();
    CV_BUILD_B(0);
    __syncthreads();

    for (int c = 0; c < IN_D; c++) {
        int stg = c & 1, nstg = (c + 1) & 1;
        if (c + 1 < IN_D) { CV_LOAD_A(c + 1, nstg); CPA_COMMIT(); CV_LOAD_XW(c + 1, nstg); }

        uint32_t astg = sbase + CV_A0 + stg * CV_A_STG;
        uint32_t bstg = sbase + CV_B0 + stg * CV_B_STG;
#pragma unroll
        for (int ks = 0; ks < 4; ks++) {
            uint32_t ah[4], al[4], bh[4][4], bl[4][4];
            {
                int s = 2 * ks + a_jl;
                uint32_t off = (uint32_t)a_row * 128 + ((uint32_t)(s ^ (a_row & 7)) << 4);
                ldsm4(ah, astg + off);
                ldsm4(al, astg + CV_A_VAR + off);
            }
            int krow = ks * 16 + b_kl;
            uint32_t koff = (uint32_t)krow * 256;
            uint32_t kx = (uint32_t)(krow & 7);
#pragma unroll
            for (int q = 0; q < 4; q++) {
                int ns = wn * 8 + 2 * q + b_nl;
                uint32_t off = koff + ((uint32_t)(ns ^ kx) << 4);
                ldsm4t(bh[q], bstg + off);
                ldsm4t(bl[q], bstg + CV_B_VAR + off);
            }
#pragma unroll
            for (int p = 0; p < 3; p++) {
#pragma unroll
                for (int in = 0; in < 8; in++) {
                    const uint32_t* af = (p == 2) ? al : ah;
                    const uint32_t* bf = (p == 1) ? &bl[in >> 1][(in & 1) * 2]
                                                  : &bh[in >> 1][(in & 1) * 2];
                    mma16816(acc[in], af, bf);
                }
            }
        }
        if (c + 1 < IN_D) {
            CPA_WAIT(0);
            __syncthreads();
            CV_BUILD_B(nstg);
            __syncthreads();
        }
    }

    const int o0 = wm * 16 + (lane >> 2);
    const int o1 = o0 + 8;
    const float b0v = bias[o0], b1v = bias[o1];
#pragma unroll
    for (int in = 0; in < 8; in++) {
        int n = n0 + wn * 64 + in * 8 + (lane & 3) * 2;
        bool ok = (n < N_NODE);
        float v00 = ok ? (acc[in][0] + b0v) : 0.f;
        float v01 = ok ? (acc[in][1] + b0v) : 0.f;
        float v10 = ok ? (acc[in][2] + b1v) : 0.f;
        float v11 = ok ? (acc[in][3] + b1v) : 0.f;
        size_t r0 = (size_t)(b * CC + o0) * NP + n;
        size_t r1 = (size_t)(b * CC + o1) * NP + n;
        __half h0, l0, h1, l1;
        fp16_split(v00, h0, l0); fp16_split(v01, h1, l1);
        *(__half2*)(g_Ahi + r0) = __half2(h0, h1);
        *(__half2*)(g_Alo + r0) = __half2(l0, l1);
        fp16_split(v10, h0, l0); fp16_split(v11, h1, l1);
        *(__half2*)(g_Ahi + r1) = __half2(h0, h1);
        *(__half2*)(g_Alo + r1) = __half2(l0, l1);
    }
#undef CV_LOAD_A
#undef CV_LOAD_XW
#undef CV_BUILD_B
}

// ---------------- kernel 3: mixprop GEMM on HMMA (fp16 single-product, KC=64) ----
__global__ __launch_bounds__(256, 2) void k_mix_mma(int src, int dst) {
    extern __shared__ char smem[];
    const uint32_t sbase = smem_u32(smem);

    const int tid = threadIdx.x;
    const int wid = tid >> 5, lane = tid & 31;
    const int wm = wid >> 2;
    const int wn = wid & 3;
    const int m0 = blockIdx.y * TILE_M;
    const int n0 = blockIdx.x * TILE_N;

    const __half* Ahi = g_Ahi + (size_t)src * MROWS * NP;

    const int lr = tid >> 1;
    const int ls = (tid & 1) * 4;
    const uint32_t lswz = (uint32_t)(lr & 7);          // SW128
    const char* gA = (const char*)(Ahi + (size_t)(m0 + lr) * NP) + ls * 16;
    const char* gB = (const char*)(g_Bh + (size_t)(n0 + lr) * NP) + ls * 16;

#define LOAD_CHUNK(cidx, buf) do {                                                   \
    uint32_t sb = sbase + (buf) * STAGE_BYTES + lr * 128;                            \
    size_t go = (size_t)(cidx) * 128;                                                \
    _Pragma("unroll")                                                                \
    for (int j = 0; j < 4; j++) {                                                    \
        uint32_t so = ((uint32_t)(ls + j) ^ lswz) << 4;                              \
        cpa16(sb + OFF_AH + so, gA + go + j * 16);                                   \
        cpa16(sb + OFF_BH + so, gB + go + j * 16);                                   \
    }                                                                                \
} while (0)

    float acc[4][4][4];
#pragma unroll
    for (int im = 0; im < 4; im++)
#pragma unroll
        for (int in = 0; in < 4; in++)
#pragma unroll
            for (int q = 0; q < 4; q++) acc[im][in][q] = 0.f;

    const int a_row_l = (lane & 15);
    const int a_jl = lane >> 4;
    const int b_row_l = ((lane >> 4) << 3) + (lane & 7);
    const int b_jl = (lane >> 3) & 1;

    LOAD_CHUNK(0, 0); CPA_COMMIT();
    LOAD_CHUNK(1, 1); CPA_COMMIT();

    int buf = 0, nbuf = 2;
    for (int c = 0; c < NCHUNK; c++) {
        if (c + 1 < NCHUNK) { CPA_WAIT(1); } else { CPA_WAIT(0); }
        __syncthreads();
        if (c + 2 < NCHUNK) { LOAD_CHUNK(c + 2, nbuf); CPA_COMMIT(); }

        uint32_t sb = sbase + buf * STAGE_BYTES;
#pragma unroll
        for (int ks = 0; ks < 4; ks++) {
            uint32_t ah[4][4], bh[2][4];
#pragma unroll
            for (int im = 0; im < 4; im++) {
                int row = wm * 64 + im * 16 + a_row_l;
                uint32_t off = (uint32_t)row * 128 +
                               ((uint32_t)((2 * ks + a_jl) ^ (row & 7)) << 4);
                ldsm4(ah[im], sb + OFF_AH + off);
            }
#pragma unroll
            for (int inb = 0; inb < 2; inb++) {
                int row = wn * 32 + inb * 16 + b_row_l;
                uint32_t off = (uint32_t)row * 128 +
                               ((uint32_t)((2 * ks + b_jl) ^ (row & 7)) << 4);
                ldsm4(bh[inb], sb + OFF_BH + off);
            }
#pragma unroll
            for (int im = 0; im < 4; im++) {
#pragma unroll
                for (int in = 0; in < 4; in++) {
                    mma16816(acc[im][in], ah[im], &bh[in >> 1][(in & 1) * 2]);
                }
            }
        }
        buf = (buf == NSTAGE - 1) ? 0 : buf + 1;
        nbuf = (nbuf == NSTAGE - 1) ? 0 : nbuf + 1;
    }

    // epilogue: C = ALPHA*(h0 hi+lo) + BETA*acc -> fp16 hi/lo
    const __half* Xh = g_Ahi;
    const __half* Xl = g_Alo;
    __half* Hh = g_Ahi + (size_t)dst * MROWS * NP;
    __half* Hl = g_Alo + (size_t)dst * MROWS * NP;

#pragma unroll
    for (int im = 0; im < 4; im++) {
#pragma unroll
        for (int half = 0; half < 2; half++) {
            int m = m0 + wm * 64 + im * 16 + (lane >> 2) + half * 8;
            size_t rowo = (size_t)m * NP;
#pragma unroll
            for (int in = 0; in < 4; in++) {
                int n = n0 + wn * 32 + in * 8 + (lane & 3) * 2;
                float d0 = acc[im][in][half * 2 + 0];
                float d1 = acc[im][in][half * 2 + 1];
                __half2 xh = *(const __half2*)(Xh + rowo + n);
                __half2 xl = *(const __half2*)(Xl + rowo + n);
                float x0 = __half2float(xh.x) + __half2float(xl.x);
                float x1 = __half2float(xh.y) + __half2float(xl.y);
                float o0 = ALPHA_C * x0 + BETA_C * d0;
                float o1 = ALPHA_C * x1 + BETA_C * d1;
                __half h0, l0, h1, l1;
                fp16_split(o0, h0, l0); fp16_split(o1, h1, l1);
                *(__half2*)(Hh + rowo + n) = __half2(h0, h1);
                *(__half2*)(Hl + rowo + n) = __half2(l0, l1);
            }
        }
    }
#undef LOAD_CHUNK
}

// ---------------- kernel 4: MLP on HMMA + fused GELU + end dot (fp16) ----------------
__global__ __launch_bounds__(256) void k_mlp_mma(const float* __restrict__ wmlp,
                                                 const float* __restrict__ bmlp,
                                                 const float* __restrict__ wend,
                                                 const float* __restrict__ bend) {
    extern __shared__ char smem[];
    __shared__ float red[4][128];
    const uint32_t sbase = smem_u32(smem);
    const int tid = threadIdx.x;
    const int wid = tid >> 5, lane = tid & 31;
    const int wm = wid >> 1;
    const int wn = wid & 1;
    const int b  = blockIdx.y;
    const int n0 = blockIdx.x * 128;

#pragma unroll
    for (int i = 0; i < 8; i++) {
        int idx = tid + i * 256;
        int o = idx >> 5, s = idx & 31;
        const float* wp = wmlp + o * 256 + s * 8;
        float4 v0 = *(const float4*)wp;
        float4 v1 = *(const float4*)(wp + 4);
        float vv[8] = {v0.x, v0.y, v0.z, v0.w, v1.x, v1.y, v1.z, v1.w};
        uint32_t hp[4], lp[4];
#pragma unroll
        for (int j = 0; j < 4; j++) {
            __half h0, l0, h1, l1;
            fp16_split(vv[2 * j], h0, l0);
            fp16_split(vv[2 * j + 1], h1, l1);
            __half2 hh(h0, h1), ll(l0, l1);
            hp[j] = *reinterpret_cast<uint32_t*>(&hh);
            lp[j] = *reinterpret_cast<uint32_t*>(&ll);
        }
        uint32_t phys = (uint32_t)(s ^ (o & 15));
        *(uint4*)(smem + MLP_A_HI + o * 512 + phys * 16) = make_uint4(hp[0], hp[1], hp[2], hp[3]);
        *(uint4*)(smem + MLP_A_LO + o * 512 + phys * 16) = make_uint4(lp[0], lp[1], lp[2], lp[3]);
    }

#define LOAD_BCH(chunk, stg) do {                                                        \
    const __half* HBh = g_Ahi + ((size_t)(chunk) * MROWS + b * 64) * NP + n0;            \
    const __half* HBl = g_Alo + ((size_t)(chunk) * MROWS + b * 64) * NP + n0;            \
    _Pragma("unroll")                                                                    \
    for (int i = 0; i < 4; i++) {                                                        \
        int idx = tid + i * 256;                                                         \
        int k = idx >> 4, s = idx & 15;                                                  \
        uint32_t phys = (uint32_t)(s ^ (k & 7));                                         \
        uint32_t dst = sbase + MLP_B_BASE + (stg) * MLP_B_STG + k * 256 + phys * 16;     \
        cpa16(dst,             (const char*)HBh + (size_t)k * NP * 2 + s * 16);          \
        cpa16(dst + MLP_B_VAR, (const char*)HBl + (size_t)k * NP * 2 + s * 16);          \
    }                                                                                    \
} while (0)

    float acc[8][4];
#pragma unroll
    for (int in = 0; in < 8; in++)
#pragma unroll
        for (int q = 0; q < 4; q++) acc[in][q] = 0.f;

    const int a_row = wm * 16 + (lane & 15);
    const int a_jl  = lane >> 4;
    const int b_kl  = ((lane >> 3) & 1) * 8 + (lane & 7);
    const int b_nl  = lane >> 4;

    LOAD_BCH(0, 0); CPA_COMMIT();

    for (int chunk = 0; chunk < 4; chunk++) {
        CPA_WAIT(0);
        __syncthreads();
        if (chunk < 3) { LOAD_BCH(chunk + 1, (chunk + 1) & 1); CPA_COMMIT(); }
        uint32_t bstg = sbase + MLP_B_BASE + (chunk & 1) * MLP_B_STG;

#pragma unroll
        for (int ks = 0; ks < 4; ks++) {
            int ksg = chunk * 4 + ks;
            uint32_t ah[4], al[4], bh[4][4], bl[4][4];
            {
                int s = 2 * ksg + a_jl;
                uint32_t off = (uint32_t)a_row * 512 + ((uint32_t)(s ^ (a_row & 15)) << 4);
                ldsm4(ah, sbase + MLP_A_HI + off);
                ldsm4(al, sbase + MLP_A_LO + off);
            }
            int krow = ks * 16 + b_kl;
            uint32_t koff = (uint32_t)krow * 256;
            uint32_t kx = (uint32_t)(krow & 7);
#pragma unroll
            for (int q = 0; q < 4; q++) {
                int ns = wn * 8 + 2 * q + b_nl;
                uint32_t off = koff + ((uint32_t)(ns ^ kx) << 4);
                ldsm4t(bh[q], bstg + off);
                ldsm4t(bl[q], bstg + MLP_B_VAR + off);
            }
#pragma unroll
            for (int p = 0; p < 3; p++) {
#pragma unroll
                for (int in = 0; in < 8; in++) {
                    const uint32_t* af = (p == 2) ? al : ah;
                    const uint32_t* bf = (p == 1) ? &bl[in >> 1][(in & 1) * 2]
                                                  : &bh[in >> 1][(in & 1) * 2];
                    mma16816(acc[in], af, bf);
                }
            }
        }
        __syncthreads();
    }

    const int o0 = wm * 16 + (lane >> 2);
    const int o1 = o0 + 8;
    const float bm0 = bmlp[o0], bm1 = bmlp[o1];
    const float we0 = wend[o0], we1 = wend[o1];

#pragma unroll
    for (int in = 0; in < 8; in++) {
        float g00 = gelu_exact(acc[in][0] + bm0);
        float g01 = gelu_exact(acc[in][1] + bm0);
        float g10 = gelu_exact(acc[in][2] + bm1);
        float g11 = gelu_exact(acc[in][3] + bm1);
        float p0 = we0 * g00 + we1 * g10;
        float p1 = we0 * g01 + we1 * g11;
#pragma unroll
        for (int d = 4; d <= 16; d <<= 1) {
            p0 += __shfl_xor_sync(0xFFFFFFFF, p0, d);
            p1 += __shfl_xor_sync(0xFFFFFFFF, p1, d);
        }
        if (lane < 4) {
            red[wm][wn * 64 + in * 8 + lane * 2 + 0] = p0;
            red[wm][wn * 64 + in * 8 + lane * 2 + 1] = p1;
        }
    }
    __syncthreads();
    if (tid < 128) {
        int n = n0 + tid;
        float s = bend[0] + red[0][tid] + red[1][tid] + red[2][tid] + red[3][tid];
        g_Sh[(size_t)b * NP + n] = __float2half_rn((n < N_NODE) ? s : 0.f);
    }
#undef LOAD_BCH
}

// ---------------- kernel 5: final linear on HMMA (fp16 single-product) ----------------
// Y[b][d] = sum_k S[b][k] * w_lin[d][k] + blin[d];  M=64(batch) N=64/CTA K=2048
__global__ __launch_bounds__(256) void k_lin_mma(const float* __restrict__ blin) {
    extern __shared__ char smem[];
    const uint32_t sbase = smem_u32(smem);
    const int tid = threadIdx.x;
    const int wid = tid >> 5, lane = tid & 31;
    const int wm = wid >> 1;          // 0..3 -> batch offset wm*16
    const int wn = wid & 1;           // 0..1 -> d offset wn*32
    const int n0 = blockIdx.x * LIN_TN;

#define LIN_LOAD(cidx, stg) do {                                                     \
    _Pragma("unroll")                                                                \
    for (int i = 0; i < 2; i++) {                                                    \
        int idx = tid + i * 256;                                                     \
        int row = idx >> 3, s = idx & 7;                                             \
        uint32_t so = ((uint32_t)(s ^ (row & 7)) << 4);                              \
        cpa16(sbase + (stg) * LIN_STG + row * 128 + so,                              \
              (const char*)(g_Sh + (size_t)row * NP) + (size_t)(cidx) * 128 + s * 16); \
        cpa16(sbase + (stg) * LIN_STG + LIN_A_BYTES + row * 128 + so,                \
              (const char*)(g_Wl + (size_t)(n0 + row) * NP) + (size_t)(cidx) * 128 + s * 16); \
    }                                                                                \
} while (0)

    float acc[4][4];
#pragma unroll
    for (int in = 0; in < 4; in++)
#pragma unroll
        for (int q = 0; q < 4; q++) acc[in][q] = 0.f;

    const int a_row_l = (lane & 15);
    const int a_jl = lane >> 4;
    const int b_row_l = ((lane >> 4) << 3) + (lane & 7);
    const int b_jl = (lane >> 3) & 1;

    LIN_LOAD(0, 0); CPA_COMMIT();

    for (int c = 0; c < 32; c++) {
        CPA_WAIT(0);
        __syncthreads();
        if (c + 1 < 32) { LIN_LOAD(c + 1, (c + 1) & 1); CPA_COMMIT(); }
        uint32_t astg = sbase + (c & 1) * LIN_STG;
        uint32_t bstg = astg + LIN_A_BYTES;
#pragma unroll
        for (int ks = 0; ks < 4; ks++) {
            uint32_t ah[4], bh[2][4];
            {
                int row = wm * 16 + a_row_l;
                uint32_t off = (uint32_t)row * 128 +
                               ((uint32_t)((2 * ks + a_jl) ^ (row & 7)) << 4);
                ldsm4(ah, astg + off);
            }
#pragma unroll
            for (int inb = 0; inb < 2; inb++) {
                int row = wn * 32 + inb * 16 + b_row_l;
                uint32_t off = (uint32_t)row * 128 +
                               ((uint32_t)((2 * ks + b_jl) ^ (row & 7)) << 4);
                ldsm4(bh[inb], bstg + off);
            }
#pragma unroll
            for (int in = 0; in < 4; in++)
                mma16816(acc[in], ah, &bh[in >> 1][(in & 1) * 2]);
        }
        __syncthreads();
    }

#pragma unroll
    for (int in = 0; in < 4; in++) {
        int d = n0 + wn * 32 + in * 8 + (lane & 3) * 2;
        int b0 = wm * 16 + (lane >> 2), b1 = b0 + 8;
        float bl0 = blin[d], bl1 = blin[d + 1];
        g_Y[(size_t)b0 * DM + d]     = acc[in][0] + bl0;
        g_Y[(size_t)b0 * DM + d + 1] = acc[in][1] + bl1;
        g_Y[(size_t)b1 * DM + d]     = acc[in][2] + bl0;
        g_Y[(size_t)b1 * DM + d + 1] = acc[in][3] + bl1;
    }
#undef LIN_LOAD
}

// ---------------- kernel 6: layernorm ----------------
__global__ void k_ln(const float* __restrict__ gam, const float* __restrict__ bet,
                     float* __restrict__ out) {
    int b = blockIdx.x;
    int tid = threadIdx.x;
    __shared__ float red[256];
    const float* y = g_Y + (size_t)b * DM;

    float s = 0.f;
    for (int d = tid; d < DM; d += 256) s += y[d];
    red[tid] = s; __syncthreads();
    for (int st = 128; st > 0; st >>= 1) { if (tid < st) red[tid] += red[tid + st]; __syncthreads(); }
    float mu = red[0] / DM;
    __syncthreads();

    float v = 0.f;
    for (int d = tid; d < DM; d += 256) { float t = y[d] - mu; v += t * t; }
    red[tid] = v; __syncthreads();
    for (int st = 128; st > 0; st >>= 1) { if (tid < st) red[tid] += red[tid + st]; __syncthreads(); }
    float rinv = rsqrtf(red[0] / DM + 1e-5f);

    for (int d = tid; d < DM; d += 256)
        out[(size_t)b * DM + d] = (y[d] - mu) * rinv * gam[d] + bet[d];
}

// ---------------- launch ----------------
extern "C" void kernel_launch(void* const* d_in, const int* in_sizes, int n_in,
                              void* d_out, int out_size) {
    const float* x       = (const float*)d_in[0];
    const float* nv1     = (const float*)d_in[1];
    const float* nv2     = (const float*)d_in[2];
    const float* w_start = (const float*)d_in[3];
    const float* b_start = (const float*)d_in[4];
    const float* w_mlp   = (const float*)d_in[5];
    const float* b_mlp   = (const float*)d_in[6];
    const float* w_end   = (const float*)d_in[7];
    const float* b_end   = (const float*)d_in[8];
    const float* w_lin   = (const float*)d_in[9];
    const float* b_lin   = (const float*)d_in[10];
    const float* ln_g    = (const float*)d_in[11];
    const float* ln_b    = (const float*)d_in[12];
    float* out = (float*)d_out;

    cudaFuncSetAttribute(k_mix_mma,  cudaFuncAttributeMaxDynamicSharedMemorySize, MIX_SMEM);
    cudaFuncSetAttribute(k_mlp_mma,  cudaFuncAttributeMaxDynamicSharedMemorySize, MLP_SMEM);
    cudaFuncSetAttribute(k_conv_mma, cudaFuncAttributeMaxDynamicSharedMemorySize, CV_SMEM);
    cudaFuncSetAttribute(k_adj,      cudaFuncAttributeMaxDynamicSharedMemorySize, ADJ_SMEM);
    cudaFuncSetAttribute(k_lin_mma,  cudaFuncAttributeMaxDynamicSharedMemorySize, LIN_SMEM);

    k_prepw<<<IN_D, 256>>>(w_start);
    k_prepl<<<DM, 256>>>(w_lin);
    k_adj<<<NP / ADJ_R, 256, ADJ_SMEM>>>(nv1, nv2);
    k_conv_mma<<<dim3(NP / 128, BATCH), 256, CV_SMEM>>>(x, b_start);
    dim3 mixg(NP / TILE_N, MROWS / TILE_M);
    k_mix_mma<<<mixg, 256, MIX_SMEM>>>(0, 1);
    k_mix_mma<<<mixg, 256, MIX_SMEM>>>(1, 2);
    k_mix_mma<<<mixg, 256, MIX_SMEM>>>(2, 3);
    k_mlp_mma<<<dim3(NP / 128, BATCH), 256, MLP_SMEM>>>(w_mlp, b_mlp, w_end, b_end);
    k_lin_mma<<<NP / LIN_TN, 256, LIN_SMEM>>>(b_lin);
    k_ln<<<BATCH, 256>>>(ln_g, ln_b, out);
}

// round 11
// speedup vs baseline: 5.6977x; 1.0665x over previous
#include <cuda_runtime.h>
#include <cuda_fp16.h>
#include <math.h>
#include <stdint.h>

// ---------------- problem constants ----------------
#define N_NODE 2000
#define NP     2048
#define BATCH  64
#define CC     64
#define MROWS  (BATCH*CC)    // 4096
#define DM     2048
#define IN_D   7
#define KW     49
#define ND     40
#define ALPHA_C 0.05f
#define BETA_C  0.95f

// mix GEMM tiling: k-chunk 64 (128B rows, SW128), 2 tiles (Ah, Bh) per stage
#define NCHUNK  32
#define TILE_M  128
#define TILE_N  128
#define VAR_BYTES (128 * 128)         // 16384 B
#define OFF_AH  0
#define OFF_BH  (VAR_BYTES)
#define STAGE_BYTES (2 * VAR_BYTES)   // 32768
#define NSTAGE  3
#define MIX_SMEM (NSTAGE * STAGE_BYTES)  // 98304 -> 2 CTAs/SM

// mlp GEMM smem layout (B = H hi only now)
#define MLP_A_HI   0
#define MLP_A_LO   32768
#define MLP_B_BASE 65536
#define MLP_B_STG  16384
#define MLP_SMEM   98304

// conv GEMM smem layout (B = x fp16 single now)
#define CV_A_STG   16384
#define CV_A_VAR   8192
#define CV_B_STG   16384
#define CV_A0      0
#define CV_B0      (2 * CV_A_STG)              // 32768
#define CV_XW      (CV_B0 + 2 * CV_B_STG)      // 65536
#define CV_SMEM    (CV_XW + 2 * 768)           // 67072

// adj
#define ADJ_R   8
#define ADJ_SMEM (ADJ_R * NP * 4)     // 65536

// lin GEMM
#define LIN_TN  64
#define LIN_A_BYTES (64 * 128)
#define LIN_B_BYTES (LIN_TN * 128)
#define LIN_STG (LIN_A_BYTES + LIN_B_BYTES)
#define LIN_SMEM (2 * LIN_STG)

// ---------------- scratch ----------------
__device__ __half  g_Ahi[4 * MROWS * NP];   // fp16 hi of hops
__device__ __half  g_Alo[4 * MROWS * NP];   // fp16 lo of hops
__device__ __half  g_Bh[NP * NP];           // adjacency a[v][w], fp16
__device__ __half  g_Whi[IN_D * CC * 64];   // conv weights hi [ci][co][64]
__device__ __half  g_Wlo[IN_D * CC * 64];
__device__ __half  g_Wl[NP * NP];           // w_lin fp16 [d][node], padded
__device__ __half  g_Sh[BATCH * NP];        // skip output fp16
__device__ float   g_Y[BATCH * DM];

// ---------------- helpers ----------------
__device__ __forceinline__ uint32_t smem_u32(const void* p) {
    uint32_t a;
    asm("{ .reg .u64 t; cvta.to.shared.u64 t, %1; cvt.u32.u64 %0, t; }" : "=r"(a) : "l"(p));
    return a;
}
__device__ __forceinline__ void cpa16(uint32_t s, const void* g) {
    asm volatile("cp.async.cg.shared.global [%0], [%1], 16;" :: "r"(s), "l"(g));
}
#define CPA_COMMIT() asm volatile("cp.async.commit_group;" ::: "memory")
#define CPA_WAIT(n)  asm volatile("cp.async.wait_group %0;" :: "n"(n) : "memory")

__device__ __forceinline__ void ldsm4(uint32_t* r, uint32_t addr) {
    asm volatile("ldmatrix.sync.aligned.m8n8.x4.shared.b16 {%0,%1,%2,%3}, [%4];"
                 : "=r"(r[0]), "=r"(r[1]), "=r"(r[2]), "=r"(r[3]) : "r"(addr));
}
__device__ __forceinline__ void ldsm4t(uint32_t* r, uint32_t addr) {
    asm volatile("ldmatrix.sync.aligned.m8n8.x4.trans.shared.b16 {%0,%1,%2,%3}, [%4];"
                 : "=r"(r[0]), "=r"(r[1]), "=r"(r[2]), "=r"(r[3]) : "r"(addr));
}
__device__ __forceinline__ void mma16816(float* d, const uint32_t* a, const uint32_t* b) {
    asm volatile("mma.sync.aligned.m16n8k16.row.col.f32.f16.f16.f32 "
                 "{%0,%1,%2,%3}, {%4,%5,%6,%7}, {%8,%9}, {%0,%1,%2,%3};"
                 : "+f"(d[0]), "+f"(d[1]), "+f"(d[2]), "+f"(d[3])
                 : "r"(a[0]), "r"(a[1]), "r"(a[2]), "r"(a[3]), "r"(b[0]), "r"(b[1]));
}
__device__ __forceinline__ void fp16_split(float v, __half& hi, __half& lo) {
    hi = __float2half_rn(v);
    lo = __float2half_rn(v - __half2float(hi));
}
__device__ __forceinline__ float gelu_exact(float v) {
    return 0.5f * v * (1.f + erff(v * 0.70710678118654752f));
}

// ---------------- kernel 0a: prep conv weights ----------------
__global__ void k_prepw(const float* __restrict__ w) {
    int ci = blockIdx.x;
    for (int idx = threadIdx.x; idx < CC * 64; idx += 256) {
        int co = idx >> 6, t = idx & 63;
        float v = (t < KW) ? w[co * (IN_D * KW) + ci * KW + t] : 0.f;
        __half h, l; fp16_split(v, h, l);
        g_Whi[ci * CC * 64 + idx] = h;
        g_Wlo[ci * CC * 64 + idx] = l;
    }
}

// ---------------- kernel 0b: prep w_lin -> fp16 padded [d][2048] ----------------
__global__ void k_prepl(const float* __restrict__ wlin) {
    int d = blockIdx.x;
    for (int w = threadIdx.x; w < NP; w += 256) {
        float v = (w < N_NODE) ? wlin[(size_t)d * N_NODE + w] : 0.f;
        g_Wl[(size_t)d * NP + w] = __float2half_rn(v);
    }
}

// ---------------- kernel 1: adjacency, 8 rows per CTA ----------------
__global__ void k_adj(const float* __restrict__ E1, const float* __restrict__ E2) {
    extern __shared__ float z[];             // [ADJ_R][NP]
    __shared__ float e1s[ADJ_R][ND];
    __shared__ float red[256];
    __shared__ float srow[ADJ_R];
    int tid = threadIdx.x;
    int r0 = blockIdx.x * ADJ_R;

    if (r0 >= N_NODE) {
        for (int r = 0; r < ADJ_R; r++) {
            int v = r0 + r;
            if (v < NP)
                for (int w = tid; w < NP; w += 256) g_Bh[(size_t)v * NP + w] = __float2half(0.f);
        }
        return;
    }

    for (int idx = tid; idx < ADJ_R * ND; idx += 256)
        e1s[idx / ND][idx % ND] = E1[(r0 + idx / ND) * ND + idx % ND];
    __syncthreads();

    float lmax[ADJ_R];
#pragma unroll
    for (int r = 0; r < ADJ_R; r++) lmax[r] = -1e30f;

    for (int w = tid; w < N_NODE; w += 256) {
        float acc[ADJ_R];
#pragma unroll
        for (int r = 0; r < ADJ_R; r++) acc[r] = 0.f;
#pragma unroll 8
        for (int k = 0; k < ND; k++) {
            float e2 = E2[k * N_NODE + w];
#pragma unroll
            for (int r = 0; r < ADJ_R; r++) acc[r] += e1s[r][k] * e2;
        }
#pragma unroll
        for (int r = 0; r < ADJ_R; r++) {
            float v = fmaxf(acc[r], 0.f);
            z[r * NP + w] = v;
            lmax[r] = fmaxf(lmax[r], v);
        }
    }
#pragma unroll
    for (int r = 0; r < ADJ_R; r++) {
        red[tid] = lmax[r]; __syncthreads();
        for (int s = 128; s > 0; s >>= 1) { if (tid < s) red[tid] = fmaxf(red[tid], red[tid + s]); __syncthreads(); }
        if (tid == 0) srow[r] = red[0];
        __syncthreads();
    }
    float lsum[ADJ_R];
#pragma unroll
    for (int r = 0; r < ADJ_R; r++) lsum[r] = 0.f;
    for (int w = tid; w < N_NODE; w += 256) {
#pragma unroll
        for (int r = 0; r < ADJ_R; r++) {
            float e = expf(z[r * NP + w] - srow[r]);
            z[r * NP + w] = e;
            lsum[r] += e;
        }
    }
#pragma unroll
    for (int r = 0; r < ADJ_R; r++) {
        red[tid] = lsum[r]; __syncthreads();
        for (int s = 128; s > 0; s >>= 1) { if (tid < s) red[tid] += red[tid + s]; __syncthreads(); }
        if (tid == 0) srow[r] = 0.5f / red[0];   // a = (softmax + I)/2
        __syncthreads();
    }
    for (int w = tid; w < NP; w += 256) {
#pragma unroll
        for (int r = 0; r < ADJ_R; r++) {
            int v = r0 + r;
            float val = (w < N_NODE) ? (z[r * NP + w] * srow[r] + ((w == v) ? 0.5f : 0.f)) : 0.f;
            g_Bh[(size_t)v * NP + w] = __float2half_rn(val);
        }
    }
}

// ---------------- kernel 2: start conv on HMMA (2-product: W hi/lo x fp16 x) ---------
__global__ __launch_bounds__(256, 2) void k_conv_mma(const float* __restrict__ x,
                                                     const float* __restrict__ bias) {
    extern __shared__ char smem[];
    const uint32_t sbase = smem_u32(smem);
    float* xw = (float*)(smem + CV_XW);
    const int tid = threadIdx.x;
    const int wid = tid >> 5, lane = tid & 31;
    const int wm = wid >> 1;
    const int wn = wid & 1;
    const int b  = blockIdx.y;
    const int n0 = blockIdx.x * 128;

#define CV_LOAD_A(ci, stg) do {                                                      \
    _Pragma("unroll")                                                                \
    for (int i = 0; i < 2; i++) {                                                    \
        int idx = tid + i * 256;                                                     \
        int co = idx >> 3, s = idx & 7;                                              \
        uint32_t dst = sbase + CV_A0 + (stg) * CV_A_STG + co * 128 +                 \
                       ((uint32_t)(s ^ (co & 7)) << 4);                              \
        cpa16(dst,            (const char*)(g_Whi + (ci) * CC * 64 + co * 64 + s * 8)); \
        cpa16(dst + CV_A_VAR, (const char*)(g_Wlo + (ci) * CC * 64 + co * 64 + s * 8)); \
    }                                                                                \
} while (0)

#define CV_LOAD_XW(ci, stg) do {                                                     \
    if (tid < 192) {                                                                 \
        int p = n0 + tid;                                                            \
        xw[(stg) * 192 + tid] = (p < DM) ? x[(size_t)b * IN_D * DM + (ci) * DM + p] : 0.f; \
    }                                                                                \
} while (0)

#define CV_BUILD_B(stg) do {                                                         \
    const float* xwp = xw + (stg) * 192;                                             \
    _Pragma("unroll")                                                                \
    for (int i = 0; i < 16; i++) {                                                   \
        int idx = tid + i * 256;                                                     \
        int t = idx >> 6, j2 = idx & 63;                                             \
        int n = j2 * 2;                                                              \
        __half2 hh(__float2half_rn(xwp[t + n]), __float2half_rn(xwp[t + n + 1]));    \
        int s = n >> 3;                                                              \
        uint32_t off = t * 256 + ((uint32_t)(s ^ (t & 7)) << 4) + (j2 & 3) * 4;      \
        *(uint32_t*)(smem + CV_B0 + (stg) * CV_B_STG + off) = *reinterpret_cast<uint32_t*>(&hh); \
    }                                                                                \
} while (0)

    float acc[8][4];
#pragma unroll
    for (int in = 0; in < 8; in++)
#pragma unroll
        for (int q = 0; q < 4; q++) acc[in][q] = 0.f;

    const int a_row = wm * 16 + (lane & 15);
    const int a_jl  = lane >> 4;
    const int b_kl  = ((lane >> 3) & 1) * 8 + (lane & 7);
    const int b_nl  = lane >> 4;

    CV_LOAD_A(0, 0); CPA_COMMIT();
    CV_LOAD_XW(0, 0);
    CPA_WAIT(0);
    __syncthreads();
    CV_BUILD_B(0);
    __syncthreads();

    for (int c = 0; c < IN_D; c++) {
        int stg = c & 1, nstg = (c + 1) & 1;
        if (c + 1 < IN_D) { CV_LOAD_A(c + 1, nstg); CPA_COMMIT(); CV_LOAD_XW(c + 1, nstg); }

        uint32_t astg = sbase + CV_A0 + stg * CV_A_STG;
        uint32_t bstg = sbase + CV_B0 + stg * CV_B_STG;
#pragma unroll
        for (int ks = 0; ks < 4; ks++) {
            uint32_t ah[4], al[4], bh[4][4];
            {
                int s = 2 * ks + a_jl;
                uint32_t off = (uint32_t)a_row * 128 + ((uint32_t)(s ^ (a_row & 7)) << 4);
                ldsm4(ah, astg + off);
                ldsm4(al, astg + CV_A_VAR + off);
            }
            int krow = ks * 16 + b_kl;
            uint32_t koff = (uint32_t)krow * 256;
            uint32_t kx = (uint32_t)(krow & 7);
#pragma unroll
            for (int q = 0; q < 4; q++) {
                int ns = wn * 8 + 2 * q + b_nl;
                uint32_t off = koff + ((uint32_t)(ns ^ kx) << 4);
                ldsm4t(bh[q], bstg + off);
            }
#pragma unroll
            for (int p = 0; p < 2; p++) {
#pragma unroll
                for (int in = 0; in < 8; in++) {
                    const uint32_t* af = (p == 1) ? al : ah;
                    mma16816(acc[in], af, &bh[in >> 1][(in & 1) * 2]);
                }
            }
        }
        if (c + 1 < IN_D) {
            CPA_WAIT(0);
            __syncthreads();
            CV_BUILD_B(nstg);
            __syncthreads();
        }
    }

    const int o0 = wm * 16 + (lane >> 2);
    const int o1 = o0 + 8;
    const float b0v = bias[o0], b1v = bias[o1];
#pragma unroll
    for (int in = 0; in < 8; in++) {
        int n = n0 + wn * 64 + in * 8 + (lane & 3) * 2;
        bool ok = (n < N_NODE);
        float v00 = ok ? (acc[in][0] + b0v) : 0.f;
        float v01 = ok ? (acc[in][1] + b0v) : 0.f;
        float v10 = ok ? (acc[in][2] + b1v) : 0.f;
        float v11 = ok ? (acc[in][3] + b1v) : 0.f;
        size_t r0 = (size_t)(b * CC + o0) * NP + n;
        size_t r1 = (size_t)(b * CC + o1) * NP + n;
        __half h0, l0, h1, l1;
        fp16_split(v00, h0, l0); fp16_split(v01, h1, l1);
        *(__half2*)(g_Ahi + r0) = __half2(h0, h1);
        *(__half2*)(g_Alo + r0) = __half2(l0, l1);
        fp16_split(v10, h0, l0); fp16_split(v11, h1, l1);
        *(__half2*)(g_Ahi + r1) = __half2(h0, h1);
        *(__half2*)(g_Alo + r1) = __half2(l0, l1);
    }
#undef CV_LOAD_A
#undef CV_LOAD_XW
#undef CV_BUILD_B
}

// ---------------- kernel 3: mixprop GEMM on HMMA (fp16 single-product, KC=64) ----
__global__ __launch_bounds__(256, 2) void k_mix_mma(int src, int dst) {
    extern __shared__ char smem[];
    const uint32_t sbase = smem_u32(smem);

    const int tid = threadIdx.x;
    const int wid = tid >> 5, lane = tid & 31;
    const int wm = wid >> 2;
    const int wn = wid & 3;
    const int m0 = blockIdx.y * TILE_M;
    const int n0 = blockIdx.x * TILE_N;

    const __half* Ahi = g_Ahi + (size_t)src * MROWS * NP;

    const int lr = tid >> 1;
    const int ls = (tid & 1) * 4;
    const uint32_t lswz = (uint32_t)(lr & 7);          // SW128
    const char* gA = (const char*)(Ahi + (size_t)(m0 + lr) * NP) + ls * 16;
    const char* gB = (const char*)(g_Bh + (size_t)(n0 + lr) * NP) + ls * 16;

#define LOAD_CHUNK(cidx, buf) do {                                                   \
    uint32_t sb = sbase + (buf) * STAGE_BYTES + lr * 128;                            \
    size_t go = (size_t)(cidx) * 128;                                                \
    _Pragma("unroll")                                                                \
    for (int j = 0; j < 4; j++) {                                                    \
        uint32_t so = ((uint32_t)(ls + j) ^ lswz) << 4;                              \
        cpa16(sb + OFF_AH + so, gA + go + j * 16);                                   \
        cpa16(sb + OFF_BH + so, gB + go + j * 16);                                   \
    }                                                                                \
} while (0)

    float acc[4][4][4];
#pragma unroll
    for (int im = 0; im < 4; im++)
#pragma unroll
        for (int in = 0; in < 4; in++)
#pragma unroll
            for (int q = 0; q < 4; q++) acc[im][in][q] = 0.f;

    const int a_row_l = (lane & 15);
    const int a_jl = lane >> 4;
    const int b_row_l = ((lane >> 4) << 3) + (lane & 7);
    const int b_jl = (lane >> 3) & 1;

    LOAD_CHUNK(0, 0); CPA_COMMIT();
    LOAD_CHUNK(1, 1); CPA_COMMIT();

    int buf = 0, nbuf = 2;
    for (int c = 0; c < NCHUNK; c++) {
        if (c + 1 < NCHUNK) { CPA_WAIT(1); } else { CPA_WAIT(0); }
        __syncthreads();
        if (c + 2 < NCHUNK) { LOAD_CHUNK(c + 2, nbuf); CPA_COMMIT(); }

        uint32_t sb = sbase + buf * STAGE_BYTES;
#pragma unroll
        for (int ks = 0; ks < 4; ks++) {
            uint32_t ah[4][4], bh[2][4];
#pragma unroll
            for (int im = 0; im < 4; im++) {
                int row = wm * 64 + im * 16 + a_row_l;
                uint32_t off = (uint32_t)row * 128 +
                               ((uint32_t)((2 * ks + a_jl) ^ (row & 7)) << 4);
                ldsm4(ah[im], sb + OFF_AH + off);
            }
#pragma unroll
            for (int inb = 0; inb < 2; inb++) {
                int row = wn * 32 + inb * 16 + b_row_l;
                uint32_t off = (uint32_t)row * 128 +
                               ((uint32_t)((2 * ks + b_jl) ^ (row & 7)) << 4);
                ldsm4(bh[inb], sb + OFF_BH + off);
            }
#pragma unroll
            for (int im = 0; im < 4; im++) {
#pragma unroll
                for (int in = 0; in < 4; in++) {
                    mma16816(acc[im][in], ah[im], &bh[in >> 1][(in & 1) * 2]);
                }
            }
        }
        buf = (buf == NSTAGE - 1) ? 0 : buf + 1;
        nbuf = (nbuf == NSTAGE - 1) ? 0 : nbuf + 1;
    }

    // epilogue: C = ALPHA*(h0 hi+lo) + BETA*acc -> fp16 hi/lo
    const __half* Xh = g_Ahi;
    const __half* Xl = g_Alo;
    __half* Hh = g_Ahi + (size_t)dst * MROWS * NP;
    __half* Hl = g_Alo + (size_t)dst * MROWS * NP;

#pragma unroll
    for (int im = 0; im < 4; im++) {
#pragma unroll
        for (int half = 0; half < 2; half++) {
            int m = m0 + wm * 64 + im * 16 + (lane >> 2) + half * 8;
            size_t rowo = (size_t)m * NP;
#pragma unroll
            for (int in = 0; in < 4; in++) {
                int n = n0 + wn * 32 + in * 8 + (lane & 3) * 2;
                float d0 = acc[im][in][half * 2 + 0];
                float d1 = acc[im][in][half * 2 + 1];
                __half2 xh = *(const __half2*)(Xh + rowo + n);
                __half2 xl = *(const __half2*)(Xl + rowo + n);
                float x0 = __half2float(xh.x) + __half2float(xl.x);
                float x1 = __half2float(xh.y) + __half2float(xl.y);
                float o0 = ALPHA_C * x0 + BETA_C * d0;
                float o1 = ALPHA_C * x1 + BETA_C * d1;
                __half h0, l0, h1, l1;
                fp16_split(o0, h0, l0); fp16_split(o1, h1, l1);
                *(__half2*)(Hh + rowo + n) = __half2(h0, h1);
                *(__half2*)(Hl + rowo + n) = __half2(l0, l1);
            }
        }
    }
#undef LOAD_CHUNK
}

// ---------------- kernel 4: MLP on HMMA (2-product: W hi/lo x H hi) + GELU + end ----
__global__ __launch_bounds__(256) void k_mlp_mma(const float* __restrict__ wmlp,
                                                 const float* __restrict__ bmlp,
                                                 const float* __restrict__ wend,
                                                 const float* __restrict__ bend) {
    extern __shared__ char smem[];
    __shared__ float red[4][128];
    const uint32_t sbase = smem_u32(smem);
    const int tid = threadIdx.x;
    const int wid = tid >> 5, lane = tid & 31;
    const int wm = wid >> 1;
    const int wn = wid & 1;
    const int b  = blockIdx.y;
    const int n0 = blockIdx.x * 128;

#pragma unroll
    for (int i = 0; i < 8; i++) {
        int idx = tid + i * 256;
        int o = idx >> 5, s = idx & 31;
        const float* wp = wmlp + o * 256 + s * 8;
        float4 v0 = *(const float4*)wp;
        float4 v1 = *(const float4*)(wp + 4);
        float vv[8] = {v0.x, v0.y, v0.z, v0.w, v1.x, v1.y, v1.z, v1.w};
        uint32_t hp[4], lp[4];
#pragma unroll
        for (int j = 0; j < 4; j++) {
            __half h0, l0, h1, l1;
            fp16_split(vv[2 * j], h0, l0);
            fp16_split(vv[2 * j + 1], h1, l1);
            __half2 hh(h0, h1), ll(l0, l1);
            hp[j] = *reinterpret_cast<uint32_t*>(&hh);
            lp[j] = *reinterpret_cast<uint32_t*>(&ll);
        }
        uint32_t phys = (uint32_t)(s ^ (o & 15));
        *(uint4*)(smem + MLP_A_HI + o * 512 + phys * 16) = make_uint4(hp[0], hp[1], hp[2], hp[3]);
        *(uint4*)(smem + MLP_A_LO + o * 512 + phys * 16) = make_uint4(lp[0], lp[1], lp[2], lp[3]);
    }

#define LOAD_BCH(chunk, stg) do {                                                        \
    const __half* HBh = g_Ahi + ((size_t)(chunk) * MROWS + b * 64) * NP + n0;            \
    _Pragma("unroll")                                                                    \
    for (int i = 0; i < 2; i++) {                                                        \
        int idx = tid + i * 256;                                                         \
        int k = idx >> 4, s = idx & 15;  /* 512 entries covers 32 rows? no: */           \
        /* need 64 rows x 16 segs = 1024 entries */                                      \
        (void)k; (void)s;                                                                \
    }                                                                                    \
    _Pragma("unroll")                                                                    \
    for (int i = 0; i < 4; i++) {                                                        \
        int idx = tid + i * 256;                                                         \
        int k = idx >> 4, s = idx & 15;                                                  \
        uint32_t phys = (uint32_t)(s ^ (k & 7));                                         \
        uint32_t dst = sbase + MLP_B_BASE + (stg) * MLP_B_STG + k * 256 + phys * 16;     \
        cpa16(dst, (const char*)HBh + (size_t)k * NP * 2 + s * 16);                      \
    }                                                                                    \
} while (0)

    float acc[8][4];
#pragma unroll
    for (int in = 0; in < 8; in++)
#pragma unroll
        for (int q = 0; q < 4; q++) acc[in][q] = 0.f;

    const int a_row = wm * 16 + (lane & 15);
    const int a_jl  = lane >> 4;
    const int b_kl  = ((lane >> 3) & 1) * 8 + (lane & 7);
    const int b_nl  = lane >> 4;

    LOAD_BCH(0, 0); CPA_COMMIT();

    for (int chunk = 0; chunk < 4; chunk++) {
        CPA_WAIT(0);
        __syncthreads();
        if (chunk < 3) { LOAD_BCH(chunk + 1, (chunk + 1) & 1); CPA_COMMIT(); }
        uint32_t bstg = sbase + MLP_B_BASE + (chunk & 1) * MLP_B_STG;

#pragma unroll
        for (int ks = 0; ks < 4; ks++) {
            int ksg = chunk * 4 + ks;
            uint32_t ah[4], al[4], bh[4][4];
            {
                int s = 2 * ksg + a_jl;
                uint32_t off = (uint32_t)a_row * 512 + ((uint32_t)(s ^ (a_row & 15)) << 4);
                ldsm4(ah, sbase + MLP_A_HI + off);
                ldsm4(al, sbase + MLP_A_LO + off);
            }
            int krow = ks * 16 + b_kl;
            uint32_t koff = (uint32_t)krow * 256;
            uint32_t kx = (uint32_t)(krow & 7);
#pragma unroll
            for (int q = 0; q < 4; q++) {
                int ns = wn * 8 + 2 * q + b_nl;
                uint32_t off = koff + ((uint32_t)(ns ^ kx) << 4);
                ldsm4t(bh[q], bstg + off);
            }
#pragma unroll
            for (int p = 0; p < 2; p++) {
#pragma unroll
                for (int in = 0; in < 8; in++) {
                    const uint32_t* af = (p == 1) ? al : ah;
                    mma16816(acc[in], af, &bh[in >> 1][(in & 1) * 2]);
                }
            }
        }
        __syncthreads();
    }

    const int o0 = wm * 16 + (lane >> 2);
    const int o1 = o0 + 8;
    const float bm0 = bmlp[o0], bm1 = bmlp[o1];
    const float we0 = wend[o0], we1 = wend[o1];

#pragma unroll
    for (int in = 0; in < 8; in++) {
        float g00 = gelu_exact(acc[in][0] + bm0);
        float g01 = gelu_exact(acc[in][1] + bm0);
        float g10 = gelu_exact(acc[in][2] + bm1);
        float g11 = gelu_exact(acc[in][3] + bm1);
        float p0 = we0 * g00 + we1 * g10;
        float p1 = we0 * g01 + we1 * g11;
#pragma unroll
        for (int d = 4; d <= 16; d <<= 1) {
            p0 += __shfl_xor_sync(0xFFFFFFFF, p0, d);
            p1 += __shfl_xor_sync(0xFFFFFFFF, p1, d);
        }
        if (lane < 4) {
            red[wm][wn * 64 + in * 8 + lane * 2 + 0] = p0;
            red[wm][wn * 64 + in * 8 + lane * 2 + 1] = p1;
        }
    }
    __syncthreads();
    if (tid < 128) {
        int n = n0 + tid;
        float s = bend[0] + red[0][tid] + red[1][tid] + red[2][tid] + red[3][tid];
        g_Sh[(size_t)b * NP + n] = __float2half_rn((n < N_NODE) ? s : 0.f);
    }
#undef LOAD_BCH
}

// ---------------- kernel 5: final linear on HMMA (fp16 single-product) ----------------
__global__ __launch_bounds__(256) void k_lin_mma(const float* __restrict__ blin) {
    extern __shared__ char smem[];
    const uint32_t sbase = smem_u32(smem);
    const int tid = threadIdx.x;
    const int wid = tid >> 5, lane = tid & 31;
    const int wm = wid >> 1;
    const int wn = wid & 1;
    const int n0 = blockIdx.x * LIN_TN;

#define LIN_LOAD(cidx, stg) do {                                                     \
    _Pragma("unroll")                                                                \
    for (int i = 0; i < 2; i++) {                                                    \
        int idx = tid + i * 256;                                                     \
        int row = idx >> 3, s = idx & 7;                                             \
        uint32_t so = ((uint32_t)(s ^ (row & 7)) << 4);                              \
        cpa16(sbase + (stg) * LIN_STG + row * 128 + so,                              \
              (const char*)(g_Sh + (size_t)row * NP) + (size_t)(cidx) * 128 + s * 16); \
        cpa16(sbase + (stg) * LIN_STG + LIN_A_BYTES + row * 128 + so,                \
              (const char*)(g_Wl + (size_t)(n0 + row) * NP) + (size_t)(cidx) * 128 + s * 16); \
    }                                                                                \
} while (0)

    float acc[4][4];
#pragma unroll
    for (int in = 0; in < 4; in++)
#pragma unroll
        for (int q = 0; q < 4; q++) acc[in][q] = 0.f;

    const int a_row_l = (lane & 15);
    const int a_jl = lane >> 4;
    const int b_row_l = ((lane >> 4) << 3) + (lane & 7);
    const int b_jl = (lane >> 3) & 1;

    LIN_LOAD(0, 0); CPA_COMMIT();

    for (int c = 0; c < 32; c++) {
        CPA_WAIT(0);
        __syncthreads();
        if (c + 1 < 32) { LIN_LOAD(c + 1, (c + 1) & 1); CPA_COMMIT(); }
        uint32_t astg = sbase + (c & 1) * LIN_STG;
        uint32_t bstg = astg + LIN_A_BYTES;
#pragma unroll
        for (int ks = 0; ks < 4; ks++) {
            uint32_t ah[4], bh[2][4];
            {
                int row = wm * 16 + a_row_l;
                uint32_t off = (uint32_t)row * 128 +
                               ((uint32_t)((2 * ks + a_jl) ^ (row & 7)) << 4);
                ldsm4(ah, astg + off);
            }
#pragma unroll
            for (int inb = 0; inb < 2; inb++) {
                int row = wn * 32 + inb * 16 + b_row_l;
                uint32_t off = (uint32_t)row * 128 +
                               ((uint32_t)((2 * ks + b_jl) ^ (row & 7)) << 4);
                ldsm4(bh[inb], bstg + off);
            }
#pragma unroll
            for (int in = 0; in < 4; in++)
                mma16816(acc[in], ah, &bh[in >> 1][(in & 1) * 2]);
        }
        __syncthreads();
    }

#pragma unroll
    for (int in = 0; in < 4; in++) {
        int d = n0 + wn * 32 + in * 8 + (lane & 3) * 2;
        int b0 = wm * 16 + (lane >> 2), b1 = b0 + 8;
        float bl0 = blin[d], bl1 = blin[d + 1];
        g_Y[(size_t)b0 * DM + d]     = acc[in][0] + bl0;
        g_Y[(size_t)b0 * DM + d + 1] = acc[in][1] + bl1;
        g_Y[(size_t)b1 * DM + d]     = acc[in][2] + bl0;
        g_Y[(size_t)b1 * DM + d + 1] = acc[in][3] + bl1;
    }
#undef LIN_LOAD
}

// ---------------- kernel 6: layernorm ----------------
__global__ void k_ln(const float* __restrict__ gam, const float* __restrict__ bet,
                     float* __restrict__ out) {
    int b = blockIdx.x;
    int tid = threadIdx.x;
    __shared__ float red[256];
    const float* y = g_Y + (size_t)b * DM;

    float s = 0.f;
    for (int d = tid; d < DM; d += 256) s += y[d];
    red[tid] = s; __syncthreads();
    for (int st = 128; st > 0; st >>= 1) { if (tid < st) red[tid] += red[tid + st]; __syncthreads(); }
    float mu = red[0] / DM;
    __syncthreads();

    float v = 0.f;
    for (int d = tid; d < DM; d += 256) { float t = y[d] - mu; v += t * t; }
    red[tid] = v; __syncthreads();
    for (int st = 128; st > 0; st >>= 1) { if (tid < st) red[tid] += red[tid + st]; __syncthreads(); }
    float rinv = rsqrtf(red[0] / DM + 1e-5f);

    for (int d = tid; d < DM; d += 256)
        out[(size_t)b * DM + d] = (y[d] - mu) * rinv * gam[d] + bet[d];
}

// ---------------- launch ----------------
extern "C" void kernel_launch(void* const* d_in, const int* in_sizes, int n_in,
                              void* d_out, int out_size) {
    const float* x       = (const float*)d_in[0];
    const float* nv1     = (const float*)d_in[1];
    const float* nv2     = (const float*)d_in[2];
    const float* w_start = (const float*)d_in[3];
    const float* b_start = (const float*)d_in[4];
    const float* w_mlp   = (const float*)d_in[5];
    const float* b_mlp   = (const float*)d_in[6];
    const float* w_end   = (const float*)d_in[7];
    const float* b_end   = (const float*)d_in[8];
    const float* w_lin   = (const float*)d_in[9];
    const float* b_lin   = (const float*)d_in[10];
    const float* ln_g    = (const float*)d_in[11];
    const float* ln_b    = (const float*)d_in[12];
    float* out = (float*)d_out;

    cudaFuncSetAttribute(k_mix_mma,  cudaFuncAttributeMaxDynamicSharedMemorySize, MIX_SMEM);
    cudaFuncSetAttribute(k_mlp_mma,  cudaFuncAttributeMaxDynamicSharedMemorySize, MLP_SMEM);
    cudaFuncSetAttribute(k_conv_mma, cudaFuncAttributeMaxDynamicSharedMemorySize, CV_SMEM);
    cudaFuncSetAttribute(k_adj,      cudaFuncAttributeMaxDynamicSharedMemorySize, ADJ_SMEM);
    cudaFuncSetAttribute(k_lin_mma,  cudaFuncAttributeMaxDynamicSharedMemorySize, LIN_SMEM);

    k_prepw<<<IN_D, 256>>>(w_start);
    k_prepl<<<DM, 256>>>(w_lin);
    k_adj<<<NP / ADJ_R, 256, ADJ_SMEM>>>(nv1, nv2);
    k_conv_mma<<<dim3(NP / 128, BATCH), 256, CV_SMEM>>>(x, b_start);
    dim3 mixg(NP / TILE_N, MROWS / TILE_M);
    k_mix_mma<<<mixg, 256, MIX_SMEM>>>(0, 1);
    k_mix_mma<<<mixg, 256, MIX_SMEM>>>(1, 2);
    k_mix_mma<<<mixg, 256, MIX_SMEM>>>(2, 3);
    k_mlp_mma<<<dim3(NP / 128, BATCH), 256, MLP_SMEM>>>(w_mlp, b_mlp, w_end, b_end);
    k_lin_mma<<<NP / LIN_TN, 256, LIN_SMEM>>>(b_lin);
    k_ln<<<BATCH, 256>>>(ln_g, ln_b, out);
}

// round 12
// speedup vs baseline: 5.8490x; 1.0266x over previous
#include <cuda_runtime.h>
#include <cuda_fp16.h>
#include <math.h>
#include <stdint.h>

// ---------------- problem constants ----------------
#define N_NODE 2000
#define NP     2048
#define BATCH  64
#define CC     64
#define MROWS  (BATCH*CC)    // 4096
#define DM     2048
#define IN_D   7
#define KW     49
#define ND     40
#define ALPHA_C 0.05f
#define BETA_C  0.95f

// mix GEMM tiling
#define NCHUNK  32
#define TILE_M  128
#define TILE_N  128
#define VAR_BYTES (128 * 128)
#define OFF_AH  0
#define OFF_BH  (VAR_BYTES)
#define STAGE_BYTES (2 * VAR_BYTES)
#define NSTAGE  3
#define MIX_SMEM (NSTAGE * STAGE_BYTES)  // 98304

// mlp GEMM smem layout
#define MLP_A_HI   0
#define MLP_A_LO   32768
#define MLP_B_BASE 65536
#define MLP_B_STG  16384
#define MLP_SMEM   98304

// conv GEMM smem layout (x window fp16)
#define CV_A_STG   16384
#define CV_A_VAR   8192
#define CV_B_STG   16384
#define CV_A0      0
#define CV_B0      (2 * CV_A_STG)              // 32768
#define CV_XW      (CV_B0 + 2 * CV_B_STG)      // 65536
#define CV_SMEM    (CV_XW + 2 * 384)           // 66304

// adj
#define ADJ_R   8
#define ADJ_SMEM (ADJ_R * NP * 4)

// lin GEMM (d-tile 32 -> 64 CTAs)
#define LIN_TN  32
#define LIN_A_BYTES (64 * 128)
#define LIN_B_BYTES (LIN_TN * 128)
#define LIN_STG (LIN_A_BYTES + LIN_B_BYTES)   // 12288
#define LIN_SMEM (2 * LIN_STG)                // 24576

// fused prep block ranges
#define PREP_W 7
#define PREP_L 2048
#define PREP_X 448
#define PREP_M 64
#define PREP_BLOCKS (PREP_W + PREP_L + PREP_X + PREP_M)   // 2567

// ---------------- scratch ----------------
__device__ __half  g_Ahi[4 * MROWS * NP];   // fp16 hi of hops
__device__ __half  g_Alo[4 * MROWS * NP];   // fp16 lo of hops
__device__ __half  g_Bh[NP * NP];           // adjacency
__device__ __half  g_Whi[IN_D * CC * 64];   // conv weights hi [ci][co][64]
__device__ __half  g_Wlo[IN_D * CC * 64];
__device__ __half  g_Wl[NP * NP];           // w_lin fp16 [d][node]
__device__ __half  g_Mhi[CC * 256];         // w_mlp hi [o][256]
__device__ __half  g_Mlo[CC * 256];
__device__ __half  g_Xh[BATCH * IN_D * DM + 128];  // x fp16 (+zeroed pad)
__device__ __half  g_Sh[BATCH * NP];        // skip output fp16
__device__ float   g_Y[BATCH * DM];

// ---------------- helpers ----------------
__device__ __forceinline__ uint32_t smem_u32(const void* p) {
    uint32_t a;
    asm("{ .reg .u64 t; cvta.to.shared.u64 t, %1; cvt.u32.u64 %0, t; }" : "=r"(a) : "l"(p));
    return a;
}
__device__ __forceinline__ void cpa16(uint32_t s, const void* g) {
    asm volatile("cp.async.cg.shared.global [%0], [%1], 16;" :: "r"(s), "l"(g));
}
#define CPA_COMMIT() asm volatile("cp.async.commit_group;" ::: "memory")
#define CPA_WAIT(n)  asm volatile("cp.async.wait_group %0;" :: "n"(n) : "memory")

__device__ __forceinline__ void ldsm4(uint32_t* r, uint32_t addr) {
    asm volatile("ldmatrix.sync.aligned.m8n8.x4.shared.b16 {%0,%1,%2,%3}, [%4];"
                 : "=r"(r[0]), "=r"(r[1]), "=r"(r[2]), "=r"(r[3]) : "r"(addr));
}
__device__ __forceinline__ void ldsm4t(uint32_t* r, uint32_t addr) {
    asm volatile("ldmatrix.sync.aligned.m8n8.x4.trans.shared.b16 {%0,%1,%2,%3}, [%4];"
                 : "=r"(r[0]), "=r"(r[1]), "=r"(r[2]), "=r"(r[3]) : "r"(addr));
}
__device__ __forceinline__ void mma16816(float* d, const uint32_t* a, const uint32_t* b) {
    asm volatile("mma.sync.aligned.m16n8k16.row.col.f32.f16.f16.f32 "
                 "{%0,%1,%2,%3}, {%4,%5,%6,%7}, {%8,%9}, {%0,%1,%2,%3};"
                 : "+f"(d[0]), "+f"(d[1]), "+f"(d[2]), "+f"(d[3])
                 : "r"(a[0]), "r"(a[1]), "r"(a[2]), "r"(a[3]), "r"(b[0]), "r"(b[1]));
}
__device__ __forceinline__ void fp16_split(float v, __half& hi, __half& lo) {
    hi = __float2half_rn(v);
    lo = __float2half_rn(v - __half2float(hi));
}
__device__ __forceinline__ float gelu_exact(float v) {
    return 0.5f * v * (1.f + erff(v * 0.70710678118654752f));
}

// ---------------- kernel 0: fused prep (conv w, w_lin, x, w_mlp) ----------------
__global__ void k_prep(const float* __restrict__ w_start,
                       const float* __restrict__ wlin,
                       const float* __restrict__ x,
                       const float* __restrict__ wmlp) {
    int bid = blockIdx.x;
    int tid = threadIdx.x;
    if (bid < PREP_W) {
        int ci = bid;
        for (int idx = tid; idx < CC * 64; idx += 256) {
            int co = idx >> 6, t = idx & 63;
            float v = (t < KW) ? w_start[co * (IN_D * KW) + ci * KW + t] : 0.f;
            __half h, l; fp16_split(v, h, l);
            g_Whi[ci * CC * 64 + idx] = h;
            g_Wlo[ci * CC * 64 + idx] = l;
        }
    } else if (bid < PREP_W + PREP_L) {
        int d = bid - PREP_W;
        for (int w = tid; w < NP; w += 256) {
            float v = (w < N_NODE) ? wlin[(size_t)d * N_NODE + w] : 0.f;
            g_Wl[(size_t)d * NP + w] = __float2half_rn(v);
        }
    } else if (bid < PREP_W + PREP_L + PREP_X) {
        int row = bid - PREP_W - PREP_L;           // 0..447 = b*7+ci
        size_t base = (size_t)row * DM;
        for (int i = tid; i < DM; i += 256)
            g_Xh[base + i] = __float2half_rn(x[base + i]);
        if (row == PREP_X - 1 && tid < 128)        // zero pad tail
            g_Xh[(size_t)BATCH * IN_D * DM + tid] = __float2half(0.f);
    } else {
        int o = bid - PREP_W - PREP_L - PREP_X;    // 0..63
        for (int i = tid; i < 256; i += 256) {
            float v = wmlp[o * 256 + i];
            __half h, l; fp16_split(v, h, l);
            g_Mhi[o * 256 + i] = h;
            g_Mlo[o * 256 + i] = l;
        }
    }
}

// ---------------- kernel 1: adjacency, 8 rows per CTA ----------------
__global__ void k_adj(const float* __restrict__ E1, const float* __restrict__ E2) {
    extern __shared__ float z[];
    __shared__ float e1s[ADJ_R][ND];
    __shared__ float red[256];
    __shared__ float srow[ADJ_R];
    int tid = threadIdx.x;
    int r0 = blockIdx.x * ADJ_R;

    if (r0 >= N_NODE) {
        for (int r = 0; r < ADJ_R; r++) {
            int v = r0 + r;
            if (v < NP)
                for (int w = tid; w < NP; w += 256) g_Bh[(size_t)v * NP + w] = __float2half(0.f);
        }
        return;
    }

    for (int idx = tid; idx < ADJ_R * ND; idx += 256)
        e1s[idx / ND][idx % ND] = E1[(r0 + idx / ND) * ND + idx % ND];
    __syncthreads();

    float lmax[ADJ_R];
#pragma unroll
    for (int r = 0; r < ADJ_R; r++) lmax[r] = -1e30f;

    for (int w = tid; w < N_NODE; w += 256) {
        float acc[ADJ_R];
#pragma unroll
        for (int r = 0; r < ADJ_R; r++) acc[r] = 0.f;
#pragma unroll 8
        for (int k = 0; k < ND; k++) {
            float e2 = E2[k * N_NODE + w];
#pragma unroll
            for (int r = 0; r < ADJ_R; r++) acc[r] += e1s[r][k] * e2;
        }
#pragma unroll
        for (int r = 0; r < ADJ_R; r++) {
            float v = fmaxf(acc[r], 0.f);
            z[r * NP + w] = v;
            lmax[r] = fmaxf(lmax[r], v);
        }
    }
#pragma unroll
    for (int r = 0; r < ADJ_R; r++) {
        red[tid] = lmax[r]; __syncthreads();
        for (int s = 128; s > 0; s >>= 1) { if (tid < s) red[tid] = fmaxf(red[tid], red[tid + s]); __syncthreads(); }
        if (tid == 0) srow[r] = red[0];
        __syncthreads();
    }
    float lsum[ADJ_R];
#pragma unroll
    for (int r = 0; r < ADJ_R; r++) lsum[r] = 0.f;
    for (int w = tid; w < N_NODE; w += 256) {
#pragma unroll
        for (int r = 0; r < ADJ_R; r++) {
            float e = expf(z[r * NP + w] - srow[r]);
            z[r * NP + w] = e;
            lsum[r] += e;
        }
    }
#pragma unroll
    for (int r = 0; r < ADJ_R; r++) {
        red[tid] = lsum[r]; __syncthreads();
        for (int s = 128; s > 0; s >>= 1) { if (tid < s) red[tid] += red[tid + s]; __syncthreads(); }
        if (tid == 0) srow[r] = 0.5f / red[0];
        __syncthreads();
    }
    for (int w = tid; w < NP; w += 256) {
#pragma unroll
        for (int r = 0; r < ADJ_R; r++) {
            int v = r0 + r;
            float val = (w < N_NODE) ? (z[r * NP + w] * srow[r] + ((w == v) ? 0.5f : 0.f)) : 0.f;
            g_Bh[(size_t)v * NP + w] = __float2half_rn(val);
        }
    }
}

// ---------------- kernel 2: start conv on HMMA (2-product, fp16 x prepped) ---------
__global__ __launch_bounds__(256, 2) void k_conv_mma(const float* __restrict__ bias) {
    extern __shared__ char smem[];
    const uint32_t sbase = smem_u32(smem);
    __half* xw = (__half*)(smem + CV_XW);          // [2][192] fp16 windows
    const int tid = threadIdx.x;
    const int wid = tid >> 5, lane = tid & 31;
    const int wm = wid >> 1;
    const int wn = wid & 1;
    const int b  = blockIdx.y;
    const int n0 = blockIdx.x * 128;

#define CV_LOAD_A(ci, stg) do {                                                      \
    _Pragma("unroll")                                                                \
    for (int i = 0; i < 2; i++) {                                                    \
        int idx = tid + i * 256;                                                     \
        int co = idx >> 3, s = idx & 7;                                              \
        uint32_t dst = sbase + CV_A0 + (stg) * CV_A_STG + co * 128 +                 \
                       ((uint32_t)(s ^ (co & 7)) << 4);                              \
        cpa16(dst,            (const char*)(g_Whi + (ci) * CC * 64 + co * 64 + s * 8)); \
        cpa16(dst + CV_A_VAR, (const char*)(g_Wlo + (ci) * CC * 64 + co * 64 + s * 8)); \
    }                                                                                \
} while (0)

// 192 halves = 384 B = 24 x 16B (overread past n=2047 hits next row / zeroed pad;
// those positions only multiply zero-weight taps or masked outputs)
#define CV_LOAD_XW(ci, stg) do {                                                     \
    if (tid < 24)                                                                    \
        cpa16(sbase + CV_XW + (stg) * 384 + tid * 16,                                \
              (const char*)(g_Xh + (size_t)b * IN_D * DM + (ci) * DM + n0) + tid * 16); \
} while (0)

#define CV_BUILD_B(stg) do {                                                         \
    const __half* xwp = xw + (stg) * 192;                                            \
    _Pragma("unroll")                                                                \
    for (int i = 0; i < 16; i++) {                                                   \
        int idx = tid + i * 256;                                                     \
        int t = idx >> 6, j2 = idx & 63;                                             \
        int n = j2 * 2;                                                              \
        __half2 hh(xwp[t + n], xwp[t + n + 1]);                                      \
        int s = n >> 3;                                                              \
        uint32_t off = t * 256 + ((uint32_t)(s ^ (t & 7)) << 4) + (j2 & 3) * 4;      \
        *(uint32_t*)(smem + CV_B0 + (stg) * CV_B_STG + off) = *reinterpret_cast<uint32_t*>(&hh); \
    }                                                                                \
} while (0)

    float acc[8][4];
#pragma unroll
    for (int in = 0; in < 8; in++)
#pragma unroll
        for (int q = 0; q < 4; q++) acc[in][q] = 0.f;

    const int a_row = wm * 16 + (lane & 15);
    const int a_jl  = lane >> 4;
    const int b_kl  = ((lane >> 3) & 1) * 8 + (lane & 7);
    const int b_nl  = lane >> 4;

    CV_LOAD_A(0, 0);
    CV_LOAD_XW(0, 0);
    CPA_COMMIT();
    CPA_WAIT(0);
    __syncthreads();
    CV_BUILD_B(0);
    __syncthreads();

    for (int c = 0; c < IN_D; c++) {
        int stg = c & 1, nstg = (c + 1) & 1;
        if (c + 1 < IN_D) { CV_LOAD_A(c + 1, nstg); CV_LOAD_XW(c + 1, nstg); CPA_COMMIT(); }

        uint32_t astg = sbase + CV_A0 + stg * CV_A_STG;
        uint32_t bstg = sbase + CV_B0 + stg * CV_B_STG;
#pragma unroll
        for (int ks = 0; ks < 4; ks++) {
            uint32_t ah[4], al[4], bh[4][4];
            {
                int s = 2 * ks + a_jl;
                uint32_t off = (uint32_t)a_row * 128 + ((uint32_t)(s ^ (a_row & 7)) << 4);
                ldsm4(ah, astg + off);
                ldsm4(al, astg + CV_A_VAR + off);
            }
            int krow = ks * 16 + b_kl;
            uint32_t koff = (uint32_t)krow * 256;
            uint32_t kx = (uint32_t)(krow & 7);
#pragma unroll
            for (int q = 0; q < 4; q++) {
                int ns = wn * 8 + 2 * q + b_nl;
                uint32_t off = koff + ((uint32_t)(ns ^ kx) << 4);
                ldsm4t(bh[q], bstg + off);
            }
#pragma unroll
            for (int p = 0; p < 2; p++) {
#pragma unroll
                for (int in = 0; in < 8; in++) {
                    const uint32_t* af = (p == 1) ? al : ah;
                    mma16816(acc[in], af, &bh[in >> 1][(in & 1) * 2]);
                }
            }
        }
        if (c + 1 < IN_D) {
            CPA_WAIT(0);
            __syncthreads();
            CV_BUILD_B(nstg);
            __syncthreads();
        }
    }

    const int o0 = wm * 16 + (lane >> 2);
    const int o1 = o0 + 8;
    const float b0v = bias[o0], b1v = bias[o1];
#pragma unroll
    for (int in = 0; in < 8; in++) {
        int n = n0 + wn * 64 + in * 8 + (lane & 3) * 2;
        bool ok = (n < N_NODE);
        float v00 = ok ? (acc[in][0] + b0v) : 0.f;
        float v01 = ok ? (acc[in][1] + b0v) : 0.f;
        float v10 = ok ? (acc[in][2] + b1v) : 0.f;
        float v11 = ok ? (acc[in][3] + b1v) : 0.f;
        size_t r0 = (size_t)(b * CC + o0) * NP + n;
        size_t r1 = (size_t)(b * CC + o1) * NP + n;
        __half h0, l0, h1, l1;
        fp16_split(v00, h0, l0); fp16_split(v01, h1, l1);
        *(__half2*)(g_Ahi + r0) = __half2(h0, h1);
        *(__half2*)(g_Alo + r0) = __half2(l0, l1);
        fp16_split(v10, h0, l0); fp16_split(v11, h1, l1);
        *(__half2*)(g_Ahi + r1) = __half2(h0, h1);
        *(__half2*)(g_Alo + r1) = __half2(l0, l1);
    }
#undef CV_LOAD_A
#undef CV_LOAD_XW
#undef CV_BUILD_B
}

// ---------------- kernel 3: mixprop GEMM on HMMA (fp16 single-product, KC=64) ----
__global__ __launch_bounds__(256, 2) void k_mix_mma(int src, int dst) {
    extern __shared__ char smem[];
    const uint32_t sbase = smem_u32(smem);

    const int tid = threadIdx.x;
    const int wid = tid >> 5, lane = tid & 31;
    const int wm = wid >> 2;
    const int wn = wid & 3;
    const int m0 = blockIdx.y * TILE_M;
    const int n0 = blockIdx.x * TILE_N;

    const __half* Ahi = g_Ahi + (size_t)src * MROWS * NP;

    const int lr = tid >> 1;
    const int ls = (tid & 1) * 4;
    const uint32_t lswz = (uint32_t)(lr & 7);
    const char* gA = (const char*)(Ahi + (size_t)(m0 + lr) * NP) + ls * 16;
    const char* gB = (const char*)(g_Bh + (size_t)(n0 + lr) * NP) + ls * 16;

#define LOAD_CHUNK(cidx, buf) do {                                                   \
    uint32_t sb = sbase + (buf) * STAGE_BYTES + lr * 128;                            \
    size_t go = (size_t)(cidx) * 128;                                                \
    _Pragma("unroll")                                                                \
    for (int j = 0; j < 4; j++) {                                                    \
        uint32_t so = ((uint32_t)(ls + j) ^ lswz) << 4;                              \
        cpa16(sb + OFF_AH + so, gA + go + j * 16);                                   \
        cpa16(sb + OFF_BH + so, gB + go + j * 16);                                   \
    }                                                                                \
} while (0)

    float acc[4][4][4];
#pragma unroll
    for (int im = 0; im < 4; im++)
#pragma unroll
        for (int in = 0; in < 4; in++)
#pragma unroll
            for (int q = 0; q < 4; q++) acc[im][in][q] = 0.f;

    const int a_row_l = (lane & 15);
    const int a_jl = lane >> 4;
    const int b_row_l = ((lane >> 4) << 3) + (lane & 7);
    const int b_jl = (lane >> 3) & 1;

    LOAD_CHUNK(0, 0); CPA_COMMIT();
    LOAD_CHUNK(1, 1); CPA_COMMIT();

    int buf = 0, nbuf = 2;
    for (int c = 0; c < NCHUNK; c++) {
        if (c + 1 < NCHUNK) { CPA_WAIT(1); } else { CPA_WAIT(0); }
        __syncthreads();
        if (c + 2 < NCHUNK) { LOAD_CHUNK(c + 2, nbuf); CPA_COMMIT(); }

        uint32_t sb = sbase + buf * STAGE_BYTES;
#pragma unroll
        for (int ks = 0; ks < 4; ks++) {
            uint32_t ah[4][4], bh[2][4];
#pragma unroll
            for (int im = 0; im < 4; im++) {
                int row = wm * 64 + im * 16 + a_row_l;
                uint32_t off = (uint32_t)row * 128 +
                               ((uint32_t)((2 * ks + a_jl) ^ (row & 7)) << 4);
                ldsm4(ah[im], sb + OFF_AH + off);
            }
#pragma unroll
            for (int inb = 0; inb < 2; inb++) {
                int row = wn * 32 + inb * 16 + b_row_l;
                uint32_t off = (uint32_t)row * 128 +
                               ((uint32_t)((2 * ks + b_jl) ^ (row & 7)) << 4);
                ldsm4(bh[inb], sb + OFF_BH + off);
            }
#pragma unroll
            for (int im = 0; im < 4; im++) {
#pragma unroll
                for (int in = 0; in < 4; in++) {
                    mma16816(acc[im][in], ah[im], &bh[in >> 1][(in & 1) * 2]);
                }
            }
        }
        buf = (buf == NSTAGE - 1) ? 0 : buf + 1;
        nbuf = (nbuf == NSTAGE - 1) ? 0 : nbuf + 1;
    }

    const __half* Xh = g_Ahi;
    const __half* Xl = g_Alo;
    __half* Hh = g_Ahi + (size_t)dst * MROWS * NP;
    __half* Hl = g_Alo + (size_t)dst * MROWS * NP;

#pragma unroll
    for (int im = 0; im < 4; im++) {
#pragma unroll
        for (int half = 0; half < 2; half++) {
            int m = m0 + wm * 64 + im * 16 + (lane >> 2) + half * 8;
            size_t rowo = (size_t)m * NP;
#pragma unroll
            for (int in = 0; in < 4; in++) {
                int n = n0 + wn * 32 + in * 8 + (lane & 3) * 2;
                float d0 = acc[im][in][half * 2 + 0];
                float d1 = acc[im][in][half * 2 + 1];
                __half2 xh = *(const __half2*)(Xh + rowo + n);
                __half2 xl = *(const __half2*)(Xl + rowo + n);
                float x0 = __half2float(xh.x) + __half2float(xl.x);
                float x1 = __half2float(xh.y) + __half2float(xl.y);
                float o0 = ALPHA_C * x0 + BETA_C * d0;
                float o1 = ALPHA_C * x1 + BETA_C * d1;
                __half h0, l0, h1, l1;
                fp16_split(o0, h0, l0); fp16_split(o1, h1, l1);
                *(__half2*)(Hh + rowo + n) = __half2(h0, h1);
                *(__half2*)(Hl + rowo + n) = __half2(l0, l1);
            }
        }
    }
#undef LOAD_CHUNK
}

// ---------------- kernel 4: MLP on HMMA (2-product) + GELU + end dot ----------------
__global__ __launch_bounds__(256) void k_mlp_mma(const float* __restrict__ bmlp,
                                                 const float* __restrict__ wend,
                                                 const float* __restrict__ bend) {
    extern __shared__ char smem[];
    __shared__ float red[4][128];
    const uint32_t sbase = smem_u32(smem);
    const int tid = threadIdx.x;
    const int wid = tid >> 5, lane = tid & 31;
    const int wm = wid >> 1;
    const int wn = wid & 1;
    const int b  = blockIdx.y;
    const int n0 = blockIdx.x * 128;

    // A tiles: cp.async prepped w_mlp hi/lo into swizzled smem (rows 512B, 32 segs)
#pragma unroll
    for (int i = 0; i < 8; i++) {
        int idx = tid + i * 256;            // 2048 = 64 rows x 32 segs
        int o = idx >> 5, s = idx & 31;
        uint32_t phys = (uint32_t)(s ^ (o & 15));
        uint32_t dst = sbase + o * 512 + phys * 16;
        cpa16(dst + MLP_A_HI, (const char*)(g_Mhi + o * 256 + s * 8));
        cpa16(dst + MLP_A_LO, (const char*)(g_Mlo + o * 256 + s * 8));
    }

#define LOAD_BCH(chunk, stg) do {                                                        \
    const __half* HBh = g_Ahi + ((size_t)(chunk) * MROWS + b * 64) * NP + n0;            \
    _Pragma("unroll")                                                                    \
    for (int i = 0; i < 4; i++) {                                                        \
        int idx = tid + i * 256;                                                         \
        int k = idx >> 4, s = idx & 15;                                                  \
        uint32_t phys = (uint32_t)(s ^ (k & 7));                                         \
        uint32_t dst = sbase + MLP_B_BASE + (stg) * MLP_B_STG + k * 256 + phys * 16;     \
        cpa16(dst, (const char*)HBh + (size_t)k * NP * 2 + s * 16);                      \
    }                                                                                    \
} while (0)

    float acc[8][4];
#pragma unroll
    for (int in = 0; in < 8; in++)
#pragma unroll
        for (int q = 0; q < 4; q++) acc[in][q] = 0.f;

    const int a_row = wm * 16 + (lane & 15);
    const int a_jl  = lane >> 4;
    const int b_kl  = ((lane >> 3) & 1) * 8 + (lane & 7);
    const int b_nl  = lane >> 4;

    LOAD_BCH(0, 0); CPA_COMMIT();

    for (int chunk = 0; chunk < 4; chunk++) {
        CPA_WAIT(0);
        __syncthreads();
        if (chunk < 3) { LOAD_BCH(chunk + 1, (chunk + 1) & 1); CPA_COMMIT(); }
        uint32_t bstg = sbase + MLP_B_BASE + (chunk & 1) * MLP_B_STG;

#pragma unroll
        for (int ks = 0; ks < 4; ks++) {
            int ksg = chunk * 4 + ks;
            uint32_t ah[4], al[4], bh[4][4];
            {
                int s = 2 * ksg + a_jl;
                uint32_t off = (uint32_t)a_row * 512 + ((uint32_t)(s ^ (a_row & 15)) << 4);
                ldsm4(ah, sbase + MLP_A_HI + off);
                ldsm4(al, sbase + MLP_A_LO + off);
            }
            int krow = ks * 16 + b_kl;
            uint32_t koff = (uint32_t)krow * 256;
            uint32_t kx = (uint32_t)(krow & 7);
#pragma unroll
            for (int q = 0; q < 4; q++) {
                int ns = wn * 8 + 2 * q + b_nl;
                uint32_t off = koff + ((uint32_t)(ns ^ kx) << 4);
                ldsm4t(bh[q], bstg + off);
            }
#pragma unroll
            for (int p = 0; p < 2; p++) {
#pragma unroll
                for (int in = 0; in < 8; in++) {
                    const uint32_t* af = (p == 1) ? al : ah;
                    mma16816(acc[in], af, &bh[in >> 1][(in & 1) * 2]);
                }
            }
        }
        __syncthreads();
    }

    const int o0 = wm * 16 + (lane >> 2);
    const int o1 = o0 + 8;
    const float bm0 = bmlp[o0], bm1 = bmlp[o1];
    const float we0 = wend[o0], we1 = wend[o1];

#pragma unroll
    for (int in = 0; in < 8; in++) {
        float g00 = gelu_exact(acc[in][0] + bm0);
        float g01 = gelu_exact(acc[in][1] + bm0);
        float g10 = gelu_exact(acc[in][2] + bm1);
        float g11 = gelu_exact(acc[in][3] + bm1);
        float p0 = we0 * g00 + we1 * g10;
        float p1 = we0 * g01 + we1 * g11;
#pragma unroll
        for (int d = 4; d <= 16; d <<= 1) {
            p0 += __shfl_xor_sync(0xFFFFFFFF, p0, d);
            p1 += __shfl_xor_sync(0xFFFFFFFF, p1, d);
        }
        if (lane < 4) {
            red[wm][wn * 64 + in * 8 + lane * 2 + 0] = p0;
            red[wm][wn * 64 + in * 8 + lane * 2 + 1] = p1;
        }
    }
    __syncthreads();
    if (tid < 128) {
        int n = n0 + tid;
        float s = bend[0] + red[0][tid] + red[1][tid] + red[2][tid] + red[3][tid];
        g_Sh[(size_t)b * NP + n] = __float2half_rn((n < N_NODE) ? s : 0.f);
    }
#undef LOAD_BCH
}

// ---------------- kernel 5: final linear on HMMA (d-tile 32, 64 CTAs) ----------------
__global__ __launch_bounds__(256) void k_lin_mma(const float* __restrict__ blin) {
    extern __shared__ char smem[];
    const uint32_t sbase = smem_u32(smem);
    const int tid = threadIdx.x;
    const int wid = tid >> 5, lane = tid & 31;
    const int wm = wid >> 1;          // 0..3 batch 16-row group
    const int wn = wid & 1;           // 0..1 d 16-col half
    const int n0 = blockIdx.x * LIN_TN;

#define LIN_LOAD(cidx, stg) do {                                                     \
    _Pragma("unroll")                                                                \
    for (int i = 0; i < 2; i++) {                                                    \
        int idx = tid + i * 256;                                                     \
        int row = idx >> 3, s = idx & 7;                                             \
        uint32_t so = ((uint32_t)(s ^ (row & 7)) << 4);                              \
        cpa16(sbase + (stg) * LIN_STG + row * 128 + so,                              \
              (const char*)(g_Sh + (size_t)row * NP) + (size_t)(cidx) * 128 + s * 16); \
    }                                                                                \
    {                                                                                \
        int row = tid >> 3, s = tid & 7;    /* 256 entries = 32 rows x 8 segs */     \
        uint32_t so = ((uint32_t)(s ^ (row & 7)) << 4);                              \
        cpa16(sbase + (stg) * LIN_STG + LIN_A_BYTES + row * 128 + so,                \
              (const char*)(g_Wl + (size_t)(n0 + row) * NP) + (size_t)(cidx) * 128 + s * 16); \
    }                                                                                \
} while (0)

    float acc[2][4];
#pragma unroll
    for (int in = 0; in < 2; in++)
#pragma unroll
        for (int q = 0; q < 4; q++) acc[in][q] = 0.f;

    const int a_row_l = (lane & 15);
    const int a_jl = lane >> 4;
    const int b_row_l = ((lane >> 4) << 3) + (lane & 7);
    const int b_jl = (lane >> 3) & 1;

    LIN_LOAD(0, 0); CPA_COMMIT();

    for (int c = 0; c < 32; c++) {
        CPA_WAIT(0);
        __syncthreads();
        if (c + 1 < 32) { LIN_LOAD(c + 1, (c + 1) & 1); CPA_COMMIT(); }
        uint32_t astg = sbase + (c & 1) * LIN_STG;
        uint32_t bstg = astg + LIN_A_BYTES;
#pragma unroll
        for (int ks = 0; ks < 4; ks++) {
            uint32_t ah[4], bh[4];
            {
                int row = wm * 16 + a_row_l;
                uint32_t off = (uint32_t)row * 128 +
                               ((uint32_t)((2 * ks + a_jl) ^ (row & 7)) << 4);
                ldsm4(ah, astg + off);
            }
            {
                int row = wn * 16 + b_row_l;
                uint32_t off = (uint32_t)row * 128 +
                               ((uint32_t)((2 * ks + b_jl) ^ (row & 7)) << 4);
                ldsm4(bh, bstg + off);
            }
#pragma unroll
            for (int in = 0; in < 2; in++)
                mma16816(acc[in], ah, &bh[in * 2]);
        }
        __syncthreads();
    }

#pragma unroll
    for (int in = 0; in < 2; in++) {
        int d = n0 + wn * 16 + in * 8 + (lane & 3) * 2;
        int b0 = wm * 16 + (lane >> 2), b1 = b0 + 8;
        float bl0 = blin[d], bl1 = blin[d + 1];
        g_Y[(size_t)b0 * DM + d]     = acc[in][0] + bl0;
        g_Y[(size_t)b0 * DM + d + 1] = acc[in][1] + bl1;
        g_Y[(size_t)b1 * DM + d]     = acc[in][2] + bl0;
        g_Y[(size_t)b1 * DM + d + 1] = acc[in][3] + bl1;
    }
#undef LIN_LOAD
}

// ---------------- kernel 6: layernorm ----------------
__global__ void k_ln(const float* __restrict__ gam, const float* __restrict__ bet,
                     float* __restrict__ out) {
    int b = blockIdx.x;
    int tid = threadIdx.x;
    __shared__ float red[256];
    const float* y = g_Y + (size_t)b * DM;

    float s = 0.f;
    for (int d = tid; d < DM; d += 256) s += y[d];
    red[tid] = s; __syncthreads();
    for (int st = 128; st > 0; st >>= 1) { if (tid < st) red[tid] += red[tid + st]; __syncthreads(); }
    float mu = red[0] / DM;
    __syncthreads();

    float v = 0.f;
    for (int d = tid; d < DM; d += 256) { float t = y[d] - mu; v += t * t; }
    red[tid] = v; __syncthreads();
    for (int st = 128; st > 0; st >>= 1) { if (tid < st) red[tid] += red[tid + st]; __syncthreads(); }
    float rinv = rsqrtf(red[0] / DM + 1e-5f);

    for (int d = tid; d < DM; d += 256)
        out[(size_t)b * DM + d] = (y[d] - mu) * rinv * gam[d] + bet[d];
}

// ---------------- launch ----------------
extern "C" void kernel_launch(void* const* d_in, const int* in_sizes, int n_in,
                              void* d_out, int out_size) {
    const float* x       = (const float*)d_in[0];
    const float* nv1     = (const float*)d_in[1];
    const float* nv2     = (const float*)d_in[2];
    const float* w_start = (const float*)d_in[3];
    const float* b_start = (const float*)d_in[4];
    const float* w_mlp   = (const float*)d_in[5];
    const float* b_mlp   = (const float*)d_in[6];
    const float* w_end   = (const float*)d_in[7];
    const float* b_end   = (const float*)d_in[8];
    const float* w_lin   = (const float*)d_in[9];
    const float* b_lin   = (const float*)d_in[10];
    const float* ln_g    = (const float*)d_in[11];
    const float* ln_b    = (const float*)d_in[12];
    float* out = (float*)d_out;

    cudaFuncSetAttribute(k_mix_mma,  cudaFuncAttributeMaxDynamicSharedMemorySize, MIX_SMEM);
    cudaFuncSetAttribute(k_mlp_mma,  cudaFuncAttributeMaxDynamicSharedMemorySize, MLP_SMEM);
    cudaFuncSetAttribute(k_conv_mma, cudaFuncAttributeMaxDynamicSharedMemorySize, CV_SMEM);
    cudaFuncSetAttribute(k_adj,      cudaFuncAttributeMaxDynamicSharedMemorySize, ADJ_SMEM);
    cudaFuncSetAttribute(k_lin_mma,  cudaFuncAttributeMaxDynamicSharedMemorySize, LIN_SMEM);

    k_prep<<<PREP_BLOCKS, 256>>>(w_start, w_lin, x, w_mlp);
    k_adj<<<NP / ADJ_R, 256, ADJ_SMEM>>>(nv1, nv2);
    k_conv_mma<<<dim3(NP / 128, BATCH), 256, CV_SMEM>>>(b_start);
    dim3 mixg(NP / TILE_N, MROWS / TILE_M);
    k_mix_mma<<<mixg, 256, MIX_SMEM>>>(0, 1);
    k_mix_mma<<<mixg, 256, MIX_SMEM>>>(1, 2);
    k_mix_mma<<<mixg, 256, MIX_SMEM>>>(2, 3);
    k_mlp_mma<<<dim3(NP / 128, BATCH), 256, MLP_SMEM>>>(b_mlp, w_end, b_end);
    k_lin_mma<<<NP / LIN_TN, 256, LIN_SMEM>>>(b_lin);
    k_ln<<<BATCH, 256>>>(ln_g, ln_b, out);
}

// round 13
// speedup vs baseline: 6.1703x; 1.0549x over previous
#include <cuda_runtime.h>
#include <cuda_fp16.h>
#include <math.h>
#include <stdint.h>

// ---------------- problem constants ----------------
#define N_NODE 2000
#define NP     2048
#define BATCH  64
#define CC     64
#define MROWS  (BATCH*CC)    // 4096
#define DM     2048
#define IN_D   7
#define KW     49
#define ND     40
#define ALPHA_C 0.05f
#define BETA_C  0.95f

// mix GEMM tiling: CTA 256Mx128N, 512 thr, KC=64 (128B rows, SW128)
#define NCHUNK  32
#define TILE_M  256
#define TILE_N  128
#define A_BYTES (256 * 128)           // 32768
#define B_BYTES (128 * 128)           // 16384
#define OFF_AH  0
#define OFF_BH  (A_BYTES)
#define STAGE_BYTES (A_BYTES + B_BYTES)   // 49152
#define NSTAGE  3
#define MIX_SMEM (NSTAGE * STAGE_BYTES)   // 147456 -> 1 CTA/SM, 16 warps

// mlp GEMM smem layout
#define MLP_A_HI   0
#define MLP_A_LO   32768
#define MLP_B_BASE 65536
#define MLP_B_STG  16384
#define MLP_SMEM   98304

// conv GEMM smem layout
#define CV_A_STG   16384
#define CV_A_VAR   8192
#define CV_B_STG   16384
#define CV_A0      0
#define CV_B0      (2 * CV_A_STG)
#define CV_XW      (CV_B0 + 2 * CV_B_STG)
#define CV_SMEM    (CV_XW + 2 * 384)

// adj
#define ADJ_R   8
#define ADJ_SMEM (ADJ_R * NP * 4)

// lin GEMM
#define LIN_TN  32
#define LIN_A_BYTES (64 * 128)
#define LIN_B_BYTES (LIN_TN * 128)
#define LIN_STG (LIN_A_BYTES + LIN_B_BYTES)
#define LIN_SMEM (2 * LIN_STG)

// fused prep block ranges
#define PREP_W 7
#define PREP_L 2048
#define PREP_X 448
#define PREP_M 64
#define PREP_BLOCKS (PREP_W + PREP_L + PREP_X + PREP_M)

// ---------------- scratch ----------------
__device__ __half  g_Ahi[4 * MROWS * NP];   // fp16 hi of hops
__device__ __half  g_Alo[MROWS * NP];       // fp16 lo of hop0 only
__device__ __half  g_Bh[NP * NP];           // adjacency
__device__ __half  g_Whi[IN_D * CC * 64];
__device__ __half  g_Wlo[IN_D * CC * 64];
__device__ __half  g_Wl[NP * NP];
__device__ __half  g_Mhi[CC * 256];
__device__ __half  g_Mlo[CC * 256];
__device__ __half  g_Xh[BATCH * IN_D * DM + 128];
__device__ __half  g_Sh[BATCH * NP];
__device__ float   g_Y[BATCH * DM];

// ---------------- helpers ----------------
__device__ __forceinline__ uint32_t smem_u32(const void* p) {
    uint32_t a;
    asm("{ .reg .u64 t; cvta.to.shared.u64 t, %1; cvt.u32.u64 %0, t; }" : "=r"(a) : "l"(p));
    return a;
}
__device__ __forceinline__ void cpa16(uint32_t s, const void* g) {
    asm volatile("cp.async.cg.shared.global [%0], [%1], 16;" :: "r"(s), "l"(g));
}
#define CPA_COMMIT() asm volatile("cp.async.commit_group;" ::: "memory")
#define CPA_WAIT(n)  asm volatile("cp.async.wait_group %0;" :: "n"(n) : "memory")

__device__ __forceinline__ void ldsm4(uint32_t* r, uint32_t addr) {
    asm volatile("ldmatrix.sync.aligned.m8n8.x4.shared.b16 {%0,%1,%2,%3}, [%4];"
                 : "=r"(r[0]), "=r"(r[1]), "=r"(r[2]), "=r"(r[3]) : "r"(addr));
}
__device__ __forceinline__ void ldsm4t(uint32_t* r, uint32_t addr) {
    asm volatile("ldmatrix.sync.aligned.m8n8.x4.trans.shared.b16 {%0,%1,%2,%3}, [%4];"
                 : "=r"(r[0]), "=r"(r[1]), "=r"(r[2]), "=r"(r[3]) : "r"(addr));
}
__device__ __forceinline__ void mma16816(float* d, const uint32_t* a, const uint32_t* b) {
    asm volatile("mma.sync.aligned.m16n8k16.row.col.f32.f16.f16.f32 "
                 "{%0,%1,%2,%3}, {%4,%5,%6,%7}, {%8,%9}, {%0,%1,%2,%3};"
                 : "+f"(d[0]), "+f"(d[1]), "+f"(d[2]), "+f"(d[3])
                 : "r"(a[0]), "r"(a[1]), "r"(a[2]), "r"(a[3]), "r"(b[0]), "r"(b[1]));
}
__device__ __forceinline__ void fp16_split(float v, __half& hi, __half& lo) {
    hi = __float2half_rn(v);
    lo = __float2half_rn(v - __half2float(hi));
}
__device__ __forceinline__ float gelu_exact(float v) {
    return 0.5f * v * (1.f + erff(v * 0.70710678118654752f));
}

// ---------------- kernel 0: fused prep ----------------
__global__ void k_prep(const float* __restrict__ w_start,
                       const float* __restrict__ wlin,
                       const float* __restrict__ x,
                       const float* __restrict__ wmlp) {
    int bid = blockIdx.x;
    int tid = threadIdx.x;
    if (bid < PREP_W) {
        int ci = bid;
        for (int idx = tid; idx < CC * 64; idx += 256) {
            int co = idx >> 6, t = idx & 63;
            float v = (t < KW) ? w_start[co * (IN_D * KW) + ci * KW + t] : 0.f;
            __half h, l; fp16_split(v, h, l);
            g_Whi[ci * CC * 64 + idx] = h;
            g_Wlo[ci * CC * 64 + idx] = l;
        }
    } else if (bid < PREP_W + PREP_L) {
        int d = bid - PREP_W;
        for (int w = tid; w < NP; w += 256) {
            float v = (w < N_NODE) ? wlin[(size_t)d * N_NODE + w] : 0.f;
            g_Wl[(size_t)d * NP + w] = __float2half_rn(v);
        }
    } else if (bid < PREP_W + PREP_L + PREP_X) {
        int row = bid - PREP_W - PREP_L;
        size_t base = (size_t)row * DM;
        for (int i = tid; i < DM; i += 256)
            g_Xh[base + i] = __float2half_rn(x[base + i]);
        if (row == PREP_X - 1 && tid < 128)
            g_Xh[(size_t)BATCH * IN_D * DM + tid] = __float2half(0.f);
    } else {
        int o = bid - PREP_W - PREP_L - PREP_X;
        for (int i = tid; i < 256; i += 256) {
            float v = wmlp[o * 256 + i];
            __half h, l; fp16_split(v, h, l);
            g_Mhi[o * 256 + i] = h;
            g_Mlo[o * 256 + i] = l;
        }
    }
}

// ---------------- kernel 1: adjacency, 8 rows per CTA ----------------
__global__ void k_adj(const float* __restrict__ E1, const float* __restrict__ E2) {
    extern __shared__ float z[];
    __shared__ float e1s[ADJ_R][ND];
    __shared__ float red[256];
    __shared__ float srow[ADJ_R];
    int tid = threadIdx.x;
    int r0 = blockIdx.x * ADJ_R;

    if (r0 >= N_NODE) {
        for (int r = 0; r < ADJ_R; r++) {
            int v = r0 + r;
            if (v < NP)
                for (int w = tid; w < NP; w += 256) g_Bh[(size_t)v * NP + w] = __float2half(0.f);
        }
        return;
    }

    for (int idx = tid; idx < ADJ_R * ND; idx += 256)
        e1s[idx / ND][idx % ND] = E1[(r0 + idx / ND) * ND + idx % ND];
    __syncthreads();

    float lmax[ADJ_R];
#pragma unroll
    for (int r = 0; r < ADJ_R; r++) lmax[r] = -1e30f;

    for (int w = tid; w < N_NODE; w += 256) {
        float acc[ADJ_R];
#pragma unroll
        for (int r = 0; r < ADJ_R; r++) acc[r] = 0.f;
#pragma unroll 8
        for (int k = 0; k < ND; k++) {
            float e2 = E2[k * N_NODE + w];
#pragma unroll
            for (int r = 0; r < ADJ_R; r++) acc[r] += e1s[r][k] * e2;
        }
#pragma unroll
        for (int r = 0; r < ADJ_R; r++) {
            float v = fmaxf(acc[r], 0.f);
            z[r * NP + w] = v;
            lmax[r] = fmaxf(lmax[r], v);
        }
    }
#pragma unroll
    for (int r = 0; r < ADJ_R; r++) {
        red[tid] = lmax[r]; __syncthreads();
        for (int s = 128; s > 0; s >>= 1) { if (tid < s) red[tid] = fmaxf(red[tid], red[tid + s]); __syncthreads(); }
        if (tid == 0) srow[r] = red[0];
        __syncthreads();
    }
    float lsum[ADJ_R];
#pragma unroll
    for (int r = 0; r < ADJ_R; r++) lsum[r] = 0.f;
    for (int w = tid; w < N_NODE; w += 256) {
#pragma unroll
        for (int r = 0; r < ADJ_R; r++) {
            float e = expf(z[r * NP + w] - srow[r]);
            z[r * NP + w] = e;
            lsum[r] += e;
        }
    }
#pragma unroll
    for (int r = 0; r < ADJ_R; r++) {
        red[tid] = lsum[r]; __syncthreads();
        for (int s = 128; s > 0; s >>= 1) { if (tid < s) red[tid] += red[tid + s]; __syncthreads(); }
        if (tid == 0) srow[r] = 0.5f / red[0];
        __syncthreads();
    }
    for (int w = tid; w < NP; w += 256) {
#pragma unroll
        for (int r = 0; r < ADJ_R; r++) {
            int v = r0 + r;
            float val = (w < N_NODE) ? (z[r * NP + w] * srow[r] + ((w == v) ? 0.5f : 0.f)) : 0.f;
            g_Bh[(size_t)v * NP + w] = __float2half_rn(val);
        }
    }
}

// ---------------- kernel 2: start conv on HMMA (2-product, fp16 x prepped) ---------
__global__ __launch_bounds__(256, 2) void k_conv_mma(const float* __restrict__ bias) {
    extern __shared__ char smem[];
    const uint32_t sbase = smem_u32(smem);
    __half* xw = (__half*)(smem + CV_XW);
    const int tid = threadIdx.x;
    const int wid = tid >> 5, lane = tid & 31;
    const int wm = wid >> 1;
    const int wn = wid & 1;
    const int b  = blockIdx.y;
    const int n0 = blockIdx.x * 128;

#define CV_LOAD_A(ci, stg) do {                                                      \
    _Pragma("unroll")                                                                \
    for (int i = 0; i < 2; i++) {                                                    \
        int idx = tid + i * 256;                                                     \
        int co = idx >> 3, s = idx & 7;                                              \
        uint32_t dst = sbase + CV_A0 + (stg) * CV_A_STG + co * 128 +                 \
                       ((uint32_t)(s ^ (co & 7)) << 4);                              \
        cpa16(dst,            (const char*)(g_Whi + (ci) * CC * 64 + co * 64 + s * 8)); \
        cpa16(dst + CV_A_VAR, (const char*)(g_Wlo + (ci) * CC * 64 + co * 64 + s * 8)); \
    }                                                                                \
} while (0)

#define CV_LOAD_XW(ci, stg) do {                                                     \
    if (tid < 24)                                                                    \
        cpa16(sbase + CV_XW + (stg) * 384 + tid * 16,                                \
              (const char*)(g_Xh + (size_t)b * IN_D * DM + (ci) * DM + n0) + tid * 16); \
} while (0)

#define CV_BUILD_B(stg) do {                                                         \
    const __half* xwp = xw + (stg) * 192;                                            \
    _Pragma("unroll")                                                                \
    for (int i = 0; i < 16; i++) {                                                   \
        int idx = tid + i * 256;                                                     \
        int t = idx >> 6, j2 = idx & 63;                                             \
        int n = j2 * 2;                                                              \
        __half2 hh(xwp[t + n], xwp[t + n + 1]);                                      \
        int s = n >> 3;                                                              \
        uint32_t off = t * 256 + ((uint32_t)(s ^ (t & 7)) << 4) + (j2 & 3) * 4;      \
        *(uint32_t*)(smem + CV_B0 + (stg) * CV_B_STG + off) = *reinterpret_cast<uint32_t*>(&hh); \
    }                                                                                \
} while (0)

    float acc[8][4];
#pragma unroll
    for (int in = 0; in < 8; in++)
#pragma unroll
        for (int q = 0; q < 4; q++) acc[in][q] = 0.f;

    const int a_row = wm * 16 + (lane & 15);
    const int a_jl  = lane >> 4;
    const int b_kl  = ((lane >> 3) & 1) * 8 + (lane & 7);
    const int b_nl  = lane >> 4;

    CV_LOAD_A(0, 0);
    CV_LOAD_XW(0, 0);
    CPA_COMMIT();
    CPA_WAIT(0);
    __syncthreads();
    CV_BUILD_B(0);
    __syncthreads();

    for (int c = 0; c < IN_D; c++) {
        int stg = c & 1, nstg = (c + 1) & 1;
        if (c + 1 < IN_D) { CV_LOAD_A(c + 1, nstg); CV_LOAD_XW(c + 1, nstg); CPA_COMMIT(); }

        uint32_t astg = sbase + CV_A0 + stg * CV_A_STG;
        uint32_t bstg = sbase + CV_B0 + stg * CV_B_STG;
#pragma unroll
        for (int ks = 0; ks < 4; ks++) {
            uint32_t ah[4], al[4], bh[4][4];
            {
                int s = 2 * ks + a_jl;
                uint32_t off = (uint32_t)a_row * 128 + ((uint32_t)(s ^ (a_row & 7)) << 4);
                ldsm4(ah, astg + off);
                ldsm4(al, astg + CV_A_VAR + off);
            }
            int krow = ks * 16 + b_kl;
            uint32_t koff = (uint32_t)krow * 256;
            uint32_t kx = (uint32_t)(krow & 7);
#pragma unroll
            for (int q = 0; q < 4; q++) {
                int ns = wn * 8 + 2 * q + b_nl;
                uint32_t off = koff + ((uint32_t)(ns ^ kx) << 4);
                ldsm4t(bh[q], bstg + off);
            }
#pragma unroll
            for (int p = 0; p < 2; p++) {
#pragma unroll
                for (int in = 0; in < 8; in++) {
                    const uint32_t* af = (p == 1) ? al : ah;
                    mma16816(acc[in], af, &bh[in >> 1][(in & 1) * 2]);
                }
            }
        }
        if (c + 1 < IN_D) {
            CPA_WAIT(0);
            __syncthreads();
            CV_BUILD_B(nstg);
            __syncthreads();
        }
    }

    const int o0 = wm * 16 + (lane >> 2);
    const int o1 = o0 + 8;
    const float b0v = bias[o0], b1v = bias[o1];
#pragma unroll
    for (int in = 0; in < 8; in++) {
        int n = n0 + wn * 64 + in * 8 + (lane & 3) * 2;
        bool ok = (n < N_NODE);
        float v00 = ok ? (acc[in][0] + b0v) : 0.f;
        float v01 = ok ? (acc[in][1] + b0v) : 0.f;
        float v10 = ok ? (acc[in][2] + b1v) : 0.f;
        float v11 = ok ? (acc[in][3] + b1v) : 0.f;
        size_t r0 = (size_t)(b * CC + o0) * NP + n;
        size_t r1 = (size_t)(b * CC + o1) * NP + n;
        __half h0, l0, h1, l1;
        fp16_split(v00, h0, l0); fp16_split(v01, h1, l1);
        *(__half2*)(g_Ahi + r0) = __half2(h0, h1);
        *(__half2*)(g_Alo + r0) = __half2(l0, l1);
        fp16_split(v10, h0, l0); fp16_split(v11, h1, l1);
        *(__half2*)(g_Ahi + r1) = __half2(h0, h1);
        *(__half2*)(g_Alo + r1) = __half2(l0, l1);
    }
#undef CV_LOAD_A
#undef CV_LOAD_XW
#undef CV_BUILD_B
}

// ---------------- kernel 3: mixprop GEMM on HMMA (256x128 CTA, 512 thr) ----------
__global__ __launch_bounds__(512, 1) void k_mix_mma(int src, int dst) {
    extern __shared__ char smem[];
    const uint32_t sbase = smem_u32(smem);

    const int tid = threadIdx.x;
    const int wid = tid >> 5, lane = tid & 31;
    const int wm = wid >> 2;            // 0..3 -> m offset wm*64
    const int wn = wid & 3;             // 0..3 -> n offset wn*32
    const int m0 = blockIdx.y * TILE_M;
    const int n0 = blockIdx.x * TILE_N;

    const __half* Ahi = g_Ahi + (size_t)src * MROWS * NP;

    // loaders: A 256 rows x 8 segs (2048 ops / 512 thr = 4), B 128 x 8 (1024 / 512 = 2)
    const int ar = tid >> 1;
    const int as_ = (tid & 1) * 4;
    const uint32_t aswz = (uint32_t)(ar & 7);
    const int br = tid >> 2;
    const int bs_ = (tid & 3) * 2;
    const uint32_t bswz = (uint32_t)(br & 7);
    const char* gA = (const char*)(Ahi + (size_t)(m0 + ar) * NP) + as_ * 16;
    const char* gB = (const char*)(g_Bh + (size_t)(n0 + br) * NP) + bs_ * 16;

#define LOAD_CHUNK(cidx, buf) do {                                                   \
    uint32_t sb = sbase + (buf) * STAGE_BYTES;                                       \
    size_t go = (size_t)(cidx) * 128;                                                \
    uint32_t sa = sb + OFF_AH + ar * 128;                                            \
    _Pragma("unroll")                                                                \
    for (int j = 0; j < 4; j++) {                                                    \
        uint32_t so = ((uint32_t)(as_ + j) ^ aswz) << 4;                             \
        cpa16(sa + so, gA + go + j * 16);                                            \
    }                                                                                \
    uint32_t sbb = sb + OFF_BH + br * 128;                                           \
    _Pragma("unroll")                                                                \
    for (int j = 0; j < 2; j++) {                                                    \
        uint32_t so = ((uint32_t)(bs_ + j) ^ bswz) << 4;                             \
        cpa16(sbb + so, gB + go + j * 16);                                           \
    }                                                                                \
} while (0)

    float acc[4][4][4];
#pragma unroll
    for (int im = 0; im < 4; im++)
#pragma unroll
        for (int in = 0; in < 4; in++)
#pragma unroll
            for (int q = 0; q < 4; q++) acc[im][in][q] = 0.f;

    const int a_row_l = (lane & 15);
    const int a_jl = lane >> 4;
    const int b_row_l = ((lane >> 4) << 3) + (lane & 7);
    const int b_jl = (lane >> 3) & 1;

    LOAD_CHUNK(0, 0); CPA_COMMIT();
    LOAD_CHUNK(1, 1); CPA_COMMIT();

    int buf = 0, nbuf = 2;
    for (int c = 0; c < NCHUNK; c++) {
        if (c + 1 < NCHUNK) { CPA_WAIT(1); } else { CPA_WAIT(0); }
        __syncthreads();
        if (c + 2 < NCHUNK) { LOAD_CHUNK(c + 2, nbuf); CPA_COMMIT(); }

        uint32_t sb = sbase + buf * STAGE_BYTES;
#pragma unroll
        for (int ks = 0; ks < 4; ks++) {
            uint32_t ah[4][4], bh[2][4];
#pragma unroll
            for (int im = 0; im < 4; im++) {
                int row = wm * 64 + im * 16 + a_row_l;
                uint32_t off = (uint32_t)row * 128 +
                               ((uint32_t)((2 * ks + a_jl) ^ (row & 7)) << 4);
                ldsm4(ah[im], sb + OFF_AH + off);
            }
#pragma unroll
            for (int inb = 0; inb < 2; inb++) {
                int row = wn * 32 + inb * 16 + b_row_l;
                uint32_t off = (uint32_t)row * 128 +
                               ((uint32_t)((2 * ks + b_jl) ^ (row & 7)) << 4);
                ldsm4(bh[inb], sb + OFF_BH + off);
            }
#pragma unroll
            for (int im = 0; im < 4; im++) {
#pragma unroll
                for (int in = 0; in < 4; in++) {
                    mma16816(acc[im][in], ah[im], &bh[in >> 1][(in & 1) * 2]);
                }
            }
        }
        buf = (buf == NSTAGE - 1) ? 0 : buf + 1;
        nbuf = (nbuf == NSTAGE - 1) ? 0 : nbuf + 1;
    }

    // epilogue: C = ALPHA*(h0 hi+lo) + BETA*acc -> fp16 hi ONLY (lo never read)
    const __half* Xh = g_Ahi;
    const __half* Xl = g_Alo;
    __half* Hh = g_Ahi + (size_t)dst * MROWS * NP;

#pragma unroll
    for (int im = 0; im < 4; im++) {
#pragma unroll
        for (int half = 0; half < 2; half++) {
            int m = m0 + wm * 64 + im * 16 + (lane >> 2) + half * 8;
            size_t rowo = (size_t)m * NP;
#pragma unroll
            for (int in = 0; in < 4; in++) {
                int n = n0 + wn * 32 + in * 8 + (lane & 3) * 2;
                float d0 = acc[im][in][half * 2 + 0];
                float d1 = acc[im][in][half * 2 + 1];
                __half2 xh = *(const __half2*)(Xh + rowo + n);
                __half2 xl = *(const __half2*)(Xl + rowo + n);
                float x0 = __half2float(xh.x) + __half2float(xl.x);
                float x1 = __half2float(xh.y) + __half2float(xl.y);
                float o0 = ALPHA_C * x0 + BETA_C * d0;
                float o1 = ALPHA_C * x1 + BETA_C * d1;
                *(__half2*)(Hh + rowo + n) =
                    __half2(__float2half_rn(o0), __float2half_rn(o1));
            }
        }
    }
#undef LOAD_CHUNK
}

// ---------------- kernel 4: MLP on HMMA (2-product) + GELU + end dot ----------------
__global__ __launch_bounds__(256) void k_mlp_mma(const float* __restrict__ bmlp,
                                                 const float* __restrict__ wend,
                                                 const float* __restrict__ bend) {
    extern __shared__ char smem[];
    __shared__ float red[4][128];
    const uint32_t sbase = smem_u32(smem);
    const int tid = threadIdx.x;
    const int wid = tid >> 5, lane = tid & 31;
    const int wm = wid >> 1;
    const int wn = wid & 1;
    const int b  = blockIdx.y;
    const int n0 = blockIdx.x * 128;

#pragma unroll
    for (int i = 0; i < 8; i++) {
        int idx = tid + i * 256;
        int o = idx >> 5, s = idx & 31;
        uint32_t phys = (uint32_t)(s ^ (o & 15));
        uint32_t dst = sbase + o * 512 + phys * 16;
        cpa16(dst + MLP_A_HI, (const char*)(g_Mhi + o * 256 + s * 8));
        cpa16(dst + MLP_A_LO, (const char*)(g_Mlo + o * 256 + s * 8));
    }

#define LOAD_BCH(chunk, stg) do {                                                        \
    const __half* HBh = g_Ahi + ((size_t)(chunk) * MROWS + b * 64) * NP + n0;            \
    _Pragma("unroll")                                                                    \
    for (int i = 0; i < 4; i++) {                                                        \
        int idx = tid + i * 256;                                                         \
        int k = idx >> 4, s = idx & 15;                                                  \
        uint32_t phys = (uint32_t)(s ^ (k & 7));                                         \
        uint32_t dst = sbase + MLP_B_BASE + (stg) * MLP_B_STG + k * 256 + phys * 16;     \
        cpa16(dst, (const char*)HBh + (size_t)k * NP * 2 + s * 16);                      \
    }                                                                                    \
} while (0)

    float acc[8][4];
#pragma unroll
    for (int in = 0; in < 8; in++)
#pragma unroll
        for (int q = 0; q < 4; q++) acc[in][q] = 0.f;

    const int a_row = wm * 16 + (lane & 15);
    const int a_jl  = lane >> 4;
    const int b_kl  = ((lane >> 3) & 1) * 8 + (lane & 7);
    const int b_nl  = lane >> 4;

    LOAD_BCH(0, 0); CPA_COMMIT();

    for (int chunk = 0; chunk < 4; chunk++) {
        CPA_WAIT(0);
        __syncthreads();
        if (chunk < 3) { LOAD_BCH(chunk + 1, (chunk + 1) & 1); CPA_COMMIT(); }
        uint32_t bstg = sbase + MLP_B_BASE + (chunk & 1) * MLP_B_STG;

#pragma unroll
        for (int ks = 0; ks < 4; ks++) {
            int ksg = chunk * 4 + ks;
            uint32_t ah[4], al[4], bh[4][4];
            {
                int s = 2 * ksg + a_jl;
                uint32_t off = (uint32_t)a_row * 512 + ((uint32_t)(s ^ (a_row & 15)) << 4);
                ldsm4(ah, sbase + MLP_A_HI + off);
                ldsm4(al, sbase + MLP_A_LO + off);
            }
            int krow = ks * 16 + b_kl;
            uint32_t koff = (uint32_t)krow * 256;
            uint32_t kx = (uint32_t)(krow & 7);
#pragma unroll
            for (int q = 0; q < 4; q++) {
                int ns = wn * 8 + 2 * q + b_nl;
                uint32_t off = koff + ((uint32_t)(ns ^ kx) << 4);
                ldsm4t(bh[q], bstg + off);
            }
#pragma unroll
            for (int p = 0; p < 2; p++) {
#pragma unroll
                for (int in = 0; in < 8; in++) {
                    const uint32_t* af = (p == 1) ? al : ah;
                    mma16816(acc[in], af, &bh[in >> 1][(in & 1) * 2]);
                }
            }
        }
        __syncthreads();
    }

    const int o0 = wm * 16 + (lane >> 2);
    const int o1 = o0 + 8;
    const float bm0 = bmlp[o0], bm1 = bmlp[o1];
    const float we0 = wend[o0], we1 = wend[o1];

#pragma unroll
    for (int in = 0; in < 8; in++) {
        float g00 = gelu_exact(acc[in][0] + bm0);
        float g01 = gelu_exact(acc[in][1] + bm0);
        float g10 = gelu_exact(acc[in][2] + bm1);
        float g11 = gelu_exact(acc[in][3] + bm1);
        float p0 = we0 * g00 + we1 * g10;
        float p1 = we0 * g01 + we1 * g11;
#pragma unroll
        for (int d = 4; d <= 16; d <<= 1) {
            p0 += __shfl_xor_sync(0xFFFFFFFF, p0, d);
            p1 += __shfl_xor_sync(0xFFFFFFFF, p1, d);
        }
        if (lane < 4) {
            red[wm][wn * 64 + in * 8 + lane * 2 + 0] = p0;
            red[wm][wn * 64 + in * 8 + lane * 2 + 1] = p1;
        }
    }
    __syncthreads();
    if (tid < 128) {
        int n = n0 + tid;
        float s = bend[0] + red[0][tid] + red[1][tid] + red[2][tid] + red[3][tid];
        g_Sh[(size_t)b * NP + n] = __float2half_rn((n < N_NODE) ? s : 0.f);
    }
#undef LOAD_BCH
}

// ---------------- kernel 5: final linear on HMMA ----------------
__global__ __launch_bounds__(256) void k_lin_mma(const float* __restrict__ blin) {
    extern __shared__ char smem[];
    const uint32_t sbase = smem_u32(smem);
    const int tid = threadIdx.x;
    const int wid = tid >> 5, lane = tid & 31;
    const int wm = wid >> 1;
    const int wn = wid & 1;
    const int n0 = blockIdx.x * LIN_TN;

#define LIN_LOAD(cidx, stg) do {                                                     \
    _Pragma("unroll")                                                                \
    for (int i = 0; i < 2; i++) {                                                    \
        int idx = tid + i * 256;                                                     \
        int row = idx >> 3, s = idx & 7;                                             \
        uint32_t so = ((uint32_t)(s ^ (row & 7)) << 4);                              \
        cpa16(sbase + (stg) * LIN_STG + row * 128 + so,                              \
              (const char*)(g_Sh + (size_t)row * NP) + (size_t)(cidx) * 128 + s * 16); \
    }                                                                                \
    {                                                                                \
        int row = tid >> 3, s = tid & 7;                                             \
        uint32_t so = ((uint32_t)(s ^ (row & 7)) << 4);                              \
        cpa16(sbase + (stg) * LIN_STG + LIN_A_BYTES + row * 128 + so,                \
              (const char*)(g_Wl + (size_t)(n0 + row) * NP) + (size_t)(cidx) * 128 + s * 16); \
    }                                                                                \
} while (0)

    float acc[2][4];
#pragma unroll
    for (int in = 0; in < 2; in++)
#pragma unroll
        for (int q = 0; q < 4; q++) acc[in][q] = 0.f;

    const int a_row_l = (lane & 15);
    const int a_jl = lane >> 4;
    const int b_row_l = ((lane >> 4) << 3) + (lane & 7);
    const int b_jl = (lane >> 3) & 1;

    LIN_LOAD(0, 0); CPA_COMMIT();

    for (int c = 0; c < 32; c++) {
        CPA_WAIT(0);
        __syncthreads();
        if (c + 1 < 32) { LIN_LOAD(c + 1, (c + 1) & 1); CPA_COMMIT(); }
        uint32_t astg = sbase + (c & 1) * LIN_STG;
        uint32_t bstg = astg + LIN_A_BYTES;
#pragma unroll
        for (int ks = 0; ks < 4; ks++) {
            uint32_t ah[4], bh[4];
            {
                int row = wm * 16 + a_row_l;
                uint32_t off = (uint32_t)row * 128 +
                               ((uint32_t)((2 * ks + a_jl) ^ (row & 7)) << 4);
                ldsm4(ah, astg + off);
            }
            {
                int row = wn * 16 + b_row_l;
                uint32_t off = (uint32_t)row * 128 +
                               ((uint32_t)((2 * ks + b_jl) ^ (row & 7)) << 4);
                ldsm4(bh, bstg + off);
            }
#pragma unroll
            for (int in = 0; in < 2; in++)
                mma16816(acc[in], ah, &bh[in * 2]);
        }
        __syncthreads();
    }

#pragma unroll
    for (int in = 0; in < 2; in++) {
        int d = n0 + wn * 16 + in * 8 + (lane & 3) * 2;
        int b0 = wm * 16 + (lane >> 2), b1 = b0 + 8;
        float bl0 = blin[d], bl1 = blin[d + 1];
        g_Y[(size_t)b0 * DM + d]     = acc[in][0] + bl0;
        g_Y[(size_t)b0 * DM + d + 1] = acc[in][1] + bl1;
        g_Y[(size_t)b1 * DM + d]     = acc[in][2] + bl0;
        g_Y[(size_t)b1 * DM + d + 1] = acc[in][3] + bl1;
    }
#undef LIN_LOAD
}

// ---------------- kernel 6: layernorm ----------------
__global__ void k_ln(const float* __restrict__ gam, const float* __restrict__ bet,
                     float* __restrict__ out) {
    int b = blockIdx.x;
    int tid = threadIdx.x;
    __shared__ float red[256];
    const float* y = g_Y + (size_t)b * DM;

    float s = 0.f;
    for (int d = tid; d < DM; d += 256) s += y[d];
    red[tid] = s; __syncthreads();
    for (int st = 128; st > 0; st >>= 1) { if (tid < st) red[tid] += red[tid + st]; __syncthreads(); }
    float mu = red[0] / DM;
    __syncthreads();

    float v = 0.f;
    for (int d = tid; d < DM; d += 256) { float t = y[d] - mu; v += t * t; }
    red[tid] = v; __syncthreads();
    for (int st = 128; st > 0; st >>= 1) { if (tid < st) red[tid] += red[tid + st]; __syncthreads(); }
    float rinv = rsqrtf(red[0] / DM + 1e-5f);

    for (int d = tid; d < DM; d += 256)
        out[(size_t)b * DM + d] = (y[d] - mu) * rinv * gam[d] + bet[d];
}

// ---------------- launch ----------------
extern "C" void kernel_launch(void* const* d_in, const int* in_sizes, int n_in,
                              void* d_out, int out_size) {
    const float* x       = (const float*)d_in[0];
    const float* nv1     = (const float*)d_in[1];
    const float* nv2     = (const float*)d_in[2];
    const float* w_start = (const float*)d_in[3];
    const float* b_start = (const float*)d_in[4];
    const float* w_mlp   = (const float*)d_in[5];
    const float* b_mlp   = (const float*)d_in[6];
    const float* w_end   = (const float*)d_in[7];
    const float* b_end   = (const float*)d_in[8];
    const float* w_lin   = (const float*)d_in[9];
    const float* b_lin   = (const float*)d_in[10];
    const float* ln_g    = (const float*)d_in[11];
    const float* ln_b    = (const float*)d_in[12];
    float* out = (float*)d_out;

    cudaFuncSetAttribute(k_mix_mma,  cudaFuncAttributeMaxDynamicSharedMemorySize, MIX_SMEM);
    cudaFuncSetAttribute(k_mlp_mma,  cudaFuncAttributeMaxDynamicSharedMemorySize, MLP_SMEM);
    cudaFuncSetAttribute(k_conv_mma, cudaFuncAttributeMaxDynamicSharedMemorySize, CV_SMEM);
    cudaFuncSetAttribute(k_adj,      cudaFuncAttributeMaxDynamicSharedMemorySize, ADJ_SMEM);
    cudaFuncSetAttribute(k_lin_mma,  cudaFuncAttributeMaxDynamicSharedMemorySize, LIN_SMEM);

    k_prep<<<PREP_BLOCKS, 256>>>(w_start, w_lin, x, w_mlp);
    k_adj<<<NP / ADJ_R, 256, ADJ_SMEM>>>(nv1, nv2);
    k_conv_mma<<<dim3(NP / 128, BATCH), 256, CV_SMEM>>>(b_start);
    dim3 mixg(NP / TILE_N, MROWS / TILE_M);
    k_mix_mma<<<mixg, 512, MIX_SMEM>>>(0, 1);
    k_mix_mma<<<mixg, 512, MIX_SMEM>>>(1, 2);
    k_mix_mma<<<mixg, 512, MIX_SMEM>>>(2, 3);
    k_mlp_mma<<<dim3(NP / 128, BATCH), 256, MLP_SMEM>>>(b_mlp, w_end, b_end);
    k_lin_mma<<<NP / LIN_TN, 256, LIN_SMEM>>>(b_lin);
    k_ln<<<BATCH, 256>>>(ln_g, ln_b, out);
}

// round 14
// speedup vs baseline: 6.3737x; 1.0330x over previous
#include <cuda_runtime.h>
#include <cuda_fp16.h>
#include <math.h>
#include <stdint.h>

// ---------------- problem constants ----------------
#define N_NODE 2000
#define NP     2048
#define BATCH  64
#define CC     64
#define MROWS  (BATCH*CC)    // 4096
#define DM     2048
#define IN_D   7
#define KW     49
#define ND     40
#define ALPHA_C 0.05f
#define BETA_C  0.95f

// mix GEMM tiling: CTA 256Mx128N, 512 thr, KC=64 (128B rows, SW128), 4 stages
#define NCHUNK  32
#define TILE_M  256
#define TILE_N  128
#define A_BYTES (256 * 128)
#define B_BYTES (128 * 128)
#define OFF_AH  0
#define OFF_BH  (A_BYTES)
#define STAGE_BYTES (A_BYTES + B_BYTES)   // 49152
#define NSTAGE  4
#define MIX_SMEM (NSTAGE * STAGE_BYTES)   // 196608

// mlp GEMM smem layout
#define MLP_A_HI   0
#define MLP_A_LO   32768
#define MLP_B_BASE 65536
#define MLP_B_STG  16384
#define MLP_SMEM   98304

// conv GEMM smem layout
#define CV_A_STG   16384
#define CV_A_VAR   8192
#define CV_B_STG   16384
#define CV_A0      0
#define CV_B0      (2 * CV_A_STG)
#define CV_XW      (CV_B0 + 2 * CV_B_STG)
#define CV_SMEM    (CV_XW + 2 * 384)

// adj
#define ADJ_R   8
#define ADJ_BLOCKS (NP / ADJ_R)        // 256
#define ADJ_SMEM (ADJ_R * NP * 4)      // 65536

// lin GEMM
#define LIN_TN  32
#define LIN_A_BYTES (64 * 128)
#define LIN_B_BYTES (LIN_TN * 128)
#define LIN_STG (LIN_A_BYTES + LIN_B_BYTES)
#define LIN_SMEM (2 * LIN_STG)

// fused prep+adj block ranges (adj first, then prep sections)
#define PREP_W 7
#define PREP_L 2048
#define PREP_X 448
#define PREP_M 64
#define PA_BLOCKS (ADJ_BLOCKS + PREP_W + PREP_L + PREP_X + PREP_M)

// ---------------- scratch ----------------
__device__ __half  g_Ahi[4 * MROWS * NP];
__device__ __half  g_Alo[MROWS * NP];       // lo of hop0 only
__device__ __half  g_Bh[NP * NP];
__device__ __half  g_Whi[IN_D * CC * 64];
__device__ __half  g_Wlo[IN_D * CC * 64];
__device__ __half  g_Wl[NP * NP];
__device__ __half  g_Mhi[CC * 256];
__device__ __half  g_Mlo[CC * 256];
__device__ __half  g_Xh[BATCH * IN_D * DM + 128];
__device__ __half  g_Sh[BATCH * NP];
__device__ float   g_Y[BATCH * DM];

// ---------------- helpers ----------------
__device__ __forceinline__ uint32_t smem_u32(const void* p) {
    uint32_t a;
    asm("{ .reg .u64 t; cvta.to.shared.u64 t, %1; cvt.u32.u64 %0, t; }" : "=r"(a) : "l"(p));
    return a;
}
__device__ __forceinline__ void cpa16(uint32_t s, const void* g) {
    asm volatile("cp.async.cg.shared.global [%0], [%1], 16;" :: "r"(s), "l"(g));
}
#define CPA_COMMIT() asm volatile("cp.async.commit_group;" ::: "memory")
#define CPA_WAIT(n)  asm volatile("cp.async.wait_group %0;" :: "n"(n) : "memory")

__device__ __forceinline__ void ldsm4(uint32_t* r, uint32_t addr) {
    asm volatile("ldmatrix.sync.aligned.m8n8.x4.shared.b16 {%0,%1,%2,%3}, [%4];"
                 : "=r"(r[0]), "=r"(r[1]), "=r"(r[2]), "=r"(r[3]) : "r"(addr));
}
__device__ __forceinline__ void ldsm4t(uint32_t* r, uint32_t addr) {
    asm volatile("ldmatrix.sync.aligned.m8n8.x4.trans.shared.b16 {%0,%1,%2,%3}, [%4];"
                 : "=r"(r[0]), "=r"(r[1]), "=r"(r[2]), "=r"(r[3]) : "r"(addr));
}
__device__ __forceinline__ void mma16816(float* d, const uint32_t* a, const uint32_t* b) {
    asm volatile("mma.sync.aligned.m16n8k16.row.col.f32.f16.f16.f32 "
                 "{%0,%1,%2,%3}, {%4,%5,%6,%7}, {%8,%9}, {%0,%1,%2,%3};"
                 : "+f"(d[0]), "+f"(d[1]), "+f"(d[2]), "+f"(d[3])
                 : "r"(a[0]), "r"(a[1]), "r"(a[2]), "r"(a[3]), "r"(b[0]), "r"(b[1]));
}
__device__ __forceinline__ void fp16_split(float v, __half& hi, __half& lo) {
    hi = __float2half_rn(v);
    lo = __float2half_rn(v - __half2float(hi));
}
__device__ __forceinline__ float gelu_exact(float v) {
    return 0.5f * v * (1.f + erff(v * 0.70710678118654752f));
}

// ---------------- kernel 1: fused adjacency + prep ----------------
__global__ void k_padj(const float* __restrict__ E1, const float* __restrict__ E2,
                       const float* __restrict__ w_start,
                       const float* __restrict__ wlin,
                       const float* __restrict__ x,
                       const float* __restrict__ wmlp) {
    int bid = blockIdx.x;
    int tid = threadIdx.x;

    if (bid >= ADJ_BLOCKS) {
        int pb = bid - ADJ_BLOCKS;
        if (pb < PREP_W) {
            int ci = pb;
            for (int idx = tid; idx < CC * 64; idx += 256) {
                int co = idx >> 6, t = idx & 63;
                float v = (t < KW) ? w_start[co * (IN_D * KW) + ci * KW + t] : 0.f;
                __half h, l; fp16_split(v, h, l);
                g_Whi[ci * CC * 64 + idx] = h;
                g_Wlo[ci * CC * 64 + idx] = l;
            }
        } else if (pb < PREP_W + PREP_L) {
            int d = pb - PREP_W;
            for (int w = tid; w < NP; w += 256) {
                float v = (w < N_NODE) ? wlin[(size_t)d * N_NODE + w] : 0.f;
                g_Wl[(size_t)d * NP + w] = __float2half_rn(v);
            }
        } else if (pb < PREP_W + PREP_L + PREP_X) {
            int row = pb - PREP_W - PREP_L;
            size_t base = (size_t)row * DM;
            for (int i = tid; i < DM; i += 256)
                g_Xh[base + i] = __float2half_rn(x[base + i]);
            if (row == PREP_X - 1 && tid < 128)
                g_Xh[(size_t)BATCH * IN_D * DM + tid] = __float2half(0.f);
        } else {
            int o = pb - PREP_W - PREP_L - PREP_X;
            for (int i = tid; i < 256; i += 256) {
                float v = wmlp[o * 256 + i];
                __half h, l; fp16_split(v, h, l);
                g_Mhi[o * 256 + i] = h;
                g_Mlo[o * 256 + i] = l;
            }
        }
        return;
    }

    // -------- adjacency section --------
    extern __shared__ float z[];
    __shared__ float e1s[ADJ_R][ND];
    __shared__ float red[256];
    __shared__ float srow[ADJ_R];
    int r0 = bid * ADJ_R;

    if (r0 >= N_NODE) {
        for (int r = 0; r < ADJ_R; r++) {
            int v = r0 + r;
            if (v < NP)
                for (int w = tid; w < NP; w += 256) g_Bh[(size_t)v * NP + w] = __float2half(0.f);
        }
        return;
    }

    for (int idx = tid; idx < ADJ_R * ND; idx += 256)
        e1s[idx / ND][idx % ND] = E1[(r0 + idx / ND) * ND + idx % ND];
    __syncthreads();

    float lmax[ADJ_R];
#pragma unroll
    for (int r = 0; r < ADJ_R; r++) lmax[r] = -1e30f;

    for (int w = tid; w < N_NODE; w += 256) {
        float acc[ADJ_R];
#pragma unroll
        for (int r = 0; r < ADJ_R; r++) acc[r] = 0.f;
#pragma unroll 8
        for (int k = 0; k < ND; k++) {
            float e2 = E2[k * N_NODE + w];
#pragma unroll
            for (int r = 0; r < ADJ_R; r++) acc[r] += e1s[r][k] * e2;
        }
#pragma unroll
        for (int r = 0; r < ADJ_R; r++) {
            float v = fmaxf(acc[r], 0.f);
            z[r * NP + w] = v;
            lmax[r] = fmaxf(lmax[r], v);
        }
    }
#pragma unroll
    for (int r = 0; r < ADJ_R; r++) {
        red[tid] = lmax[r]; __syncthreads();
        for (int s = 128; s > 0; s >>= 1) { if (tid < s) red[tid] = fmaxf(red[tid], red[tid + s]); __syncthreads(); }
        if (tid == 0) srow[r] = red[0];
        __syncthreads();
    }
    float lsum[ADJ_R];
#pragma unroll
    for (int r = 0; r < ADJ_R; r++) lsum[r] = 0.f;
    for (int w = tid; w < N_NODE; w += 256) {
#pragma unroll
        for (int r = 0; r < ADJ_R; r++) {
            float e = expf(z[r * NP + w] - srow[r]);
            z[r * NP + w] = e;
            lsum[r] += e;
        }
    }
#pragma unroll
    for (int r = 0; r < ADJ_R; r++) {
        red[tid] = lsum[r]; __syncthreads();
        for (int s = 128; s > 0; s >>= 1) { if (tid < s) red[tid] += red[tid + s]; __syncthreads(); }
        if (tid == 0) srow[r] = 0.5f / red[0];
        __syncthreads();
    }
    for (int w = tid; w < NP; w += 256) {
#pragma unroll
        for (int r = 0; r < ADJ_R; r++) {
            int v = r0 + r;
            float val = (w < N_NODE) ? (z[r * NP + w] * srow[r] + ((w == v) ? 0.5f : 0.f)) : 0.f;
            g_Bh[(size_t)v * NP + w] = __float2half_rn(val);
        }
    }
}

// ---------------- kernel 2: start conv on HMMA (2-product) ----------------
__global__ __launch_bounds__(256, 2) void k_conv_mma(const float* __restrict__ bias) {
    extern __shared__ char smem[];
    const uint32_t sbase = smem_u32(smem);
    __half* xw = (__half*)(smem + CV_XW);
    const int tid = threadIdx.x;
    const int wid = tid >> 5, lane = tid & 31;
    const int wm = wid >> 1;
    const int wn = wid & 1;
    const int b  = blockIdx.y;
    const int n0 = blockIdx.x * 128;

#define CV_LOAD_A(ci, stg) do {                                                      \
    _Pragma("unroll")                                                                \
    for (int i = 0; i < 2; i++) {                                                    \
        int idx = tid + i * 256;                                                     \
        int co = idx >> 3, s = idx & 7;                                              \
        uint32_t dst = sbase + CV_A0 + (stg) * CV_A_STG + co * 128 +                 \
                       ((uint32_t)(s ^ (co & 7)) << 4);                              \
        cpa16(dst,            (const char*)(g_Whi + (ci) * CC * 64 + co * 64 + s * 8)); \
        cpa16(dst + CV_A_VAR, (const char*)(g_Wlo + (ci) * CC * 64 + co * 64 + s * 8)); \
    }                                                                                \
} while (0)

#define CV_LOAD_XW(ci, stg) do {                                                     \
    if (tid < 24)                                                                    \
        cpa16(sbase + CV_XW + (stg) * 384 + tid * 16,                                \
              (const char*)(g_Xh + (size_t)b * IN_D * DM + (ci) * DM + n0) + tid * 16); \
} while (0)

#define CV_BUILD_B(stg) do {                                                         \
    const __half* xwp = xw + (stg) * 192;                                            \
    _Pragma("unroll")                                                                \
    for (int i = 0; i < 16; i++) {                                                   \
        int idx = tid + i * 256;                                                     \
        int t = idx >> 6, j2 = idx & 63;                                             \
        int n = j2 * 2;                                                              \
        __half2 hh(xwp[t + n], xwp[t + n + 1]);                                      \
        int s = n >> 3;                                                              \
        uint32_t off = t * 256 + ((uint32_t)(s ^ (t & 7)) << 4) + (j2 & 3) * 4;      \
        *(uint32_t*)(smem + CV_B0 + (stg) * CV_B_STG + off) = *reinterpret_cast<uint32_t*>(&hh); \
    }                                                                                \
} while (0)

    float acc[8][4];
#pragma unroll
    for (int in = 0; in < 8; in++)
#pragma unroll
        for (int q = 0; q < 4; q++) acc[in][q] = 0.f;

    const int a_row = wm * 16 + (lane & 15);
    const int a_jl  = lane >> 4;
    const int b_kl  = ((lane >> 3) & 1) * 8 + (lane & 7);
    const int b_nl  = lane >> 4;

    CV_LOAD_A(0, 0);
    CV_LOAD_XW(0, 0);
    CPA_COMMIT();
    CPA_WAIT(0);
    __syncthreads();
    CV_BUILD_B(0);
    __syncthreads();

    for (int c = 0; c < IN_D; c++) {
        int stg = c & 1, nstg = (c + 1) & 1;
        if (c + 1 < IN_D) { CV_LOAD_A(c + 1, nstg); CV_LOAD_XW(c + 1, nstg); CPA_COMMIT(); }

        uint32_t astg = sbase + CV_A0 + stg * CV_A_STG;
        uint32_t bstg = sbase + CV_B0 + stg * CV_B_STG;
#pragma unroll
        for (int ks = 0; ks < 4; ks++) {
            uint32_t ah[4], al[4], bh[4][4];
            {
                int s = 2 * ks + a_jl;
                uint32_t off = (uint32_t)a_row * 128 + ((uint32_t)(s ^ (a_row & 7)) << 4);
                ldsm4(ah, astg + off);
                ldsm4(al, astg + CV_A_VAR + off);
            }
            int krow = ks * 16 + b_kl;
            uint32_t koff = (uint32_t)krow * 256;
            uint32_t kx = (uint32_t)(krow & 7);
#pragma unroll
            for (int q = 0; q < 4; q++) {
                int ns = wn * 8 + 2 * q + b_nl;
                uint32_t off = koff + ((uint32_t)(ns ^ kx) << 4);
                ldsm4t(bh[q], bstg + off);
            }
#pragma unroll
            for (int p = 0; p < 2; p++) {
#pragma unroll
                for (int in = 0; in < 8; in++) {
                    const uint32_t* af = (p == 1) ? al : ah;
                    mma16816(acc[in], af, &bh[in >> 1][(in & 1) * 2]);
                }
            }
        }
        if (c + 1 < IN_D) {
            CPA_WAIT(0);
            __syncthreads();
            CV_BUILD_B(nstg);
            __syncthreads();
        }
    }

    const int o0 = wm * 16 + (lane >> 2);
    const int o1 = o0 + 8;
    const float b0v = bias[o0], b1v = bias[o1];
#pragma unroll
    for (int in = 0; in < 8; in++) {
        int n = n0 + wn * 64 + in * 8 + (lane & 3) * 2;
        bool ok = (n < N_NODE);
        float v00 = ok ? (acc[in][0] + b0v) : 0.f;
        float v01 = ok ? (acc[in][1] + b0v) : 0.f;
        float v10 = ok ? (acc[in][2] + b1v) : 0.f;
        float v11 = ok ? (acc[in][3] + b1v) : 0.f;
        size_t r0 = (size_t)(b * CC + o0) * NP + n;
        size_t r1 = (size_t)(b * CC + o1) * NP + n;
        __half h0, l0, h1, l1;
        fp16_split(v00, h0, l0); fp16_split(v01, h1, l1);
        *(__half2*)(g_Ahi + r0) = __half2(h0, h1);
        *(__half2*)(g_Alo + r0) = __half2(l0, l1);
        fp16_split(v10, h0, l0); fp16_split(v11, h1, l1);
        *(__half2*)(g_Ahi + r1) = __half2(h0, h1);
        *(__half2*)(g_Alo + r1) = __half2(l0, l1);
    }
#undef CV_LOAD_A
#undef CV_LOAD_XW
#undef CV_BUILD_B
}

// ---------------- kernel 3: mixprop GEMM (256x128 CTA, 4 stages, sync per 2 chunks) --
__global__ __launch_bounds__(512, 1) void k_mix_mma(int src, int dst) {
    extern __shared__ char smem[];
    const uint32_t sbase = smem_u32(smem);

    const int tid = threadIdx.x;
    const int wid = tid >> 5, lane = tid & 31;
    const int wm = wid >> 2;
    const int wn = wid & 3;
    const int m0 = blockIdx.y * TILE_M;
    const int n0 = blockIdx.x * TILE_N;

    const __half* Ahi = g_Ahi + (size_t)src * MROWS * NP;

    const int ar = tid >> 1;
    const int as_ = (tid & 1) * 4;
    const uint32_t aswz = (uint32_t)(ar & 7);
    const int br = tid >> 2;
    const int bs_ = (tid & 3) * 2;
    const uint32_t bswz = (uint32_t)(br & 7);
    const char* gA = (const char*)(Ahi + (size_t)(m0 + ar) * NP) + as_ * 16;
    const char* gB = (const char*)(g_Bh + (size_t)(n0 + br) * NP) + bs_ * 16;

#define LOAD_CHUNK(cidx, buf) do {                                                   \
    uint32_t sb = sbase + (buf) * STAGE_BYTES;                                       \
    size_t go = (size_t)(cidx) * 128;                                                \
    uint32_t sa = sb + OFF_AH + ar * 128;                                            \
    _Pragma("unroll")                                                                \
    for (int j = 0; j < 4; j++) {                                                    \
        uint32_t so = ((uint32_t)(as_ + j) ^ aswz) << 4;                             \
        cpa16(sa + so, gA + go + j * 16);                                            \
    }                                                                                \
    uint32_t sbb = sb + OFF_BH + br * 128;                                           \
    _Pragma("unroll")                                                                \
    for (int j = 0; j < 2; j++) {                                                    \
        uint32_t so = ((uint32_t)(bs_ + j) ^ bswz) << 4;                             \
        cpa16(sbb + so, gB + go + j * 16);                                           \
    }                                                                                \
} while (0)

    float acc[4][4][4];
#pragma unroll
    for (int im = 0; im < 4; im++)
#pragma unroll
        for (int in = 0; in < 4; in++)
#pragma unroll
            for (int q = 0; q < 4; q++) acc[im][in][q] = 0.f;

    const int a_row_l = (lane & 15);
    const int a_jl = lane >> 4;
    const int b_row_l = ((lane >> 4) << 3) + (lane & 7);
    const int b_jl = (lane >> 3) & 1;

#define COMPUTE_CHUNK(buf) do {                                                      \
    uint32_t sb = sbase + (buf) * STAGE_BYTES;                                       \
    _Pragma("unroll")                                                                \
    for (int ks = 0; ks < 4; ks++) {                                                 \
        uint32_t ah[4][4], bh[2][4];                                                 \
        _Pragma("unroll")                                                            \
        for (int im = 0; im < 4; im++) {                                             \
            int row = wm * 64 + im * 16 + a_row_l;                                   \
            uint32_t off = (uint32_t)row * 128 +                                     \
                           ((uint32_t)((2 * ks + a_jl) ^ (row & 7)) << 4);           \
            ldsm4(ah[im], sb + OFF_AH + off);                                        \
        }                                                                            \
        _Pragma("unroll")                                                            \
        for (int inb = 0; inb < 2; inb++) {                                          \
            int row = wn * 32 + inb * 16 + b_row_l;                                  \
            uint32_t off = (uint32_t)row * 128 +                                     \
                           ((uint32_t)((2 * ks + b_jl) ^ (row & 7)) << 4);           \
            ldsm4(bh[inb], sb + OFF_BH + off);                                       \
        }                                                                            \
        _Pragma("unroll")                                                            \
        for (int im = 0; im < 4; im++)                                               \
            _Pragma("unroll")                                                        \
            for (int in = 0; in < 4; in++)                                           \
                mma16816(acc[im][in], ah[im], &bh[in >> 1][(in & 1) * 2]);           \
    }                                                                                \
} while (0)

    LOAD_CHUNK(0, 0); CPA_COMMIT();
    LOAD_CHUNK(1, 1); CPA_COMMIT();

    for (int cc = 0; cc < NCHUNK; cc += 2) {
        __syncthreads();   // all warps done with window cc-2 (buffers (cc+2)&3,(cc+3)&3)
        if (cc + 2 < NCHUNK) {
            LOAD_CHUNK(cc + 2, (cc + 2) & 3); CPA_COMMIT();
            LOAD_CHUNK(cc + 3, (cc + 3) & 3); CPA_COMMIT();
            CPA_WAIT(2);            // chunks cc, cc+1 landed
        } else {
            CPA_WAIT(0);
        }
        COMPUTE_CHUNK(cc & 3);
        COMPUTE_CHUNK((cc + 1) & 3);
    }

    // epilogue: C = ALPHA*(h0 hi+lo) + BETA*acc -> fp16 hi only
    const __half* Xh = g_Ahi;
    const __half* Xl = g_Alo;
    __half* Hh = g_Ahi + (size_t)dst * MROWS * NP;

#pragma unroll
    for (int im = 0; im < 4; im++) {
#pragma unroll
        for (int half = 0; half < 2; half++) {
            int m = m0 + wm * 64 + im * 16 + (lane >> 2) + half * 8;
            size_t rowo = (size_t)m * NP;
#pragma unroll
            for (int in = 0; in < 4; in++) {
                int n = n0 + wn * 32 + in * 8 + (lane & 3) * 2;
                float d0 = acc[im][in][half * 2 + 0];
                float d1 = acc[im][in][half * 2 + 1];
                __half2 xh = *(const __half2*)(Xh + rowo + n);
                __half2 xl = *(const __half2*)(Xl + rowo + n);
                float x0 = __half2float(xh.x) + __half2float(xl.x);
                float x1 = __half2float(xh.y) + __half2float(xl.y);
                float o0 = ALPHA_C * x0 + BETA_C * d0;
                float o1 = ALPHA_C * x1 + BETA_C * d1;
                *(__half2*)(Hh + rowo + n) =
                    __half2(__float2half_rn(o0), __float2half_rn(o1));
            }
        }
    }
#undef LOAD_CHUNK
#undef COMPUTE_CHUNK
}

// ---------------- kernel 4: MLP on HMMA (2-product) + GELU + end dot ----------------
__global__ __launch_bounds__(256) void k_mlp_mma(const float* __restrict__ bmlp,
                                                 const float* __restrict__ wend,
                                                 const float* __restrict__ bend) {
    extern __shared__ char smem[];
    __shared__ float red[4][128];
    const uint32_t sbase = smem_u32(smem);
    const int tid = threadIdx.x;
    const int wid = tid >> 5, lane = tid & 31;
    const int wm = wid >> 1;
    const int wn = wid & 1;
    const int b  = blockIdx.y;
    const int n0 = blockIdx.x * 128;

#pragma unroll
    for (int i = 0; i < 8; i++) {
        int idx = tid + i * 256;
        int o = idx >> 5, s = idx & 31;
        uint32_t phys = (uint32_t)(s ^ (o & 15));
        uint32_t dst = sbase + o * 512 + phys * 16;
        cpa16(dst + MLP_A_HI, (const char*)(g_Mhi + o * 256 + s * 8));
        cpa16(dst + MLP_A_LO, (const char*)(g_Mlo + o * 256 + s * 8));
    }

#define LOAD_BCH(chunk, stg) do {                                                        \
    const __half* HBh = g_Ahi + ((size_t)(chunk) * MROWS + b * 64) * NP + n0;            \
    _Pragma("unroll")                                                                    \
    for (int i = 0; i < 4; i++) {                                                        \
        int idx = tid + i * 256;                                                         \
        int k = idx >> 4, s = idx & 15;                                                  \
        uint32_t phys = (uint32_t)(s ^ (k & 7));                                         \
        uint32_t dst = sbase + MLP_B_BASE + (stg) * MLP_B_STG + k * 256 + phys * 16;     \
        cpa16(dst, (const char*)HBh + (size_t)k * NP * 2 + s * 16);                      \
    }                                                                                    \
} while (0)

    float acc[8][4];
#pragma unroll
    for (int in = 0; in < 8; in++)
#pragma unroll
        for (int q = 0; q < 4; q++) acc[in][q] = 0.f;

    const int a_row = wm * 16 + (lane & 15);
    const int a_jl  = lane >> 4;
    const int b_kl  = ((lane >> 3) & 1) * 8 + (lane & 7);
    const int b_nl  = lane >> 4;

    LOAD_BCH(0, 0); CPA_COMMIT();

    for (int chunk = 0; chunk < 4; chunk++) {
        CPA_WAIT(0);
        __syncthreads();
        if (chunk < 3) { LOAD_BCH(chunk + 1, (chunk + 1) & 1); CPA_COMMIT(); }
        uint32_t bstg = sbase + MLP_B_BASE + (chunk & 1) * MLP_B_STG;

#pragma unroll
        for (int ks = 0; ks < 4; ks++) {
            int ksg = chunk * 4 + ks;
            uint32_t ah[4], al[4], bh[4][4];
            {
                int s = 2 * ksg + a_jl;
                uint32_t off = (uint32_t)a_row * 512 + ((uint32_t)(s ^ (a_row & 15)) << 4);
                ldsm4(ah, sbase + MLP_A_HI + off);
                ldsm4(al, sbase + MLP_A_LO + off);
            }
            int krow = ks * 16 + b_kl;
            uint32_t koff = (uint32_t)krow * 256;
            uint32_t kx = (uint32_t)(krow & 7);
#pragma unroll
            for (int q = 0; q < 4; q++) {
                int ns = wn * 8 + 2 * q + b_nl;
                uint32_t off = koff + ((uint32_t)(ns ^ kx) << 4);
                ldsm4t(bh[q], bstg + off);
            }
#pragma unroll
            for (int p = 0; p < 2; p++) {
#pragma unroll
                for (int in = 0; in < 8; in++) {
                    const uint32_t* af = (p == 1) ? al : ah;
                    mma16816(acc[in], af, &bh[in >> 1][(in & 1) * 2]);
                }
            }
        }
        __syncthreads();
    }

    const int o0 = wm * 16 + (lane >> 2);
    const int o1 = o0 + 8;
    const float bm0 = bmlp[o0], bm1 = bmlp[o1];
    const float we0 = wend[o0], we1 = wend[o1];

#pragma unroll
    for (int in = 0; in < 8; in++) {
        float g00 = gelu_exact(acc[in][0] + bm0);
        float g01 = gelu_exact(acc[in][1] + bm0);
        float g10 = gelu_exact(acc[in][2] + bm1);
        float g11 = gelu_exact(acc[in][3] + bm1);
        float p0 = we0 * g00 + we1 * g10;
        float p1 = we0 * g01 + we1 * g11;
#pragma unroll
        for (int d = 4; d <= 16; d <<= 1) {
            p0 += __shfl_xor_sync(0xFFFFFFFF, p0, d);
            p1 += __shfl_xor_sync(0xFFFFFFFF, p1, d);
        }
        if (lane < 4) {
            red[wm][wn * 64 + in * 8 + lane * 2 + 0] = p0;
            red[wm][wn * 64 + in * 8 + lane * 2 + 1] = p1;
        }
    }
    __syncthreads();
    if (tid < 128) {
        int n = n0 + tid;
        float s = bend[0] + red[0][tid] + red[1][tid] + red[2][tid] + red[3][tid];
        g_Sh[(size_t)b * NP + n] = __float2half_rn((n < N_NODE) ? s : 0.f);
    }
#undef LOAD_BCH
}

// ---------------- kernel 5: final linear on HMMA ----------------
__global__ __launch_bounds__(256) void k_lin_mma(const float* __restrict__ blin) {
    extern __shared__ char smem[];
    const uint32_t sbase = smem_u32(smem);
    const int tid = threadIdx.x;
    const int wid = tid >> 5, lane = tid & 31;
    const int wm = wid >> 1;
    const int wn = wid & 1;
    const int n0 = blockIdx.x * LIN_TN;

#define LIN_LOAD(cidx, stg) do {                                                     \
    _Pragma("unroll")                                                                \
    for (int i = 0; i < 2; i++) {                                                    \
        int idx = tid + i * 256;                                                     \
        int row = idx >> 3, s = idx & 7;                                             \
        uint32_t so = ((uint32_t)(s ^ (row & 7)) << 4);                              \
        cpa16(sbase + (stg) * LIN_STG + row * 128 + so,                              \
              (const char*)(g_Sh + (size_t)row * NP) + (size_t)(cidx) * 128 + s * 16); \
    }                                                                                \
    {                                                                                \
        int row = tid >> 3, s = tid & 7;                                             \
        uint32_t so = ((uint32_t)(s ^ (row & 7)) << 4);                              \
        cpa16(sbase + (stg) * LIN_STG + LIN_A_BYTES + row * 128 + so,                \
              (const char*)(g_Wl + (size_t)(n0 + row) * NP) + (size_t)(cidx) * 128 + s * 16); \
    }                                                                                \
} while (0)

    float acc[2][4];
#pragma unroll
    for (int in = 0; in < 2; in++)
#pragma unroll
        for (int q = 0; q < 4; q++) acc[in][q] = 0.f;

    const int a_row_l = (lane & 15);
    const int a_jl = lane >> 4;
    const int b_row_l = ((lane >> 4) << 3) + (lane & 7);
    const int b_jl = (lane >> 3) & 1;

    LIN_LOAD(0, 0); CPA_COMMIT();

    for (int c = 0; c < 32; c++) {
        CPA_WAIT(0);
        __syncthreads();
        if (c + 1 < 32) { LIN_LOAD(c + 1, (c + 1) & 1); CPA_COMMIT(); }
        uint32_t astg = sbase + (c & 1) * LIN_STG;
        uint32_t bstg = astg + LIN_A_BYTES;
#pragma unroll
        for (int ks = 0; ks < 4; ks++) {
            uint32_t ah[4], bh[4];
            {
                int row = wm * 16 + a_row_l;
                uint32_t off = (uint32_t)row * 128 +
                               ((uint32_t)((2 * ks + a_jl) ^ (row & 7)) << 4);
                ldsm4(ah, astg + off);
            }
            {
                int row = wn * 16 + b_row_l;
                uint32_t off = (uint32_t)row * 128 +
                               ((uint32_t)((2 * ks + b_jl) ^ (row & 7)) << 4);
                ldsm4(bh, bstg + off);
            }
#pragma unroll
            for (int in = 0; in < 2; in++)
                mma16816(acc[in], ah, &bh[in * 2]);
        }
        __syncthreads();
    }

#pragma unroll
    for (int in = 0; in < 2; in++) {
        int d = n0 + wn * 16 + in * 8 + (lane & 3) * 2;
        int b0 = wm * 16 + (lane >> 2), b1 = b0 + 8;
        float bl0 = blin[d], bl1 = blin[d + 1];
        g_Y[(size_t)b0 * DM + d]     = acc[in][0] + bl0;
        g_Y[(size_t)b0 * DM + d + 1] = acc[in][1] + bl1;
        g_Y[(size_t)b1 * DM + d]     = acc[in][2] + bl0;
        g_Y[(size_t)b1 * DM + d + 1] = acc[in][3] + bl1;
    }
#undef LIN_LOAD
}

// ---------------- kernel 6: layernorm ----------------
__global__ void k_ln(const float* __restrict__ gam, const float* __restrict__ bet,
                     float* __restrict__ out) {
    int b = blockIdx.x;
    int tid = threadIdx.x;
    __shared__ float red[256];
    const float* y = g_Y + (size_t)b * DM;

    float s = 0.f;
    for (int d = tid; d < DM; d += 256) s += y[d];
    red[tid] = s; __syncthreads();
    for (int st = 128; st > 0; st >>= 1) { if (tid < st) red[tid] += red[tid + st]; __syncthreads(); }
    float mu = red[0] / DM;
    __syncthreads();

    float v = 0.f;
    for (int d = tid; d < DM; d += 256) { float t = y[d] - mu; v += t * t; }
    red[tid] = v; __syncthreads();
    for (int st = 128; st > 0; st >>= 1) { if (tid < st) red[tid] += red[tid + st]; __syncthreads(); }
    float rinv = rsqrtf(red[0] / DM + 1e-5f);

    for (int d = tid; d < DM; d += 256)
        out[(size_t)b * DM + d] = (y[d] - mu) * rinv * gam[d] + bet[d];
}

// ---------------- launch ----------------
extern "C" void kernel_launch(void* const* d_in, const int* in_sizes, int n_in,
                              void* d_out, int out_size) {
    const float* x       = (const float*)d_in[0];
    const float* nv1     = (const float*)d_in[1];
    const float* nv2     = (const float*)d_in[2];
    const float* w_start = (const float*)d_in[3];
    const float* b_start = (const float*)d_in[4];
    const float* w_mlp   = (const float*)d_in[5];
    const float* b_mlp   = (const float*)d_in[6];
    const float* w_end   = (const float*)d_in[7];
    const float* b_end   = (const float*)d_in[8];
    const float* w_lin   = (const float*)d_in[9];
    const float* b_lin   = (const float*)d_in[10];
    const float* ln_g    = (const float*)d_in[11];
    const float* ln_b    = (const float*)d_in[12];
    float* out = (float*)d_out;

    cudaFuncSetAttribute(k_mix_mma,  cudaFuncAttributeMaxDynamicSharedMemorySize, MIX_SMEM);
    cudaFuncSetAttribute(k_mlp_mma,  cudaFuncAttributeMaxDynamicSharedMemorySize, MLP_SMEM);
    cudaFuncSetAttribute(k_conv_mma, cudaFuncAttributeMaxDynamicSharedMemorySize, CV_SMEM);
    cudaFuncSetAttribute(k_padj,     cudaFuncAttributeMaxDynamicSharedMemorySize, ADJ_SMEM);
    cudaFuncSetAttribute(k_lin_mma,  cudaFuncAttributeMaxDynamicSharedMemorySize, LIN_SMEM);

    k_padj<<<PA_BLOCKS, 256, ADJ_SMEM>>>(nv1, nv2, w_start, w_lin, x, w_mlp);
    k_conv_mma<<<dim3(NP / 128, BATCH), 256, CV_SMEM>>>(b_start);
    dim3 mixg(NP / TILE_N, MROWS / TILE_M);
    k_mix_mma<<<mixg, 512, MIX_SMEM>>>(0, 1);
    k_mix_mma<<<mixg, 512, MIX_SMEM>>>(1, 2);
    k_mix_mma<<<mixg, 512, MIX_SMEM>>>(2, 3);
    k_mlp_mma<<<dim3(NP / 128, BATCH), 256, MLP_SMEM>>>(b_mlp, w_end, b_end);
    k_lin_mma<<<NP / LIN_TN, 256, LIN_SMEM>>>(b_lin);
    k_ln<<<BATCH, 256>>>(ln_g, ln_b, out);
}

// round 15
// speedup vs baseline: 6.5430x; 1.0266x over previous
#include <cuda_runtime.h>
#include <cuda_fp16.h>
#include <math.h>
#include <stdint.h>

// ---------------- problem constants ----------------
#define N_NODE 2000
#define NP     2048
#define BATCH  64
#define CC     64
#define MROWS  (BATCH*CC)    // 4096
#define DM     2048
#define IN_D   7
#define KW     49
#define ND     40
#define ALPHA_C 0.05f
#define BETA_C  0.95f

// mix GEMM tiling: CTA 256Mx128N, 512 thr, KC=64 (128B rows, SW128), 4 stages
#define NCHUNK  32
#define TILE_M  256
#define TILE_N  128
#define A_BYTES (256 * 128)
#define B_BYTES (128 * 128)
#define OFF_AH  0
#define OFF_BH  (A_BYTES)
#define STAGE_BYTES (A_BYTES + B_BYTES)   // 49152
#define NSTAGE  4
#define MIX_SMEM (NSTAGE * STAGE_BYTES)   // 196608

// mlp GEMM smem layout
#define MLP_A_HI   0
#define MLP_A_LO   32768
#define MLP_B_BASE 65536
#define MLP_B_STG  16384
#define MLP_SMEM   98304

// conv GEMM smem layout
#define CV_A_STG   16384
#define CV_A_VAR   8192
#define CV_B_STG   16384
#define CV_A0      0
#define CV_B0      (2 * CV_A_STG)
#define CV_XW      (CV_B0 + 2 * CV_B_STG)
#define CV_SMEM    (CV_XW + 2 * 384)

// adj
#define ADJ_R   8
#define ADJ_BLOCKS (NP / ADJ_R)        // 256
#define ADJ_SMEM (ADJ_R * NP * 4)      // 65536

// lin GEMM
#define LIN_TN  32
#define LIN_A_BYTES (64 * 128)
#define LIN_B_BYTES (LIN_TN * 128)
#define LIN_STG (LIN_A_BYTES + LIN_B_BYTES)
#define LIN_SMEM (2 * LIN_STG)

// prep1 block ranges (w_start, x, w_mlp)
#define PREP_W 7
#define PREP_X 448
#define PREP_M 64
#define PREP1_BLOCKS (PREP_W + PREP_X + PREP_M)   // 519

// ---------------- scratch ----------------
__device__ __half  g_Ahi[4 * MROWS * NP];
__device__ __half  g_Alo[MROWS * NP];       // lo of hop0 only
__device__ __half  g_Bh[NP * NP];
__device__ __half  g_Whi[IN_D * CC * 64];
__device__ __half  g_Wlo[IN_D * CC * 64];
__device__ __half  g_Wl[NP * NP];
__device__ __half  g_Mhi[CC * 256];
__device__ __half  g_Mlo[CC * 256];
__device__ __half  g_Xh[BATCH * IN_D * DM + 128];
__device__ __half  g_Sh[BATCH * NP];
__device__ float   g_Y[BATCH * DM];

// ---------------- helpers ----------------
__device__ __forceinline__ uint32_t smem_u32(const void* p) {
    uint32_t a;
    asm("{ .reg .u64 t; cvta.to.shared.u64 t, %1; cvt.u32.u64 %0, t; }" : "=r"(a) : "l"(p));
    return a;
}
__device__ __forceinline__ void cpa16(uint32_t s, const void* g) {
    asm volatile("cp.async.cg.shared.global [%0], [%1], 16;" :: "r"(s), "l"(g));
}
#define CPA_COMMIT() asm volatile("cp.async.commit_group;" ::: "memory")
#define CPA_WAIT(n)  asm volatile("cp.async.wait_group %0;" :: "n"(n) : "memory")

__device__ __forceinline__ void ldsm4(uint32_t* r, uint32_t addr) {
    asm volatile("ldmatrix.sync.aligned.m8n8.x4.shared.b16 {%0,%1,%2,%3}, [%4];"
                 : "=r"(r[0]), "=r"(r[1]), "=r"(r[2]), "=r"(r[3]) : "r"(addr));
}
__device__ __forceinline__ void ldsm4t(uint32_t* r, uint32_t addr) {
    asm volatile("ldmatrix.sync.aligned.m8n8.x4.trans.shared.b16 {%0,%1,%2,%3}, [%4];"
                 : "=r"(r[0]), "=r"(r[1]), "=r"(r[2]), "=r"(r[3]) : "r"(addr));
}
__device__ __forceinline__ void mma16816(float* d, const uint32_t* a, const uint32_t* b) {
    asm volatile("mma.sync.aligned.m16n8k16.row.col.f32.f16.f16.f32 "
                 "{%0,%1,%2,%3}, {%4,%5,%6,%7}, {%8,%9}, {%0,%1,%2,%3};"
                 : "+f"(d[0]), "+f"(d[1]), "+f"(d[2]), "+f"(d[3])
                 : "r"(a[0]), "r"(a[1]), "r"(a[2]), "r"(a[3]), "r"(b[0]), "r"(b[1]));
}
__device__ __forceinline__ void fp16_split(float v, __half& hi, __half& lo) {
    hi = __float2half_rn(v);
    lo = __float2half_rn(v - __half2float(hi));
}
__device__ __forceinline__ float gelu_exact(float v) {
    return 0.5f * v * (1.f + erff(v * 0.70710678118654752f));
}

// ---------------- kernel 0a: prep1 (conv w, x, w_mlp) ----------------
__global__ void k_prep1(const float* __restrict__ w_start,
                        const float* __restrict__ x,
                        const float* __restrict__ wmlp) {
    int bid = blockIdx.x;
    int tid = threadIdx.x;
    if (bid < PREP_W) {
        int ci = bid;
        for (int idx = tid; idx < CC * 64; idx += 256) {
            int co = idx >> 6, t = idx & 63;
            float v = (t < KW) ? w_start[co * (IN_D * KW) + ci * KW + t] : 0.f;
            __half h, l; fp16_split(v, h, l);
            g_Whi[ci * CC * 64 + idx] = h;
            g_Wlo[ci * CC * 64 + idx] = l;
        }
    } else if (bid < PREP_W + PREP_X) {
        int row = bid - PREP_W;
        size_t base = (size_t)row * DM;
        for (int i = tid; i < DM; i += 256)
            g_Xh[base + i] = __float2half_rn(x[base + i]);
        if (row == PREP_X - 1 && tid < 128)
            g_Xh[(size_t)BATCH * IN_D * DM + tid] = __float2half(0.f);
    } else {
        int o = bid - PREP_W - PREP_X;
        for (int i = tid; i < 256; i += 256) {
            float v = wmlp[o * 256 + i];
            __half h, l; fp16_split(v, h, l);
            g_Mhi[o * 256 + i] = h;
            g_Mlo[o * 256 + i] = l;
        }
    }
}

// ---------------- kernel 0b: prep w_lin -> fp16 padded ----------------
__global__ void k_prepl(const float* __restrict__ wlin) {
    int d = blockIdx.x;
    for (int w = threadIdx.x; w < NP; w += 256) {
        float v = (w < N_NODE) ? wlin[(size_t)d * N_NODE + w] : 0.f;
        g_Wl[(size_t)d * NP + w] = __float2half_rn(v);
    }
}

// ---------------- kernel 1: adjacency, 8 rows per CTA ----------------
__global__ void k_adj(const float* __restrict__ E1, const float* __restrict__ E2) {
    extern __shared__ float z[];
    __shared__ float e1s[ADJ_R][ND];
    __shared__ float red[256];
    __shared__ float srow[ADJ_R];
    int tid = threadIdx.x;
    int r0 = blockIdx.x * ADJ_R;

    if (r0 >= N_NODE) {
        for (int r = 0; r < ADJ_R; r++) {
            int v = r0 + r;
            if (v < NP)
                for (int w = tid; w < NP; w += 256) g_Bh[(size_t)v * NP + w] = __float2half(0.f);
        }
        return;
    }

    for (int idx = tid; idx < ADJ_R * ND; idx += 256)
        e1s[idx / ND][idx % ND] = E1[(r0 + idx / ND) * ND + idx % ND];
    __syncthreads();

    float lmax[ADJ_R];
#pragma unroll
    for (int r = 0; r < ADJ_R; r++) lmax[r] = -1e30f;

    for (int w = tid; w < N_NODE; w += 256) {
        float acc[ADJ_R];
#pragma unroll
        for (int r = 0; r < ADJ_R; r++) acc[r] = 0.f;
#pragma unroll 8
        for (int k = 0; k < ND; k++) {
            float e2 = E2[k * N_NODE + w];
#pragma unroll
            for (int r = 0; r < ADJ_R; r++) acc[r] += e1s[r][k] * e2;
        }
#pragma unroll
        for (int r = 0; r < ADJ_R; r++) {
            float v = fmaxf(acc[r], 0.f);
            z[r * NP + w] = v;
            lmax[r] = fmaxf(lmax[r], v);
        }
    }
#pragma unroll
    for (int r = 0; r < ADJ_R; r++) {
        red[tid] = lmax[r]; __syncthreads();
        for (int s = 128; s > 0; s >>= 1) { if (tid < s) red[tid] = fmaxf(red[tid], red[tid + s]); __syncthreads(); }
        if (tid == 0) srow[r] = red[0];
        __syncthreads();
    }
    float lsum[ADJ_R];
#pragma unroll
    for (int r = 0; r < ADJ_R; r++) lsum[r] = 0.f;
    for (int w = tid; w < N_NODE; w += 256) {
#pragma unroll
        for (int r = 0; r < ADJ_R; r++) {
            float e = __expf(z[r * NP + w] - srow[r]);
            z[r * NP + w] = e;
            lsum[r] += e;
        }
    }
#pragma unroll
    for (int r = 0; r < ADJ_R; r++) {
        red[tid] = lsum[r]; __syncthreads();
        for (int s = 128; s > 0; s >>= 1) { if (tid < s) red[tid] += red[tid + s]; __syncthreads(); }
        if (tid == 0) srow[r] = 0.5f / red[0];
        __syncthreads();
    }
    for (int w = tid; w < NP; w += 256) {
#pragma unroll
        for (int r = 0; r < ADJ_R; r++) {
            int v = r0 + r;
            float val = (w < N_NODE) ? (z[r * NP + w] * srow[r] + ((w == v) ? 0.5f : 0.f)) : 0.f;
            g_Bh[(size_t)v * NP + w] = __float2half_rn(val);
        }
    }
}

// ---------------- kernel 2: start conv on HMMA (2-product) ----------------
__global__ __launch_bounds__(256, 2) void k_conv_mma(const float* __restrict__ bias) {
    extern __shared__ char smem[];
    const uint32_t sbase = smem_u32(smem);
    __half* xw = (__half*)(smem + CV_XW);
    const int tid = threadIdx.x;
    const int wid = tid >> 5, lane = tid & 31;
    const int wm = wid >> 1;
    const int wn = wid & 1;
    const int b  = blockIdx.y;
    const int n0 = blockIdx.x * 128;

#define CV_LOAD_A(ci, stg) do {                                                      \
    _Pragma("unroll")                                                                \
    for (int i = 0; i < 2; i++) {                                                    \
        int idx = tid + i * 256;                                                     \
        int co = idx >> 3, s = idx & 7;                                              \
        uint32_t dst = sbase + CV_A0 + (stg) * CV_A_STG + co * 128 +                 \
                       ((uint32_t)(s ^ (co & 7)) << 4);                              \
        cpa16(dst,            (const char*)(g_Whi + (ci) * CC * 64 + co * 64 + s * 8)); \
        cpa16(dst + CV_A_VAR, (const char*)(g_Wlo + (ci) * CC * 64 + co * 64 + s * 8)); \
    }                                                                                \
} while (0)

#define CV_LOAD_XW(ci, stg) do {                                                     \
    if (tid < 24)                                                                    \
        cpa16(sbase + CV_XW + (stg) * 384 + tid * 16,                                \
              (const char*)(g_Xh + (size_t)b * IN_D * DM + (ci) * DM + n0) + tid * 16); \
} while (0)

#define CV_BUILD_B(stg) do {                                                         \
    const __half* xwp = xw + (stg) * 192;                                            \
    _Pragma("unroll")                                                                \
    for (int i = 0; i < 16; i++) {                                                   \
        int idx = tid + i * 256;                                                     \
        int t = idx >> 6, j2 = idx & 63;                                             \
        int n = j2 * 2;                                                              \
        __half2 hh(xwp[t + n], xwp[t + n + 1]);                                      \
        int s = n >> 3;                                                              \
        uint32_t off = t * 256 + ((uint32_t)(s ^ (t & 7)) << 4) + (j2 & 3) * 4;      \
        *(uint32_t*)(smem + CV_B0 + (stg) * CV_B_STG + off) = *reinterpret_cast<uint32_t*>(&hh); \
    }                                                                                \
} while (0)

    float acc[8][4];
#pragma unroll
    for (int in = 0; in < 8; in++)
#pragma unroll
        for (int q = 0; q < 4; q++) acc[in][q] = 0.f;

    const int a_row = wm * 16 + (lane & 15);
    const int a_jl  = lane >> 4;
    const int b_kl  = ((lane >> 3) & 1) * 8 + (lane & 7);
    const int b_nl  = lane >> 4;

    CV_LOAD_A(0, 0);
    CV_LOAD_XW(0, 0);
    CPA_COMMIT();
    CPA_WAIT(0);
    __syncthreads();
    CV_BUILD_B(0);
    __syncthreads();

    for (int c = 0; c < IN_D; c++) {
        int stg = c & 1, nstg = (c + 1) & 1;
        if (c + 1 < IN_D) { CV_LOAD_A(c + 1, nstg); CV_LOAD_XW(c + 1, nstg); CPA_COMMIT(); }

        uint32_t astg = sbase + CV_A0 + stg * CV_A_STG;
        uint32_t bstg = sbase + CV_B0 + stg * CV_B_STG;
#pragma unroll
        for (int ks = 0; ks < 4; ks++) {
            uint32_t ah[4], al[4], bh[4][4];
            {
                int s = 2 * ks + a_jl;
                uint32_t off = (uint32_t)a_row * 128 + ((uint32_t)(s ^ (a_row & 7)) << 4);
                ldsm4(ah, astg + off);
                ldsm4(al, astg + CV_A_VAR + off);
            }
            int krow = ks * 16 + b_kl;
            uint32_t koff = (uint32_t)krow * 256;
            uint32_t kx = (uint32_t)(krow & 7);
#pragma unroll
            for (int q = 0; q < 4; q++) {
                int ns = wn * 8 + 2 * q + b_nl;
                uint32_t off = koff + ((uint32_t)(ns ^ kx) << 4);
                ldsm4t(bh[q], bstg + off);
            }
#pragma unroll
            for (int p = 0; p < 2; p++) {
#pragma unroll
                for (int in = 0; in < 8; in++) {
                    const uint32_t* af = (p == 1) ? al : ah;
                    mma16816(acc[in], af, &bh[in >> 1][(in & 1) * 2]);
                }
            }
        }
        if (c + 1 < IN_D) {
            CPA_WAIT(0);
            __syncthreads();
            CV_BUILD_B(nstg);
            __syncthreads();
        }
    }

    const int o0 = wm * 16 + (lane >> 2);
    const int o1 = o0 + 8;
    const float b0v = bias[o0], b1v = bias[o1];
#pragma unroll
    for (int in = 0; in < 8; in++) {
        int n = n0 + wn * 64 + in * 8 + (lane & 3) * 2;
        bool ok = (n < N_NODE);
        float v00 = ok ? (acc[in][0] + b0v) : 0.f;
        float v01 = ok ? (acc[in][1] + b0v) : 0.f;
        float v10 = ok ? (acc[in][2] + b1v) : 0.f;
        float v11 = ok ? (acc[in][3] + b1v) : 0.f;
        size_t r0 = (size_t)(b * CC + o0) * NP + n;
        size_t r1 = (size_t)(b * CC + o1) * NP + n;
        __half h0, l0, h1, l1;
        fp16_split(v00, h0, l0); fp16_split(v01, h1, l1);
        *(__half2*)(g_Ahi + r0) = __half2(h0, h1);
        *(__half2*)(g_Alo + r0) = __half2(l0, l1);
        fp16_split(v10, h0, l0); fp16_split(v11, h1, l1);
        *(__half2*)(g_Ahi + r1) = __half2(h0, h1);
        *(__half2*)(g_Alo + r1) = __half2(l0, l1);
    }
#undef CV_LOAD_A
#undef CV_LOAD_XW
#undef CV_BUILD_B
}

// ---------------- kernel 3: mixprop GEMM (256x128 CTA, 4 stages, sync per 2 chunks) --
__global__ __launch_bounds__(512, 1) void k_mix_mma(int src, int dst) {
    extern __shared__ char smem[];
    const uint32_t sbase = smem_u32(smem);

    const int tid = threadIdx.x;
    const int wid = tid >> 5, lane = tid & 31;
    const int wm = wid >> 2;
    const int wn = wid & 3;
    const int m0 = blockIdx.y * TILE_M;
    const int n0 = blockIdx.x * TILE_N;

    const __half* Ahi = g_Ahi + (size_t)src * MROWS * NP;

    const int ar = tid >> 1;
    const int as_ = (tid & 1) * 4;
    const uint32_t aswz = (uint32_t)(ar & 7);
    const int br = tid >> 2;
    const int bs_ = (tid & 3) * 2;
    const uint32_t bswz = (uint32_t)(br & 7);
    const char* gA = (const char*)(Ahi + (size_t)(m0 + ar) * NP) + as_ * 16;
    const char* gB = (const char*)(g_Bh + (size_t)(n0 + br) * NP) + bs_ * 16;

#define LOAD_CHUNK(cidx, buf) do {                                                   \
    uint32_t sb = sbase + (buf) * STAGE_BYTES;                                       \
    size_t go = (size_t)(cidx) * 128;                                                \
    uint32_t sa = sb + OFF_AH + ar * 128;                                            \
    _Pragma("unroll")                                                                \
    for (int j = 0; j < 4; j++) {                                                    \
        uint32_t so = ((uint32_t)(as_ + j) ^ aswz) << 4;                             \
        cpa16(sa + so, gA + go + j * 16);                                            \
    }                                                                                \
    uint32_t sbb = sb + OFF_BH + br * 128;                                           \
    _Pragma("unroll")                                                                \
    for (int j = 0; j < 2; j++) {                                                    \
        uint32_t so = ((uint32_t)(bs_ + j) ^ bswz) << 4;                             \
        cpa16(sbb + so, gB + go + j * 16);                                           \
    }                                                                                \
} while (0)

    float acc[4][4][4];
#pragma unroll
    for (int im = 0; im < 4; im++)
#pragma unroll
        for (int in = 0; in < 4; in++)
#pragma unroll
            for (int q = 0; q < 4; q++) acc[im][in][q] = 0.f;

    const int a_row_l = (lane & 15);
    const int a_jl = lane >> 4;
    const int b_row_l = ((lane >> 4) << 3) + (lane & 7);
    const int b_jl = (lane >> 3) & 1;

#define COMPUTE_CHUNK(buf) do {                                                      \
    uint32_t sb = sbase + (buf) * STAGE_BYTES;                                       \
    _Pragma("unroll")                                                                \
    for (int ks = 0; ks < 4; ks++) {                                                 \
        uint32_t ah[4][4], bh[2][4];                                                 \
        _Pragma("unroll")                                                            \
        for (int im = 0; im < 4; im++) {                                             \
            int row = wm * 64 + im * 16 + a_row_l;                                   \
            uint32_t off = (uint32_t)row * 128 +                                     \
                           ((uint32_t)((2 * ks + a_jl) ^ (row & 7)) << 4);           \
            ldsm4(ah[im], sb + OFF_AH + off);                                        \
        }                                                                            \
        _Pragma("unroll")                                                            \
        for (int inb = 0; inb < 2; inb++) {                                          \
            int row = wn * 32 + inb * 16 + b_row_l;                                  \
            uint32_t off = (uint32_t)row * 128 +                                     \
                           ((uint32_t)((2 * ks + b_jl) ^ (row & 7)) << 4);           \
            ldsm4(bh[inb], sb + OFF_BH + off);                                       \
        }                                                                            \
        _Pragma("unroll")                                                            \
        for (int im = 0; im < 4; im++)                                               \
            _Pragma("unroll")                                                        \
            for (int in = 0; in < 4; in++)                                           \
                mma16816(acc[im][in], ah[im], &bh[in >> 1][(in & 1) * 2]);           \
    }                                                                                \
} while (0)

    LOAD_CHUNK(0, 0); CPA_COMMIT();
    LOAD_CHUNK(1, 1); CPA_COMMIT();

    for (int cc = 0; cc < NCHUNK; cc += 2) {
        __syncthreads();
        if (cc + 2 < NCHUNK) {
            LOAD_CHUNK(cc + 2, (cc + 2) & 3); CPA_COMMIT();
            LOAD_CHUNK(cc + 3, (cc + 3) & 3); CPA_COMMIT();
            CPA_WAIT(2);
        } else {
            CPA_WAIT(0);
        }
        COMPUTE_CHUNK(cc & 3);
        COMPUTE_CHUNK((cc + 1) & 3);
    }

    // epilogue: C = ALPHA*(h0 hi+lo) + BETA*acc -> fp16 hi only
    const __half* Xh = g_Ahi;
    const __half* Xl = g_Alo;
    __half* Hh = g_Ahi + (size_t)dst * MROWS * NP;

#pragma unroll
    for (int im = 0; im < 4; im++) {
#pragma unroll
        for (int half = 0; half < 2; half++) {
            int m = m0 + wm * 64 + im * 16 + (lane >> 2) + half * 8;
            size_t rowo = (size_t)m * NP;
#pragma unroll
            for (int in = 0; in < 4; in++) {
                int n = n0 + wn * 32 + in * 8 + (lane & 3) * 2;
                float d0 = acc[im][in][half * 2 + 0];
                float d1 = acc[im][in][half * 2 + 1];
                __half2 xh = *(const __half2*)(Xh + rowo + n);
                __half2 xl = *(const __half2*)(Xl + rowo + n);
                float x0 = __half2float(xh.x) + __half2float(xl.x);
                float x1 = __half2float(xh.y) + __half2float(xl.y);
                float o0 = ALPHA_C * x0 + BETA_C * d0;
                float o1 = ALPHA_C * x1 + BETA_C * d1;
                *(__half2*)(Hh + rowo + n) =
                    __half2(__float2half_rn(o0), __float2half_rn(o1));
            }
        }
    }
#undef LOAD_CHUNK
#undef COMPUTE_CHUNK
}

// ---------------- kernel 4: MLP on HMMA (2-product) + GELU + end dot ----------------
__global__ __launch_bounds__(256) void k_mlp_mma(const float* __restrict__ bmlp,
                                                 const float* __restrict__ wend,
                                                 const float* __restrict__ bend) {
    extern __shared__ char smem[];
    __shared__ float red[4][128];
    const uint32_t sbase = smem_u32(smem);
    const int tid = threadIdx.x;
    const int wid = tid >> 5, lane = tid & 31;
    const int wm = wid >> 1;
    const int wn = wid & 1;
    const int b  = blockIdx.y;
    const int n0 = blockIdx.x * 128;

#pragma unroll
    for (int i = 0; i < 8; i++) {
        int idx = tid + i * 256;
        int o = idx >> 5, s = idx & 31;
        uint32_t phys = (uint32_t)(s ^ (o & 15));
        uint32_t dst = sbase + o * 512 + phys * 16;
        cpa16(dst + MLP_A_HI, (const char*)(g_Mhi + o * 256 + s * 8));
        cpa16(dst + MLP_A_LO, (const char*)(g_Mlo + o * 256 + s * 8));
    }

#define LOAD_BCH(chunk, stg) do {                                                        \
    const __half* HBh = g_Ahi + ((size_t)(chunk) * MROWS + b * 64) * NP + n0;            \
    _Pragma("unroll")                                                                    \
    for (int i = 0; i < 4; i++) {                                                        \
        int idx = tid + i * 256;                                                         \
        int k = idx >> 4, s = idx & 15;                                                  \
        uint32_t phys = (uint32_t)(s ^ (k & 7));                                         \
        uint32_t dst = sbase + MLP_B_BASE + (stg) * MLP_B_STG + k * 256 + phys * 16;     \
        cpa16(dst, (const char*)HBh + (size_t)k * NP * 2 + s * 16);                      \
    }                                                                                    \
} while (0)

    float acc[8][4];
#pragma unroll
    for (int in = 0; in < 8; in++)
#pragma unroll
        for (int q = 0; q < 4; q++) acc[in][q] = 0.f;

    const int a_row = wm * 16 + (lane & 15);
    const int a_jl  = lane >> 4;
    const int b_kl  = ((lane >> 3) & 1) * 8 + (lane & 7);
    const int b_nl  = lane >> 4;

    LOAD_BCH(0, 0); CPA_COMMIT();

    for (int chunk = 0; chunk < 4; chunk++) {
        CPA_WAIT(0);
        __syncthreads();
        if (chunk < 3) { LOAD_BCH(chunk + 1, (chunk + 1) & 1); CPA_COMMIT(); }
        uint32_t bstg = sbase + MLP_B_BASE + (chunk & 1) * MLP_B_STG;

#pragma unroll
        for (int ks = 0; ks < 4; ks++) {
            int ksg = chunk * 4 + ks;
            uint32_t ah[4], al[4], bh[4][4];
            {
                int s = 2 * ksg + a_jl;
                uint32_t off = (uint32_t)a_row * 512 + ((uint32_t)(s ^ (a_row & 15)) << 4);
                ldsm4(ah, sbase + MLP_A_HI + off);
                ldsm4(al, sbase + MLP_A_LO + off);
            }
            int krow = ks * 16 + b_kl;
            uint32_t koff = (uint32_t)krow * 256;
            uint32_t kx = (uint32_t)(krow & 7);
#pragma unroll
            for (int q = 0; q < 4; q++) {
                int ns = wn * 8 + 2 * q + b_nl;
                uint32_t off = koff + ((uint32_t)(ns ^ kx) << 4);
                ldsm4t(bh[q], bstg + off);
            }
#pragma unroll
            for (int p = 0; p < 2; p++) {
#pragma unroll
                for (int in = 0; in < 8; in++) {
                    const uint32_t* af = (p == 1) ? al : ah;
                    mma16816(acc[in], af, &bh[in >> 1][(in & 1) * 2]);
                }
            }
        }
        __syncthreads();
    }

    const int o0 = wm * 16 + (lane >> 2);
    const int o1 = o0 + 8;
    const float bm0 = bmlp[o0], bm1 = bmlp[o1];
    const float we0 = wend[o0], we1 = wend[o1];

#pragma unroll
    for (int in = 0; in < 8; in++) {
        float g00 = gelu_exact(acc[in][0] + bm0);
        float g01 = gelu_exact(acc[in][1] + bm0);
        float g10 = gelu_exact(acc[in][2] + bm1);
        float g11 = gelu_exact(acc[in][3] + bm1);
        float p0 = we0 * g00 + we1 * g10;
        float p1 = we0 * g01 + we1 * g11;
#pragma unroll
        for (int d = 4; d <= 16; d <<= 1) {
            p0 += __shfl_xor_sync(0xFFFFFFFF, p0, d);
            p1 += __shfl_xor_sync(0xFFFFFFFF, p1, d);
        }
        if (lane < 4) {
            red[wm][wn * 64 + in * 8 + lane * 2 + 0] = p0;
            red[wm][wn * 64 + in * 8 + lane * 2 + 1] = p1;
        }
    }
    __syncthreads();
    if (tid < 128) {
        int n = n0 + tid;
        float s = bend[0] + red[0][tid] + red[1][tid] + red[2][tid] + red[3][tid];
        g_Sh[(size_t)b * NP + n] = __float2half_rn((n < N_NODE) ? s : 0.f);
    }
#undef LOAD_BCH
}

// ---------------- kernel 5: final linear on HMMA ----------------
__global__ __launch_bounds__(256) void k_lin_mma(const float* __restrict__ blin) {
    extern __shared__ char smem[];
    const uint32_t sbase = smem_u32(smem);
    const int tid = threadIdx.x;
    const int wid = tid >> 5, lane = tid & 31;
    const int wm = wid >> 1;
    const int wn = wid & 1;
    const int n0 = blockIdx.x * LIN_TN;

#define LIN_LOAD(cidx, stg) do {                                                     \
    _Pragma("unroll")                                                                \
    for (int i = 0; i < 2; i++) {                                                    \
        int idx = tid + i * 256;                                                     \
        int row = idx >> 3, s = idx & 7;                                             \
        uint32_t so = ((uint32_t)(s ^ (row & 7)) << 4);                              \
        cpa16(sbase + (stg) * LIN_STG + row * 128 + so,                              \
              (const char*)(g_Sh + (size_t)row * NP) + (size_t)(cidx) * 128 + s * 16); \
    }                                                                                \
    {                                                                                \
        int row = tid >> 3, s = tid & 7;                                             \
        uint32_t so = ((uint32_t)(s ^ (row & 7)) << 4);                              \
        cpa16(sbase + (stg) * LIN_STG + LIN_A_BYTES + row * 128 + so,                \
              (const char*)(g_Wl + (size_t)(n0 + row) * NP) + (size_t)(cidx) * 128 + s * 16); \
    }                                                                                \
} while (0)

    float acc[2][4];
#pragma unroll
    for (int in = 0; in < 2; in++)
#pragma unroll
        for (int q = 0; q < 4; q++) acc[in][q] = 0.f;

    const int a_row_l = (lane & 15);
    const int a_jl = lane >> 4;
    const int b_row_l = ((lane >> 4) << 3) + (lane & 7);
    const int b_jl = (lane >> 3) & 1;

    LIN_LOAD(0, 0); CPA_COMMIT();

    for (int c = 0; c < 32; c++) {
        CPA_WAIT(0);
        __syncthreads();
        if (c + 1 < 32) { LIN_LOAD(c + 1, (c + 1) & 1); CPA_COMMIT(); }
        uint32_t astg = sbase + (c & 1) * LIN_STG;
        uint32_t bstg = astg + LIN_A_BYTES;
#pragma unroll
        for (int ks = 0; ks < 4; ks++) {
            uint32_t ah[4], bh[4];
            {
                int row = wm * 16 + a_row_l;
                uint32_t off = (uint32_t)row * 128 +
                               ((uint32_t)((2 * ks + a_jl) ^ (row & 7)) << 4);
                ldsm4(ah, astg + off);
            }
            {
                int row = wn * 16 + b_row_l;
                uint32_t off = (uint32_t)row * 128 +
                               ((uint32_t)((2 * ks + b_jl) ^ (row & 7)) << 4);
                ldsm4(bh, bstg + off);
            }
#pragma unroll
            for (int in = 0; in < 2; in++)
                mma16816(acc[in], ah, &bh[in * 2]);
        }
        __syncthreads();
    }

#pragma unroll
    for (int in = 0; in < 2; in++) {
        int d = n0 + wn * 16 + in * 8 + (lane & 3) * 2;
        int b0 = wm * 16 + (lane >> 2), b1 = b0 + 8;
        float bl0 = blin[d], bl1 = blin[d + 1];
        g_Y[(size_t)b0 * DM + d]     = acc[in][0] + bl0;
        g_Y[(size_t)b0 * DM + d + 1] = acc[in][1] + bl1;
        g_Y[(size_t)b1 * DM + d]     = acc[in][2] + bl0;
        g_Y[(size_t)b1 * DM + d + 1] = acc[in][3] + bl1;
    }
#undef LIN_LOAD
}

// ---------------- kernel 6: layernorm ----------------
__global__ void k_ln(const float* __restrict__ gam, const float* __restrict__ bet,
                     float* __restrict__ out) {
    int b = blockIdx.x;
    int tid = threadIdx.x;
    __shared__ float red[256];
    const float* y = g_Y + (size_t)b * DM;

    float s = 0.f;
    for (int d = tid; d < DM; d += 256) s += y[d];
    red[tid] = s; __syncthreads();
    for (int st = 128; st > 0; st >>= 1) { if (tid < st) red[tid] += red[tid + st]; __syncthreads(); }
    float mu = red[0] / DM;
    __syncthreads();

    float v = 0.f;
    for (int d = tid; d < DM; d += 256) { float t = y[d] - mu; v += t * t; }
    red[tid] = v; __syncthreads();
    for (int st = 128; st > 0; st >>= 1) { if (tid < st) red[tid] += red[tid + st]; __syncthreads(); }
    float rinv = rsqrtf(red[0] / DM + 1e-5f);

    for (int d = tid; d < DM; d += 256)
        out[(size_t)b * DM + d] = (y[d] - mu) * rinv * gam[d] + bet[d];
}

// ---------------- launch (forked-capture: conv/prepl overlap adj/mix) ----------------
extern "C" void kernel_launch(void* const* d_in, const int* in_sizes, int n_in,
                              void* d_out, int out_size) {
    const float* x       = (const float*)d_in[0];
    const float* nv1     = (const float*)d_in[1];
    const float* nv2     = (const float*)d_in[2];
    const float* w_start = (const float*)d_in[3];
    const float* b_start = (const float*)d_in[4];
    const float* w_mlp   = (const float*)d_in[5];
    const float* b_mlp   = (const float*)d_in[6];
    const float* w_end   = (const float*)d_in[7];
    const float* b_end   = (const float*)d_in[8];
    const float* w_lin   = (const float*)d_in[9];
    const float* b_lin   = (const float*)d_in[10];
    const float* ln_g    = (const float*)d_in[11];
    const float* ln_b    = (const float*)d_in[12];
    float* out = (float*)d_out;

    static bool init = false;
    static cudaStream_t s2;
    static cudaEvent_t e_prep, e_conv, e_lin;
    if (!init) {
        cudaStreamCreateWithFlags(&s2, cudaStreamNonBlocking);
        cudaEventCreateWithFlags(&e_prep, cudaEventDisableTiming);
        cudaEventCreateWithFlags(&e_conv, cudaEventDisableTiming);
        cudaEventCreateWithFlags(&e_lin,  cudaEventDisableTiming);
        cudaFuncSetAttribute(k_mix_mma,  cudaFuncAttributeMaxDynamicSharedMemorySize, MIX_SMEM);
        cudaFuncSetAttribute(k_mlp_mma,  cudaFuncAttributeMaxDynamicSharedMemorySize, MLP_SMEM);
        cudaFuncSetAttribute(k_conv_mma, cudaFuncAttributeMaxDynamicSharedMemorySize, CV_SMEM);
        cudaFuncSetAttribute(k_adj,      cudaFuncAttributeMaxDynamicSharedMemorySize, ADJ_SMEM);
        cudaFuncSetAttribute(k_lin_mma,  cudaFuncAttributeMaxDynamicSharedMemorySize, LIN_SMEM);
        init = true;
    }

    // stream 0: prep1 -> adj     stream s2: (after prep1) conv -> prepl
    k_prep1<<<PREP1_BLOCKS, 256>>>(w_start, x, w_mlp);
    cudaEventRecord(e_prep, 0);
    k_adj<<<ADJ_BLOCKS, 256, ADJ_SMEM>>>(nv1, nv2);

    cudaStreamWaitEvent(s2, e_prep, 0);
    k_conv_mma<<<dim3(NP / 128, BATCH), 256, CV_SMEM, s2>>>(b_start);
    cudaEventRecord(e_conv, s2);
    k_prepl<<<DM, 256, 0, s2>>>(w_lin);
    cudaEventRecord(e_lin, s2);

    cudaStreamWaitEvent(0, e_conv, 0);      // mix needs adj (stream 0) + conv
    dim3 mixg(NP / TILE_N, MROWS / TILE_M);
    k_mix_mma<<<mixg, 512, MIX_SMEM>>>(0, 1);
    k_mix_mma<<<mixg, 512, MIX_SMEM>>>(1, 2);
    k_mix_mma<<<mixg, 512, MIX_SMEM>>>(2, 3);
    k_mlp_mma<<<dim3(NP / 128, BATCH), 256, MLP_SMEM>>>(b_mlp, w_end, b_end);
    cudaStreamWaitEvent(0, e_lin, 0);       // lin needs prepl (joins s2)
    k_lin_mma<<<NP / LIN_TN, 256, LIN_SMEM>>>(b_lin);
    k_ln<<<BATCH, 256>>>(ln_g, ln_b, out);
}